// round 3
// baseline (speedup 1.0000x reference)
#include <cuda_runtime.h>

// ---------------------------------------------------------------------------
// Problem constants
// ---------------------------------------------------------------------------
constexpr int B_  = 4;
constexpr int S_  = 4096;
constexpr int D_  = 256;
constexpr int H_  = 4;
constexpr int DH_ = 64;
constexpr int NL_ = 4;
constexpr int PM_ = 266;          // nb_features
constexpr int FF_ = 1024;
constexpr int BS_ = B_ * S_;      // 16384 rows
constexpr int BH_ = B_ * H_;      // 16

constexpr float DN_    = 0.35355339059327373f;  // 64^-0.25
constexpr float HDN2_  = 0.0625f;               // 0.5 * dn^2
constexpr float RATIO_ = 0.06131392f;           // 266^-0.5
constexpr float KEPS_  = 1e-4f;
constexpr float LNEPS_ = 1e-12f;

// ---------------------------------------------------------------------------
// Scratch (static device globals: no allocations allowed)
// ---------------------------------------------------------------------------
__device__ float g_x  [BS_ * D_];
__device__ float g_h  [BS_ * D_];
__device__ float g_q  [BS_ * D_];
__device__ float g_k  [BS_ * D_];
__device__ float g_v  [BS_ * D_];
__device__ float g_o  [BS_ * D_];
__device__ float g_qp [(size_t)BH_ * S_ * PM_];
__device__ float g_kp [(size_t)BH_ * S_ * PM_];
__device__ float g_diagq[BH_ * S_];
__device__ float g_diagk[BH_ * S_];
__device__ float g_dinv [BH_ * S_];
__device__ float g_ksum [BH_ * PM_];
__device__ float g_ctx  [BH_ * PM_ * DH_];
__device__ float g_ffn [(size_t)BS_ * FF_];
__device__ float g_score[BS_];
__device__ float g_ssum [B_];
__device__ unsigned g_kmaxu;

// ---------------------------------------------------------------------------
// Reduction helpers
// ---------------------------------------------------------------------------
__device__ __forceinline__ float warpsum(float v) {
#pragma unroll
    for (int o = 16; o > 0; o >>= 1) v += __shfl_xor_sync(0xffffffffu, v, o);
    return v;
}
__device__ __forceinline__ float warpmax(float v) {
#pragma unroll
    for (int o = 16; o > 0; o >>= 1) v = fmaxf(v, __shfl_xor_sync(0xffffffffu, v, o));
    return v;
}
// blockDim.x must be a multiple of 32, <= 256. sh must hold >= 8 floats.
__device__ __forceinline__ float block_sum(float v, float* sh) {
    int lane = threadIdx.x & 31, w = threadIdx.x >> 5, nw = blockDim.x >> 5;
    v = warpsum(v);
    if (lane == 0) sh[w] = v;
    __syncthreads();
    if (w == 0) {
        float x = (lane < nw) ? sh[lane] : 0.f;
        x = warpsum(x);
        if (lane == 0) sh[0] = x;
    }
    __syncthreads();
    float r = sh[0];
    __syncthreads();   // safe reuse of sh by caller
    return r;
}

// Ordered-uint mapping for float atomicMax (monotone for all finite floats)
__device__ __forceinline__ unsigned fmap(float f) {
    unsigned u = __float_as_uint(f);
    return (u & 0x80000000u) ? ~u : (u | 0x80000000u);
}
__device__ __forceinline__ float funmap(unsigned u) {
    u = (u & 0x80000000u) ? (u & 0x7FFFFFFFu) : ~u;
    return __uint_as_float(u);
}

// ---------------------------------------------------------------------------
// LayerNorm kernels (one 256-thread block per row of 256)
// ---------------------------------------------------------------------------
__global__ void embed_ln_kernel(const float* __restrict__ emb, const float* __restrict__ pos,
                                const float* __restrict__ g, const float* __restrict__ bb,
                                float* __restrict__ out) {
    __shared__ float sh[8];
    int row = blockIdx.x, t = threadIdx.x;
    float v = emb[(size_t)row * D_ + t] + pos[(size_t)(row & (S_ - 1)) * D_ + t];
    float mu = block_sum(v, sh) * (1.0f / D_);
    float d  = v - mu;
    float var = block_sum(d * d, sh) * (1.0f / D_);
    float rs = rsqrtf(var + LNEPS_);
    out[(size_t)row * D_ + t] = d * rs * g[t] + bb[t];
}

__global__ void ln_kernel(const float* __restrict__ in, float* __restrict__ out,
                          const float* __restrict__ g, const float* __restrict__ bb) {
    __shared__ float sh[8];
    int row = blockIdx.x, t = threadIdx.x;
    float v = in[(size_t)row * D_ + t];
    float mu = block_sum(v, sh) * (1.0f / D_);
    float d  = v - mu;
    float var = block_sum(d * d, sh) * (1.0f / D_);
    float rs = rsqrtf(var + LNEPS_);
    out[(size_t)row * D_ + t] = d * rs * g[t] + bb[t];
}

// ---------------------------------------------------------------------------
// Dense SGEMM: C[M,N] = A[M,K] @ W[K,N] + bias  (+epilogue)
// 128x128 block tile, BK=8, 256 threads, 8x8 per thread.
// Requires M%128==0, N%128==0, K%8==0 (all shapes here satisfy this).
// MODE: 0 = bias; 1 = bias+gelu(tanh); 2 = bias + C += (residual); 3 = bias+tanh
// ---------------------------------------------------------------------------
template <int MODE>
__global__ __launch_bounds__(256) void gemm_kernel(
    const float* __restrict__ A, const float* __restrict__ W,
    const float* __restrict__ bias, float* __restrict__ C, int K, int N) {
    __shared__ float As[8][128];
    __shared__ float Bs[8][128];
    int t  = threadIdx.x;
    int tx = t & 15, ty = t >> 4;
    int row0 = blockIdx.y * 128;
    int col0 = blockIdx.x * 128;
    float acc[8][8] = {};

    int arow = t >> 1;            // 0..127
    int acol = (t & 1) * 4;       // 0 or 4
    int brow = t >> 5;            // 0..7
    int bcol = (t & 31) * 4;      // 0..124
    const float* Ap = A + (size_t)(row0 + arow) * K + acol;
    const float* Wp = W + (size_t)brow * N + col0 + bcol;

    for (int k0 = 0; k0 < K; k0 += 8) {
        float4 av = *(const float4*)(Ap + k0);
        As[acol + 0][arow] = av.x; As[acol + 1][arow] = av.y;
        As[acol + 2][arow] = av.z; As[acol + 3][arow] = av.w;
        *(float4*)&Bs[brow][bcol] = *(const float4*)(Wp + (size_t)k0 * N);
        __syncthreads();
#pragma unroll
        for (int k = 0; k < 8; k++) {
            float4 a0 = *(const float4*)&As[k][ty * 8];
            float4 a1 = *(const float4*)&As[k][ty * 8 + 4];
            float4 b0 = *(const float4*)&Bs[k][tx * 8];
            float4 b1 = *(const float4*)&Bs[k][tx * 8 + 4];
            float a[8] = {a0.x, a0.y, a0.z, a0.w, a1.x, a1.y, a1.z, a1.w};
            float bv[8] = {b0.x, b0.y, b0.z, b0.w, b1.x, b1.y, b1.z, b1.w};
#pragma unroll
            for (int i = 0; i < 8; i++)
#pragma unroll
                for (int j = 0; j < 8; j++)
                    acc[i][j] = fmaf(a[i], bv[j], acc[i][j]);
        }
        __syncthreads();
    }

#pragma unroll
    for (int i = 0; i < 8; i++) {
        int row = row0 + ty * 8 + i;
#pragma unroll
        for (int j = 0; j < 8; j++) {
            int col = col0 + tx * 8 + j;
            float v = acc[i][j] + bias[col];
            if (MODE == 1) {  // tanh-approx GELU (JAX default)
                float u = 0.7978845608028654f * (v + 0.044715f * v * v * v);
                v = 0.5f * v * (1.f + tanhf(u));
            }
            if (MODE == 3) v = tanhf(v);
            size_t idx = (size_t)row * N + col;
            if (MODE == 2) C[idx] += v;
            else           C[idx] = v;
        }
    }
}

// ---------------------------------------------------------------------------
// FAVOR dash: dash[bh,s,m] = dn * sum_d X[b,s,h*64+d] * P[m,d]; also
// diag[bh,s] = 0.0625 * ||X_row||^2.  Block = 64 s-rows, loops m in 5 chunks.
// grid (S/64, BH)
// ---------------------------------------------------------------------------
__global__ __launch_bounds__(256) void dash_kernel(
    const float* __restrict__ X, const float* __restrict__ P,
    float* __restrict__ dash, float* __restrict__ diag) {
    __shared__ float Xs[DH_][65];   // [d][s]
    __shared__ float Ps[DH_][64];   // [d][m_local]
    int bh = blockIdx.y, b = bh >> 2, h = bh & 3;
    int s0 = blockIdx.x * 64;
    int t  = threadIdx.x;
    int tx = t & 15, ty = t >> 4;

#pragma unroll
    for (int it = 0; it < 4; it++) {
        int id = t + it * 256;
        int r = id >> 4, c4 = (id & 15) * 4;
        float4 v4 = *(const float4*)&X[((size_t)(b * S_ + s0 + r)) * D_ + h * DH_ + c4];
        Xs[c4 + 0][r] = v4.x; Xs[c4 + 1][r] = v4.y;
        Xs[c4 + 2][r] = v4.z; Xs[c4 + 3][r] = v4.w;
    }
    __syncthreads();
    if (t < 64) {
        float s = 0.f;
#pragma unroll
        for (int d = 0; d < DH_; d++) { float x = Xs[d][t]; s = fmaf(x, x, s); }
        diag[(size_t)bh * S_ + s0 + t] = HDN2_ * s;
    }

    for (int m0 = 0; m0 < PM_; m0 += 64) {
        __syncthreads();
#pragma unroll
        for (int it = 0; it < 4; it++) {
            int id = t + it * 256;
            int r = id >> 4, c4 = (id & 15) * 4;
            int m = m0 + r;
            float4 v4 = (m < PM_) ? *(const float4*)&P[(size_t)m * DH_ + c4]
                                  : make_float4(0.f, 0.f, 0.f, 0.f);
            Ps[c4 + 0][r] = v4.x; Ps[c4 + 1][r] = v4.y;
            Ps[c4 + 2][r] = v4.z; Ps[c4 + 3][r] = v4.w;
        }
        __syncthreads();
        float acc[4][4] = {};
#pragma unroll
        for (int d = 0; d < DH_; d++) {
            float a[4], bv[4];
#pragma unroll
            for (int i = 0; i < 4; i++) a[i] = Xs[d][ty * 4 + i];
#pragma unroll
            for (int j = 0; j < 4; j++) bv[j] = Ps[d][tx * 4 + j];
#pragma unroll
            for (int i = 0; i < 4; i++)
#pragma unroll
                for (int j = 0; j < 4; j++)
                    acc[i][j] = fmaf(a[i], bv[j], acc[i][j]);
        }
#pragma unroll
        for (int i = 0; i < 4; i++) {
            int srow = s0 + ty * 4 + i;
#pragma unroll
            for (int j = 0; j < 4; j++) {
                int m = m0 + tx * 4 + j;
                if (m < PM_) dash[((size_t)bh * S_ + srow) * PM_ + m] = DN_ * acc[i][j];
            }
        }
    }
}

// ---------------------------------------------------------------------------
// Zero ctx + reset global k-max (per layer)
// ---------------------------------------------------------------------------
__global__ void layer_init_kernel(float* __restrict__ ctx, unsigned* __restrict__ km) {
    int i = blockIdx.x * blockDim.x + threadIdx.x;
    if (i < BH_ * PM_ * DH_) ctx[i] = 0.f;
    if (i == 0) *km = 0u;
}

// Global max over raw k-dash (reference uses a tensor-wide stabilizer for keys)
__global__ void kmax_kernel(const float* __restrict__ kp, unsigned* __restrict__ out) {
    __shared__ float sh[8];
    const size_t n = (size_t)BH_ * S_ * PM_;
    float m = -3.4e38f;
    for (size_t i = (size_t)blockIdx.x * blockDim.x + threadIdx.x; i < n;
         i += (size_t)gridDim.x * blockDim.x)
        m = fmaxf(m, kp[i]);
    m = warpmax(m);
    int lane = threadIdx.x & 31, w = threadIdx.x >> 5;
    if (lane == 0) sh[w] = m;
    __syncthreads();
    if (threadIdx.x == 0) {
        float v = sh[0];
#pragma unroll
        for (int i = 1; i < 8; i++) v = fmaxf(v, sh[i]);
        atomicMax(out, fmap(v));
    }
}

// phi = ratio * (exp(dash - diag - stab) + eps), stab = rowmax (q) or global (k)
__global__ void phi_exp_kernel(float* __restrict__ p, const float* __restrict__ diag,
                               const unsigned* __restrict__ gmaxu, int use_global) {
    __shared__ float sh[4];
    int row = blockIdx.x, t = threadIdx.x;   // 128 threads
    float* r = p + (size_t)row * PM_;
    float stab;
    if (use_global) {
        stab = funmap(*gmaxu);
    } else {
        float m = -3.4e38f;
        for (int i = t; i < PM_; i += 128) m = fmaxf(m, r[i]);
        m = warpmax(m);
        int lane = t & 31, w = t >> 5;
        if (lane == 0) sh[w] = m;
        __syncthreads();
        if (t == 0) sh[0] = fmaxf(fmaxf(sh[0], sh[1]), fmaxf(sh[2], sh[3]));
        __syncthreads();
        stab = sh[0];
    }
    float sub = diag[row] + stab;
    for (int i = t; i < PM_; i += 128) r[i] = RATIO_ * (expf(r[i] - sub) + KEPS_);
}

// ksum[bh,m] = sum_s kp[bh,s,m]; grid (BH, 3) x 128
__global__ void ksum_kernel(const float* __restrict__ kp, float* __restrict__ ksum) {
    int bh = blockIdx.x;
    int m = blockIdx.y * 128 + threadIdx.x;
    if (m >= PM_) return;
    const float* base = kp + (size_t)bh * S_ * PM_ + m;
    float s = 0.f;
    for (int i = 0; i < S_; i++) s += base[(size_t)i * PM_];
    ksum[bh * PM_ + m] = s;
}

// ctx[bh,m,e] = sum_s kp[bh,s,m] * v[b,s,h*64+e]; split-K over 8 s-chunks (atomic)
// grid (5 m-tiles, 8 chunks, BH), 256 threads, 4x4/thread
__global__ __launch_bounds__(256) void ctx_kernel(
    const float* __restrict__ kp, const float* __restrict__ v, float* __restrict__ ctx) {
    __shared__ float Kp[16][65];
    __shared__ float Vs[16][64];
    int bh = blockIdx.z, b = bh >> 2, h = bh & 3;
    int m0 = blockIdx.x * 64;
    int sch = blockIdx.y * 512;
    int t = threadIdx.x, tx = t & 15, ty = t >> 4;
    float acc[4][4] = {};
    for (int k0 = 0; k0 < 512; k0 += 16) {
        int sbase = sch + k0;
#pragma unroll
        for (int it = 0; it < 4; it++) {
            int id = t + it * 256;
            int r = id >> 6, c = id & 63;
            int m = m0 + c;
            Kp[r][c] = (m < PM_) ? kp[((size_t)bh * S_ + sbase + r) * PM_ + m] : 0.f;
        }
        {
            int r = t >> 4, c4 = (t & 15) * 4;
            *(float4*)&Vs[r][c4] =
                *(const float4*)&v[((size_t)(b * S_ + sbase + r)) * D_ + h * DH_ + c4];
        }
        __syncthreads();
#pragma unroll
        for (int k = 0; k < 16; k++) {
            float a[4], bv[4];
#pragma unroll
            for (int i = 0; i < 4; i++) a[i] = Kp[k][ty * 4 + i];
#pragma unroll
            for (int j = 0; j < 4; j++) bv[j] = Vs[k][tx * 4 + j];
#pragma unroll
            for (int i = 0; i < 4; i++)
#pragma unroll
                for (int j = 0; j < 4; j++)
                    acc[i][j] = fmaf(a[i], bv[j], acc[i][j]);
        }
        __syncthreads();
    }
#pragma unroll
    for (int i = 0; i < 4; i++) {
        int m = m0 + ty * 4 + i;
        if (m < PM_) {
#pragma unroll
            for (int j = 0; j < 4; j++)
                atomicAdd(&ctx[((size_t)bh * PM_ + m) * DH_ + tx * 4 + j], acc[i][j]);
        }
    }
}

// dinv[bh,s] = 1 / (qp_row . ksum_row); grid BH*S x 128
__global__ void dinv_kernel(const float* __restrict__ qp, const float* __restrict__ ksum,
                            float* __restrict__ dinv) {
    __shared__ float sh[8];
    int row = blockIdx.x, t = threadIdx.x;
    int bh = row >> 12;                  // S_ = 4096
    const float* q = qp + (size_t)row * PM_;
    const float* ks = ksum + bh * PM_;
    float s = 0.f;
    for (int i = t; i < PM_; i += 128) s = fmaf(q[i], ks[i], s);
    s = block_sum(s, sh);
    if (t == 0) dinv[row] = 1.f / s;
}

// o[b,s,h*64+e] = dinv[bh,s] * sum_m qp[bh,s,m] * ctx[bh,m,e]
// grid (S/64, BH), 256 threads, 4x4/thread, K=266 in 17 chunks of 16
__global__ __launch_bounds__(256) void attnout_kernel(
    const float* __restrict__ qp, const float* __restrict__ ctx,
    const float* __restrict__ dinv, float* __restrict__ o) {
    __shared__ float Qs[16][65];   // [k][s]
    __shared__ float Cs[16][64];   // [k][e]
    int bh = blockIdx.y, b = bh >> 2, h = bh & 3;
    int s0 = blockIdx.x * 64;
    int t = threadIdx.x, tx = t & 15, ty = t >> 4;
    float acc[4][4] = {};
    for (int k0 = 0; k0 < PM_; k0 += 16) {
#pragma unroll
        for (int it = 0; it < 4; it++) {
            int id = t + it * 256;
            int r = id >> 4, c = id & 15;
            int m = k0 + c;
            Qs[c][r] = (m < PM_) ? qp[((size_t)bh * S_ + s0 + r) * PM_ + m] : 0.f;
        }
        {
            int r = t >> 4, c4 = (t & 15) * 4;
            int m = k0 + r;
            float4 v4 = (m < PM_) ? *(const float4*)&ctx[((size_t)bh * PM_ + m) * DH_ + c4]
                                  : make_float4(0.f, 0.f, 0.f, 0.f);
            *(float4*)&Cs[r][c4] = v4;
        }
        __syncthreads();
#pragma unroll
        for (int k = 0; k < 16; k++) {
            float a[4], bv[4];
#pragma unroll
            for (int i = 0; i < 4; i++) a[i] = Qs[k][ty * 4 + i];
#pragma unroll
            for (int j = 0; j < 4; j++) bv[j] = Cs[k][tx * 4 + j];
#pragma unroll
            for (int i = 0; i < 4; i++)
#pragma unroll
                for (int j = 0; j < 4; j++)
                    acc[i][j] = fmaf(a[i], bv[j], acc[i][j]);
        }
        __syncthreads();
    }
#pragma unroll
    for (int i = 0; i < 4; i++) {
        int s = s0 + ty * 4 + i;
        float di = dinv[(size_t)bh * S_ + s];
#pragma unroll
        for (int j = 0; j < 4; j++)
            o[((size_t)(b * S_ + s)) * D_ + h * DH_ + tx * 4 + j] = acc[i][j] * di;
    }
}

// ---------------------------------------------------------------------------
// Pooling
// ---------------------------------------------------------------------------
// score[b,s] = exp(e_row . p2_w + p2_b) * mask  (e = tanh(x@p1+b1) already in h)
__global__ void score_kernel(const float* __restrict__ h, const float* __restrict__ p2w,
                             const float* __restrict__ p2b, const float* __restrict__ mask,
                             float* __restrict__ score) {
    __shared__ float sh[8];
    int row = blockIdx.x, t = threadIdx.x;
    float v = h[(size_t)row * D_ + t] * p2w[t];
    float s = block_sum(v, sh);
    if (t == 0) score[row] = expf(s + p2b[0]) * mask[row];
}

__global__ void ssum_kernel(const float* __restrict__ score, float* __restrict__ ssum) {
    __shared__ float sh[8];
    int b = blockIdx.x;
    float s = 0.f;
    for (int i = threadIdx.x; i < S_; i += 256) s += score[b * S_ + i];
    s = block_sum(s, sh);
    if (threadIdx.x == 0) ssum[b] = s;
}

__global__ void outzero_kernel(float* __restrict__ out) {
    int i = blockIdx.x * blockDim.x + threadIdx.x;
    if (i < B_ * D_) out[i] = 0.f;
}

// out[b,d] = (sum_s x[b,s,d]*score[b,s]) / (ssum[b]+1e-8); grid (B,16) chunks
__global__ void pool_kernel(const float* __restrict__ x, const float* __restrict__ score,
                            const float* __restrict__ ssum, float* __restrict__ out) {
    int b = blockIdx.x, chunk = blockIdx.y, d = threadIdx.x;
    float inv = 1.f / (ssum[b] + 1e-8f);
    float acc = 0.f;
    int s0 = chunk * (S_ / 16);
    for (int s = s0; s < s0 + S_ / 16; s++)
        acc = fmaf(x[((size_t)(b * S_ + s)) * D_ + d], score[b * S_ + s], acc);
    atomicAdd(&out[b * D_ + d], acc * inv);
}

// ---------------------------------------------------------------------------
// Host launcher
// ---------------------------------------------------------------------------
static void launch_gemm(int mode, const float* A, const float* W, const float* bias,
                        float* C, int Mrows, int K, int N) {
    dim3 grid(N / 128, Mrows / 128);
    switch (mode) {
        case 0: gemm_kernel<0><<<grid, 256>>>(A, W, bias, C, K, N); break;
        case 1: gemm_kernel<1><<<grid, 256>>>(A, W, bias, C, K, N); break;
        case 2: gemm_kernel<2><<<grid, 256>>>(A, W, bias, C, K, N); break;
        case 3: gemm_kernel<3><<<grid, 256>>>(A, W, bias, C, K, N); break;
    }
}

extern "C" void kernel_launch(void* const* d_in, const int* in_sizes, int n_in,
                              void* d_out, int out_size) {
    const float* emb  = (const float*)d_in[0];
    const float* mask = (const float*)d_in[1];
    const float* pos  = (const float*)d_in[2];
    const float* ln_g = (const float*)d_in[3];
    const float* ln_b = (const float*)d_in[4];
    const float* proj = (const float*)d_in[5];
    const float* Wq = (const float*)d_in[6];   const float* bq = (const float*)d_in[7];
    const float* Wk = (const float*)d_in[8];   const float* bk = (const float*)d_in[9];
    const float* Wv = (const float*)d_in[10];  const float* bv = (const float*)d_in[11];
    const float* Wo = (const float*)d_in[12];  const float* bo = (const float*)d_in[13];
    const float* ln1g = (const float*)d_in[14]; const float* ln1b = (const float*)d_in[15];
    const float* W1 = (const float*)d_in[16];  const float* b1 = (const float*)d_in[17];
    const float* W2 = (const float*)d_in[18];  const float* b2 = (const float*)d_in[19];
    const float* ln2g = (const float*)d_in[20]; const float* ln2b = (const float*)d_in[21];
    const float* p1w = (const float*)d_in[22]; const float* p1b = (const float*)d_in[23];
    const float* p2w = (const float*)d_in[24]; const float* p2b = (const float*)d_in[25];
    float* out = (float*)d_out;

    void* tp;
    float *x, *h, *q, *k, *v, *o, *qp, *kp, *dq, *dk, *di, *ks, *cx, *fn, *sc, *ss;
    unsigned* km;
    cudaGetSymbolAddress(&tp, g_x);     x  = (float*)tp;
    cudaGetSymbolAddress(&tp, g_h);     h  = (float*)tp;
    cudaGetSymbolAddress(&tp, g_q);     q  = (float*)tp;
    cudaGetSymbolAddress(&tp, g_k);     k  = (float*)tp;
    cudaGetSymbolAddress(&tp, g_v);     v  = (float*)tp;
    cudaGetSymbolAddress(&tp, g_o);     o  = (float*)tp;
    cudaGetSymbolAddress(&tp, g_qp);    qp = (float*)tp;
    cudaGetSymbolAddress(&tp, g_kp);    kp = (float*)tp;
    cudaGetSymbolAddress(&tp, g_diagq); dq = (float*)tp;
    cudaGetSymbolAddress(&tp, g_diagk); dk = (float*)tp;
    cudaGetSymbolAddress(&tp, g_dinv);  di = (float*)tp;
    cudaGetSymbolAddress(&tp, g_ksum);  ks = (float*)tp;
    cudaGetSymbolAddress(&tp, g_ctx);   cx = (float*)tp;
    cudaGetSymbolAddress(&tp, g_ffn);   fn = (float*)tp;
    cudaGetSymbolAddress(&tp, g_score); sc = (float*)tp;
    cudaGetSymbolAddress(&tp, g_ssum);  ss = (float*)tp;
    cudaGetSymbolAddress(&tp, g_kmaxu); km = (unsigned*)tp;

    // x = LN(embeddings + positional)
    embed_ln_kernel<<<BS_, 256>>>(emb, pos, ln_g, ln_b, x);

    for (int l = 0; l < NL_; l++) {
        const float* pj = proj + (size_t)l * PM_ * DH_;

        // --- attention block ---
        ln_kernel<<<BS_, 256>>>(x, h, ln1g + l * D_, ln1b + l * D_);
        launch_gemm(0, h, Wq + (size_t)l * D_ * D_, bq + l * D_, q, BS_, D_, D_);
        launch_gemm(0, h, Wk + (size_t)l * D_ * D_, bk + l * D_, k, BS_, D_, D_);
        launch_gemm(0, h, Wv + (size_t)l * D_ * D_, bv + l * D_, v, BS_, D_, D_);

        dash_kernel<<<dim3(S_ / 64, BH_), 256>>>(q, pj, qp, dq);
        dash_kernel<<<dim3(S_ / 64, BH_), 256>>>(k, pj, kp, dk);

        layer_init_kernel<<<(BH_ * PM_ * DH_ + 255) / 256, 256>>>(cx, km);
        kmax_kernel<<<2048, 256>>>(kp, km);

        phi_exp_kernel<<<BH_ * S_, 128>>>(qp, dq, km, 0);   // per-row stabilizer
        phi_exp_kernel<<<BH_ * S_, 128>>>(kp, dk, km, 1);   // global stabilizer

        ksum_kernel<<<dim3(BH_, 3), 128>>>(kp, ks);
        ctx_kernel<<<dim3(5, 8, BH_), 256>>>(kp, v, cx);
        dinv_kernel<<<BH_ * S_, 128>>>(qp, ks, di);
        attnout_kernel<<<dim3(S_ / 64, BH_), 256>>>(qp, cx, di, o);

        launch_gemm(2, o, Wo + (size_t)l * D_ * D_, bo + l * D_, x, BS_, D_, D_);

        // --- FFN block ---
        ln_kernel<<<BS_, 256>>>(x, h, ln2g + l * D_, ln2b + l * D_);
        launch_gemm(1, h, W1 + (size_t)l * D_ * FF_, b1 + l * FF_, fn, BS_, D_, FF_);
        launch_gemm(2, fn, W2 + (size_t)l * FF_ * D_, b2 + l * D_, x, BS_, FF_, D_);
    }

    // --- attention pooling ---
    launch_gemm(3, x, p1w, p1b, h, BS_, D_, D_);           // e = tanh(x@p1+b1)
    score_kernel<<<BS_, 256>>>(h, p2w, p2b, mask, sc);
    ssum_kernel<<<B_, 256>>>(sc, ss);
    outzero_kernel<<<(B_ * D_ + 255) / 256, 256>>>(out);
    pool_kernel<<<dim3(B_, 16), 256>>>(x, sc, ss, out);
}

// round 4
// speedup vs baseline: 1.1171x; 1.1171x over previous
#include <cuda_runtime.h>

// ---------------------------------------------------------------------------
// Problem constants
// ---------------------------------------------------------------------------
constexpr int B_  = 4;
constexpr int S_  = 4096;
constexpr int D_  = 256;
constexpr int DH_ = 64;
constexpr int NL_ = 4;
constexpr int PM_ = 266;          // nb_features
constexpr int FF_ = 1024;
constexpr int BS_ = B_ * S_;      // 16384 rows
constexpr int BH_ = B_ * 4;       // 16

constexpr float DN_    = 0.35355339059327373f;  // 64^-0.25
constexpr float HDN2_  = 0.0625f;               // 0.5 * dn^2
constexpr float RATIO_ = 0.06131392f;           // 266^-0.5
constexpr float KEPS_  = 1e-4f;
constexpr float LNEPS_ = 1e-12f;

typedef unsigned long long ull;

// ---------------------------------------------------------------------------
// Scratch (static device globals: no allocations allowed)
// ---------------------------------------------------------------------------
__device__ float g_x  [BS_ * D_];
__device__ float g_h  [BS_ * D_];
__device__ float g_q  [BS_ * D_];
__device__ float g_k  [BS_ * D_];
__device__ float g_v  [BS_ * D_];
__device__ float g_o  [BS_ * D_];
__device__ float g_qp [(size_t)BH_ * S_ * PM_];
__device__ float g_kp [(size_t)BH_ * S_ * PM_];
__device__ float g_diagq[BH_ * S_];
__device__ float g_diagk[BH_ * S_];
__device__ float g_dinv [BH_ * S_];
__device__ float g_ksum [BH_ * PM_];
__device__ float g_ctx  [BH_ * PM_ * DH_];
__device__ float g_ffn [(size_t)BS_ * FF_];
__device__ float g_score[BS_];
__device__ float g_ssum [B_];
__device__ unsigned g_kmaxu;

// ---------------------------------------------------------------------------
// Packed f32x2 helpers (Blackwell FFMA2 — ptxas never auto-fuses these)
// ---------------------------------------------------------------------------
__device__ __forceinline__ void fma2(ull& d, ull a, ull b) {
    asm("fma.rn.f32x2 %0, %1, %2, %0;" : "+l"(d) : "l"(a), "l"(b));
}
__device__ __forceinline__ ull bcast2(float x) {
    ull r;
    asm("mov.b64 %0, {%1, %1};" : "=l"(r) : "r"(__float_as_uint(x)));
    return r;
}
__device__ __forceinline__ float2 unpack2(ull d) {
    unsigned lo, hi;
    asm("mov.b64 {%0, %1}, %2;" : "=r"(lo), "=r"(hi) : "l"(d));
    return make_float2(__uint_as_float(lo), __uint_as_float(hi));
}

// ---------------------------------------------------------------------------
// Reduction helpers
// ---------------------------------------------------------------------------
__device__ __forceinline__ float warpsum(float v) {
#pragma unroll
    for (int o = 16; o > 0; o >>= 1) v += __shfl_xor_sync(0xffffffffu, v, o);
    return v;
}
__device__ __forceinline__ float warpmax(float v) {
#pragma unroll
    for (int o = 16; o > 0; o >>= 1) v = fmaxf(v, __shfl_xor_sync(0xffffffffu, v, o));
    return v;
}
__device__ __forceinline__ float block_sum(float v, float* sh) {
    int lane = threadIdx.x & 31, w = threadIdx.x >> 5, nw = blockDim.x >> 5;
    v = warpsum(v);
    if (lane == 0) sh[w] = v;
    __syncthreads();
    if (w == 0) {
        float x = (lane < nw) ? sh[lane] : 0.f;
        x = warpsum(x);
        if (lane == 0) sh[0] = x;
    }
    __syncthreads();
    float r = sh[0];
    __syncthreads();
    return r;
}

// Ordered-uint mapping for float atomicMax
__device__ __forceinline__ unsigned fmap(float f) {
    unsigned u = __float_as_uint(f);
    return (u & 0x80000000u) ? ~u : (u | 0x80000000u);
}
__device__ __forceinline__ float funmap(unsigned u) {
    u = (u & 0x80000000u) ? (u & 0x7FFFFFFFu) : ~u;
    return __uint_as_float(u);
}

// ---------------------------------------------------------------------------
// LayerNorm kernels
// ---------------------------------------------------------------------------
__global__ void embed_ln_kernel(const float* __restrict__ emb, const float* __restrict__ pos,
                                const float* __restrict__ g, const float* __restrict__ bb,
                                float* __restrict__ out) {
    __shared__ float sh[8];
    int row = blockIdx.x, t = threadIdx.x;
    float v = emb[(size_t)row * D_ + t] + pos[(size_t)(row & (S_ - 1)) * D_ + t];
    float mu = block_sum(v, sh) * (1.0f / D_);
    float d  = v - mu;
    float var = block_sum(d * d, sh) * (1.0f / D_);
    float rs = rsqrtf(var + LNEPS_);
    out[(size_t)row * D_ + t] = d * rs * g[t] + bb[t];
}

__global__ void ln_kernel(const float* __restrict__ in, float* __restrict__ out,
                          const float* __restrict__ g, const float* __restrict__ bb) {
    __shared__ float sh[8];
    int row = blockIdx.x, t = threadIdx.x;
    float v = in[(size_t)row * D_ + t];
    float mu = block_sum(v, sh) * (1.0f / D_);
    float d  = v - mu;
    float var = block_sum(d * d, sh) * (1.0f / D_);
    float rs = rsqrtf(var + LNEPS_);
    out[(size_t)row * D_ + t] = d * rs * g[t] + bb[t];
}

// ---------------------------------------------------------------------------
// Dense SGEMM with FFMA2: C[M,N] = A[M,K] @ W[K,N] + bias (+epilogue)
// 128x128 tile, BK=16, 256 threads, 8x8 per thread (packed as 8x4 f32x2),
// double-buffered smem, one __syncthreads per k-tile, LDG hidden by compute.
// MODE: 0 = bias; 1 = bias+gelu(tanh); 2 = bias + accumulate; 3 = bias+tanh
// ---------------------------------------------------------------------------
template <int MODE>
__global__ __launch_bounds__(256, 2) void gemm_kernel(
    const float* __restrict__ A, const float* __restrict__ W,
    const float* __restrict__ bias, float* __restrict__ C, int K, int N) {
    __shared__ float As[2][16][132];   // [buf][k][m]  (m-stride 132: 16B-aligned rows)
    __shared__ float Bs[2][16][128];   // [buf][k][n]
    int t  = threadIdx.x;
    int tx = t & 15, ty = t >> 4;
    int row0 = blockIdx.y * 128;
    int col0 = blockIdx.x * 128;

    ull acc[8][4] = {};

    // global-load coordinates
    int m_a = t >> 2;            // 0..63
    int k_a = (t & 3) * 4;       // 0,4,8,12
    int k_b = t >> 5;            // 0..7
    int n_b = (t & 31) * 4;      // 0..124
    const float* Ap0 = A + (size_t)(row0 + m_a) * K + k_a;
    const float* Ap1 = A + (size_t)(row0 + m_a + 64) * K + k_a;
    const float* Wp0 = W + (size_t)k_b * N + col0 + n_b;
    const float* Wp1 = W + (size_t)(k_b + 8) * N + col0 + n_b;

    int NT = K >> 4;

    // prologue: tile 0
    float4 ar0 = *(const float4*)(Ap0);
    float4 ar1 = *(const float4*)(Ap1);
    float4 br0 = *(const float4*)(Wp0);
    float4 br1 = *(const float4*)(Wp1);
    {
        float av0[4] = {ar0.x, ar0.y, ar0.z, ar0.w};
        float av1[4] = {ar1.x, ar1.y, ar1.z, ar1.w};
#pragma unroll
        for (int j = 0; j < 4; j++) {
            As[0][k_a + j][m_a]      = av0[j];
            As[0][k_a + j][m_a + 64] = av1[j];
        }
        *(float4*)&Bs[0][k_b][n_b]     = br0;
        *(float4*)&Bs[0][k_b + 8][n_b] = br1;
    }
    __syncthreads();

    for (int kt = 0; kt < NT; kt++) {
        int buf = kt & 1;
        bool more = (kt + 1) < NT;
        if (more) {
            int ko = (kt + 1) << 4;
            ar0 = *(const float4*)(Ap0 + ko);
            ar1 = *(const float4*)(Ap1 + ko);
            br0 = *(const float4*)(Wp0 + (size_t)ko * N);
            br1 = *(const float4*)(Wp1 + (size_t)ko * N);
        }
#pragma unroll
        for (int k = 0; k < 16; k++) {
            float4 a0 = *(const float4*)&As[buf][k][ty * 8];
            float4 a1 = *(const float4*)&As[buf][k][ty * 8 + 4];
            ull ap[8];
            ap[0] = bcast2(a0.x); ap[1] = bcast2(a0.y);
            ap[2] = bcast2(a0.z); ap[3] = bcast2(a0.w);
            ap[4] = bcast2(a1.x); ap[5] = bcast2(a1.y);
            ap[6] = bcast2(a1.z); ap[7] = bcast2(a1.w);
            ull bp0 = *(const ull*)&Bs[buf][k][tx * 8];
            ull bp1 = *(const ull*)&Bs[buf][k][tx * 8 + 2];
            ull bp2 = *(const ull*)&Bs[buf][k][tx * 8 + 4];
            ull bp3 = *(const ull*)&Bs[buf][k][tx * 8 + 6];
#pragma unroll
            for (int i = 0; i < 8; i++) {
                fma2(acc[i][0], ap[i], bp0);
                fma2(acc[i][1], ap[i], bp1);
                fma2(acc[i][2], ap[i], bp2);
                fma2(acc[i][3], ap[i], bp3);
            }
        }
        if (more) {
            int nb = (kt + 1) & 1;
            float av0[4] = {ar0.x, ar0.y, ar0.z, ar0.w};
            float av1[4] = {ar1.x, ar1.y, ar1.z, ar1.w};
#pragma unroll
            for (int j = 0; j < 4; j++) {
                As[nb][k_a + j][m_a]      = av0[j];
                As[nb][k_a + j][m_a + 64] = av1[j];
            }
            *(float4*)&Bs[nb][k_b][n_b]     = br0;
            *(float4*)&Bs[nb][k_b + 8][n_b] = br1;
            __syncthreads();
        }
    }

#pragma unroll
    for (int i = 0; i < 8; i++) {
        int row = row0 + ty * 8 + i;
#pragma unroll
        for (int j2 = 0; j2 < 4; j2++) {
            float2 f = unpack2(acc[i][j2]);
            int col = col0 + tx * 8 + 2 * j2;
            float vv[2] = {f.x + bias[col], f.y + bias[col + 1]};
#pragma unroll
            for (int e = 0; e < 2; e++) {
                float v = vv[e];
                if (MODE == 1) {  // tanh-approx GELU (JAX default)
                    float u = 0.7978845608028654f * (v + 0.044715f * v * v * v);
                    v = 0.5f * v * (1.f + tanhf(u));
                }
                if (MODE == 3) v = tanhf(v);
                size_t idx = (size_t)row * N + col + e;
                if (MODE == 2) C[idx] += v;
                else           C[idx] = v;
            }
        }
    }
}

// ---------------------------------------------------------------------------
// FAVOR dash (FFMA2): dash[bh,s,m] = dn * X[b,s,h]·P[m], diag = 0.0625*||x||^2
// If gmax != nullptr, also atomicMax the block max of raw dash (key stabilizer).
// grid (S/64, BH), 256 threads.
// ---------------------------------------------------------------------------
__global__ __launch_bounds__(256) void dash_kernel(
    const float* __restrict__ X, const float* __restrict__ P,
    float* __restrict__ dash, float* __restrict__ diag, unsigned* gmax) {
    __shared__ float Xs[DH_][65];   // [d][s]
    __shared__ float Ps[DH_][64];   // [d][m_local]
    __shared__ float shm[8];
    int bh = blockIdx.y, b = bh >> 2, h = bh & 3;
    int s0 = blockIdx.x * 64;
    int t  = threadIdx.x;
    int tx = t & 15, ty = t >> 4;

#pragma unroll
    for (int it = 0; it < 4; it++) {
        int id = t + it * 256;
        int r = id >> 4, c4 = (id & 15) * 4;
        float4 v4 = *(const float4*)&X[((size_t)(b * S_ + s0 + r)) * D_ + h * DH_ + c4];
        Xs[c4 + 0][r] = v4.x; Xs[c4 + 1][r] = v4.y;
        Xs[c4 + 2][r] = v4.z; Xs[c4 + 3][r] = v4.w;
    }
    __syncthreads();
    if (t < 64) {
        float s = 0.f;
#pragma unroll
        for (int d = 0; d < DH_; d++) { float x = Xs[d][t]; s = fmaf(x, x, s); }
        diag[(size_t)bh * S_ + s0 + t] = HDN2_ * s;
    }

    float lmax = -3.4e38f;
    for (int m0 = 0; m0 < PM_; m0 += 64) {
        __syncthreads();
#pragma unroll
        for (int it = 0; it < 4; it++) {
            int id = t + it * 256;
            int r = id >> 4, c4 = (id & 15) * 4;
            int m = m0 + r;
            float4 v4 = (m < PM_) ? *(const float4*)&P[(size_t)m * DH_ + c4]
                                  : make_float4(0.f, 0.f, 0.f, 0.f);
            Ps[c4 + 0][r] = v4.x; Ps[c4 + 1][r] = v4.y;
            Ps[c4 + 2][r] = v4.z; Ps[c4 + 3][r] = v4.w;
        }
        __syncthreads();
        ull acc[4][2] = {};
#pragma unroll
        for (int d = 0; d < DH_; d++) {
            ull ap[4];
#pragma unroll
            for (int i = 0; i < 4; i++) ap[i] = bcast2(Xs[d][ty * 4 + i]);
            ull bp0 = *(const ull*)&Ps[d][tx * 4];
            ull bp1 = *(const ull*)&Ps[d][tx * 4 + 2];
#pragma unroll
            for (int i = 0; i < 4; i++) {
                fma2(acc[i][0], ap[i], bp0);
                fma2(acc[i][1], ap[i], bp1);
            }
        }
#pragma unroll
        for (int i = 0; i < 4; i++) {
            int srow = s0 + ty * 4 + i;
#pragma unroll
            for (int j2 = 0; j2 < 2; j2++) {
                int m = m0 + tx * 4 + 2 * j2;
                if (m < PM_) {       // m always even; m<PM_ => m+1<PM_ (PM_ even)
                    float2 f = unpack2(acc[i][j2]);
                    float v0 = DN_ * f.x, v1 = DN_ * f.y;
                    size_t base = ((size_t)bh * S_ + srow) * PM_ + m;
                    dash[base] = v0; dash[base + 1] = v1;
                    lmax = fmaxf(lmax, fmaxf(v0, v1));
                }
            }
        }
    }
    if (gmax) {
        lmax = warpmax(lmax);
        int lane = t & 31, w = t >> 5;
        if (lane == 0) shm[w] = lmax;
        __syncthreads();
        if (t == 0) {
            float v = shm[0];
#pragma unroll
            for (int i = 1; i < 8; i++) v = fmaxf(v, shm[i]);
            atomicMax(gmax, fmap(v));
        }
    }
}

// ---------------------------------------------------------------------------
// Zero ctx + ksum + reset global k-max (per layer)
// ---------------------------------------------------------------------------
__global__ void layer_init_kernel(float* __restrict__ ctx, float* __restrict__ ksum,
                                  unsigned* __restrict__ km) {
    int i = blockIdx.x * blockDim.x + threadIdx.x;
    if (i < BH_ * PM_ * DH_) ctx[i] = 0.f;
    if (i < BH_ * PM_) ksum[i] = 0.f;
    if (i == 0) *km = 0u;
}

// phi = ratio * (exp(dash - diag - stab) + eps), stab = rowmax (q) or global (k)
__global__ void phi_exp_kernel(float* __restrict__ p, const float* __restrict__ diag,
                               const unsigned* __restrict__ gmaxu, int use_global) {
    __shared__ float sh[4];
    int row = blockIdx.x, t = threadIdx.x;   // 128 threads
    float* r = p + (size_t)row * PM_;
    float stab;
    if (use_global) {
        stab = funmap(*gmaxu);
    } else {
        float m = -3.4e38f;
        for (int i = t; i < PM_; i += 128) m = fmaxf(m, r[i]);
        m = warpmax(m);
        int lane = t & 31, w = t >> 5;
        if (lane == 0) sh[w] = m;
        __syncthreads();
        if (t == 0) sh[0] = fmaxf(fmaxf(sh[0], sh[1]), fmaxf(sh[2], sh[3]));
        __syncthreads();
        stab = sh[0];
    }
    float sub = diag[row] + stab;
    for (int i = t; i < PM_; i += 128) r[i] = RATIO_ * (__expf(r[i] - sub) + KEPS_);
}

// ksum[bh,m] += partial sums over s-chunks; grid (BH, 3, 8) x 128
__global__ void ksum_kernel(const float* __restrict__ kp, float* __restrict__ ksum) {
    int bh = blockIdx.x;
    int m = blockIdx.y * 128 + threadIdx.x;
    if (m >= PM_) return;
    int s0 = blockIdx.z * (S_ / 8);
    const float* base = kp + ((size_t)bh * S_ + s0) * PM_ + m;
    float s = 0.f;
    for (int i = 0; i < S_ / 8; i++) s += base[(size_t)i * PM_];
    atomicAdd(&ksum[bh * PM_ + m], s);
}

// ctx[bh,m,e] = sum_s kp[bh,s,m] * v[b,s,h*64+e]; split-K over 8 s-chunks
// grid (5, 8, BH), 256 threads, FFMA2 4x(2x2)/thread
__global__ __launch_bounds__(256) void ctx_kernel(
    const float* __restrict__ kp, const float* __restrict__ v, float* __restrict__ ctx) {
    __shared__ float Kp[16][65];
    __shared__ float Vs[16][64];
    int bh = blockIdx.z, b = bh >> 2, h = bh & 3;
    int m0 = blockIdx.x * 64;
    int sch = blockIdx.y * 512;
    int t = threadIdx.x, tx = t & 15, ty = t >> 4;
    ull acc[4][2] = {};
    for (int k0 = 0; k0 < 512; k0 += 16) {
        int sbase = sch + k0;
#pragma unroll
        for (int it = 0; it < 4; it++) {
            int id = t + it * 256;
            int r = id >> 6, c = id & 63;
            int m = m0 + c;
            Kp[r][c] = (m < PM_) ? kp[((size_t)bh * S_ + sbase + r) * PM_ + m] : 0.f;
        }
        {
            int r = t >> 4, c4 = (t & 15) * 4;
            *(float4*)&Vs[r][c4] =
                *(const float4*)&v[((size_t)(b * S_ + sbase + r)) * D_ + h * DH_ + c4];
        }
        __syncthreads();
#pragma unroll
        for (int k = 0; k < 16; k++) {
            ull ap[4];
#pragma unroll
            for (int i = 0; i < 4; i++) ap[i] = bcast2(Kp[k][ty * 4 + i]);
            ull bp0 = *(const ull*)&Vs[k][tx * 4];
            ull bp1 = *(const ull*)&Vs[k][tx * 4 + 2];
#pragma unroll
            for (int i = 0; i < 4; i++) {
                fma2(acc[i][0], ap[i], bp0);
                fma2(acc[i][1], ap[i], bp1);
            }
        }
        __syncthreads();
    }
#pragma unroll
    for (int i = 0; i < 4; i++) {
        int m = m0 + ty * 4 + i;
        if (m < PM_) {
#pragma unroll
            for (int j2 = 0; j2 < 2; j2++) {
                float2 f = unpack2(acc[i][j2]);
                int e = tx * 4 + 2 * j2;
                atomicAdd(&ctx[((size_t)bh * PM_ + m) * DH_ + e], f.x);
                atomicAdd(&ctx[((size_t)bh * PM_ + m) * DH_ + e + 1], f.y);
            }
        }
    }
}

// dinv[bh,s] = 1 / (qp_row . ksum_row)
__global__ void dinv_kernel(const float* __restrict__ qp, const float* __restrict__ ksum,
                            float* __restrict__ dinv) {
    __shared__ float sh[8];
    int row = blockIdx.x, t = threadIdx.x;
    int bh = row >> 12;
    const float* q = qp + (size_t)row * PM_;
    const float* ks = ksum + bh * PM_;
    float s = 0.f;
    for (int i = t; i < PM_; i += 128) s = fmaf(q[i], ks[i], s);
    s = block_sum(s, sh);
    if (t == 0) dinv[row] = 1.f / s;
}

// o = dinv * (qp @ ctx); grid (S/64, BH), FFMA2
__global__ __launch_bounds__(256) void attnout_kernel(
    const float* __restrict__ qp, const float* __restrict__ ctx,
    const float* __restrict__ dinv, float* __restrict__ o) {
    __shared__ float Qs[16][65];   // [k(m)][s]
    __shared__ float Cs[16][64];   // [k(m)][e]
    int bh = blockIdx.y, b = bh >> 2, h = bh & 3;
    int s0 = blockIdx.x * 64;
    int t = threadIdx.x, tx = t & 15, ty = t >> 4;
    ull acc[4][2] = {};
    for (int k0 = 0; k0 < PM_; k0 += 16) {
#pragma unroll
        for (int it = 0; it < 4; it++) {
            int id = t + it * 256;
            int r = id >> 4, c = id & 15;
            int m = k0 + c;
            Qs[c][r] = (m < PM_) ? qp[((size_t)bh * S_ + s0 + r) * PM_ + m] : 0.f;
        }
        {
            int r = t >> 4, c4 = (t & 15) * 4;
            int m = k0 + r;
            float4 v4 = (m < PM_) ? *(const float4*)&ctx[((size_t)bh * PM_ + m) * DH_ + c4]
                                  : make_float4(0.f, 0.f, 0.f, 0.f);
            *(float4*)&Cs[r][c4] = v4;
        }
        __syncthreads();
#pragma unroll
        for (int k = 0; k < 16; k++) {
            ull ap[4];
#pragma unroll
            for (int i = 0; i < 4; i++) ap[i] = bcast2(Qs[k][ty * 4 + i]);
            ull bp0 = *(const ull*)&Cs[k][tx * 4];
            ull bp1 = *(const ull*)&Cs[k][tx * 4 + 2];
#pragma unroll
            for (int i = 0; i < 4; i++) {
                fma2(acc[i][0], ap[i], bp0);
                fma2(acc[i][1], ap[i], bp1);
            }
        }
        __syncthreads();
    }
#pragma unroll
    for (int i = 0; i < 4; i++) {
        int s = s0 + ty * 4 + i;
        float di = dinv[(size_t)bh * S_ + s];
#pragma unroll
        for (int j2 = 0; j2 < 2; j2++) {
            float2 f = unpack2(acc[i][j2]);
            int e = tx * 4 + 2 * j2;
            size_t base = ((size_t)(b * S_ + s)) * D_ + h * DH_ + e;
            o[base]     = f.x * di;
            o[base + 1] = f.y * di;
        }
    }
}

// ---------------------------------------------------------------------------
// Pooling
// ---------------------------------------------------------------------------
__global__ void score_kernel(const float* __restrict__ h, const float* __restrict__ p2w,
                             const float* __restrict__ p2b, const float* __restrict__ mask,
                             float* __restrict__ score) {
    __shared__ float sh[8];
    int row = blockIdx.x, t = threadIdx.x;
    float v = h[(size_t)row * D_ + t] * p2w[t];
    float s = block_sum(v, sh);
    if (t == 0) score[row] = expf(s + p2b[0]) * mask[row];
}

__global__ void ssum_kernel(const float* __restrict__ score, float* __restrict__ ssum) {
    __shared__ float sh[8];
    int b = blockIdx.x;
    float s = 0.f;
    for (int i = threadIdx.x; i < S_; i += 256) s += score[b * S_ + i];
    s = block_sum(s, sh);
    if (threadIdx.x == 0) ssum[b] = s;
}

__global__ void outzero_kernel(float* __restrict__ out) {
    int i = blockIdx.x * blockDim.x + threadIdx.x;
    if (i < B_ * D_) out[i] = 0.f;
}

__global__ void pool_kernel(const float* __restrict__ x, const float* __restrict__ score,
                            const float* __restrict__ ssum, float* __restrict__ out) {
    int b = blockIdx.x, chunk = blockIdx.y, d = threadIdx.x;
    float inv = 1.f / (ssum[b] + 1e-8f);
    float acc = 0.f;
    int s0 = chunk * (S_ / 16);
    for (int s = s0; s < s0 + S_ / 16; s++)
        acc = fmaf(x[((size_t)(b * S_ + s)) * D_ + d], score[b * S_ + s], acc);
    atomicAdd(&out[b * D_ + d], acc * inv);
}

// ---------------------------------------------------------------------------
// Host launcher
// ---------------------------------------------------------------------------
static void launch_gemm(int mode, const float* A, const float* W, const float* bias,
                        float* C, int Mrows, int K, int N) {
    dim3 grid(N / 128, Mrows / 128);
    switch (mode) {
        case 0: gemm_kernel<0><<<grid, 256>>>(A, W, bias, C, K, N); break;
        case 1: gemm_kernel<1><<<grid, 256>>>(A, W, bias, C, K, N); break;
        case 2: gemm_kernel<2><<<grid, 256>>>(A, W, bias, C, K, N); break;
        case 3: gemm_kernel<3><<<grid, 256>>>(A, W, bias, C, K, N); break;
    }
}

extern "C" void kernel_launch(void* const* d_in, const int* in_sizes, int n_in,
                              void* d_out, int out_size) {
    const float* emb  = (const float*)d_in[0];
    const float* mask = (const float*)d_in[1];
    const float* pos  = (const float*)d_in[2];
    const float* ln_g = (const float*)d_in[3];
    const float* ln_b = (const float*)d_in[4];
    const float* proj = (const float*)d_in[5];
    const float* Wq = (const float*)d_in[6];   const float* bq = (const float*)d_in[7];
    const float* Wk = (const float*)d_in[8];   const float* bk = (const float*)d_in[9];
    const float* Wv = (const float*)d_in[10];  const float* bv = (const float*)d_in[11];
    const float* Wo = (const float*)d_in[12];  const float* bo = (const float*)d_in[13];
    const float* ln1g = (const float*)d_in[14]; const float* ln1b = (const float*)d_in[15];
    const float* W1 = (const float*)d_in[16];  const float* b1 = (const float*)d_in[17];
    const float* W2 = (const float*)d_in[18];  const float* b2 = (const float*)d_in[19];
    const float* ln2g = (const float*)d_in[20]; const float* ln2b = (const float*)d_in[21];
    const float* p1w = (const float*)d_in[22]; const float* p1b = (const float*)d_in[23];
    const float* p2w = (const float*)d_in[24]; const float* p2b = (const float*)d_in[25];
    float* out = (float*)d_out;

    void* tp;
    float *x, *h, *q, *k, *v, *o, *qp, *kp, *dq, *dk, *di, *ks, *cx, *fn, *sc, *ss;
    unsigned* km;
    cudaGetSymbolAddress(&tp, g_x);     x  = (float*)tp;
    cudaGetSymbolAddress(&tp, g_h);     h  = (float*)tp;
    cudaGetSymbolAddress(&tp, g_q);     q  = (float*)tp;
    cudaGetSymbolAddress(&tp, g_k);     k  = (float*)tp;
    cudaGetSymbolAddress(&tp, g_v);     v  = (float*)tp;
    cudaGetSymbolAddress(&tp, g_o);     o  = (float*)tp;
    cudaGetSymbolAddress(&tp, g_qp);    qp = (float*)tp;
    cudaGetSymbolAddress(&tp, g_kp);    kp = (float*)tp;
    cudaGetSymbolAddress(&tp, g_diagq); dq = (float*)tp;
    cudaGetSymbolAddress(&tp, g_diagk); dk = (float*)tp;
    cudaGetSymbolAddress(&tp, g_dinv);  di = (float*)tp;
    cudaGetSymbolAddress(&tp, g_ksum);  ks = (float*)tp;
    cudaGetSymbolAddress(&tp, g_ctx);   cx = (float*)tp;
    cudaGetSymbolAddress(&tp, g_ffn);   fn = (float*)tp;
    cudaGetSymbolAddress(&tp, g_score); sc = (float*)tp;
    cudaGetSymbolAddress(&tp, g_ssum);  ss = (float*)tp;
    cudaGetSymbolAddress(&tp, g_kmaxu); km = (unsigned*)tp;

    embed_ln_kernel<<<BS_, 256>>>(emb, pos, ln_g, ln_b, x);

    for (int l = 0; l < NL_; l++) {
        const float* pj = proj + (size_t)l * PM_ * DH_;

        // --- attention block ---
        ln_kernel<<<BS_, 256>>>(x, h, ln1g + l * D_, ln1b + l * D_);
        launch_gemm(0, h, Wq + (size_t)l * D_ * D_, bq + l * D_, q, BS_, D_, D_);
        launch_gemm(0, h, Wk + (size_t)l * D_ * D_, bk + l * D_, k, BS_, D_, D_);
        launch_gemm(0, h, Wv + (size_t)l * D_ * D_, bv + l * D_, v, BS_, D_, D_);

        layer_init_kernel<<<(BH_ * PM_ * DH_ + 255) / 256, 256>>>(cx, ks, km);

        dash_kernel<<<dim3(S_ / 64, BH_), 256>>>(q, pj, qp, dq, nullptr);
        dash_kernel<<<dim3(S_ / 64, BH_), 256>>>(k, pj, kp, dk, km);

        phi_exp_kernel<<<BH_ * S_, 128>>>(qp, dq, km, 0);   // per-row stabilizer
        phi_exp_kernel<<<BH_ * S_, 128>>>(kp, dk, km, 1);   // global stabilizer

        ksum_kernel<<<dim3(BH_, 3, 8), 128>>>(kp, ks);
        ctx_kernel<<<dim3(5, 8, BH_), 256>>>(kp, v, cx);
        dinv_kernel<<<BH_ * S_, 128>>>(qp, ks, di);
        attnout_kernel<<<dim3(S_ / 64, BH_), 256>>>(qp, cx, di, o);

        launch_gemm(2, o, Wo + (size_t)l * D_ * D_, bo + l * D_, x, BS_, D_, D_);

        // --- FFN block ---
        ln_kernel<<<BS_, 256>>>(x, h, ln2g + l * D_, ln2b + l * D_);
        launch_gemm(1, h, W1 + (size_t)l * D_ * FF_, b1 + l * FF_, fn, BS_, D_, FF_);
        launch_gemm(2, fn, W2 + (size_t)l * FF_ * D_, b2 + l * D_, x, BS_, FF_, D_);
    }

    // --- attention pooling ---
    launch_gemm(3, x, p1w, p1b, h, BS_, D_, D_);
    score_kernel<<<BS_, 256>>>(h, p2w, p2b, mask, sc);
    ssum_kernel<<<B_, 256>>>(sc, ss);
    outzero_kernel<<<(B_ * D_ + 255) / 256, 256>>>(out);
    pool_kernel<<<dim3(B_, 16), 256>>>(x, sc, ss, out);
}

// round 6
// speedup vs baseline: 1.5206x; 1.3611x over previous
#include <cuda_runtime.h>
#include <cuda_bf16.h>
#include <cstdint>

// ---------------------------------------------------------------------------
// Problem constants
// ---------------------------------------------------------------------------
constexpr int B_  = 4;
constexpr int S_  = 4096;
constexpr int D_  = 256;
constexpr int DH_ = 64;
constexpr int NL_ = 4;
constexpr int PM_ = 266;          // nb_features
constexpr int FF_ = 1024;
constexpr int BS_ = B_ * S_;      // 16384 rows
constexpr int BH_ = B_ * 4;       // 16

constexpr float DN_    = 0.35355339059327373f;  // 64^-0.25
constexpr float HDN2_  = 0.0625f;               // 0.5 * dn^2
constexpr float RATIO_ = 0.06131392f;           // 266^-0.5
constexpr float KEPS_  = 1e-4f;
constexpr float LNEPS_ = 1e-12f;

typedef unsigned long long ull;

// ---------------------------------------------------------------------------
// Scratch (static device globals)
// ---------------------------------------------------------------------------
__device__ float g_x  [BS_ * D_];
__device__ float g_h  [BS_ * D_];     // pooling tanh output (fp32)
__device__ float g_q  [BS_ * D_];
__device__ float g_k  [BS_ * D_];
__device__ float g_v  [BS_ * D_];
__device__ float g_qp [(size_t)BH_ * S_ * PM_];
__device__ float g_kp [(size_t)BH_ * S_ * PM_];
__device__ float g_diagq[BH_ * S_];
__device__ float g_diagk[BH_ * S_];
__device__ float g_dinv [BH_ * S_];
__device__ float g_ksum [BH_ * PM_];
__device__ float g_ctx  [BH_ * PM_ * DH_];
__device__ float g_score[BS_];
__device__ float g_ssum [B_];
__device__ unsigned g_kmaxu;

// bf16 hi/lo operand buffers
// weight layout (transposed, row-major [N,K]):
constexpr size_t OFF_QKV = 0;
constexpr size_t OFF_WO  = OFF_QKV + (size_t)NL_ * 768 * 256;
constexpr size_t OFF_W1  = OFF_WO  + (size_t)NL_ * 256 * 256;
constexpr size_t OFF_W2  = OFF_W1  + (size_t)NL_ * 1024 * 256;
constexpr size_t OFF_P1  = OFF_W2  + (size_t)NL_ * 256 * 1024;
constexpr size_t WT_TOT  = OFF_P1 + 256 * 256;

__device__ __nv_bfloat16 g_wth[WT_TOT], g_wtl[WT_TOT];
__device__ float g_bqkv[NL_ * 768];
__device__ __nv_bfloat16 g_hh[BS_ * D_], g_hl[BS_ * D_];      // LN outputs
__device__ __nv_bfloat16 g_oh[BS_ * D_], g_ol[BS_ * D_];      // attnout
__device__ __nv_bfloat16 g_fh[(size_t)BS_ * FF_], g_fl[(size_t)BS_ * FF_]; // gelu
__device__ __nv_bfloat16 g_xh[BS_ * D_], g_xl[BS_ * D_];      // residual (for pooling)

// ---------------------------------------------------------------------------
// PTX helpers (family-portable only: no tcgen05 on compute_103 targets)
// ---------------------------------------------------------------------------
__device__ __forceinline__ uint32_t smem_u32(const void* p) {
    uint32_t a;
    asm("{ .reg .u64 t; cvta.to.shared.u64 t, %1; cvt.u32.u64 %0, t; }" : "=r"(a) : "l"(p));
    return a;
}
__device__ __forceinline__ void ldsm4(unsigned& r0, unsigned& r1, unsigned& r2, unsigned& r3,
                                      uint32_t addr) {
    asm volatile("ldmatrix.sync.aligned.m8n8.x4.shared.b16 {%0,%1,%2,%3}, [%4];"
                 : "=r"(r0), "=r"(r1), "=r"(r2), "=r"(r3) : "r"(addr));
}
__device__ __forceinline__ void mma_bf16(float* d, const unsigned* a, const unsigned* b) {
    asm volatile("mma.sync.aligned.m16n8k16.row.col.f32.bf16.bf16.f32 "
                 "{%0,%1,%2,%3}, {%4,%5,%6,%7}, {%8,%9}, {%0,%1,%2,%3};"
                 : "+f"(d[0]), "+f"(d[1]), "+f"(d[2]), "+f"(d[3])
                 : "r"(a[0]), "r"(a[1]), "r"(a[2]), "r"(a[3]), "r"(b[0]), "r"(b[1]));
}
#define CP_ASYNC16(dst, src) \
    asm volatile("cp.async.cg.shared.global [%0], [%1], 16;" :: "r"(dst), "l"(src) : "memory")
#define CP_COMMIT() asm volatile("cp.async.commit_group;" ::: "memory")
#define CP_WAIT(n)  asm volatile("cp.async.wait_group %0;" :: "n"(n) : "memory")

__device__ __forceinline__ void bf16_split(float v, __nv_bfloat16& hi, __nv_bfloat16& lo) {
    hi = __float2bfloat16(v);
    lo = __float2bfloat16(v - __bfloat162float(hi));
}

// ---------------------------------------------------------------------------
// Packed f32x2 helpers (FAVOR kernels)
// ---------------------------------------------------------------------------
__device__ __forceinline__ void fma2(ull& d, ull a, ull b) {
    asm("fma.rn.f32x2 %0, %1, %2, %0;" : "+l"(d) : "l"(a), "l"(b));
}
__device__ __forceinline__ ull bcast2(float x) {
    ull r;
    asm("mov.b64 %0, {%1, %1};" : "=l"(r) : "r"(__float_as_uint(x)));
    return r;
}
__device__ __forceinline__ float2 unpack2(ull d) {
    unsigned lo, hi;
    asm("mov.b64 {%0, %1}, %2;" : "=r"(lo), "=r"(hi) : "l"(d));
    return make_float2(__uint_as_float(lo), __uint_as_float(hi));
}

// ---------------------------------------------------------------------------
// Reductions
// ---------------------------------------------------------------------------
__device__ __forceinline__ float warpsum(float v) {
#pragma unroll
    for (int o = 16; o > 0; o >>= 1) v += __shfl_xor_sync(0xffffffffu, v, o);
    return v;
}
__device__ __forceinline__ float warpmax(float v) {
#pragma unroll
    for (int o = 16; o > 0; o >>= 1) v = fmaxf(v, __shfl_xor_sync(0xffffffffu, v, o));
    return v;
}
__device__ __forceinline__ float block_sum(float v, float* sh) {
    int lane = threadIdx.x & 31, w = threadIdx.x >> 5, nw = blockDim.x >> 5;
    v = warpsum(v);
    if (lane == 0) sh[w] = v;
    __syncthreads();
    if (w == 0) {
        float x = (lane < nw) ? sh[lane] : 0.f;
        x = warpsum(x);
        if (lane == 0) sh[0] = x;
    }
    __syncthreads();
    float r = sh[0];
    __syncthreads();
    return r;
}
__device__ __forceinline__ unsigned fmap(float f) {
    unsigned u = __float_as_uint(f);
    return (u & 0x80000000u) ? ~u : (u | 0x80000000u);
}
__device__ __forceinline__ float funmap(unsigned u) {
    u = (u & 0x80000000u) ? (u & 0x7FFFFFFFu) : ~u;
    return __uint_as_float(u);
}

// ---------------------------------------------------------------------------
// Weight transpose + bf16 split: W [K,N] fp32 -> Th/Tl [N,K] bf16
// ---------------------------------------------------------------------------
__global__ void wsplit_kernel(const float* __restrict__ W, __nv_bfloat16* __restrict__ Th,
                              __nv_bfloat16* __restrict__ Tl, int K, int N, int rowOff) {
    __shared__ float ts[32][33];
    int kb = blockIdx.y * 32, nb = blockIdx.x * 32;
    int tx = threadIdx.x, ty = threadIdx.y;
#pragma unroll
    for (int i = 0; i < 4; i++) {
        int k = kb + ty + i * 8;
        ts[ty + i * 8][tx] = W[(size_t)k * N + nb + tx];
    }
    __syncthreads();
#pragma unroll
    for (int i = 0; i < 4; i++) {
        int n = nb + ty + i * 8;
        int k = kb + tx;
        float v = ts[tx][ty + i * 8];
        __nv_bfloat16 hi, lo;
        bf16_split(v, hi, lo);
        size_t idx = (size_t)(rowOff + n) * K + k;
        Th[idx] = hi; Tl[idx] = lo;
    }
}

__global__ void bconcat_kernel(const float* __restrict__ bq, const float* __restrict__ bk,
                               const float* __restrict__ bv, float* __restrict__ dst) {
    int l = blockIdx.x, t = threadIdx.x;
    dst[l * 768 + t]       = bq[l * 256 + t];
    dst[l * 768 + 256 + t] = bk[l * 256 + t];
    dst[l * 768 + 512 + t] = bv[l * 256 + t];
}

// ---------------------------------------------------------------------------
// LayerNorm
// ---------------------------------------------------------------------------
__global__ void embed_ln_kernel(const float* __restrict__ emb, const float* __restrict__ pos,
                                const float* __restrict__ g, const float* __restrict__ bb,
                                float* __restrict__ out) {
    __shared__ float sh[8];
    int row = blockIdx.x, t = threadIdx.x;
    float v = emb[(size_t)row * D_ + t] + pos[(size_t)(row & (S_ - 1)) * D_ + t];
    float mu = block_sum(v, sh) * (1.0f / D_);
    float d  = v - mu;
    float var = block_sum(d * d, sh) * (1.0f / D_);
    float rs = rsqrtf(var + LNEPS_);
    out[(size_t)row * D_ + t] = d * rs * g[t] + bb[t];
}

__global__ void ln_kernel(const float* __restrict__ in,
                          __nv_bfloat16* __restrict__ oh, __nv_bfloat16* __restrict__ ol,
                          const float* __restrict__ g, const float* __restrict__ bb) {
    __shared__ float sh[8];
    int row = blockIdx.x, t = threadIdx.x;
    float v = in[(size_t)row * D_ + t];
    float mu = block_sum(v, sh) * (1.0f / D_);
    float d  = v - mu;
    float var = block_sum(d * d, sh) * (1.0f / D_);
    float rs = rsqrtf(var + LNEPS_);
    float val = d * rs * g[t] + bb[t];
    __nv_bfloat16 hi, lo;
    bf16_split(val, hi, lo);
    size_t idx = (size_t)row * D_ + t;
    oh[idx] = hi; ol[idx] = lo;
}

// ---------------------------------------------------------------------------
// mma.sync bf16 GEMM: C[M,N] = A[M,K] @ Bt^T (+ bias + epilogue)
// A (hi/lo) [M,K]; Bt (hi/lo) [N,K]; 3-term split, fp32 accum.
// Block 128x128, K-stage 32, 8 warps (32m x 64n each), cp.async double buffer.
// MODE: 0 = QKV split; 1 = GELU->Oh/Ol; 2 = residual accumulate (+emit); 3 = tanh
// ---------------------------------------------------------------------------
constexpr int ROWB    = 80;              // 32 bf16 + 8 pad = 80 bytes (conflict-free ldmatrix)
constexpr int ARR_B   = 128 * ROWB;      // 10240 bytes per operand array
constexpr int STAGE_B = 4 * ARR_B;       // Ah, Al, Bh, Bl
constexpr int MM_SMEM = 2 * STAGE_B;     // 81920 bytes

__device__ __forceinline__ void stage_cp(uint32_t sbase,
    const __nv_bfloat16* __restrict__ Ah, const __nv_bfloat16* __restrict__ Al,
    const __nv_bfloat16* __restrict__ Bh, const __nv_bfloat16* __restrict__ Bl,
    int row0, int col0, int K, int k0, int tid) {
#pragma unroll
    for (int i = 0; i < 8; i++) {
        const int arr = i >> 1;                 // compile-time per unrolled i
        int cc = tid + (i & 1) * 256;           // 0..511
        int row = cc >> 2, kc = cc & 3;
        const __nv_bfloat16* src;
        int gr;
        if (arr == 0)      { src = Ah; gr = row0 + row; }
        else if (arr == 1) { src = Al; gr = row0 + row; }
        else if (arr == 2) { src = Bh; gr = col0 + row; }
        else               { src = Bl; gr = col0 + row; }
        uint32_t dst = sbase + arr * ARR_B + row * ROWB + kc * 16;
        CP_ASYNC16(dst, src + (size_t)gr * K + k0 + kc * 8);
    }
}

template <int MODE, bool EMIT>
__global__ __launch_bounds__(256) void mm_gemm(
    const __nv_bfloat16* __restrict__ Ah, const __nv_bfloat16* __restrict__ Al,
    const __nv_bfloat16* __restrict__ Bth, const __nv_bfloat16* __restrict__ Btl,
    const float* __restrict__ bias,
    float* __restrict__ O0, float* __restrict__ O1, float* __restrict__ O2,
    __nv_bfloat16* __restrict__ Oh, __nv_bfloat16* __restrict__ Ol,
    int K, int N) {
    extern __shared__ char smem[];
    uint32_t sb = smem_u32(smem);
    int tid = threadIdx.x, lane = tid & 31, warp = tid >> 5;
    int row0 = blockIdx.y * 128, col0 = blockIdx.x * 128;
    int wm = (warp >> 1) * 32, wn = (warp & 1) * 64;

    float acc[2][8][4] = {};

    int NT = K >> 5;
    stage_cp(sb, Ah, Al, Bth, Btl, row0, col0, K, 0, tid);
    CP_COMMIT();
    if (NT > 1) {
        stage_cp(sb + STAGE_B, Ah, Al, Bth, Btl, row0, col0, K, 32, tid);
        CP_COMMIT();
    }

    // ldmatrix lane-invariant offsets
    uint32_t aoff = (uint32_t)((wm + (lane & 15)) * ROWB + (lane >> 4) * 16);
    uint32_t boff = (uint32_t)((wn + ((lane >> 4) << 3) + (lane & 7)) * ROWB +
                               ((lane >> 3) & 1) * 16);

    for (int t = 0; t < NT; t++) {
        if (t + 1 < NT) CP_WAIT(1); else CP_WAIT(0);
        __syncthreads();
        uint32_t bs = sb + (t & 1) * STAGE_B;
#pragma unroll
        for (int kt = 0; kt < 2; kt++) {
            unsigned ah[2][4], al[2][4], bh[8][2], bl[8][2];
#pragma unroll
            for (int mt = 0; mt < 2; mt++) {
                uint32_t a = bs + aoff + mt * (16 * ROWB) + kt * 32;
                ldsm4(ah[mt][0], ah[mt][1], ah[mt][2], ah[mt][3], a);
                ldsm4(al[mt][0], al[mt][1], al[mt][2], al[mt][3], a + ARR_B);
            }
#pragma unroll
            for (int n2 = 0; n2 < 4; n2++) {
                uint32_t a = bs + 2 * ARR_B + boff + n2 * (16 * ROWB) + kt * 32;
                ldsm4(bh[2 * n2][0], bh[2 * n2][1], bh[2 * n2 + 1][0], bh[2 * n2 + 1][1], a);
                ldsm4(bl[2 * n2][0], bl[2 * n2][1], bl[2 * n2 + 1][0], bl[2 * n2 + 1][1],
                      a + ARR_B);
            }
#pragma unroll
            for (int mt = 0; mt < 2; mt++)
#pragma unroll
                for (int nt = 0; nt < 8; nt++) {
                    mma_bf16(acc[mt][nt], ah[mt], bh[nt]);
                    mma_bf16(acc[mt][nt], ah[mt], bl[nt]);
                    mma_bf16(acc[mt][nt], al[mt], bh[nt]);
                }
        }
        __syncthreads();
        if (t + 2 < NT) {
            stage_cp(sb + (t & 1) * STAGE_B, Ah, Al, Bth, Btl, row0, col0, K,
                     (t + 2) * 32, tid);
            CP_COMMIT();
        }
    }

    // epilogue
#pragma unroll
    for (int mt = 0; mt < 2; mt++)
#pragma unroll
        for (int nt = 0; nt < 8; nt++) {
            int rbase = row0 + wm + mt * 16 + (lane >> 2);
            int cg = col0 + wn + nt * 8 + (lane & 3) * 2;
            float b0 = __ldg(&bias[cg]), b1 = __ldg(&bias[cg + 1]);
#pragma unroll
            for (int half = 0; half < 2; half++) {
                int row = rbase + half * 8;
                float v0 = acc[mt][nt][half * 2]     + b0;
                float v1 = acc[mt][nt][half * 2 + 1] + b1;
                if (MODE == 0) {
                    int which = cg >> 8, cl = cg & 255;
                    float* dst = (which == 0) ? O0 : (which == 1) ? O1 : O2;
                    dst[(size_t)row * 256 + cl]     = v0;
                    dst[(size_t)row * 256 + cl + 1] = v1;
                } else if (MODE == 1) {
                    float u0 = 0.7978845608028654f * (v0 + 0.044715f * v0 * v0 * v0);
                    float u1 = 0.7978845608028654f * (v1 + 0.044715f * v1 * v1 * v1);
                    float g0 = 0.5f * v0 * (1.f + tanhf(u0));
                    float g1 = 0.5f * v1 * (1.f + tanhf(u1));
                    size_t idx = (size_t)row * N + cg;
                    __nv_bfloat16 hi, lo;
                    bf16_split(g0, hi, lo); Oh[idx] = hi;     Ol[idx] = lo;
                    bf16_split(g1, hi, lo); Oh[idx + 1] = hi; Ol[idx + 1] = lo;
                } else if (MODE == 2) {
                    size_t idx = (size_t)row * N + cg;
                    float n0 = O0[idx] + v0, n1 = O0[idx + 1] + v1;
                    O0[idx] = n0; O0[idx + 1] = n1;
                    if (EMIT) {
                        __nv_bfloat16 hi, lo;
                        bf16_split(n0, hi, lo); Oh[idx] = hi;     Ol[idx] = lo;
                        bf16_split(n1, hi, lo); Oh[idx + 1] = hi; Ol[idx + 1] = lo;
                    }
                } else {
                    size_t idx = (size_t)row * N + cg;
                    O0[idx]     = tanhf(v0);
                    O0[idx + 1] = tanhf(v1);
                }
            }
        }
}

// ---------------------------------------------------------------------------
// FAVOR dash (FFMA2): dash = dn * X·P^T, diag = 0.0625*||x||^2, optional global max
// ---------------------------------------------------------------------------
__global__ __launch_bounds__(256) void dash_kernel(
    const float* __restrict__ X, const float* __restrict__ P,
    float* __restrict__ dash, float* __restrict__ diag, unsigned* gmax) {
    __shared__ float Xs[DH_][65];
    __shared__ float Ps[DH_][64];
    __shared__ float shm[8];
    int bh = blockIdx.y, b = bh >> 2, h = bh & 3;
    int s0 = blockIdx.x * 64;
    int t  = threadIdx.x;
    int tx = t & 15, ty = t >> 4;

#pragma unroll
    for (int it = 0; it < 4; it++) {
        int id = t + it * 256;
        int r = id >> 4, c4 = (id & 15) * 4;
        float4 v4 = *(const float4*)&X[((size_t)(b * S_ + s0 + r)) * D_ + h * DH_ + c4];
        Xs[c4 + 0][r] = v4.x; Xs[c4 + 1][r] = v4.y;
        Xs[c4 + 2][r] = v4.z; Xs[c4 + 3][r] = v4.w;
    }
    __syncthreads();
    if (t < 64) {
        float s = 0.f;
#pragma unroll
        for (int d = 0; d < DH_; d++) { float x = Xs[d][t]; s = fmaf(x, x, s); }
        diag[(size_t)bh * S_ + s0 + t] = HDN2_ * s;
    }

    float lmax = -3.4e38f;
    for (int m0 = 0; m0 < PM_; m0 += 64) {
        __syncthreads();
#pragma unroll
        for (int it = 0; it < 4; it++) {
            int id = t + it * 256;
            int r = id >> 4, c4 = (id & 15) * 4;
            int m = m0 + r;
            float4 v4 = (m < PM_) ? *(const float4*)&P[(size_t)m * DH_ + c4]
                                  : make_float4(0.f, 0.f, 0.f, 0.f);
            Ps[c4 + 0][r] = v4.x; Ps[c4 + 1][r] = v4.y;
            Ps[c4 + 2][r] = v4.z; Ps[c4 + 3][r] = v4.w;
        }
        __syncthreads();
        ull acc[4][2] = {};
#pragma unroll
        for (int d = 0; d < DH_; d++) {
            ull ap[4];
#pragma unroll
            for (int i = 0; i < 4; i++) ap[i] = bcast2(Xs[d][ty * 4 + i]);
            ull bp0 = *(const ull*)&Ps[d][tx * 4];
            ull bp1 = *(const ull*)&Ps[d][tx * 4 + 2];
#pragma unroll
            for (int i = 0; i < 4; i++) {
                fma2(acc[i][0], ap[i], bp0);
                fma2(acc[i][1], ap[i], bp1);
            }
        }
#pragma unroll
        for (int i = 0; i < 4; i++) {
            int srow = s0 + ty * 4 + i;
#pragma unroll
            for (int j2 = 0; j2 < 2; j2++) {
                int m = m0 + tx * 4 + 2 * j2;
                if (m < PM_) {
                    float2 f = unpack2(acc[i][j2]);
                    float v0 = DN_ * f.x, v1 = DN_ * f.y;
                    size_t base = ((size_t)bh * S_ + srow) * PM_ + m;
                    dash[base] = v0; dash[base + 1] = v1;
                    lmax = fmaxf(lmax, fmaxf(v0, v1));
                }
            }
        }
    }
    if (gmax) {
        lmax = warpmax(lmax);
        int lane = t & 31, w = t >> 5;
        if (lane == 0) shm[w] = lmax;
        __syncthreads();
        if (t == 0) {
            float v = shm[0];
#pragma unroll
            for (int i = 1; i < 8; i++) v = fmaxf(v, shm[i]);
            atomicMax(gmax, fmap(v));
        }
    }
}

__global__ void layer_init_kernel(float* __restrict__ ctx, float* __restrict__ ksum,
                                  unsigned* __restrict__ km) {
    int i = blockIdx.x * blockDim.x + threadIdx.x;
    if (i < BH_ * PM_ * DH_) ctx[i] = 0.f;
    if (i < BH_ * PM_) ksum[i] = 0.f;
    if (i == 0) *km = 0u;
}

__global__ void phi_exp_kernel(float* __restrict__ p, const float* __restrict__ diag,
                               const unsigned* __restrict__ gmaxu, int use_global) {
    __shared__ float sh[4];
    int row = blockIdx.x, t = threadIdx.x;   // 128 threads
    float* r = p + (size_t)row * PM_;
    float stab;
    if (use_global) {
        stab = funmap(*gmaxu);
    } else {
        float m = -3.4e38f;
        for (int i = t; i < PM_; i += 128) m = fmaxf(m, r[i]);
        m = warpmax(m);
        int lane = t & 31, w = t >> 5;
        if (lane == 0) sh[w] = m;
        __syncthreads();
        if (t == 0) sh[0] = fmaxf(fmaxf(sh[0], sh[1]), fmaxf(sh[2], sh[3]));
        __syncthreads();
        stab = sh[0];
    }
    float sub = diag[row] + stab;
    for (int i = t; i < PM_; i += 128) r[i] = RATIO_ * (__expf(r[i] - sub) + KEPS_);
}

__global__ void ksum_kernel(const float* __restrict__ kp, float* __restrict__ ksum) {
    int bh = blockIdx.x;
    int m = blockIdx.y * 128 + threadIdx.x;
    if (m >= PM_) return;
    int s0 = blockIdx.z * (S_ / 8);
    const float* base = kp + ((size_t)bh * S_ + s0) * PM_ + m;
    float s = 0.f;
    for (int i = 0; i < S_ / 8; i++) s += base[(size_t)i * PM_];
    atomicAdd(&ksum[bh * PM_ + m], s);
}

__global__ __launch_bounds__(256) void ctx_kernel(
    const float* __restrict__ kp, const float* __restrict__ v, float* __restrict__ ctx) {
    __shared__ float Kp[16][65];
    __shared__ float Vs[16][64];
    int bh = blockIdx.z, b = bh >> 2, h = bh & 3;
    int m0 = blockIdx.x * 64;
    int sch = blockIdx.y * 512;
    int t = threadIdx.x, tx = t & 15, ty = t >> 4;
    ull acc[4][2] = {};
    for (int k0 = 0; k0 < 512; k0 += 16) {
        int sbase = sch + k0;
#pragma unroll
        for (int it = 0; it < 4; it++) {
            int id = t + it * 256;
            int r = id >> 6, c = id & 63;
            int m = m0 + c;
            Kp[r][c] = (m < PM_) ? kp[((size_t)bh * S_ + sbase + r) * PM_ + m] : 0.f;
        }
        {
            int r = t >> 4, c4 = (t & 15) * 4;
            *(float4*)&Vs[r][c4] =
                *(const float4*)&v[((size_t)(b * S_ + sbase + r)) * D_ + h * DH_ + c4];
        }
        __syncthreads();
#pragma unroll
        for (int k = 0; k < 16; k++) {
            ull ap[4];
#pragma unroll
            for (int i = 0; i < 4; i++) ap[i] = bcast2(Kp[k][ty * 4 + i]);
            ull bp0 = *(const ull*)&Vs[k][tx * 4];
            ull bp1 = *(const ull*)&Vs[k][tx * 4 + 2];
#pragma unroll
            for (int i = 0; i < 4; i++) {
                fma2(acc[i][0], ap[i], bp0);
                fma2(acc[i][1], ap[i], bp1);
            }
        }
        __syncthreads();
    }
#pragma unroll
    for (int i = 0; i < 4; i++) {
        int m = m0 + ty * 4 + i;
        if (m < PM_) {
#pragma unroll
            for (int j2 = 0; j2 < 2; j2++) {
                float2 f = unpack2(acc[i][j2]);
                int e = tx * 4 + 2 * j2;
                atomicAdd(&ctx[((size_t)bh * PM_ + m) * DH_ + e], f.x);
                atomicAdd(&ctx[((size_t)bh * PM_ + m) * DH_ + e + 1], f.y);
            }
        }
    }
}

__global__ void dinv_kernel(const float* __restrict__ qp, const float* __restrict__ ksum,
                            float* __restrict__ dinv) {
    __shared__ float sh[8];
    int row = blockIdx.x, t = threadIdx.x;
    int bh = row >> 12;
    const float* q = qp + (size_t)row * PM_;
    const float* ks = ksum + bh * PM_;
    float s = 0.f;
    for (int i = t; i < PM_; i += 128) s = fmaf(q[i], ks[i], s);
    s = block_sum(s, sh);
    if (t == 0) dinv[row] = 1.f / s;
}

// o (bf16 hi/lo) = dinv * (qp @ ctx)
__global__ __launch_bounds__(256) void attnout_kernel(
    const float* __restrict__ qp, const float* __restrict__ ctx,
    const float* __restrict__ dinv,
    __nv_bfloat16* __restrict__ oh, __nv_bfloat16* __restrict__ ol) {
    __shared__ float Qs[16][65];
    __shared__ float Cs[16][64];
    int bh = blockIdx.y, b = bh >> 2, h = bh & 3;
    int s0 = blockIdx.x * 64;
    int t = threadIdx.x, tx = t & 15, ty = t >> 4;
    ull acc[4][2] = {};
    for (int k0 = 0; k0 < PM_; k0 += 16) {
#pragma unroll
        for (int it = 0; it < 4; it++) {
            int id = t + it * 256;
            int r = id >> 4, c = id & 15;
            int m = k0 + c;
            Qs[c][r] = (m < PM_) ? qp[((size_t)bh * S_ + s0 + r) * PM_ + m] : 0.f;
        }
        {
            int r = t >> 4, c4 = (t & 15) * 4;
            int m = k0 + r;
            float4 v4 = (m < PM_) ? *(const float4*)&ctx[((size_t)bh * PM_ + m) * DH_ + c4]
                                  : make_float4(0.f, 0.f, 0.f, 0.f);
            *(float4*)&Cs[r][c4] = v4;
        }
        __syncthreads();
#pragma unroll
        for (int k = 0; k < 16; k++) {
            ull ap[4];
#pragma unroll
            for (int i = 0; i < 4; i++) ap[i] = bcast2(Qs[k][ty * 4 + i]);
            ull bp0 = *(const ull*)&Cs[k][tx * 4];
            ull bp1 = *(const ull*)&Cs[k][tx * 4 + 2];
#pragma unroll
            for (int i = 0; i < 4; i++) {
                fma2(acc[i][0], ap[i], bp0);
                fma2(acc[i][1], ap[i], bp1);
            }
        }
        __syncthreads();
    }
#pragma unroll
    for (int i = 0; i < 4; i++) {
        int s = s0 + ty * 4 + i;
        float di = dinv[(size_t)bh * S_ + s];
#pragma unroll
        for (int j2 = 0; j2 < 2; j2++) {
            float2 f = unpack2(acc[i][j2]);
            int e = tx * 4 + 2 * j2;
            size_t base = ((size_t)(b * S_ + s)) * D_ + h * DH_ + e;
            float v0 = f.x * di, v1 = f.y * di;
            __nv_bfloat16 hi, lo;
            bf16_split(v0, hi, lo); oh[base] = hi;     ol[base] = lo;
            bf16_split(v1, hi, lo); oh[base + 1] = hi; ol[base + 1] = lo;
        }
    }
}

// ---------------------------------------------------------------------------
// Pooling
// ---------------------------------------------------------------------------
__global__ void score_kernel(const float* __restrict__ h, const float* __restrict__ p2w,
                             const float* __restrict__ p2b, const float* __restrict__ mask,
                             float* __restrict__ score) {
    __shared__ float sh[8];
    int row = blockIdx.x, t = threadIdx.x;
    float v = h[(size_t)row * D_ + t] * p2w[t];
    float s = block_sum(v, sh);
    if (t == 0) score[row] = expf(s + p2b[0]) * mask[row];
}

__global__ void ssum_kernel(const float* __restrict__ score, float* __restrict__ ssum) {
    __shared__ float sh[8];
    int b = blockIdx.x;
    float s = 0.f;
    for (int i = threadIdx.x; i < S_; i += 256) s += score[b * S_ + i];
    s = block_sum(s, sh);
    if (threadIdx.x == 0) ssum[b] = s;
}

__global__ void outzero_kernel(float* __restrict__ out) {
    int i = blockIdx.x * blockDim.x + threadIdx.x;
    if (i < B_ * D_) out[i] = 0.f;
}

__global__ void pool_kernel(const float* __restrict__ x, const float* __restrict__ score,
                            const float* __restrict__ ssum, float* __restrict__ out) {
    int b = blockIdx.x, chunk = blockIdx.y, d = threadIdx.x;
    float inv = 1.f / (ssum[b] + 1e-8f);
    float acc = 0.f;
    int s0 = chunk * (S_ / 16);
    for (int s = s0; s < s0 + S_ / 16; s++)
        acc = fmaf(x[((size_t)(b * S_ + s)) * D_ + d], score[b * S_ + s], acc);
    atomicAdd(&out[b * D_ + d], acc * inv);
}

// ---------------------------------------------------------------------------
// Host launcher
// ---------------------------------------------------------------------------
extern "C" void kernel_launch(void* const* d_in, const int* in_sizes, int n_in,
                              void* d_out, int out_size) {
    const float* emb  = (const float*)d_in[0];
    const float* mask = (const float*)d_in[1];
    const float* pos  = (const float*)d_in[2];
    const float* ln_g = (const float*)d_in[3];
    const float* ln_b = (const float*)d_in[4];
    const float* proj = (const float*)d_in[5];
    const float* Wq = (const float*)d_in[6];   const float* bq = (const float*)d_in[7];
    const float* Wk = (const float*)d_in[8];   const float* bk = (const float*)d_in[9];
    const float* Wv = (const float*)d_in[10];  const float* bv = (const float*)d_in[11];
    const float* Wo = (const float*)d_in[12];  const float* bo = (const float*)d_in[13];
    const float* ln1g = (const float*)d_in[14]; const float* ln1b = (const float*)d_in[15];
    const float* W1 = (const float*)d_in[16];  const float* b1 = (const float*)d_in[17];
    const float* W2 = (const float*)d_in[18];  const float* b2 = (const float*)d_in[19];
    const float* ln2g = (const float*)d_in[20]; const float* ln2b = (const float*)d_in[21];
    const float* p1w = (const float*)d_in[22]; const float* p1b = (const float*)d_in[23];
    const float* p2w = (const float*)d_in[24]; const float* p2b = (const float*)d_in[25];
    float* out = (float*)d_out;

    void* tp;
    float *x, *h, *q, *k, *v, *qp, *kp, *dq, *dk, *di, *ks, *cx, *sc, *ss, *bqkv;
    unsigned* km;
    __nv_bfloat16 *wth, *wtl, *hh, *hl, *oh, *ol, *fh, *fl, *xh, *xl;
    cudaGetSymbolAddress(&tp, g_x);     x  = (float*)tp;
    cudaGetSymbolAddress(&tp, g_h);     h  = (float*)tp;
    cudaGetSymbolAddress(&tp, g_q);     q  = (float*)tp;
    cudaGetSymbolAddress(&tp, g_k);     k  = (float*)tp;
    cudaGetSymbolAddress(&tp, g_v);     v  = (float*)tp;
    cudaGetSymbolAddress(&tp, g_qp);    qp = (float*)tp;
    cudaGetSymbolAddress(&tp, g_kp);    kp = (float*)tp;
    cudaGetSymbolAddress(&tp, g_diagq); dq = (float*)tp;
    cudaGetSymbolAddress(&tp, g_diagk); dk = (float*)tp;
    cudaGetSymbolAddress(&tp, g_dinv);  di = (float*)tp;
    cudaGetSymbolAddress(&tp, g_ksum);  ks = (float*)tp;
    cudaGetSymbolAddress(&tp, g_ctx);   cx = (float*)tp;
    cudaGetSymbolAddress(&tp, g_score); sc = (float*)tp;
    cudaGetSymbolAddress(&tp, g_ssum);  ss = (float*)tp;
    cudaGetSymbolAddress(&tp, g_kmaxu); km = (unsigned*)tp;
    cudaGetSymbolAddress(&tp, g_bqkv);  bqkv = (float*)tp;
    cudaGetSymbolAddress(&tp, g_wth);   wth = (__nv_bfloat16*)tp;
    cudaGetSymbolAddress(&tp, g_wtl);   wtl = (__nv_bfloat16*)tp;
    cudaGetSymbolAddress(&tp, g_hh);    hh = (__nv_bfloat16*)tp;
    cudaGetSymbolAddress(&tp, g_hl);    hl = (__nv_bfloat16*)tp;
    cudaGetSymbolAddress(&tp, g_oh);    oh = (__nv_bfloat16*)tp;
    cudaGetSymbolAddress(&tp, g_ol);    ol = (__nv_bfloat16*)tp;
    cudaGetSymbolAddress(&tp, g_fh);    fh = (__nv_bfloat16*)tp;
    cudaGetSymbolAddress(&tp, g_fl);    fl = (__nv_bfloat16*)tp;
    cudaGetSymbolAddress(&tp, g_xh);    xh = (__nv_bfloat16*)tp;
    cudaGetSymbolAddress(&tp, g_xl);    xl = (__nv_bfloat16*)tp;

    static bool attr_done = false;
    if (!attr_done) {
        cudaFuncSetAttribute(mm_gemm<0, false>, cudaFuncAttributeMaxDynamicSharedMemorySize, MM_SMEM);
        cudaFuncSetAttribute(mm_gemm<1, false>, cudaFuncAttributeMaxDynamicSharedMemorySize, MM_SMEM);
        cudaFuncSetAttribute(mm_gemm<2, false>, cudaFuncAttributeMaxDynamicSharedMemorySize, MM_SMEM);
        cudaFuncSetAttribute(mm_gemm<2, true>,  cudaFuncAttributeMaxDynamicSharedMemorySize, MM_SMEM);
        cudaFuncSetAttribute(mm_gemm<3, false>, cudaFuncAttributeMaxDynamicSharedMemorySize, MM_SMEM);
        attr_done = true;
    }

    // --- weight prep: transpose + bf16 split ---
    dim3 wb(32, 8);
    for (int l = 0; l < NL_; l++) {
        __nv_bfloat16* qh = wth + OFF_QKV + (size_t)l * 768 * 256;
        __nv_bfloat16* ql = wtl + OFF_QKV + (size_t)l * 768 * 256;
        wsplit_kernel<<<dim3(8, 8), wb>>>(Wq + (size_t)l * 65536, qh, ql, 256, 256, 0);
        wsplit_kernel<<<dim3(8, 8), wb>>>(Wk + (size_t)l * 65536, qh, ql, 256, 256, 256);
        wsplit_kernel<<<dim3(8, 8), wb>>>(Wv + (size_t)l * 65536, qh, ql, 256, 256, 512);
        wsplit_kernel<<<dim3(8, 8), wb>>>(Wo + (size_t)l * 65536,
            wth + OFF_WO + (size_t)l * 65536, wtl + OFF_WO + (size_t)l * 65536, 256, 256, 0);
        wsplit_kernel<<<dim3(32, 8), wb>>>(W1 + (size_t)l * 262144,
            wth + OFF_W1 + (size_t)l * 262144, wtl + OFF_W1 + (size_t)l * 262144, 256, 1024, 0);
        wsplit_kernel<<<dim3(8, 32), wb>>>(W2 + (size_t)l * 262144,
            wth + OFF_W2 + (size_t)l * 262144, wtl + OFF_W2 + (size_t)l * 262144, 1024, 256, 0);
    }
    wsplit_kernel<<<dim3(8, 8), wb>>>(p1w, wth + OFF_P1, wtl + OFF_P1, 256, 256, 0);
    bconcat_kernel<<<NL_, 256>>>(bq, bk, bv, bqkv);

    embed_ln_kernel<<<BS_, 256>>>(emb, pos, ln_g, ln_b, x);

    for (int l = 0; l < NL_; l++) {
        const float* pj = proj + (size_t)l * PM_ * DH_;

        // --- attention block ---
        ln_kernel<<<BS_, 256>>>(x, hh, hl, ln1g + l * D_, ln1b + l * D_);
        mm_gemm<0, false><<<dim3(6, 128), 256, MM_SMEM>>>(
            hh, hl, wth + OFF_QKV + (size_t)l * 768 * 256, wtl + OFF_QKV + (size_t)l * 768 * 256,
            bqkv + l * 768, q, k, v, nullptr, nullptr, 256, 768);

        layer_init_kernel<<<(BH_ * PM_ * DH_ + 255) / 256, 256>>>(cx, ks, km);

        dash_kernel<<<dim3(S_ / 64, BH_), 256>>>(q, pj, qp, dq, nullptr);
        dash_kernel<<<dim3(S_ / 64, BH_), 256>>>(k, pj, kp, dk, km);

        phi_exp_kernel<<<BH_ * S_, 128>>>(qp, dq, km, 0);
        phi_exp_kernel<<<BH_ * S_, 128>>>(kp, dk, km, 1);

        ksum_kernel<<<dim3(BH_, 3, 8), 128>>>(kp, ks);
        ctx_kernel<<<dim3(5, 8, BH_), 256>>>(kp, v, cx);
        dinv_kernel<<<BH_ * S_, 128>>>(qp, ks, di);
        attnout_kernel<<<dim3(S_ / 64, BH_), 256>>>(qp, cx, di, oh, ol);

        mm_gemm<2, false><<<dim3(2, 128), 256, MM_SMEM>>>(
            oh, ol, wth + OFF_WO + (size_t)l * 65536, wtl + OFF_WO + (size_t)l * 65536,
            bo + l * 256, x, nullptr, nullptr, nullptr, nullptr, 256, 256);

        // --- FFN block ---
        ln_kernel<<<BS_, 256>>>(x, hh, hl, ln2g + l * D_, ln2b + l * D_);
        mm_gemm<1, false><<<dim3(8, 128), 256, MM_SMEM>>>(
            hh, hl, wth + OFF_W1 + (size_t)l * 262144, wtl + OFF_W1 + (size_t)l * 262144,
            b1 + l * 1024, nullptr, nullptr, nullptr, fh, fl, 256, 1024);
        mm_gemm<2, true><<<dim3(2, 128), 256, MM_SMEM>>>(
            fh, fl, wth + OFF_W2 + (size_t)l * 262144, wtl + OFF_W2 + (size_t)l * 262144,
            b2 + l * 256, x, nullptr, nullptr, xh, xl, 1024, 256);
    }

    // --- attention pooling ---
    mm_gemm<3, false><<<dim3(2, 128), 256, MM_SMEM>>>(
        xh, xl, wth + OFF_P1, wtl + OFF_P1, p1b, h, nullptr, nullptr, nullptr, nullptr, 256, 256);
    score_kernel<<<BS_, 256>>>(h, p2w, p2b, mask, sc);
    ssum_kernel<<<B_, 256>>>(sc, ss);
    outzero_kernel<<<(B_ * D_ + 255) / 256, 256>>>(out);
    pool_kernel<<<dim3(B_, 16), 256>>>(x, sc, ss, out);
}

// round 7
// speedup vs baseline: 1.8228x; 1.1987x over previous
#include <cuda_runtime.h>
#include <cuda_bf16.h>
#include <cstdint>

// ---------------------------------------------------------------------------
// Problem constants
// ---------------------------------------------------------------------------
constexpr int B_  = 4;
constexpr int S_  = 4096;
constexpr int D_  = 256;
constexpr int DH_ = 64;
constexpr int NL_ = 4;
constexpr int PM_ = 266;          // nb_features
constexpr int PMP_ = 288;         // padded for mma (18 n8-tiles per half)
constexpr int FF_ = 1024;
constexpr int BS_ = B_ * S_;      // 16384 rows
constexpr int BH_ = B_ * 4;       // 16

constexpr float DN_    = 0.35355339059327373f;  // 64^-0.25
constexpr float HDN2_  = 0.0625f;               // 0.5 * dn^2
constexpr float RATIO_ = 0.06131392f;           // 266^-0.5
constexpr float KEPS_  = 1e-4f;
constexpr float LNEPS_ = 1e-12f;

typedef unsigned long long ull;

// ---------------------------------------------------------------------------
// Scratch (static device globals)
// ---------------------------------------------------------------------------
__device__ float g_x  [BS_ * D_];
__device__ float g_h  [BS_ * D_];     // pooling tanh output (fp32)
__device__ float g_v  [BS_ * D_];
__device__ float g_qp [(size_t)BH_ * S_ * PM_];
__device__ float g_kp [(size_t)BH_ * S_ * PM_];
__device__ float g_diagk[BH_ * S_];
__device__ float g_dinv [BH_ * S_];
__device__ float g_ksum [BH_ * PM_];
__device__ float g_ctx  [BH_ * PM_ * DH_];
__device__ float g_score[BS_];
__device__ float g_ssum [B_];
__device__ unsigned g_kmaxu;

// bf16 hi/lo operand buffers
constexpr size_t OFF_QKV = 0;
constexpr size_t OFF_WO  = OFF_QKV + (size_t)NL_ * 768 * 256;
constexpr size_t OFF_W1  = OFF_WO  + (size_t)NL_ * 256 * 256;
constexpr size_t OFF_W2  = OFF_W1  + (size_t)NL_ * 1024 * 256;
constexpr size_t OFF_P1  = OFF_W2  + (size_t)NL_ * 256 * 1024;
constexpr size_t WT_TOT  = OFF_P1 + 256 * 256;

__device__ __nv_bfloat16 g_wth[WT_TOT], g_wtl[WT_TOT];
__device__ float g_bqkv[NL_ * 768];
__device__ __nv_bfloat16 g_hh[BS_ * D_], g_hl[BS_ * D_];      // LN outputs
__device__ __nv_bfloat16 g_oh[BS_ * D_], g_ol[BS_ * D_];      // attnout
__device__ __nv_bfloat16 g_fh[(size_t)BS_ * FF_], g_fl[(size_t)BS_ * FF_]; // gelu
__device__ __nv_bfloat16 g_xh[BS_ * D_], g_xl[BS_ * D_];      // residual (pooling)
__device__ __nv_bfloat16 g_qh[BS_ * D_], g_ql[BS_ * D_];      // q hi/lo
__device__ __nv_bfloat16 g_kh[BS_ * D_], g_kl[BS_ * D_];      // k hi/lo
__device__ __nv_bfloat16 g_pjh[NL_ * PMP_ * DH_], g_pjl[NL_ * PMP_ * DH_];

// ---------------------------------------------------------------------------
// PTX helpers (family-portable: no tcgen05 on compute_103 targets)
// ---------------------------------------------------------------------------
__device__ __forceinline__ uint32_t smem_u32(const void* p) {
    uint32_t a;
    asm("{ .reg .u64 t; cvta.to.shared.u64 t, %1; cvt.u32.u64 %0, t; }" : "=r"(a) : "l"(p));
    return a;
}
__device__ __forceinline__ void ldsm4(unsigned& r0, unsigned& r1, unsigned& r2, unsigned& r3,
                                      uint32_t addr) {
    asm volatile("ldmatrix.sync.aligned.m8n8.x4.shared.b16 {%0,%1,%2,%3}, [%4];"
                 : "=r"(r0), "=r"(r1), "=r"(r2), "=r"(r3) : "r"(addr));
}
__device__ __forceinline__ void mma_bf16(float* d, const unsigned* a, const unsigned* b) {
    asm volatile("mma.sync.aligned.m16n8k16.row.col.f32.bf16.bf16.f32 "
                 "{%0,%1,%2,%3}, {%4,%5,%6,%7}, {%8,%9}, {%0,%1,%2,%3};"
                 : "+f"(d[0]), "+f"(d[1]), "+f"(d[2]), "+f"(d[3])
                 : "r"(a[0]), "r"(a[1]), "r"(a[2]), "r"(a[3]), "r"(b[0]), "r"(b[1]));
}
#define CP_ASYNC16(dst, src) \
    asm volatile("cp.async.cg.shared.global [%0], [%1], 16;" :: "r"(dst), "l"(src) : "memory")
#define CP_COMMIT() asm volatile("cp.async.commit_group;" ::: "memory")
#define CP_WAIT(n)  asm volatile("cp.async.wait_group %0;" :: "n"(n) : "memory")

__device__ __forceinline__ void bf16_split(float v, __nv_bfloat16& hi, __nv_bfloat16& lo) {
    hi = __float2bfloat16(v);
    lo = __float2bfloat16(v - __bfloat162float(hi));
}

// ---------------------------------------------------------------------------
// Packed f32x2 helpers (remaining FAVOR kernels)
// ---------------------------------------------------------------------------
__device__ __forceinline__ void fma2(ull& d, ull a, ull b) {
    asm("fma.rn.f32x2 %0, %1, %2, %0;" : "+l"(d) : "l"(a), "l"(b));
}
__device__ __forceinline__ ull bcast2(float x) {
    ull r;
    asm("mov.b64 %0, {%1, %1};" : "=l"(r) : "r"(__float_as_uint(x)));
    return r;
}
__device__ __forceinline__ float2 unpack2(ull d) {
    unsigned lo, hi;
    asm("mov.b64 {%0, %1}, %2;" : "=r"(lo), "=r"(hi) : "l"(d));
    return make_float2(__uint_as_float(lo), __uint_as_float(hi));
}

// ---------------------------------------------------------------------------
// Reductions
// ---------------------------------------------------------------------------
__device__ __forceinline__ float warpsum(float v) {
#pragma unroll
    for (int o = 16; o > 0; o >>= 1) v += __shfl_xor_sync(0xffffffffu, v, o);
    return v;
}
__device__ __forceinline__ float warpmax(float v) {
#pragma unroll
    for (int o = 16; o > 0; o >>= 1) v = fmaxf(v, __shfl_xor_sync(0xffffffffu, v, o));
    return v;
}
__device__ __forceinline__ float block_sum(float v, float* sh) {
    int lane = threadIdx.x & 31, w = threadIdx.x >> 5, nw = blockDim.x >> 5;
    v = warpsum(v);
    if (lane == 0) sh[w] = v;
    __syncthreads();
    if (w == 0) {
        float x = (lane < nw) ? sh[lane] : 0.f;
        x = warpsum(x);
        if (lane == 0) sh[0] = x;
    }
    __syncthreads();
    float r = sh[0];
    __syncthreads();
    return r;
}
__device__ __forceinline__ unsigned fmap(float f) {
    unsigned u = __float_as_uint(f);
    return (u & 0x80000000u) ? ~u : (u | 0x80000000u);
}
__device__ __forceinline__ float funmap(unsigned u) {
    u = (u & 0x80000000u) ? (u & 0x7FFFFFFFu) : ~u;
    return __uint_as_float(u);
}

// ---------------------------------------------------------------------------
// Weight transpose + bf16 split: W [K,N] fp32 -> Th/Tl [N,K] bf16
// ---------------------------------------------------------------------------
__global__ void wsplit_kernel(const float* __restrict__ W, __nv_bfloat16* __restrict__ Th,
                              __nv_bfloat16* __restrict__ Tl, int K, int N, int rowOff) {
    __shared__ float ts[32][33];
    int kb = blockIdx.y * 32, nb = blockIdx.x * 32;
    int tx = threadIdx.x, ty = threadIdx.y;
#pragma unroll
    for (int i = 0; i < 4; i++) {
        int k = kb + ty + i * 8;
        ts[ty + i * 8][tx] = W[(size_t)k * N + nb + tx];
    }
    __syncthreads();
#pragma unroll
    for (int i = 0; i < 4; i++) {
        int n = nb + ty + i * 8;
        int k = kb + tx;
        float v = ts[tx][ty + i * 8];
        __nv_bfloat16 hi, lo;
        bf16_split(v, hi, lo);
        size_t idx = (size_t)(rowOff + n) * K + k;
        Th[idx] = hi; Tl[idx] = lo;
    }
}

__global__ void bconcat_kernel(const float* __restrict__ bq, const float* __restrict__ bk,
                               const float* __restrict__ bv, float* __restrict__ dst) {
    int l = blockIdx.x, t = threadIdx.x;
    dst[l * 768 + t]       = bq[l * 256 + t];
    dst[l * 768 + 256 + t] = bk[l * 256 + t];
    dst[l * 768 + 512 + t] = bv[l * 256 + t];
}

// proj [L][266][64] fp32 -> [L][288][64] bf16 hi/lo, zero-padded rows
__global__ void psplit_kernel(const float* __restrict__ proj,
                              __nv_bfloat16* __restrict__ ph, __nv_bfloat16* __restrict__ pl) {
    int idx = blockIdx.x * 256 + threadIdx.x;   // < NL_ * PMP_ * 64
    int l = idx / (PMP_ * DH_);
    int rem = idx - l * (PMP_ * DH_);
    int r = rem >> 6, c = rem & 63;
    float v = (r < PM_) ? proj[((size_t)l * PM_ + r) * DH_ + c] : 0.f;
    __nv_bfloat16 hi, lo;
    bf16_split(v, hi, lo);
    ph[idx] = hi; pl[idx] = lo;
}

// ---------------------------------------------------------------------------
// LayerNorm
// ---------------------------------------------------------------------------
__global__ void embed_ln_kernel(const float* __restrict__ emb, const float* __restrict__ pos,
                                const float* __restrict__ g, const float* __restrict__ bb,
                                float* __restrict__ out) {
    __shared__ float sh[8];
    int row = blockIdx.x, t = threadIdx.x;
    float v = emb[(size_t)row * D_ + t] + pos[(size_t)(row & (S_ - 1)) * D_ + t];
    float mu = block_sum(v, sh) * (1.0f / D_);
    float d  = v - mu;
    float var = block_sum(d * d, sh) * (1.0f / D_);
    float rs = rsqrtf(var + LNEPS_);
    out[(size_t)row * D_ + t] = d * rs * g[t] + bb[t];
}

__global__ void ln_kernel(const float* __restrict__ in,
                          __nv_bfloat16* __restrict__ oh, __nv_bfloat16* __restrict__ ol,
                          const float* __restrict__ g, const float* __restrict__ bb) {
    __shared__ float sh[8];
    int row = blockIdx.x, t = threadIdx.x;
    float v = in[(size_t)row * D_ + t];
    float mu = block_sum(v, sh) * (1.0f / D_);
    float d  = v - mu;
    float var = block_sum(d * d, sh) * (1.0f / D_);
    float rs = rsqrtf(var + LNEPS_);
    float val = d * rs * g[t] + bb[t];
    __nv_bfloat16 hi, lo;
    bf16_split(val, hi, lo);
    size_t idx = (size_t)row * D_ + t;
    oh[idx] = hi; ol[idx] = lo;
}

// ---------------------------------------------------------------------------
// mma.sync bf16 GEMM: C[M,N] = A[M,K] @ Bt^T (+ bias + epilogue)
// MODE: 0 = QKV (q->Oh/Ol, k->Oh2/Ol2 bf16 hi/lo; v->O0 fp32);
//       1 = GELU->Oh/Ol; 2 = residual accumulate into O0 (+Oh/Ol if EMIT); 3 = tanh->O0
// ---------------------------------------------------------------------------
constexpr int ROWB    = 80;
constexpr int ARR_B   = 128 * ROWB;
constexpr int STAGE_B = 4 * ARR_B;
constexpr int MM_SMEM = 2 * STAGE_B;     // 81920

__device__ __forceinline__ void stage_cp(uint32_t sbase,
    const __nv_bfloat16* __restrict__ Ah, const __nv_bfloat16* __restrict__ Al,
    const __nv_bfloat16* __restrict__ Bh, const __nv_bfloat16* __restrict__ Bl,
    int row0, int col0, int K, int k0, int tid) {
#pragma unroll
    for (int i = 0; i < 8; i++) {
        const int arr = i >> 1;
        int cc = tid + (i & 1) * 256;
        int row = cc >> 2, kc = cc & 3;
        const __nv_bfloat16* src;
        int gr;
        if (arr == 0)      { src = Ah; gr = row0 + row; }
        else if (arr == 1) { src = Al; gr = row0 + row; }
        else if (arr == 2) { src = Bh; gr = col0 + row; }
        else               { src = Bl; gr = col0 + row; }
        uint32_t dst = sbase + arr * ARR_B + row * ROWB + kc * 16;
        CP_ASYNC16(dst, src + (size_t)gr * K + k0 + kc * 8);
    }
}

template <int MODE, bool EMIT>
__global__ __launch_bounds__(256) void mm_gemm(
    const __nv_bfloat16* __restrict__ Ah, const __nv_bfloat16* __restrict__ Al,
    const __nv_bfloat16* __restrict__ Bth, const __nv_bfloat16* __restrict__ Btl,
    const float* __restrict__ bias,
    float* __restrict__ O0,
    __nv_bfloat16* __restrict__ Oh, __nv_bfloat16* __restrict__ Ol,
    __nv_bfloat16* __restrict__ Oh2, __nv_bfloat16* __restrict__ Ol2,
    int K, int N) {
    extern __shared__ char smem[];
    uint32_t sb = smem_u32(smem);
    int tid = threadIdx.x, lane = tid & 31, warp = tid >> 5;
    int row0 = blockIdx.y * 128, col0 = blockIdx.x * 128;
    int wm = (warp >> 1) * 32, wn = (warp & 1) * 64;

    float acc[2][8][4] = {};

    int NT = K >> 5;
    stage_cp(sb, Ah, Al, Bth, Btl, row0, col0, K, 0, tid);
    CP_COMMIT();
    if (NT > 1) {
        stage_cp(sb + STAGE_B, Ah, Al, Bth, Btl, row0, col0, K, 32, tid);
        CP_COMMIT();
    }

    uint32_t aoff = (uint32_t)((wm + (lane & 15)) * ROWB + (lane >> 4) * 16);
    uint32_t boff = (uint32_t)((wn + ((lane >> 4) << 3) + (lane & 7)) * ROWB +
                               ((lane >> 3) & 1) * 16);

    for (int t = 0; t < NT; t++) {
        if (t + 1 < NT) CP_WAIT(1); else CP_WAIT(0);
        __syncthreads();
        uint32_t bs = sb + (t & 1) * STAGE_B;
#pragma unroll
        for (int kt = 0; kt < 2; kt++) {
            unsigned ah[2][4], al[2][4], bh[8][2], bl[8][2];
#pragma unroll
            for (int mt = 0; mt < 2; mt++) {
                uint32_t a = bs + aoff + mt * (16 * ROWB) + kt * 32;
                ldsm4(ah[mt][0], ah[mt][1], ah[mt][2], ah[mt][3], a);
                ldsm4(al[mt][0], al[mt][1], al[mt][2], al[mt][3], a + ARR_B);
            }
#pragma unroll
            for (int n2 = 0; n2 < 4; n2++) {
                uint32_t a = bs + 2 * ARR_B + boff + n2 * (16 * ROWB) + kt * 32;
                ldsm4(bh[2 * n2][0], bh[2 * n2][1], bh[2 * n2 + 1][0], bh[2 * n2 + 1][1], a);
                ldsm4(bl[2 * n2][0], bl[2 * n2][1], bl[2 * n2 + 1][0], bl[2 * n2 + 1][1],
                      a + ARR_B);
            }
#pragma unroll
            for (int mt = 0; mt < 2; mt++)
#pragma unroll
                for (int nt = 0; nt < 8; nt++) {
                    mma_bf16(acc[mt][nt], ah[mt], bh[nt]);
                    mma_bf16(acc[mt][nt], ah[mt], bl[nt]);
                    mma_bf16(acc[mt][nt], al[mt], bh[nt]);
                }
        }
        __syncthreads();
        if (t + 2 < NT) {
            stage_cp(sb + (t & 1) * STAGE_B, Ah, Al, Bth, Btl, row0, col0, K,
                     (t + 2) * 32, tid);
            CP_COMMIT();
        }
    }

#pragma unroll
    for (int mt = 0; mt < 2; mt++)
#pragma unroll
        for (int nt = 0; nt < 8; nt++) {
            int rbase = row0 + wm + mt * 16 + (lane >> 2);
            int cg = col0 + wn + nt * 8 + (lane & 3) * 2;
            float b0 = __ldg(&bias[cg]), b1 = __ldg(&bias[cg + 1]);
#pragma unroll
            for (int half = 0; half < 2; half++) {
                int row = rbase + half * 8;
                float v0 = acc[mt][nt][half * 2]     + b0;
                float v1 = acc[mt][nt][half * 2 + 1] + b1;
                if (MODE == 0) {
                    int which = cg >> 8, cl = cg & 255;
                    size_t idx = (size_t)row * 256 + cl;
                    if (which == 2) {
                        O0[idx] = v0; O0[idx + 1] = v1;
                    } else {
                        __nv_bfloat16* H = which ? Oh2 : Oh;
                        __nv_bfloat16* L = which ? Ol2 : Ol;
                        __nv_bfloat16 hi, lo;
                        bf16_split(v0, hi, lo); H[idx] = hi;     L[idx] = lo;
                        bf16_split(v1, hi, lo); H[idx + 1] = hi; L[idx + 1] = lo;
                    }
                } else if (MODE == 1) {
                    float u0 = 0.7978845608028654f * (v0 + 0.044715f * v0 * v0 * v0);
                    float u1 = 0.7978845608028654f * (v1 + 0.044715f * v1 * v1 * v1);
                    float g0 = 0.5f * v0 * (1.f + tanhf(u0));
                    float g1 = 0.5f * v1 * (1.f + tanhf(u1));
                    size_t idx = (size_t)row * N + cg;
                    __nv_bfloat16 hi, lo;
                    bf16_split(g0, hi, lo); Oh[idx] = hi;     Ol[idx] = lo;
                    bf16_split(g1, hi, lo); Oh[idx + 1] = hi; Ol[idx + 1] = lo;
                } else if (MODE == 2) {
                    size_t idx = (size_t)row * N + cg;
                    float n0 = O0[idx] + v0, n1 = O0[idx + 1] + v1;
                    O0[idx] = n0; O0[idx + 1] = n1;
                    if (EMIT) {
                        __nv_bfloat16 hi, lo;
                        bf16_split(n0, hi, lo); Oh[idx] = hi;     Ol[idx] = lo;
                        bf16_split(n1, hi, lo); Oh[idx + 1] = hi; Ol[idx + 1] = lo;
                    }
                } else {
                    size_t idx = (size_t)row * N + cg;
                    O0[idx]     = tanhf(v0);
                    O0[idx + 1] = tanhf(v1);
                }
            }
        }
}

// ---------------------------------------------------------------------------
// dash via mma: [128 s-rows] x [288 m-cols] = X[128,64] @ P^T, 3-term split.
// QPHI=true : fused phi for queries (per-row stabilizer) -> writes final qp.
// QPHI=false: writes raw dash (keys) + diag + block max -> global atomicMax.
// grid (S/128, BH), 256 threads (8 warps: 4m x 2n, warp = 32m x 144n).
// ---------------------------------------------------------------------------
constexpr int DRB = 144;                      // 64 bf16 = 128B + 16B pad
constexpr int DA_H = 0;
constexpr int DA_L = 128 * DRB;               // 18432
constexpr int DB_H = 2 * 128 * DRB;           // 36864
constexpr int DB_L = DB_H + PMP_ * DRB;       // 78336
constexpr int D_SDIAG = DB_L + PMP_ * DRB;    // 119808
constexpr int D_SRMAX = D_SDIAG + 512;
constexpr int DASH_SMEM = D_SRMAX + 512;      // 120832

template <bool QPHI>
__global__ __launch_bounds__(256, 1) void dash_mma(
    const __nv_bfloat16* __restrict__ Xh, const __nv_bfloat16* __restrict__ Xl,
    const __nv_bfloat16* __restrict__ Ph, const __nv_bfloat16* __restrict__ Pl,
    float* __restrict__ outp, float* __restrict__ diag, unsigned* __restrict__ gmax) {
    extern __shared__ char smem[];
    uint32_t sb = smem_u32(smem);
    float* sdiag = (float*)(smem + D_SDIAG);
    unsigned* srmax = (unsigned*)(smem + D_SRMAX);
    int tid = threadIdx.x, lane = tid & 31, warp = tid >> 5;
    int bh = blockIdx.y, b = bh >> 2, h = bh & 3;
    int s0 = blockIdx.x * 128;

    // stage A (q/k hi+lo, rows = s, K = 64 within head h) and B (proj hi+lo)
    for (int i = tid; i < 1024; i += 256) {
        int r = i >> 3, c = i & 7;
        const __nv_bfloat16* s1 = Xh + ((size_t)(b * S_ + s0 + r)) * D_ + h * DH_ + c * 8;
        const __nv_bfloat16* s2 = Xl + ((size_t)(b * S_ + s0 + r)) * D_ + h * DH_ + c * 8;
        CP_ASYNC16(sb + DA_H + r * DRB + c * 16, s1);
        CP_ASYNC16(sb + DA_L + r * DRB + c * 16, s2);
    }
    for (int i = tid; i < PMP_ * 8; i += 256) {
        int r = i >> 3, c = i & 7;
        CP_ASYNC16(sb + DB_H + r * DRB + c * 16, Ph + (size_t)r * DH_ + c * 8);
        CP_ASYNC16(sb + DB_L + r * DRB + c * 16, Pl + (size_t)r * DH_ + c * 8);
    }
    CP_COMMIT(); CP_WAIT(0);
    __syncthreads();

    // diag + srmax init
    if (tid < 128) {
        const __nv_bfloat16* ah = (const __nv_bfloat16*)(smem + DA_H + tid * DRB);
        const __nv_bfloat16* al = (const __nv_bfloat16*)(smem + DA_L + tid * DRB);
        float s = 0.f;
#pragma unroll
        for (int c = 0; c < DH_; c++) {
            float v = __bfloat162float(ah[c]) + __bfloat162float(al[c]);
            s = fmaf(v, v, s);
        }
        sdiag[tid] = HDN2_ * s;
        srmax[tid] = 0u;
        if (!QPHI) diag[(size_t)bh * S_ + s0 + tid] = HDN2_ * s;
    }
    __syncthreads();

    int wm = (warp >> 1) * 32, wn = (warp & 1) * 144;
    float acc[2][18][4] = {};
    uint32_t aoff = (uint32_t)((wm + (lane & 15)) * DRB + (lane >> 4) * 16);
    uint32_t boff = (uint32_t)((wn + ((lane >> 4) << 3) + (lane & 7)) * DRB +
                               ((lane >> 3) & 1) * 16);

#pragma unroll
    for (int kt = 0; kt < 4; kt++) {
        unsigned ah[2][4], al[2][4];
#pragma unroll
        for (int mt = 0; mt < 2; mt++) {
            uint32_t a = sb + DA_H + aoff + mt * (16 * DRB) + kt * 32;
            ldsm4(ah[mt][0], ah[mt][1], ah[mt][2], ah[mt][3], a);
            ldsm4(al[mt][0], al[mt][1], al[mt][2], al[mt][3], a + (DA_L - DA_H));
        }
#pragma unroll
        for (int n2 = 0; n2 < 9; n2++) {
            unsigned bhf[2][2], blf[2][2];
            uint32_t a = sb + DB_H + boff + n2 * (16 * DRB) + kt * 32;
            ldsm4(bhf[0][0], bhf[0][1], bhf[1][0], bhf[1][1], a);
            ldsm4(blf[0][0], blf[0][1], blf[1][0], blf[1][1], a + (DB_L - DB_H));
#pragma unroll
            for (int mt = 0; mt < 2; mt++)
#pragma unroll
                for (int j = 0; j < 2; j++) {
                    int nt = n2 * 2 + j;
                    mma_bf16(acc[mt][nt], ah[mt], bhf[j]);
                    mma_bf16(acc[mt][nt], ah[mt], blf[j]);
                    mma_bf16(acc[mt][nt], al[mt], bhf[j]);
                }
        }
    }

    // row-max (guarded to valid cols)
#pragma unroll
    for (int mt = 0; mt < 2; mt++)
#pragma unroll
        for (int half = 0; half < 2; half++) {
            float p = -3.4e38f;
#pragma unroll
            for (int nt = 0; nt < 18; nt++)
#pragma unroll
                for (int e = 0; e < 2; e++) {
                    int col = wn + nt * 8 + (lane & 3) * 2 + e;
                    if (col < PM_) p = fmaxf(p, DN_ * acc[mt][nt][half * 2 + e]);
                }
            p = fmaxf(p, __shfl_xor_sync(0xffffffffu, p, 1));
            p = fmaxf(p, __shfl_xor_sync(0xffffffffu, p, 2));
            if ((lane & 3) == 0)
                atomicMax(&srmax[wm + mt * 16 + (lane >> 2) + half * 8], fmap(p));
        }
    __syncthreads();

    if (!QPHI && tid == 0) {
        unsigned m = 0u;
#pragma unroll 4
        for (int i = 0; i < 128; i++) m = max(m, srmax[i]);
        atomicMax(gmax, m);
    }

    // write
#pragma unroll
    for (int mt = 0; mt < 2; mt++)
#pragma unroll
        for (int half = 0; half < 2; half++) {
            int r = wm + mt * 16 + (lane >> 2) + half * 8;
            size_t rowbase = ((size_t)bh * S_ + s0 + r) * PM_;
            float sub = 0.f;
            if (QPHI) sub = sdiag[r] + funmap(srmax[r]);
#pragma unroll
            for (int nt = 0; nt < 18; nt++)
#pragma unroll
                for (int e = 0; e < 2; e++) {
                    int col = wn + nt * 8 + (lane & 3) * 2 + e;
                    if (col < PM_) {
                        float dv = DN_ * acc[mt][nt][half * 2 + e];
                        outp[rowbase + col] =
                            QPHI ? RATIO_ * (__expf(dv - sub) + KEPS_) : dv;
                    }
                }
        }
}

// ---------------------------------------------------------------------------
// Remaining FAVOR kernels (unchanged from R6)
// ---------------------------------------------------------------------------
__global__ void layer_init_kernel(float* __restrict__ ctx, float* __restrict__ ksum,
                                  unsigned* __restrict__ km) {
    int i = blockIdx.x * blockDim.x + threadIdx.x;
    if (i < BH_ * PM_ * DH_) ctx[i] = 0.f;
    if (i < BH_ * PM_) ksum[i] = 0.f;
    if (i == 0) *km = 0u;
}

// phi for keys (global stabilizer)
__global__ void phi_exp_kernel(float* __restrict__ p, const float* __restrict__ diag,
                               const unsigned* __restrict__ gmaxu) {
    int row = blockIdx.x, t = threadIdx.x;   // 128 threads
    float* r = p + (size_t)row * PM_;
    float sub = diag[row] + funmap(*gmaxu);
    for (int i = t; i < PM_; i += 128) r[i] = RATIO_ * (__expf(r[i] - sub) + KEPS_);
}

__global__ void ksum_kernel(const float* __restrict__ kp, float* __restrict__ ksum) {
    int bh = blockIdx.x;
    int m = blockIdx.y * 128 + threadIdx.x;
    if (m >= PM_) return;
    int s0 = blockIdx.z * (S_ / 8);
    const float* base = kp + ((size_t)bh * S_ + s0) * PM_ + m;
    float s = 0.f;
    for (int i = 0; i < S_ / 8; i++) s += base[(size_t)i * PM_];
    atomicAdd(&ksum[bh * PM_ + m], s);
}

__global__ __launch_bounds__(256) void ctx_kernel(
    const float* __restrict__ kp, const float* __restrict__ v, float* __restrict__ ctx) {
    __shared__ float Kp[16][65];
    __shared__ float Vs[16][64];
    int bh = blockIdx.z, b = bh >> 2, h = bh & 3;
    int m0 = blockIdx.x * 64;
    int sch = blockIdx.y * 512;
    int t = threadIdx.x, tx = t & 15, ty = t >> 4;
    ull acc[4][2] = {};
    for (int k0 = 0; k0 < 512; k0 += 16) {
        int sbase = sch + k0;
#pragma unroll
        for (int it = 0; it < 4; it++) {
            int id = t + it * 256;
            int r = id >> 6, c = id & 63;
            int m = m0 + c;
            Kp[r][c] = (m < PM_) ? kp[((size_t)bh * S_ + sbase + r) * PM_ + m] : 0.f;
        }
        {
            int r = t >> 4, c4 = (t & 15) * 4;
            *(float4*)&Vs[r][c4] =
                *(const float4*)&v[((size_t)(b * S_ + sbase + r)) * D_ + h * DH_ + c4];
        }
        __syncthreads();
#pragma unroll
        for (int k = 0; k < 16; k++) {
            ull ap[4];
#pragma unroll
            for (int i = 0; i < 4; i++) ap[i] = bcast2(Kp[k][ty * 4 + i]);
            ull bp0 = *(const ull*)&Vs[k][tx * 4];
            ull bp1 = *(const ull*)&Vs[k][tx * 4 + 2];
#pragma unroll
            for (int i = 0; i < 4; i++) {
                fma2(acc[i][0], ap[i], bp0);
                fma2(acc[i][1], ap[i], bp1);
            }
        }
        __syncthreads();
    }
#pragma unroll
    for (int i = 0; i < 4; i++) {
        int m = m0 + ty * 4 + i;
        if (m < PM_) {
#pragma unroll
            for (int j2 = 0; j2 < 2; j2++) {
                float2 f = unpack2(acc[i][j2]);
                int e = tx * 4 + 2 * j2;
                atomicAdd(&ctx[((size_t)bh * PM_ + m) * DH_ + e], f.x);
                atomicAdd(&ctx[((size_t)bh * PM_ + m) * DH_ + e + 1], f.y);
            }
        }
    }
}

__global__ void dinv_kernel(const float* __restrict__ qp, const float* __restrict__ ksum,
                            float* __restrict__ dinv) {
    __shared__ float sh[8];
    int row = blockIdx.x, t = threadIdx.x;
    int bh = row >> 12;
    const float* q = qp + (size_t)row * PM_;
    const float* ks = ksum + bh * PM_;
    float s = 0.f;
    for (int i = t; i < PM_; i += 128) s = fmaf(q[i], ks[i], s);
    s = block_sum(s, sh);
    if (t == 0) dinv[row] = 1.f / s;
}

__global__ __launch_bounds__(256) void attnout_kernel(
    const float* __restrict__ qp, const float* __restrict__ ctx,
    const float* __restrict__ dinv,
    __nv_bfloat16* __restrict__ oh, __nv_bfloat16* __restrict__ ol) {
    __shared__ float Qs[16][65];
    __shared__ float Cs[16][64];
    int bh = blockIdx.y, b = bh >> 2, h = bh & 3;
    int s0 = blockIdx.x * 64;
    int t = threadIdx.x, tx = t & 15, ty = t >> 4;
    ull acc[4][2] = {};
    for (int k0 = 0; k0 < PM_; k0 += 16) {
#pragma unroll
        for (int it = 0; it < 4; it++) {
            int id = t + it * 256;
            int r = id >> 4, c = id & 15;
            int m = k0 + c;
            Qs[c][r] = (m < PM_) ? qp[((size_t)bh * S_ + s0 + r) * PM_ + m] : 0.f;
        }
        {
            int r = t >> 4, c4 = (t & 15) * 4;
            int m = k0 + r;
            float4 v4 = (m < PM_) ? *(const float4*)&ctx[((size_t)bh * PM_ + m) * DH_ + c4]
                                  : make_float4(0.f, 0.f, 0.f, 0.f);
            *(float4*)&Cs[r][c4] = v4;
        }
        __syncthreads();
#pragma unroll
        for (int k = 0; k < 16; k++) {
            ull ap[4];
#pragma unroll
            for (int i = 0; i < 4; i++) ap[i] = bcast2(Qs[k][ty * 4 + i]);
            ull bp0 = *(const ull*)&Cs[k][tx * 4];
            ull bp1 = *(const ull*)&Cs[k][tx * 4 + 2];
#pragma unroll
            for (int i = 0; i < 4; i++) {
                fma2(acc[i][0], ap[i], bp0);
                fma2(acc[i][1], ap[i], bp1);
            }
        }
        __syncthreads();
    }
#pragma unroll
    for (int i = 0; i < 4; i++) {
        int s = s0 + ty * 4 + i;
        float di = dinv[(size_t)bh * S_ + s];
#pragma unroll
        for (int j2 = 0; j2 < 2; j2++) {
            float2 f = unpack2(acc[i][j2]);
            int e = tx * 4 + 2 * j2;
            size_t base = ((size_t)(b * S_ + s)) * D_ + h * DH_ + e;
            float v0 = f.x * di, v1 = f.y * di;
            __nv_bfloat16 hi, lo;
            bf16_split(v0, hi, lo); oh[base] = hi;     ol[base] = lo;
            bf16_split(v1, hi, lo); oh[base + 1] = hi; ol[base + 1] = lo;
        }
    }
}

// ---------------------------------------------------------------------------
// Pooling
// ---------------------------------------------------------------------------
__global__ void score_kernel(const float* __restrict__ h, const float* __restrict__ p2w,
                             const float* __restrict__ p2b, const float* __restrict__ mask,
                             float* __restrict__ score) {
    __shared__ float sh[8];
    int row = blockIdx.x, t = threadIdx.x;
    float v = h[(size_t)row * D_ + t] * p2w[t];
    float s = block_sum(v, sh);
    if (t == 0) score[row] = expf(s + p2b[0]) * mask[row];
}

__global__ void ssum_kernel(const float* __restrict__ score, float* __restrict__ ssum) {
    __shared__ float sh[8];
    int b = blockIdx.x;
    float s = 0.f;
    for (int i = threadIdx.x; i < S_; i += 256) s += score[b * S_ + i];
    s = block_sum(s, sh);
    if (threadIdx.x == 0) ssum[b] = s;
}

__global__ void outzero_kernel(float* __restrict__ out) {
    int i = blockIdx.x * blockDim.x + threadIdx.x;
    if (i < B_ * D_) out[i] = 0.f;
}

__global__ void pool_kernel(const float* __restrict__ x, const float* __restrict__ score,
                            const float* __restrict__ ssum, float* __restrict__ out) {
    int b = blockIdx.x, chunk = blockIdx.y, d = threadIdx.x;
    float inv = 1.f / (ssum[b] + 1e-8f);
    float acc = 0.f;
    int s0 = chunk * (S_ / 16);
    for (int s = s0; s < s0 + S_ / 16; s++)
        acc = fmaf(x[((size_t)(b * S_ + s)) * D_ + d], score[b * S_ + s], acc);
    atomicAdd(&out[b * D_ + d], acc * inv);
}

// ---------------------------------------------------------------------------
// Host launcher
// ---------------------------------------------------------------------------
extern "C" void kernel_launch(void* const* d_in, const int* in_sizes, int n_in,
                              void* d_out, int out_size) {
    const float* emb  = (const float*)d_in[0];
    const float* mask = (const float*)d_in[1];
    const float* pos  = (const float*)d_in[2];
    const float* ln_g = (const float*)d_in[3];
    const float* ln_b = (const float*)d_in[4];
    const float* proj = (const float*)d_in[5];
    const float* Wq = (const float*)d_in[6];   const float* bq = (const float*)d_in[7];
    const float* Wk = (const float*)d_in[8];   const float* bk = (const float*)d_in[9];
    const float* Wv = (const float*)d_in[10];  const float* bv = (const float*)d_in[11];
    const float* Wo = (const float*)d_in[12];  const float* bo = (const float*)d_in[13];
    const float* ln1g = (const float*)d_in[14]; const float* ln1b = (const float*)d_in[15];
    const float* W1 = (const float*)d_in[16];  const float* b1 = (const float*)d_in[17];
    const float* W2 = (const float*)d_in[18];  const float* b2 = (const float*)d_in[19];
    const float* ln2g = (const float*)d_in[20]; const float* ln2b = (const float*)d_in[21];
    const float* p1w = (const float*)d_in[22]; const float* p1b = (const float*)d_in[23];
    const float* p2w = (const float*)d_in[24]; const float* p2b = (const float*)d_in[25];
    float* out = (float*)d_out;

    void* tp;
    float *x, *h, *v, *qp, *kp, *dk, *di, *ks, *cx, *sc, *ss, *bqkv;
    unsigned* km;
    __nv_bfloat16 *wth, *wtl, *hh, *hl, *oh, *ol, *fh, *fl, *xh, *xl;
    __nv_bfloat16 *qh, *ql, *kh, *kl, *pjh, *pjl;
    cudaGetSymbolAddress(&tp, g_x);     x  = (float*)tp;
    cudaGetSymbolAddress(&tp, g_h);     h  = (float*)tp;
    cudaGetSymbolAddress(&tp, g_v);     v  = (float*)tp;
    cudaGetSymbolAddress(&tp, g_qp);    qp = (float*)tp;
    cudaGetSymbolAddress(&tp, g_kp);    kp = (float*)tp;
    cudaGetSymbolAddress(&tp, g_diagk); dk = (float*)tp;
    cudaGetSymbolAddress(&tp, g_dinv);  di = (float*)tp;
    cudaGetSymbolAddress(&tp, g_ksum);  ks = (float*)tp;
    cudaGetSymbolAddress(&tp, g_ctx);   cx = (float*)tp;
    cudaGetSymbolAddress(&tp, g_score); sc = (float*)tp;
    cudaGetSymbolAddress(&tp, g_ssum);  ss = (float*)tp;
    cudaGetSymbolAddress(&tp, g_kmaxu); km = (unsigned*)tp;
    cudaGetSymbolAddress(&tp, g_bqkv);  bqkv = (float*)tp;
    cudaGetSymbolAddress(&tp, g_wth);   wth = (__nv_bfloat16*)tp;
    cudaGetSymbolAddress(&tp, g_wtl);   wtl = (__nv_bfloat16*)tp;
    cudaGetSymbolAddress(&tp, g_hh);    hh = (__nv_bfloat16*)tp;
    cudaGetSymbolAddress(&tp, g_hl);    hl = (__nv_bfloat16*)tp;
    cudaGetSymbolAddress(&tp, g_oh);    oh = (__nv_bfloat16*)tp;
    cudaGetSymbolAddress(&tp, g_ol);    ol = (__nv_bfloat16*)tp;
    cudaGetSymbolAddress(&tp, g_fh);    fh = (__nv_bfloat16*)tp;
    cudaGetSymbolAddress(&tp, g_fl);    fl = (__nv_bfloat16*)tp;
    cudaGetSymbolAddress(&tp, g_xh);    xh = (__nv_bfloat16*)tp;
    cudaGetSymbolAddress(&tp, g_xl);    xl = (__nv_bfloat16*)tp;
    cudaGetSymbolAddress(&tp, g_qh);    qh = (__nv_bfloat16*)tp;
    cudaGetSymbolAddress(&tp, g_ql);    ql = (__nv_bfloat16*)tp;
    cudaGetSymbolAddress(&tp, g_kh);    kh = (__nv_bfloat16*)tp;
    cudaGetSymbolAddress(&tp, g_kl);    kl = (__nv_bfloat16*)tp;
    cudaGetSymbolAddress(&tp, g_pjh);   pjh = (__nv_bfloat16*)tp;
    cudaGetSymbolAddress(&tp, g_pjl);   pjl = (__nv_bfloat16*)tp;

    static bool attr_done = false;
    if (!attr_done) {
        cudaFuncSetAttribute(mm_gemm<0, false>, cudaFuncAttributeMaxDynamicSharedMemorySize, MM_SMEM);
        cudaFuncSetAttribute(mm_gemm<1, false>, cudaFuncAttributeMaxDynamicSharedMemorySize, MM_SMEM);
        cudaFuncSetAttribute(mm_gemm<2, false>, cudaFuncAttributeMaxDynamicSharedMemorySize, MM_SMEM);
        cudaFuncSetAttribute(mm_gemm<2, true>,  cudaFuncAttributeMaxDynamicSharedMemorySize, MM_SMEM);
        cudaFuncSetAttribute(mm_gemm<3, false>, cudaFuncAttributeMaxDynamicSharedMemorySize, MM_SMEM);
        cudaFuncSetAttribute(dash_mma<true>,  cudaFuncAttributeMaxDynamicSharedMemorySize, DASH_SMEM);
        cudaFuncSetAttribute(dash_mma<false>, cudaFuncAttributeMaxDynamicSharedMemorySize, DASH_SMEM);
        attr_done = true;
    }

    // --- weight prep ---
    dim3 wb(32, 8);
    for (int l = 0; l < NL_; l++) {
        __nv_bfloat16* qwh = wth + OFF_QKV + (size_t)l * 768 * 256;
        __nv_bfloat16* qwl = wtl + OFF_QKV + (size_t)l * 768 * 256;
        wsplit_kernel<<<dim3(8, 8), wb>>>(Wq + (size_t)l * 65536, qwh, qwl, 256, 256, 0);
        wsplit_kernel<<<dim3(8, 8), wb>>>(Wk + (size_t)l * 65536, qwh, qwl, 256, 256, 256);
        wsplit_kernel<<<dim3(8, 8), wb>>>(Wv + (size_t)l * 65536, qwh, qwl, 256, 256, 512);
        wsplit_kernel<<<dim3(8, 8), wb>>>(Wo + (size_t)l * 65536,
            wth + OFF_WO + (size_t)l * 65536, wtl + OFF_WO + (size_t)l * 65536, 256, 256, 0);
        wsplit_kernel<<<dim3(32, 8), wb>>>(W1 + (size_t)l * 262144,
            wth + OFF_W1 + (size_t)l * 262144, wtl + OFF_W1 + (size_t)l * 262144, 256, 1024, 0);
        wsplit_kernel<<<dim3(8, 32), wb>>>(W2 + (size_t)l * 262144,
            wth + OFF_W2 + (size_t)l * 262144, wtl + OFF_W2 + (size_t)l * 262144, 1024, 256, 0);
    }
    wsplit_kernel<<<dim3(8, 8), wb>>>(p1w, wth + OFF_P1, wtl + OFF_P1, 256, 256, 0);
    bconcat_kernel<<<NL_, 256>>>(bq, bk, bv, bqkv);
    psplit_kernel<<<(NL_ * PMP_ * DH_) / 256, 256>>>(proj, pjh, pjl);

    embed_ln_kernel<<<BS_, 256>>>(emb, pos, ln_g, ln_b, x);

    for (int l = 0; l < NL_; l++) {
        // --- attention block ---
        ln_kernel<<<BS_, 256>>>(x, hh, hl, ln1g + l * D_, ln1b + l * D_);
        mm_gemm<0, false><<<dim3(6, 128), 256, MM_SMEM>>>(
            hh, hl, wth + OFF_QKV + (size_t)l * 768 * 256, wtl + OFF_QKV + (size_t)l * 768 * 256,
            bqkv + l * 768, v, qh, ql, kh, kl, 256, 768);

        layer_init_kernel<<<(BH_ * PM_ * DH_ + 255) / 256, 256>>>(cx, ks, km);

        dash_mma<true><<<dim3(S_ / 128, BH_), 256, DASH_SMEM>>>(
            qh, ql, pjh + (size_t)l * PMP_ * DH_, pjl + (size_t)l * PMP_ * DH_,
            qp, nullptr, nullptr);
        dash_mma<false><<<dim3(S_ / 128, BH_), 256, DASH_SMEM>>>(
            kh, kl, pjh + (size_t)l * PMP_ * DH_, pjl + (size_t)l * PMP_ * DH_,
            kp, dk, km);

        phi_exp_kernel<<<BH_ * S_, 128>>>(kp, dk, km);

        ksum_kernel<<<dim3(BH_, 3, 8), 128>>>(kp, ks);
        ctx_kernel<<<dim3(5, 8, BH_), 256>>>(kp, v, cx);
        dinv_kernel<<<BH_ * S_, 128>>>(qp, ks, di);
        attnout_kernel<<<dim3(S_ / 64, BH_), 256>>>(qp, cx, di, oh, ol);

        mm_gemm<2, false><<<dim3(2, 128), 256, MM_SMEM>>>(
            oh, ol, wth + OFF_WO + (size_t)l * 65536, wtl + OFF_WO + (size_t)l * 65536,
            bo + l * 256, x, nullptr, nullptr, nullptr, nullptr, 256, 256);

        // --- FFN block ---
        ln_kernel<<<BS_, 256>>>(x, hh, hl, ln2g + l * D_, ln2b + l * D_);
        mm_gemm<1, false><<<dim3(8, 128), 256, MM_SMEM>>>(
            hh, hl, wth + OFF_W1 + (size_t)l * 262144, wtl + OFF_W1 + (size_t)l * 262144,
            b1 + l * 1024, nullptr, fh, fl, nullptr, nullptr, 256, 1024);
        mm_gemm<2, true><<<dim3(2, 128), 256, MM_SMEM>>>(
            fh, fl, wth + OFF_W2 + (size_t)l * 262144, wtl + OFF_W2 + (size_t)l * 262144,
            b2 + l * 256, x, xh, xl, nullptr, nullptr, 1024, 256);
    }

    // --- attention pooling ---
    mm_gemm<3, false><<<dim3(2, 128), 256, MM_SMEM>>>(
        xh, xl, wth + OFF_P1, wtl + OFF_P1, p1b, h, nullptr, nullptr, nullptr, nullptr, 256, 256);
    score_kernel<<<BS_, 256>>>(h, p2w, p2b, mask, sc);
    ssum_kernel<<<B_, 256>>>(sc, ss);
    outzero_kernel<<<(B_ * D_ + 255) / 256, 256>>>(out);
    pool_kernel<<<dim3(B_, 16), 256>>>(x, sc, ss, out);
}

// round 8
// speedup vs baseline: 2.0595x; 1.1299x over previous
#include <cuda_runtime.h>
#include <cuda_bf16.h>
#include <cstdint>

// ---------------------------------------------------------------------------
// Problem constants
// ---------------------------------------------------------------------------
constexpr int B_  = 4;
constexpr int S_  = 4096;
constexpr int D_  = 256;
constexpr int DH_ = 64;
constexpr int NL_ = 4;
constexpr int PM_ = 266;          // nb_features
constexpr int PMP_ = 288;         // padded for mma
constexpr int FF_ = 1024;
constexpr int BS_ = B_ * S_;      // 16384 rows
constexpr int BH_ = B_ * 4;       // 16

constexpr float DN_    = 0.35355339059327373f;  // 64^-0.25
constexpr float HDN2_  = 0.0625f;               // 0.5 * dn^2
constexpr float RATIO_ = 0.06131392f;           // 266^-0.5
constexpr float KEPS_  = 1e-4f;
constexpr float LNEPS_ = 1e-12f;

// ---------------------------------------------------------------------------
// Scratch (static device globals)
// ---------------------------------------------------------------------------
__device__ float g_x  [BS_ * D_];
__device__ float g_h  [BS_ * D_];     // pooling tanh output (fp32)
__device__ float g_score[BS_];
__device__ float g_ssum [B_];
__device__ unsigned g_kmaxu;

// bf16 hi/lo operand buffers
constexpr size_t OFF_QKV = 0;
constexpr size_t OFF_WO  = OFF_QKV + (size_t)NL_ * 768 * 256;
constexpr size_t OFF_W1  = OFF_WO  + (size_t)NL_ * 256 * 256;
constexpr size_t OFF_W2  = OFF_W1  + (size_t)NL_ * 1024 * 256;
constexpr size_t OFF_P1  = OFF_W2  + (size_t)NL_ * 256 * 1024;
constexpr size_t WT_TOT  = OFF_P1 + 256 * 256;

__device__ __nv_bfloat16 g_wth[WT_TOT], g_wtl[WT_TOT];
__device__ float g_bqkv[NL_ * 768];
__device__ __nv_bfloat16 g_hh[BS_ * D_], g_hl[BS_ * D_];      // LN outputs
__device__ __nv_bfloat16 g_oh[BS_ * D_], g_ol[BS_ * D_];      // attnout
__device__ __nv_bfloat16 g_fh[(size_t)BS_ * FF_], g_fl[(size_t)BS_ * FF_]; // gelu
__device__ __nv_bfloat16 g_xh[BS_ * D_], g_xl[BS_ * D_];      // residual (pooling)
__device__ __nv_bfloat16 g_qh[BS_ * D_], g_ql[BS_ * D_];      // q hi/lo
__device__ __nv_bfloat16 g_kh[BS_ * D_], g_kl[BS_ * D_];      // k hi/lo
__device__ __nv_bfloat16 g_vh[BS_ * D_], g_vl[BS_ * D_];      // v hi/lo
__device__ __nv_bfloat16 g_pjh[NL_ * PMP_ * DH_], g_pjl[NL_ * PMP_ * DH_];

// FAVOR intermediates
__device__ __nv_bfloat16 g_qph[(size_t)BH_ * S_ * PMP_], g_qpl[(size_t)BH_ * S_ * PMP_];
__device__ __nv_bfloat16 g_eh [(size_t)BH_ * S_ * PMP_], g_el [(size_t)BH_ * S_ * PMP_];
__device__ float g_ctxE[BH_ * PMP_ * 72];
__device__ __nv_bfloat16 g_cbh[BH_ * PMP_ * 80], g_cbl[BH_ * PMP_ * 80];
__device__ float g_vsum[BH_ * 64];

// ---------------------------------------------------------------------------
// PTX helpers (family-portable: no tcgen05 on compute_103 targets)
// ---------------------------------------------------------------------------
__device__ __forceinline__ uint32_t smem_u32(const void* p) {
    uint32_t a;
    asm("{ .reg .u64 t; cvta.to.shared.u64 t, %1; cvt.u32.u64 %0, t; }" : "=r"(a) : "l"(p));
    return a;
}
__device__ __forceinline__ void ldsm4(unsigned& r0, unsigned& r1, unsigned& r2, unsigned& r3,
                                      uint32_t addr) {
    asm volatile("ldmatrix.sync.aligned.m8n8.x4.shared.b16 {%0,%1,%2,%3}, [%4];"
                 : "=r"(r0), "=r"(r1), "=r"(r2), "=r"(r3) : "r"(addr));
}
__device__ __forceinline__ void ldsm4t(unsigned& r0, unsigned& r1, unsigned& r2, unsigned& r3,
                                       uint32_t addr) {
    asm volatile("ldmatrix.sync.aligned.m8n8.x4.trans.shared.b16 {%0,%1,%2,%3}, [%4];"
                 : "=r"(r0), "=r"(r1), "=r"(r2), "=r"(r3) : "r"(addr));
}
__device__ __forceinline__ void mma_bf16(float* d, const unsigned* a, const unsigned* b) {
    asm volatile("mma.sync.aligned.m16n8k16.row.col.f32.bf16.bf16.f32 "
                 "{%0,%1,%2,%3}, {%4,%5,%6,%7}, {%8,%9}, {%0,%1,%2,%3};"
                 : "+f"(d[0]), "+f"(d[1]), "+f"(d[2]), "+f"(d[3])
                 : "r"(a[0]), "r"(a[1]), "r"(a[2]), "r"(a[3]), "r"(b[0]), "r"(b[1]));
}
#define CP_ASYNC16(dst, src) \
    asm volatile("cp.async.cg.shared.global [%0], [%1], 16;" :: "r"(dst), "l"(src) : "memory")
#define CP_COMMIT() asm volatile("cp.async.commit_group;" ::: "memory")
#define CP_WAIT(n)  asm volatile("cp.async.wait_group %0;" :: "n"(n) : "memory")

__device__ __forceinline__ void bf16_split(float v, __nv_bfloat16& hi, __nv_bfloat16& lo) {
    hi = __float2bfloat16(v);
    lo = __float2bfloat16(v - __bfloat162float(hi));
}

// ---------------------------------------------------------------------------
// Reductions
// ---------------------------------------------------------------------------
__device__ __forceinline__ float warpsum(float v) {
#pragma unroll
    for (int o = 16; o > 0; o >>= 1) v += __shfl_xor_sync(0xffffffffu, v, o);
    return v;
}
__device__ __forceinline__ float block_sum(float v, float* sh) {
    int lane = threadIdx.x & 31, w = threadIdx.x >> 5, nw = blockDim.x >> 5;
    v = warpsum(v);
    if (lane == 0) sh[w] = v;
    __syncthreads();
    if (w == 0) {
        float x = (lane < nw) ? sh[lane] : 0.f;
        x = warpsum(x);
        if (lane == 0) sh[0] = x;
    }
    __syncthreads();
    float r = sh[0];
    __syncthreads();
    return r;
}
__device__ __forceinline__ unsigned fmap(float f) {
    unsigned u = __float_as_uint(f);
    return (u & 0x80000000u) ? ~u : (u | 0x80000000u);
}
__device__ __forceinline__ float funmap(unsigned u) {
    u = (u & 0x80000000u) ? (u & 0x7FFFFFFFu) : ~u;
    return __uint_as_float(u);
}

// ---------------------------------------------------------------------------
// Weight transpose + bf16 split
// ---------------------------------------------------------------------------
__global__ void wsplit_kernel(const float* __restrict__ W, __nv_bfloat16* __restrict__ Th,
                              __nv_bfloat16* __restrict__ Tl, int K, int N, int rowOff) {
    __shared__ float ts[32][33];
    int kb = blockIdx.y * 32, nb = blockIdx.x * 32;
    int tx = threadIdx.x, ty = threadIdx.y;
#pragma unroll
    for (int i = 0; i < 4; i++) {
        int k = kb + ty + i * 8;
        ts[ty + i * 8][tx] = W[(size_t)k * N + nb + tx];
    }
    __syncthreads();
#pragma unroll
    for (int i = 0; i < 4; i++) {
        int n = nb + ty + i * 8;
        int k = kb + tx;
        float v = ts[tx][ty + i * 8];
        __nv_bfloat16 hi, lo;
        bf16_split(v, hi, lo);
        size_t idx = (size_t)(rowOff + n) * K + k;
        Th[idx] = hi; Tl[idx] = lo;
    }
}

__global__ void bconcat_kernel(const float* __restrict__ bq, const float* __restrict__ bk,
                               const float* __restrict__ bv, float* __restrict__ dst) {
    int l = blockIdx.x, t = threadIdx.x;
    dst[l * 768 + t]       = bq[l * 256 + t];
    dst[l * 768 + 256 + t] = bk[l * 256 + t];
    dst[l * 768 + 512 + t] = bv[l * 256 + t];
}

__global__ void psplit_kernel(const float* __restrict__ proj,
                              __nv_bfloat16* __restrict__ ph, __nv_bfloat16* __restrict__ pl) {
    int idx = blockIdx.x * 256 + threadIdx.x;
    int l = idx / (PMP_ * DH_);
    int rem = idx - l * (PMP_ * DH_);
    int r = rem >> 6, c = rem & 63;
    float v = (r < PM_) ? proj[((size_t)l * PM_ + r) * DH_ + c] : 0.f;
    __nv_bfloat16 hi, lo;
    bf16_split(v, hi, lo);
    ph[idx] = hi; pl[idx] = lo;
}

// ---------------------------------------------------------------------------
// LayerNorm
// ---------------------------------------------------------------------------
__global__ void embed_ln_kernel(const float* __restrict__ emb, const float* __restrict__ pos,
                                const float* __restrict__ g, const float* __restrict__ bb,
                                float* __restrict__ out) {
    __shared__ float sh[8];
    int row = blockIdx.x, t = threadIdx.x;
    float v = emb[(size_t)row * D_ + t] + pos[(size_t)(row & (S_ - 1)) * D_ + t];
    float mu = block_sum(v, sh) * (1.0f / D_);
    float d  = v - mu;
    float var = block_sum(d * d, sh) * (1.0f / D_);
    float rs = rsqrtf(var + LNEPS_);
    out[(size_t)row * D_ + t] = d * rs * g[t] + bb[t];
}

__global__ void ln_kernel(const float* __restrict__ in,
                          __nv_bfloat16* __restrict__ oh, __nv_bfloat16* __restrict__ ol,
                          const float* __restrict__ g, const float* __restrict__ bb) {
    __shared__ float sh[8];
    int row = blockIdx.x, t = threadIdx.x;
    float v = in[(size_t)row * D_ + t];
    float mu = block_sum(v, sh) * (1.0f / D_);
    float d  = v - mu;
    float var = block_sum(d * d, sh) * (1.0f / D_);
    float rs = rsqrtf(var + LNEPS_);
    float val = d * rs * g[t] + bb[t];
    __nv_bfloat16 hi, lo;
    bf16_split(val, hi, lo);
    size_t idx = (size_t)row * D_ + t;
    oh[idx] = hi; ol[idx] = lo;
}

// ---------------------------------------------------------------------------
// mma.sync bf16 GEMM (dense): C = A @ Bt^T (+bias +epilogue)
// MODE: 0 = QKV (q->Oh/Ol, k->Oh2/Ol2, v->Oh3/Ol3);
//       1 = GELU->Oh/Ol; 2 = residual accumulate into O0 (+Oh/Ol if EMIT); 3 = tanh->O0
// ---------------------------------------------------------------------------
constexpr int ROWB    = 80;
constexpr int ARR_B   = 128 * ROWB;
constexpr int STAGE_B = 4 * ARR_B;
constexpr int MM_SMEM = 2 * STAGE_B;     // 81920

__device__ __forceinline__ void stage_cp(uint32_t sbase,
    const __nv_bfloat16* __restrict__ Ah, const __nv_bfloat16* __restrict__ Al,
    const __nv_bfloat16* __restrict__ Bh, const __nv_bfloat16* __restrict__ Bl,
    int row0, int col0, int K, int k0, int tid) {
#pragma unroll
    for (int i = 0; i < 8; i++) {
        const int arr = i >> 1;
        int cc = tid + (i & 1) * 256;
        int row = cc >> 2, kc = cc & 3;
        const __nv_bfloat16* src;
        int gr;
        if (arr == 0)      { src = Ah; gr = row0 + row; }
        else if (arr == 1) { src = Al; gr = row0 + row; }
        else if (arr == 2) { src = Bh; gr = col0 + row; }
        else               { src = Bl; gr = col0 + row; }
        uint32_t dst = sbase + arr * ARR_B + row * ROWB + kc * 16;
        CP_ASYNC16(dst, src + (size_t)gr * K + k0 + kc * 8);
    }
}

template <int MODE, bool EMIT>
__global__ __launch_bounds__(256) void mm_gemm(
    const __nv_bfloat16* __restrict__ Ah, const __nv_bfloat16* __restrict__ Al,
    const __nv_bfloat16* __restrict__ Bth, const __nv_bfloat16* __restrict__ Btl,
    const float* __restrict__ bias,
    float* __restrict__ O0,
    __nv_bfloat16* __restrict__ Oh, __nv_bfloat16* __restrict__ Ol,
    __nv_bfloat16* __restrict__ Oh2, __nv_bfloat16* __restrict__ Ol2,
    __nv_bfloat16* __restrict__ Oh3, __nv_bfloat16* __restrict__ Ol3,
    int K, int N) {
    extern __shared__ char smem[];
    uint32_t sb = smem_u32(smem);
    int tid = threadIdx.x, lane = tid & 31, warp = tid >> 5;
    int row0 = blockIdx.y * 128, col0 = blockIdx.x * 128;
    int wm = (warp >> 1) * 32, wn = (warp & 1) * 64;

    float acc[2][8][4] = {};

    int NT = K >> 5;
    stage_cp(sb, Ah, Al, Bth, Btl, row0, col0, K, 0, tid);
    CP_COMMIT();
    if (NT > 1) {
        stage_cp(sb + STAGE_B, Ah, Al, Bth, Btl, row0, col0, K, 32, tid);
        CP_COMMIT();
    }

    uint32_t aoff = (uint32_t)((wm + (lane & 15)) * ROWB + (lane >> 4) * 16);
    uint32_t boff = (uint32_t)((wn + ((lane >> 4) << 3) + (lane & 7)) * ROWB +
                               ((lane >> 3) & 1) * 16);

    for (int t = 0; t < NT; t++) {
        if (t + 1 < NT) CP_WAIT(1); else CP_WAIT(0);
        __syncthreads();
        uint32_t bs = sb + (t & 1) * STAGE_B;
#pragma unroll
        for (int kt = 0; kt < 2; kt++) {
            unsigned ah[2][4], al[2][4], bh[8][2], bl[8][2];
#pragma unroll
            for (int mt = 0; mt < 2; mt++) {
                uint32_t a = bs + aoff + mt * (16 * ROWB) + kt * 32;
                ldsm4(ah[mt][0], ah[mt][1], ah[mt][2], ah[mt][3], a);
                ldsm4(al[mt][0], al[mt][1], al[mt][2], al[mt][3], a + ARR_B);
            }
#pragma unroll
            for (int n2 = 0; n2 < 4; n2++) {
                uint32_t a = bs + 2 * ARR_B + boff + n2 * (16 * ROWB) + kt * 32;
                ldsm4(bh[2 * n2][0], bh[2 * n2][1], bh[2 * n2 + 1][0], bh[2 * n2 + 1][1], a);
                ldsm4(bl[2 * n2][0], bl[2 * n2][1], bl[2 * n2 + 1][0], bl[2 * n2 + 1][1],
                      a + ARR_B);
            }
#pragma unroll
            for (int mt = 0; mt < 2; mt++)
#pragma unroll
                for (int nt = 0; nt < 8; nt++) {
                    mma_bf16(acc[mt][nt], ah[mt], bh[nt]);
                    mma_bf16(acc[mt][nt], ah[mt], bl[nt]);
                    mma_bf16(acc[mt][nt], al[mt], bh[nt]);
                }
        }
        __syncthreads();
        if (t + 2 < NT) {
            stage_cp(sb + (t & 1) * STAGE_B, Ah, Al, Bth, Btl, row0, col0, K,
                     (t + 2) * 32, tid);
            CP_COMMIT();
        }
    }

#pragma unroll
    for (int mt = 0; mt < 2; mt++)
#pragma unroll
        for (int nt = 0; nt < 8; nt++) {
            int rbase = row0 + wm + mt * 16 + (lane >> 2);
            int cg = col0 + wn + nt * 8 + (lane & 3) * 2;
            float b0 = __ldg(&bias[cg]), b1 = __ldg(&bias[cg + 1]);
#pragma unroll
            for (int half = 0; half < 2; half++) {
                int row = rbase + half * 8;
                float v0 = acc[mt][nt][half * 2]     + b0;
                float v1 = acc[mt][nt][half * 2 + 1] + b1;
                if (MODE == 0) {
                    int which = cg >> 8, cl = cg & 255;
                    size_t idx = (size_t)row * 256 + cl;
                    __nv_bfloat16* H = (which == 0) ? Oh : (which == 1) ? Oh2 : Oh3;
                    __nv_bfloat16* L = (which == 0) ? Ol : (which == 1) ? Ol2 : Ol3;
                    __nv_bfloat16 hi, lo;
                    bf16_split(v0, hi, lo); H[idx] = hi;     L[idx] = lo;
                    bf16_split(v1, hi, lo); H[idx + 1] = hi; L[idx + 1] = lo;
                } else if (MODE == 1) {
                    float u0 = 0.7978845608028654f * (v0 + 0.044715f * v0 * v0 * v0);
                    float u1 = 0.7978845608028654f * (v1 + 0.044715f * v1 * v1 * v1);
                    float g0 = 0.5f * v0 * (1.f + tanhf(u0));
                    float g1 = 0.5f * v1 * (1.f + tanhf(u1));
                    size_t idx = (size_t)row * N + cg;
                    __nv_bfloat16 hi, lo;
                    bf16_split(g0, hi, lo); Oh[idx] = hi;     Ol[idx] = lo;
                    bf16_split(g1, hi, lo); Oh[idx + 1] = hi; Ol[idx + 1] = lo;
                } else if (MODE == 2) {
                    size_t idx = (size_t)row * N + cg;
                    float n0 = O0[idx] + v0, n1 = O0[idx + 1] + v1;
                    O0[idx] = n0; O0[idx + 1] = n1;
                    if (EMIT) {
                        __nv_bfloat16 hi, lo;
                        bf16_split(n0, hi, lo); Oh[idx] = hi;     Ol[idx] = lo;
                        bf16_split(n1, hi, lo); Oh[idx + 1] = hi; Ol[idx + 1] = lo;
                    }
                } else {
                    size_t idx = (size_t)row * N + cg;
                    O0[idx]     = tanhf(v0);
                    O0[idx + 1] = tanhf(v1);
                }
            }
        }
}

// ---------------------------------------------------------------------------
// dash via mma -> bf16 hi/lo output [bh][s][288]
// QPHI=true : qp = ratio*(exp(dash - diag - rowmax) + eps)
// QPHI=false: E  = exp(dash - diag); block max of raw dash -> gmax
// ---------------------------------------------------------------------------
constexpr int DRB = 144;
constexpr int DA_H = 0;
constexpr int DA_L = 128 * DRB;
constexpr int DB_H = 2 * 128 * DRB;
constexpr int DB_L = DB_H + PMP_ * DRB;
constexpr int D_SDIAG = DB_L + PMP_ * DRB;
constexpr int D_SRMAX = D_SDIAG + 512;
constexpr int DASH_SMEM = D_SRMAX + 512;

template <bool QPHI>
__global__ __launch_bounds__(256, 1) void dash_mma(
    const __nv_bfloat16* __restrict__ Xh, const __nv_bfloat16* __restrict__ Xl,
    const __nv_bfloat16* __restrict__ Ph, const __nv_bfloat16* __restrict__ Pl,
    __nv_bfloat16* __restrict__ outh, __nv_bfloat16* __restrict__ outl,
    unsigned* __restrict__ gmax) {
    extern __shared__ char smem[];
    uint32_t sb = smem_u32(smem);
    float* sdiag = (float*)(smem + D_SDIAG);
    unsigned* srmax = (unsigned*)(smem + D_SRMAX);
    int tid = threadIdx.x, lane = tid & 31, warp = tid >> 5;
    int bh = blockIdx.y, b = bh >> 2, h = bh & 3;
    int s0 = blockIdx.x * 128;

    for (int i = tid; i < 1024; i += 256) {
        int r = i >> 3, c = i & 7;
        const __nv_bfloat16* s1 = Xh + ((size_t)(b * S_ + s0 + r)) * D_ + h * DH_ + c * 8;
        const __nv_bfloat16* s2 = Xl + ((size_t)(b * S_ + s0 + r)) * D_ + h * DH_ + c * 8;
        CP_ASYNC16(sb + DA_H + r * DRB + c * 16, s1);
        CP_ASYNC16(sb + DA_L + r * DRB + c * 16, s2);
    }
    for (int i = tid; i < PMP_ * 8; i += 256) {
        int r = i >> 3, c = i & 7;
        CP_ASYNC16(sb + DB_H + r * DRB + c * 16, Ph + (size_t)r * DH_ + c * 8);
        CP_ASYNC16(sb + DB_L + r * DRB + c * 16, Pl + (size_t)r * DH_ + c * 8);
    }
    CP_COMMIT(); CP_WAIT(0);
    __syncthreads();

    if (tid < 128) {
        const __nv_bfloat16* ah = (const __nv_bfloat16*)(smem + DA_H + tid * DRB);
        const __nv_bfloat16* al = (const __nv_bfloat16*)(smem + DA_L + tid * DRB);
        float s = 0.f;
#pragma unroll
        for (int c = 0; c < DH_; c++) {
            float v = __bfloat162float(ah[c]) + __bfloat162float(al[c]);
            s = fmaf(v, v, s);
        }
        sdiag[tid] = HDN2_ * s;
        srmax[tid] = 0u;
    }
    __syncthreads();

    int wm = (warp >> 1) * 32, wn = (warp & 1) * 144;
    float acc[2][18][4] = {};
    uint32_t aoff = (uint32_t)((wm + (lane & 15)) * DRB + (lane >> 4) * 16);
    uint32_t boff = (uint32_t)((wn + ((lane >> 4) << 3) + (lane & 7)) * DRB +
                               ((lane >> 3) & 1) * 16);

#pragma unroll
    for (int kt = 0; kt < 4; kt++) {
        unsigned ah[2][4], al[2][4];
#pragma unroll
        for (int mt = 0; mt < 2; mt++) {
            uint32_t a = sb + DA_H + aoff + mt * (16 * DRB) + kt * 32;
            ldsm4(ah[mt][0], ah[mt][1], ah[mt][2], ah[mt][3], a);
            ldsm4(al[mt][0], al[mt][1], al[mt][2], al[mt][3], a + (DA_L - DA_H));
        }
#pragma unroll
        for (int n2 = 0; n2 < 9; n2++) {
            unsigned bhf[2][2], blf[2][2];
            uint32_t a = sb + DB_H + boff + n2 * (16 * DRB) + kt * 32;
            ldsm4(bhf[0][0], bhf[0][1], bhf[1][0], bhf[1][1], a);
            ldsm4(blf[0][0], blf[0][1], blf[1][0], blf[1][1], a + (DB_L - DB_H));
#pragma unroll
            for (int mt = 0; mt < 2; mt++)
#pragma unroll
                for (int j = 0; j < 2; j++) {
                    int nt = n2 * 2 + j;
                    mma_bf16(acc[mt][nt], ah[mt], bhf[j]);
                    mma_bf16(acc[mt][nt], ah[mt], blf[j]);
                    mma_bf16(acc[mt][nt], al[mt], bhf[j]);
                }
        }
    }

    // per-row max of raw dash (valid cols only)
#pragma unroll
    for (int mt = 0; mt < 2; mt++)
#pragma unroll
        for (int half = 0; half < 2; half++) {
            float p = -3.4e38f;
#pragma unroll
            for (int nt = 0; nt < 18; nt++)
#pragma unroll
                for (int e = 0; e < 2; e++) {
                    int col = wn + nt * 8 + (lane & 3) * 2 + e;
                    if (col < PM_) p = fmaxf(p, DN_ * acc[mt][nt][half * 2 + e]);
                }
            p = fmaxf(p, __shfl_xor_sync(0xffffffffu, p, 1));
            p = fmaxf(p, __shfl_xor_sync(0xffffffffu, p, 2));
            if ((lane & 3) == 0)
                atomicMax(&srmax[wm + mt * 16 + (lane >> 2) + half * 8], fmap(p));
        }
    __syncthreads();

    if (!QPHI && tid == 0) {
        unsigned m = 0u;
#pragma unroll 4
        for (int i = 0; i < 128; i++) m = max(m, srmax[i]);
        atomicMax(gmax, m);
    }

#pragma unroll
    for (int mt = 0; mt < 2; mt++)
#pragma unroll
        for (int half = 0; half < 2; half++) {
            int r = wm + mt * 16 + (lane >> 2) + half * 8;
            size_t rowbase = ((size_t)bh * S_ + s0 + r) * PMP_;
            float sub = QPHI ? (sdiag[r] + funmap(srmax[r])) : sdiag[r];
#pragma unroll
            for (int nt = 0; nt < 18; nt++) {
                int colb = wn + nt * 8 + (lane & 3) * 2;
                float o[2];
#pragma unroll
                for (int e = 0; e < 2; e++) {
                    int col = colb + e;
                    float val = 0.f;
                    if (col < PM_) {
                        float dv = DN_ * acc[mt][nt][half * 2 + e];
                        val = QPHI ? RATIO_ * (__expf(dv - sub) + KEPS_)
                                   : __expf(dv - sub);
                    }
                    o[e] = val;
                }
                __nv_bfloat16 h0, l0, h1, l1;
                bf16_split(o[0], h0, l0);
                bf16_split(o[1], h1, l1);
                *(__nv_bfloat162*)(outh + rowbase + colb) =
                    __nv_bfloat162(h0, h1);
                *(__nv_bfloat162*)(outl + rowbase + colb) =
                    __nv_bfloat162(l0, l1);
            }
        }
}

// ---------------------------------------------------------------------------
// ctx via mma: ctxE[bh][m][e] = sum_s E[s][m] * Vx[s][e], Vx col 64 = 1 (ksum)
// grid (BH, 8) split-K; A = E^T via ldmatrix.trans; atomicAdd fp32.
// ---------------------------------------------------------------------------
constexpr int CE_ST = 592;
constexpr int CV_ST = 160;
constexpr int C_EH = 0;
constexpr int C_EL = 32 * CE_ST;
constexpr int C_VH = 2 * 32 * CE_ST;
constexpr int C_VL = C_VH + 32 * CV_ST;
constexpr int CSTAGE = C_VL + 32 * CV_ST;     // 48128
constexpr int CTX_SMEM = 2 * CSTAGE;          // 96256

__global__ __launch_bounds__(256) void ctx_mma(
    const __nv_bfloat16* __restrict__ Eh, const __nv_bfloat16* __restrict__ El,
    const __nv_bfloat16* __restrict__ Vh, const __nv_bfloat16* __restrict__ Vl,
    float* __restrict__ ctxE) {
    extern __shared__ char smem[];
    uint32_t sb = smem_u32(smem);
    int tid = threadIdx.x, lane = tid & 31, warp = tid >> 5;
    int bh = blockIdx.x, b = bh >> 2, h = bh & 3;
    int sbase = blockIdx.y * 512;

    auto stage = [&](int buf, int chunk) {
        uint32_t base = sb + buf * CSTAGE;
        int s0 = sbase + chunk * 32;
        for (int i = tid; i < 1152; i += 256) {
            int r = i / 36, c = i - r * 36;
            size_t g = ((size_t)bh * S_ + s0 + r) * PMP_ + c * 8;
            CP_ASYNC16(base + C_EH + r * CE_ST + c * 16, Eh + g);
            CP_ASYNC16(base + C_EL + r * CE_ST + c * 16, El + g);
        }
        {
            int i = tid;
            if (i < 256) {
                int r = i >> 3, c = i & 7;
                size_t g = ((size_t)(b * S_ + s0 + r)) * D_ + h * DH_ + c * 8;
                CP_ASYNC16(base + C_VH + r * CV_ST + c * 16, Vh + g);
                CP_ASYNC16(base + C_VL + r * CV_ST + c * 16, Vl + g);
            }
        }
        if (tid < 64) {
            int r = tid >> 1, half2 = tid & 1;
            uint4 z = make_uint4(0, 0, 0, 0);
            uint4 one = make_uint4(0x00003F80u, 0, 0, 0);
            uint32_t off = (uint32_t)(r * CV_ST + 128 + half2 * 16);
            *(uint4*)(smem + buf * CSTAGE + C_VH + off) = (half2 == 0) ? one : z;
            *(uint4*)(smem + buf * CSTAGE + C_VL + off) = z;
        }
    };

    stage(0, 0); CP_COMMIT();
    stage(1, 1); CP_COMMIT();

    int mts[3];
    mts[0] = warp * 2; mts[1] = warp * 2 + 1; mts[2] = (warp < 2) ? 16 + warp : -1;
    float acc[3][9][4] = {};

    for (int t = 0; t < 16; t++) {
        if (t + 1 < 16) CP_WAIT(1); else CP_WAIT(0);
        __syncthreads();
        uint32_t bs = sb + (t & 1) * CSTAGE;
#pragma unroll
        for (int kt = 0; kt < 2; kt++) {
            int krA = (lane & 7) + ((lane >> 4) & 1) * 8 + kt * 16;
            int mcolbit = ((lane >> 3) & 1) * 8;
            unsigned ah[3][4], al[3][4];
#pragma unroll
            for (int mt = 0; mt < 3; mt++) {
                if (mts[mt] < 0) break;
                uint32_t a = bs + C_EH + krA * CE_ST + (mts[mt] * 16 + mcolbit) * 2;
                ldsm4t(ah[mt][0], ah[mt][1], ah[mt][2], ah[mt][3], a);
                ldsm4t(al[mt][0], al[mt][1], al[mt][2], al[mt][3], a + (C_EL - C_EH));
            }
            int krB = (lane & 7) + ((lane >> 3) & 1) * 8 + kt * 16;
            int ncolbit = (lane >> 4) * 8;
#pragma unroll
            for (int p = 0; p < 5; p++) {
                unsigned bhf[4], blf[4];
                uint32_t a = bs + C_VH + krB * CV_ST + (p * 16 + ncolbit) * 2;
                ldsm4t(bhf[0], bhf[1], bhf[2], bhf[3], a);
                ldsm4t(blf[0], blf[1], blf[2], blf[3], a + (C_VL - C_VH));
#pragma unroll
                for (int j = 0; j < 2; j++) {
                    int nt = p * 2 + j;
                    if (nt > 8) break;
#pragma unroll
                    for (int mt = 0; mt < 3; mt++) {
                        if (mts[mt] < 0) break;
                        mma_bf16(acc[mt][nt], ah[mt], bhf + j * 2);
                        mma_bf16(acc[mt][nt], ah[mt], blf + j * 2);
                        mma_bf16(acc[mt][nt], al[mt], bhf + j * 2);
                    }
                }
            }
        }
        __syncthreads();
        if (t + 2 < 16) { stage(t & 1, t + 2); CP_COMMIT(); }
    }

#pragma unroll
    for (int mt = 0; mt < 3; mt++) {
        if (mts[mt] < 0) break;
#pragma unroll
        for (int nt = 0; nt < 9; nt++)
#pragma unroll
            for (int half = 0; half < 2; half++) {
                int m = mts[mt] * 16 + (lane >> 2) + half * 8;
                int e = nt * 8 + (lane & 3) * 2;
                float* dst = ctxE + ((size_t)bh * PMP_ + m) * 72 + e;
                atomicAdd(dst,     acc[mt][nt][half * 2]);
                atomicAdd(dst + 1, acc[mt][nt][half * 2 + 1]);
            }
    }
}

// vsum[bh][e] = sum_s v[b][s][h*64+e]
__global__ void vsum_kernel(const __nv_bfloat16* __restrict__ vh,
                            const __nv_bfloat16* __restrict__ vl,
                            float* __restrict__ vsum) {
    int bh = blockIdx.x, b = bh >> 2, h = bh & 3;
    int e = threadIdx.x;
    int s0 = blockIdx.y * 512;
    float s = 0.f;
    for (int i = 0; i < 512; i++) {
        size_t idx = ((size_t)(b * S_ + s0 + i)) * D_ + h * DH_ + e;
        s += __bfloat162float(vh[idx]) + __bfloat162float(vl[idx]);
    }
    atomicAdd(&vsum[bh * 64 + e], s);
}

// ctx_b = a*ctxE + correction; bf16 hi/lo [bh][288][80]
__global__ void ctxcorr_kernel(const float* __restrict__ ctxE, const float* __restrict__ vsum,
                               const unsigned* __restrict__ gmax,
                               __nv_bfloat16* __restrict__ cbh, __nv_bfloat16* __restrict__ cbl) {
    int idx = blockIdx.x * 256 + threadIdx.x;
    if (idx >= BH_ * PMP_ * 80) return;
    int bh = idx / (PMP_ * 80);
    int rem = idx - bh * (PMP_ * 80);
    int m = rem / 80, e = rem - m * 80;
    float a = RATIO_ * __expf(-funmap(*gmax));
    float c = RATIO_ * KEPS_;
    float val = 0.f;
    if (m < PM_ && e < 72) {
        float base = ctxE[((size_t)bh * PMP_ + m) * 72 + e];
        float corr = (e < 64) ? c * vsum[bh * 64 + e] : ((e == 64) ? c * (float)S_ : 0.f);
        val = a * base + corr;
    }
    __nv_bfloat16 hi, lo;
    bf16_split(val, hi, lo);
    cbh[idx] = hi; cbl[idx] = lo;
}

// ---------------------------------------------------------------------------
// attnout via mma: O[s][e] = (qp[s]·ctx_b[:,e]) / (qp[s]·ksum)  -> oh/ol bf16
// grid (S/128, BH); n covers 72 cols (col 64 = denominator).
// ---------------------------------------------------------------------------
constexpr int AQ_ST = 80;
constexpr int AB_ST = 160;
constexpr int A_QH = 0;
constexpr int A_QL = 128 * AQ_ST;
constexpr int A_BH2 = 2 * 128 * AQ_ST;
constexpr int A_BL2 = A_BH2 + 32 * AB_ST;
constexpr int ASTAGE = A_BL2 + 32 * AB_ST;    // 30720
constexpr int A_SDEN = 2 * ASTAGE;            // 61440
constexpr int ATT_SMEM = A_SDEN + 512;        // 61952

__global__ __launch_bounds__(256) void attnout_mma(
    const __nv_bfloat16* __restrict__ Qh, const __nv_bfloat16* __restrict__ Ql,
    const __nv_bfloat16* __restrict__ Cbh, const __nv_bfloat16* __restrict__ Cbl,
    __nv_bfloat16* __restrict__ oh, __nv_bfloat16* __restrict__ ol) {
    extern __shared__ char smem[];
    uint32_t sb = smem_u32(smem);
    float* sden = (float*)(smem + A_SDEN);
    int tid = threadIdx.x, lane = tid & 31, warp = tid >> 5;
    int bh = blockIdx.y, b = bh >> 2, h = bh & 3;
    int s0 = blockIdx.x * 128;

    auto stage = [&](int buf, int chunk) {
        uint32_t base = sb + buf * ASTAGE;
        int k0 = chunk * 32;
        for (int i = tid; i < 512; i += 256) {
            int r = i >> 2, c = i & 3;
            size_t g = ((size_t)bh * S_ + s0 + r) * PMP_ + k0 + c * 8;
            CP_ASYNC16(base + A_QH + r * AQ_ST + c * 16, Qh + g);
            CP_ASYNC16(base + A_QL + r * AQ_ST + c * 16, Ql + g);
        }
        for (int i = tid; i < 320; i += 256) {
            int r = i / 10, c = i - r * 10;
            size_t g = ((size_t)bh * PMP_ + k0 + r) * 80 + c * 8;
            CP_ASYNC16(base + A_BH2 + r * AB_ST + c * 16, Cbh + g);
            CP_ASYNC16(base + A_BL2 + r * AB_ST + c * 16, Cbl + g);
        }
    };

    stage(0, 0); CP_COMMIT();
    stage(1, 1); CP_COMMIT();

    int wm = (warp >> 1) * 32, ng = warp & 1;
    float acc[2][5][4] = {};
    uint32_t aoff = (uint32_t)((wm + (lane & 15)) * AQ_ST + (lane >> 4) * 16);

    for (int t = 0; t < 9; t++) {
        if (t + 1 < 9) CP_WAIT(1); else CP_WAIT(0);
        __syncthreads();
        uint32_t bs = sb + (t & 1) * ASTAGE;
#pragma unroll
        for (int kt = 0; kt < 2; kt++) {
            unsigned ah[2][4], al[2][4];
#pragma unroll
            for (int mt = 0; mt < 2; mt++) {
                uint32_t a = bs + A_QH + aoff + mt * (16 * AQ_ST) + kt * 32;
                ldsm4(ah[mt][0], ah[mt][1], ah[mt][2], ah[mt][3], a);
                ldsm4(al[mt][0], al[mt][1], al[mt][2], al[mt][3], a + (A_QL - A_QH));
            }
            int krB = (lane & 7) + ((lane >> 3) & 1) * 8 + kt * 16;
            int ncolbit = (lane >> 4) * 8;
#pragma unroll
            for (int pi = 0; pi < 3; pi++) {
                if (!ng && pi == 2) break;
                int p = ng ? (2 + pi) : pi;
                unsigned bhf[4], blf[4];
                uint32_t a = bs + A_BH2 + krB * AB_ST + (p * 16 + ncolbit) * 2;
                ldsm4t(bhf[0], bhf[1], bhf[2], bhf[3], a);
                ldsm4t(blf[0], blf[1], blf[2], blf[3], a + (A_BL2 - A_BH2));
#pragma unroll
                for (int j = 0; j < 2; j++) {
                    int ntg = p * 2 + j;
                    if (ntg > 8) break;
                    int ntl = ntg - ng * 4;
#pragma unroll
                    for (int mt = 0; mt < 2; mt++) {
                        mma_bf16(acc[mt][ntl], ah[mt], bhf + j * 2);
                        mma_bf16(acc[mt][ntl], ah[mt], blf + j * 2);
                        mma_bf16(acc[mt][ntl], al[mt], bhf + j * 2);
                    }
                }
            }
        }
        __syncthreads();
        if (t + 2 < 9) { stage(t & 1, t + 2); CP_COMMIT(); }
    }

    if (ng == 1 && (lane & 3) == 0) {
#pragma unroll
        for (int mt = 0; mt < 2; mt++)
#pragma unroll
            for (int half = 0; half < 2; half++) {
                int r = wm + mt * 16 + (lane >> 2) + half * 8;
                sden[r] = acc[mt][4][half * 2];   // local tile 4 = global tile 8, col 64
            }
    }
    __syncthreads();

#pragma unroll
    for (int mt = 0; mt < 2; mt++)
#pragma unroll
        for (int half = 0; half < 2; half++) {
            int r = wm + mt * 16 + (lane >> 2) + half * 8;
            float rinv = 1.f / sden[r];
            size_t obase = ((size_t)(b * S_ + s0 + r)) * D_ + h * DH_;
#pragma unroll
            for (int ntl = 0; ntl < 4; ntl++) {
                int e = (ng * 4 + ntl) * 8 + (lane & 3) * 2;
                float v0 = acc[mt][ntl][half * 2]     * rinv;
                float v1 = acc[mt][ntl][half * 2 + 1] * rinv;
                __nv_bfloat16 h0, l0, h1, l1;
                bf16_split(v0, h0, l0);
                bf16_split(v1, h1, l1);
                *(__nv_bfloat162*)(oh + obase + e) = __nv_bfloat162(h0, h1);
                *(__nv_bfloat162*)(ol + obase + e) = __nv_bfloat162(l0, l1);
            }
        }
}

// ---------------------------------------------------------------------------
// Per-layer init
// ---------------------------------------------------------------------------
__global__ void layer_init_kernel(float* __restrict__ ctxE, float* __restrict__ vsum,
                                  unsigned* __restrict__ km) {
    int i = blockIdx.x * 256 + threadIdx.x;
    if (i < BH_ * PMP_ * 72) ctxE[i] = 0.f;
    if (i < BH_ * 64) vsum[i] = 0.f;
    if (i == 0) *km = 0u;
}

// ---------------------------------------------------------------------------
// Pooling
// ---------------------------------------------------------------------------
__global__ void score_kernel(const float* __restrict__ h, const float* __restrict__ p2w,
                             const float* __restrict__ p2b, const float* __restrict__ mask,
                             float* __restrict__ score) {
    __shared__ float sh[8];
    int row = blockIdx.x, t = threadIdx.x;
    float v = h[(size_t)row * D_ + t] * p2w[t];
    float s = block_sum(v, sh);
    if (t == 0) score[row] = expf(s + p2b[0]) * mask[row];
}

__global__ void ssum_kernel(const float* __restrict__ score, float* __restrict__ ssum) {
    __shared__ float sh[8];
    int b = blockIdx.x;
    float s = 0.f;
    for (int i = threadIdx.x; i < S_; i += 256) s += score[b * S_ + i];
    s = block_sum(s, sh);
    if (threadIdx.x == 0) ssum[b] = s;
}

__global__ void outzero_kernel(float* __restrict__ out) {
    int i = blockIdx.x * blockDim.x + threadIdx.x;
    if (i < B_ * D_) out[i] = 0.f;
}

__global__ void pool_kernel(const float* __restrict__ x, const float* __restrict__ score,
                            const float* __restrict__ ssum, float* __restrict__ out) {
    int b = blockIdx.x, chunk = blockIdx.y, d = threadIdx.x;
    float inv = 1.f / (ssum[b] + 1e-8f);
    float acc = 0.f;
    int s0 = chunk * (S_ / 16);
    for (int s = s0; s < s0 + S_ / 16; s++)
        acc = fmaf(x[((size_t)(b * S_ + s)) * D_ + d], score[b * S_ + s], acc);
    atomicAdd(&out[b * D_ + d], acc * inv);
}

// ---------------------------------------------------------------------------
// Host launcher
// ---------------------------------------------------------------------------
extern "C" void kernel_launch(void* const* d_in, const int* in_sizes, int n_in,
                              void* d_out, int out_size) {
    const float* emb  = (const float*)d_in[0];
    const float* mask = (const float*)d_in[1];
    const float* pos  = (const float*)d_in[2];
    const float* ln_g = (const float*)d_in[3];
    const float* ln_b = (const float*)d_in[4];
    const float* proj = (const float*)d_in[5];
    const float* Wq = (const float*)d_in[6];   const float* bq = (const float*)d_in[7];
    const float* Wk = (const float*)d_in[8];   const float* bk = (const float*)d_in[9];
    const float* Wv = (const float*)d_in[10];  const float* bv = (const float*)d_in[11];
    const float* Wo = (const float*)d_in[12];  const float* bo = (const float*)d_in[13];
    const float* ln1g = (const float*)d_in[14]; const float* ln1b = (const float*)d_in[15];
    const float* W1 = (const float*)d_in[16];  const float* b1 = (const float*)d_in[17];
    const float* W2 = (const float*)d_in[18];  const float* b2 = (const float*)d_in[19];
    const float* ln2g = (const float*)d_in[20]; const float* ln2b = (const float*)d_in[21];
    const float* p1w = (const float*)d_in[22]; const float* p1b = (const float*)d_in[23];
    const float* p2w = (const float*)d_in[24]; const float* p2b = (const float*)d_in[25];
    float* out = (float*)d_out;

    void* tp;
    float *x, *h, *sc, *ss, *bqkv, *ctxE, *vsum;
    unsigned* km;
    __nv_bfloat16 *wth, *wtl, *hh, *hl, *oh, *ol, *fh, *fl, *xh, *xl;
    __nv_bfloat16 *qh, *ql, *kh, *kl, *vh, *vl, *pjh, *pjl;
    __nv_bfloat16 *qph, *qpl, *eh, *el, *cbh, *cbl;
    cudaGetSymbolAddress(&tp, g_x);     x  = (float*)tp;
    cudaGetSymbolAddress(&tp, g_h);     h  = (float*)tp;
    cudaGetSymbolAddress(&tp, g_score); sc = (float*)tp;
    cudaGetSymbolAddress(&tp, g_ssum);  ss = (float*)tp;
    cudaGetSymbolAddress(&tp, g_kmaxu); km = (unsigned*)tp;
    cudaGetSymbolAddress(&tp, g_bqkv);  bqkv = (float*)tp;
    cudaGetSymbolAddress(&tp, g_ctxE);  ctxE = (float*)tp;
    cudaGetSymbolAddress(&tp, g_vsum);  vsum = (float*)tp;
    cudaGetSymbolAddress(&tp, g_wth);   wth = (__nv_bfloat16*)tp;
    cudaGetSymbolAddress(&tp, g_wtl);   wtl = (__nv_bfloat16*)tp;
    cudaGetSymbolAddress(&tp, g_hh);    hh = (__nv_bfloat16*)tp;
    cudaGetSymbolAddress(&tp, g_hl);    hl = (__nv_bfloat16*)tp;
    cudaGetSymbolAddress(&tp, g_oh);    oh = (__nv_bfloat16*)tp;
    cudaGetSymbolAddress(&tp, g_ol);    ol = (__nv_bfloat16*)tp;
    cudaGetSymbolAddress(&tp, g_fh);    fh = (__nv_bfloat16*)tp;
    cudaGetSymbolAddress(&tp, g_fl);    fl = (__nv_bfloat16*)tp;
    cudaGetSymbolAddress(&tp, g_xh);    xh = (__nv_bfloat16*)tp;
    cudaGetSymbolAddress(&tp, g_xl);    xl = (__nv_bfloat16*)tp;
    cudaGetSymbolAddress(&tp, g_qh);    qh = (__nv_bfloat16*)tp;
    cudaGetSymbolAddress(&tp, g_ql);    ql = (__nv_bfloat16*)tp;
    cudaGetSymbolAddress(&tp, g_kh);    kh = (__nv_bfloat16*)tp;
    cudaGetSymbolAddress(&tp, g_kl);    kl = (__nv_bfloat16*)tp;
    cudaGetSymbolAddress(&tp, g_vh);    vh = (__nv_bfloat16*)tp;
    cudaGetSymbolAddress(&tp, g_vl);    vl = (__nv_bfloat16*)tp;
    cudaGetSymbolAddress(&tp, g_pjh);   pjh = (__nv_bfloat16*)tp;
    cudaGetSymbolAddress(&tp, g_pjl);   pjl = (__nv_bfloat16*)tp;
    cudaGetSymbolAddress(&tp, g_qph);   qph = (__nv_bfloat16*)tp;
    cudaGetSymbolAddress(&tp, g_qpl);   qpl = (__nv_bfloat16*)tp;
    cudaGetSymbolAddress(&tp, g_eh);    eh = (__nv_bfloat16*)tp;
    cudaGetSymbolAddress(&tp, g_el);    el = (__nv_bfloat16*)tp;
    cudaGetSymbolAddress(&tp, g_cbh);   cbh = (__nv_bfloat16*)tp;
    cudaGetSymbolAddress(&tp, g_cbl);   cbl = (__nv_bfloat16*)tp;

    static bool attr_done = false;
    if (!attr_done) {
        cudaFuncSetAttribute(mm_gemm<0, false>, cudaFuncAttributeMaxDynamicSharedMemorySize, MM_SMEM);
        cudaFuncSetAttribute(mm_gemm<1, false>, cudaFuncAttributeMaxDynamicSharedMemorySize, MM_SMEM);
        cudaFuncSetAttribute(mm_gemm<2, false>, cudaFuncAttributeMaxDynamicSharedMemorySize, MM_SMEM);
        cudaFuncSetAttribute(mm_gemm<2, true>,  cudaFuncAttributeMaxDynamicSharedMemorySize, MM_SMEM);
        cudaFuncSetAttribute(mm_gemm<3, false>, cudaFuncAttributeMaxDynamicSharedMemorySize, MM_SMEM);
        cudaFuncSetAttribute(dash_mma<true>,  cudaFuncAttributeMaxDynamicSharedMemorySize, DASH_SMEM);
        cudaFuncSetAttribute(dash_mma<false>, cudaFuncAttributeMaxDynamicSharedMemorySize, DASH_SMEM);
        cudaFuncSetAttribute(ctx_mma,     cudaFuncAttributeMaxDynamicSharedMemorySize, CTX_SMEM);
        cudaFuncSetAttribute(attnout_mma, cudaFuncAttributeMaxDynamicSharedMemorySize, ATT_SMEM);
        attr_done = true;
    }

    // --- weight prep ---
    dim3 wb(32, 8);
    for (int l = 0; l < NL_; l++) {
        __nv_bfloat16* qwh = wth + OFF_QKV + (size_t)l * 768 * 256;
        __nv_bfloat16* qwl = wtl + OFF_QKV + (size_t)l * 768 * 256;
        wsplit_kernel<<<dim3(8, 8), wb>>>(Wq + (size_t)l * 65536, qwh, qwl, 256, 256, 0);
        wsplit_kernel<<<dim3(8, 8), wb>>>(Wk + (size_t)l * 65536, qwh, qwl, 256, 256, 256);
        wsplit_kernel<<<dim3(8, 8), wb>>>(Wv + (size_t)l * 65536, qwh, qwl, 256, 256, 512);
        wsplit_kernel<<<dim3(8, 8), wb>>>(Wo + (size_t)l * 65536,
            wth + OFF_WO + (size_t)l * 65536, wtl + OFF_WO + (size_t)l * 65536, 256, 256, 0);
        wsplit_kernel<<<dim3(32, 8), wb>>>(W1 + (size_t)l * 262144,
            wth + OFF_W1 + (size_t)l * 262144, wtl + OFF_W1 + (size_t)l * 262144, 256, 1024, 0);
        wsplit_kernel<<<dim3(8, 32), wb>>>(W2 + (size_t)l * 262144,
            wth + OFF_W2 + (size_t)l * 262144, wtl + OFF_W2 + (size_t)l * 262144, 1024, 256, 0);
    }
    wsplit_kernel<<<dim3(8, 8), wb>>>(p1w, wth + OFF_P1, wtl + OFF_P1, 256, 256, 0);
    bconcat_kernel<<<NL_, 256>>>(bq, bk, bv, bqkv);
    psplit_kernel<<<(NL_ * PMP_ * DH_) / 256, 256>>>(proj, pjh, pjl);

    embed_ln_kernel<<<BS_, 256>>>(emb, pos, ln_g, ln_b, x);

    for (int l = 0; l < NL_; l++) {
        // --- attention block ---
        ln_kernel<<<BS_, 256>>>(x, hh, hl, ln1g + l * D_, ln1b + l * D_);
        mm_gemm<0, false><<<dim3(6, 128), 256, MM_SMEM>>>(
            hh, hl, wth + OFF_QKV + (size_t)l * 768 * 256, wtl + OFF_QKV + (size_t)l * 768 * 256,
            bqkv + l * 768, nullptr, qh, ql, kh, kl, vh, vl, 256, 768);

        layer_init_kernel<<<(BH_ * PMP_ * 72 + 255) / 256, 256>>>(ctxE, vsum, km);

        dash_mma<true><<<dim3(S_ / 128, BH_), 256, DASH_SMEM>>>(
            qh, ql, pjh + (size_t)l * PMP_ * DH_, pjl + (size_t)l * PMP_ * DH_,
            qph, qpl, nullptr);
        dash_mma<false><<<dim3(S_ / 128, BH_), 256, DASH_SMEM>>>(
            kh, kl, pjh + (size_t)l * PMP_ * DH_, pjl + (size_t)l * PMP_ * DH_,
            eh, el, km);

        vsum_kernel<<<dim3(BH_, 8), 64>>>(vh, vl, vsum);
        ctx_mma<<<dim3(BH_, 8), 256, CTX_SMEM>>>(eh, el, vh, vl, ctxE);
        ctxcorr_kernel<<<(BH_ * PMP_ * 80 + 255) / 256, 256>>>(ctxE, vsum, km, cbh, cbl);
        attnout_mma<<<dim3(S_ / 128, BH_), 256, ATT_SMEM>>>(qph, qpl, cbh, cbl, oh, ol);

        mm_gemm<2, false><<<dim3(2, 128), 256, MM_SMEM>>>(
            oh, ol, wth + OFF_WO + (size_t)l * 65536, wtl + OFF_WO + (size_t)l * 65536,
            bo + l * 256, x, nullptr, nullptr, nullptr, nullptr, nullptr, nullptr, 256, 256);

        // --- FFN block ---
        ln_kernel<<<BS_, 256>>>(x, hh, hl, ln2g + l * D_, ln2b + l * D_);
        mm_gemm<1, false><<<dim3(8, 128), 256, MM_SMEM>>>(
            hh, hl, wth + OFF_W1 + (size_t)l * 262144, wtl + OFF_W1 + (size_t)l * 262144,
            b1 + l * 1024, nullptr, fh, fl, nullptr, nullptr, nullptr, nullptr, 256, 1024);
        mm_gemm<2, true><<<dim3(2, 128), 256, MM_SMEM>>>(
            fh, fl, wth + OFF_W2 + (size_t)l * 262144, wtl + OFF_W2 + (size_t)l * 262144,
            b2 + l * 256, x, xh, xl, nullptr, nullptr, nullptr, nullptr, 1024, 256);
    }

    // --- attention pooling ---
    mm_gemm<3, false><<<dim3(2, 128), 256, MM_SMEM>>>(
        xh, xl, wth + OFF_P1, wtl + OFF_P1, p1b, h,
        nullptr, nullptr, nullptr, nullptr, nullptr, nullptr, 256, 256);
    score_kernel<<<BS_, 256>>>(h, p2w, p2b, mask, sc);
    ssum_kernel<<<B_, 256>>>(sc, ss);
    outzero_kernel<<<(B_ * D_ + 255) / 256, 256>>>(out);
    pool_kernel<<<dim3(B_, 16), 256>>>(x, sc, ss, out);
}

// round 10
// speedup vs baseline: 2.1390x; 1.0386x over previous
#include <cuda_runtime.h>
#include <cuda_bf16.h>
#include <cstdint>

// ---------------------------------------------------------------------------
// Problem constants
// ---------------------------------------------------------------------------
constexpr int B_  = 4;
constexpr int S_  = 4096;
constexpr int D_  = 256;
constexpr int DH_ = 64;
constexpr int NL_ = 4;
constexpr int PM_ = 266;          // nb_features
constexpr int PMP_ = 288;         // padded for mma
constexpr int FF_ = 1024;
constexpr int BS_ = B_ * S_;      // 16384 rows
constexpr int BH_ = B_ * 4;       // 16

constexpr float DN_    = 0.35355339059327373f;  // 64^-0.25
constexpr float HDN2_  = 0.0625f;               // 0.5 * dn^2
constexpr float RATIO_ = 0.06131392f;           // 266^-0.5
constexpr float KEPS_  = 1e-4f;
constexpr float LNEPS_ = 1e-12f;

// ---------------------------------------------------------------------------
// Scratch (static device globals)
// ---------------------------------------------------------------------------
__device__ float g_x  [BS_ * D_];
__device__ float g_h  [BS_ * D_];     // pooling tanh output (fp32)
__device__ float g_score[BS_];
__device__ float g_ssum [B_];
__device__ unsigned g_kmaxu;

// bf16 hi/lo operand buffers
constexpr size_t OFF_QKV = 0;
constexpr size_t OFF_WO  = OFF_QKV + (size_t)NL_ * 768 * 256;
constexpr size_t OFF_W1  = OFF_WO  + (size_t)NL_ * 256 * 256;
constexpr size_t OFF_W2  = OFF_W1  + (size_t)NL_ * 1024 * 256;
constexpr size_t OFF_P1  = OFF_W2  + (size_t)NL_ * 256 * 1024;
constexpr size_t WT_TOT  = OFF_P1 + 256 * 256;

__device__ __nv_bfloat16 g_wth[WT_TOT], g_wtl[WT_TOT];
__device__ float g_bqkv[NL_ * 768];
__device__ __nv_bfloat16 g_hh[BS_ * D_], g_hl[BS_ * D_];      // LN outputs
__device__ __nv_bfloat16 g_oh[BS_ * D_], g_ol[BS_ * D_];      // attnout
__device__ __nv_bfloat16 g_fh[(size_t)BS_ * FF_], g_fl[(size_t)BS_ * FF_]; // gelu
__device__ __nv_bfloat16 g_xh[BS_ * D_], g_xl[BS_ * D_];      // residual (pooling)
__device__ __nv_bfloat16 g_qh[BS_ * D_], g_ql[BS_ * D_];      // q hi/lo
__device__ __nv_bfloat16 g_kh[BS_ * D_], g_kl[BS_ * D_];      // k hi/lo
__device__ __nv_bfloat16 g_vh[BS_ * D_], g_vl[BS_ * D_];      // v hi/lo
__device__ __nv_bfloat16 g_pjh[NL_ * PMP_ * DH_], g_pjl[NL_ * PMP_ * DH_];

// FAVOR intermediates
__device__ __nv_bfloat16 g_qph[(size_t)BH_ * S_ * PMP_], g_qpl[(size_t)BH_ * S_ * PMP_];
__device__ __nv_bfloat16 g_eh [(size_t)BH_ * S_ * PMP_], g_el [(size_t)BH_ * S_ * PMP_];
__device__ float g_ctxE[BH_ * PMP_ * 72];
__device__ __nv_bfloat16 g_cbh[BH_ * PMP_ * 80], g_cbl[BH_ * PMP_ * 80];
__device__ float g_vsum[BH_ * 64];

// ---------------------------------------------------------------------------
// PTX helpers (family-portable: no tcgen05 on compute_103 targets)
// ---------------------------------------------------------------------------
__device__ __forceinline__ uint32_t smem_u32(const void* p) {
    uint32_t a;
    asm("{ .reg .u64 t; cvta.to.shared.u64 t, %1; cvt.u32.u64 %0, t; }" : "=r"(a) : "l"(p));
    return a;
}
__device__ __forceinline__ void ldsm4(unsigned& r0, unsigned& r1, unsigned& r2, unsigned& r3,
                                      uint32_t addr) {
    asm volatile("ldmatrix.sync.aligned.m8n8.x4.shared.b16 {%0,%1,%2,%3}, [%4];"
                 : "=r"(r0), "=r"(r1), "=r"(r2), "=r"(r3) : "r"(addr));
}
__device__ __forceinline__ void ldsm4t(unsigned& r0, unsigned& r1, unsigned& r2, unsigned& r3,
                                       uint32_t addr) {
    asm volatile("ldmatrix.sync.aligned.m8n8.x4.trans.shared.b16 {%0,%1,%2,%3}, [%4];"
                 : "=r"(r0), "=r"(r1), "=r"(r2), "=r"(r3) : "r"(addr));
}
__device__ __forceinline__ void mma_bf16(float* d, const unsigned* a, const unsigned* b) {
    asm volatile("mma.sync.aligned.m16n8k16.row.col.f32.bf16.bf16.f32 "
                 "{%0,%1,%2,%3}, {%4,%5,%6,%7}, {%8,%9}, {%0,%1,%2,%3};"
                 : "+f"(d[0]), "+f"(d[1]), "+f"(d[2]), "+f"(d[3])
                 : "r"(a[0]), "r"(a[1]), "r"(a[2]), "r"(a[3]), "r"(b[0]), "r"(b[1]));
}
#define CP_ASYNC16(dst, src) \
    asm volatile("cp.async.cg.shared.global [%0], [%1], 16;" :: "r"(dst), "l"(src) : "memory")
#define CP_COMMIT() asm volatile("cp.async.commit_group;" ::: "memory")
#define CP_WAIT(n)  asm volatile("cp.async.wait_group %0;" :: "n"(n) : "memory")

__device__ __forceinline__ void bf16_split(float v, __nv_bfloat16& hi, __nv_bfloat16& lo) {
    hi = __float2bfloat16(v);
    lo = __float2bfloat16(v - __bfloat162float(hi));
}
__device__ __forceinline__ float tanh_ap(float x) {
    float r;
    asm("tanh.approx.f32 %0, %1;" : "=f"(r) : "f"(x));
    return r;
}

// ---------------------------------------------------------------------------
// Reductions
// ---------------------------------------------------------------------------
__device__ __forceinline__ float warpsum(float v) {
#pragma unroll
    for (int o = 16; o > 0; o >>= 1) v += __shfl_xor_sync(0xffffffffu, v, o);
    return v;
}
__device__ __forceinline__ float block_sum(float v, float* sh) {
    int lane = threadIdx.x & 31, w = threadIdx.x >> 5, nw = blockDim.x >> 5;
    v = warpsum(v);
    if (lane == 0) sh[w] = v;
    __syncthreads();
    if (w == 0) {
        float x = (lane < nw) ? sh[lane] : 0.f;
        x = warpsum(x);
        if (lane == 0) sh[0] = x;
    }
    __syncthreads();
    float r = sh[0];
    __syncthreads();
    return r;
}
__device__ __forceinline__ unsigned fmap(float f) {
    unsigned u = __float_as_uint(f);
    return (u & 0x80000000u) ? ~u : (u | 0x80000000u);
}
__device__ __forceinline__ float funmap(unsigned u) {
    u = (u & 0x80000000u) ? (u & 0x7FFFFFFFu) : ~u;
    return __uint_as_float(u);
}

// ---------------------------------------------------------------------------
// Weight transpose + bf16 split: W [K,N] fp32 -> Th/Tl [N,K] bf16; z = layer
// ---------------------------------------------------------------------------
__global__ void wsplit_kernel(const float* __restrict__ W, __nv_bfloat16* __restrict__ Th,
                              __nv_bfloat16* __restrict__ Tl, int K, int N, int rowOff,
                              size_t sstride, size_t dstride) {
    __shared__ float ts[32][33];
    int l = blockIdx.z;
    W  += (size_t)l * sstride;
    Th += (size_t)l * dstride;
    Tl += (size_t)l * dstride;
    int kb = blockIdx.y * 32, nb = blockIdx.x * 32;
    int tx = threadIdx.x, ty = threadIdx.y;
#pragma unroll
    for (int i = 0; i < 4; i++) {
        int k = kb + ty + i * 8;
        ts[ty + i * 8][tx] = W[(size_t)k * N + nb + tx];
    }
    __syncthreads();
#pragma unroll
    for (int i = 0; i < 4; i++) {
        int n = nb + ty + i * 8;
        int k = kb + tx;
        float v = ts[tx][ty + i * 8];
        __nv_bfloat16 hi, lo;
        bf16_split(v, hi, lo);
        size_t idx = (size_t)(rowOff + n) * K + k;
        Th[idx] = hi; Tl[idx] = lo;
    }
}

__global__ void bconcat_kernel(const float* __restrict__ bq, const float* __restrict__ bk,
                               const float* __restrict__ bv, float* __restrict__ dst) {
    int l = blockIdx.x, t = threadIdx.x;
    dst[l * 768 + t]       = bq[l * 256 + t];
    dst[l * 768 + 256 + t] = bk[l * 256 + t];
    dst[l * 768 + 512 + t] = bv[l * 256 + t];
}

__global__ void psplit_kernel(const float* __restrict__ proj,
                              __nv_bfloat16* __restrict__ ph, __nv_bfloat16* __restrict__ pl) {
    int idx = blockIdx.x * 256 + threadIdx.x;
    int l = idx / (PMP_ * DH_);
    int rem = idx - l * (PMP_ * DH_);
    int r = rem >> 6, c = rem & 63;
    float v = (r < PM_) ? proj[((size_t)l * PM_ + r) * DH_ + c] : 0.f;
    __nv_bfloat16 hi, lo;
    bf16_split(v, hi, lo);
    ph[idx] = hi; pl[idx] = lo;
}

// ---------------------------------------------------------------------------
// LayerNorm — warp-per-row (8 rows per 256-thread block; shfl-only reductions)
// ---------------------------------------------------------------------------
__global__ __launch_bounds__(256) void embed_ln_kernel(
    const float* __restrict__ emb, const float* __restrict__ pos,
    const float* __restrict__ g, const float* __restrict__ bb,
    float* __restrict__ out) {
    int warp = threadIdx.x >> 5, lane = threadIdx.x & 31;
    int row = blockIdx.x * 8 + warp;
    int c0 = lane * 8;
    const float* ep = emb + (size_t)row * D_ + c0;
    const float* pp = pos + (size_t)(row & (S_ - 1)) * D_ + c0;
    float v[8];
    float4 a0 = *(const float4*)ep, a1 = *(const float4*)(ep + 4);
    float4 p0 = *(const float4*)pp, p1 = *(const float4*)(pp + 4);
    v[0] = a0.x + p0.x; v[1] = a0.y + p0.y; v[2] = a0.z + p0.z; v[3] = a0.w + p0.w;
    v[4] = a1.x + p1.x; v[5] = a1.y + p1.y; v[6] = a1.z + p1.z; v[7] = a1.w + p1.w;
    float s = 0.f;
#pragma unroll
    for (int j = 0; j < 8; j++) s += v[j];
    float mu = warpsum(s) * (1.0f / D_);
    float s2 = 0.f;
#pragma unroll
    for (int j = 0; j < 8; j++) { float d = v[j] - mu; s2 = fmaf(d, d, s2); }
    float rs = rsqrtf(warpsum(s2) * (1.0f / D_) + LNEPS_);
    float4 g0 = *(const float4*)(g + c0), g1 = *(const float4*)(g + c0 + 4);
    float4 b0 = *(const float4*)(bb + c0), b1 = *(const float4*)(bb + c0 + 4);
    float gg[8] = {g0.x, g0.y, g0.z, g0.w, g1.x, g1.y, g1.z, g1.w};
    float bbv[8] = {b0.x, b0.y, b0.z, b0.w, b1.x, b1.y, b1.z, b1.w};
    float o[8];
#pragma unroll
    for (int j = 0; j < 8; j++) o[j] = (v[j] - mu) * rs * gg[j] + bbv[j];
    float* op = out + (size_t)row * D_ + c0;
    *(float4*)op       = make_float4(o[0], o[1], o[2], o[3]);
    *(float4*)(op + 4) = make_float4(o[4], o[5], o[6], o[7]);
}

__global__ __launch_bounds__(256) void ln_kernel(
    const float* __restrict__ in,
    __nv_bfloat16* __restrict__ oh, __nv_bfloat16* __restrict__ ol,
    const float* __restrict__ g, const float* __restrict__ bb) {
    int warp = threadIdx.x >> 5, lane = threadIdx.x & 31;
    int row = blockIdx.x * 8 + warp;
    int c0 = lane * 8;
    const float* rp = in + (size_t)row * D_ + c0;
    float4 a0 = *(const float4*)rp, a1 = *(const float4*)(rp + 4);
    float v[8] = {a0.x, a0.y, a0.z, a0.w, a1.x, a1.y, a1.z, a1.w};
    float s = 0.f;
#pragma unroll
    for (int j = 0; j < 8; j++) s += v[j];
    float mu = warpsum(s) * (1.0f / D_);
    float s2 = 0.f;
#pragma unroll
    for (int j = 0; j < 8; j++) { float d = v[j] - mu; s2 = fmaf(d, d, s2); }
    float rs = rsqrtf(warpsum(s2) * (1.0f / D_) + LNEPS_);
    float4 g0 = *(const float4*)(g + c0), g1 = *(const float4*)(g + c0 + 4);
    float4 b0 = *(const float4*)(bb + c0), b1 = *(const float4*)(bb + c0 + 4);
    float gg[8] = {g0.x, g0.y, g0.z, g0.w, g1.x, g1.y, g1.z, g1.w};
    float bbv[8] = {b0.x, b0.y, b0.z, b0.w, b1.x, b1.y, b1.z, b1.w};
    size_t base = (size_t)row * D_ + c0;
#pragma unroll
    for (int j2 = 0; j2 < 4; j2++) {
        float x0 = (v[2 * j2] - mu) * rs * gg[2 * j2] + bbv[2 * j2];
        float x1 = (v[2 * j2 + 1] - mu) * rs * gg[2 * j2 + 1] + bbv[2 * j2 + 1];
        __nv_bfloat16 h0, l0, h1, l1;
        bf16_split(x0, h0, l0);
        bf16_split(x1, h1, l1);
        *(__nv_bfloat162*)(oh + base + 2 * j2) = __nv_bfloat162(h0, h1);
        *(__nv_bfloat162*)(ol + base + 2 * j2) = __nv_bfloat162(l0, l1);
    }
}

// ---------------------------------------------------------------------------
// mma.sync bf16 GEMM (dense): C = A @ Bt^T (+bias +epilogue)
// MODE: 0 = QKV (q->Oh/Ol, k->Oh2/Ol2, v->Oh3/Ol3);
//       1 = GELU->Oh/Ol; 2 = residual accumulate into O0 (+Oh/Ol if EMIT); 3 = tanh->O0
// ---------------------------------------------------------------------------
constexpr int ROWB    = 80;
constexpr int ARR_B   = 128 * ROWB;
constexpr int STAGE_B = 4 * ARR_B;
constexpr int MM_SMEM = 2 * STAGE_B;     // 81920

__device__ __forceinline__ void stage_cp(uint32_t sbase,
    const __nv_bfloat16* __restrict__ Ah, const __nv_bfloat16* __restrict__ Al,
    const __nv_bfloat16* __restrict__ Bh, const __nv_bfloat16* __restrict__ Bl,
    int row0, int col0, int K, int k0, int tid) {
#pragma unroll
    for (int i = 0; i < 8; i++) {
        const int arr = i >> 1;
        int cc = tid + (i & 1) * 256;
        int row = cc >> 2, kc = cc & 3;
        const __nv_bfloat16* src;
        int gr;
        if (arr == 0)      { src = Ah; gr = row0 + row; }
        else if (arr == 1) { src = Al; gr = row0 + row; }
        else if (arr == 2) { src = Bh; gr = col0 + row; }
        else               { src = Bl; gr = col0 + row; }
        uint32_t dst = sbase + arr * ARR_B + row * ROWB + kc * 16;
        CP_ASYNC16(dst, src + (size_t)gr * K + k0 + kc * 8);
    }
}

template <int MODE, bool EMIT>
__global__ __launch_bounds__(256) void mm_gemm(
    const __nv_bfloat16* __restrict__ Ah, const __nv_bfloat16* __restrict__ Al,
    const __nv_bfloat16* __restrict__ Bth, const __nv_bfloat16* __restrict__ Btl,
    const float* __restrict__ bias,
    float* __restrict__ O0,
    __nv_bfloat16* __restrict__ Oh, __nv_bfloat16* __restrict__ Ol,
    __nv_bfloat16* __restrict__ Oh2, __nv_bfloat16* __restrict__ Ol2,
    __nv_bfloat16* __restrict__ Oh3, __nv_bfloat16* __restrict__ Ol3,
    int K, int N) {
    extern __shared__ char smem[];
    uint32_t sb = smem_u32(smem);
    int tid = threadIdx.x, lane = tid & 31, warp = tid >> 5;
    int row0 = blockIdx.y * 128, col0 = blockIdx.x * 128;
    int wm = (warp >> 1) * 32, wn = (warp & 1) * 64;

    float acc[2][8][4] = {};

    int NT = K >> 5;
    stage_cp(sb, Ah, Al, Bth, Btl, row0, col0, K, 0, tid);
    CP_COMMIT();
    if (NT > 1) {
        stage_cp(sb + STAGE_B, Ah, Al, Bth, Btl, row0, col0, K, 32, tid);
        CP_COMMIT();
    }

    uint32_t aoff = (uint32_t)((wm + (lane & 15)) * ROWB + (lane >> 4) * 16);
    uint32_t boff = (uint32_t)((wn + ((lane >> 4) << 3) + (lane & 7)) * ROWB +
                               ((lane >> 3) & 1) * 16);

    for (int t = 0; t < NT; t++) {
        if (t + 1 < NT) CP_WAIT(1); else CP_WAIT(0);
        __syncthreads();
        uint32_t bs = sb + (t & 1) * STAGE_B;
#pragma unroll
        for (int kt = 0; kt < 2; kt++) {
            unsigned ah[2][4], al[2][4], bh[8][2], bl[8][2];
#pragma unroll
            for (int mt = 0; mt < 2; mt++) {
                uint32_t a = bs + aoff + mt * (16 * ROWB) + kt * 32;
                ldsm4(ah[mt][0], ah[mt][1], ah[mt][2], ah[mt][3], a);
                ldsm4(al[mt][0], al[mt][1], al[mt][2], al[mt][3], a + ARR_B);
            }
#pragma unroll
            for (int n2 = 0; n2 < 4; n2++) {
                uint32_t a = bs + 2 * ARR_B + boff + n2 * (16 * ROWB) + kt * 32;
                ldsm4(bh[2 * n2][0], bh[2 * n2][1], bh[2 * n2 + 1][0], bh[2 * n2 + 1][1], a);
                ldsm4(bl[2 * n2][0], bl[2 * n2][1], bl[2 * n2 + 1][0], bl[2 * n2 + 1][1],
                      a + ARR_B);
            }
#pragma unroll
            for (int mt = 0; mt < 2; mt++)
#pragma unroll
                for (int nt = 0; nt < 8; nt++) {
                    mma_bf16(acc[mt][nt], ah[mt], bh[nt]);
                    mma_bf16(acc[mt][nt], ah[mt], bl[nt]);
                    mma_bf16(acc[mt][nt], al[mt], bh[nt]);
                }
        }
        __syncthreads();
        if (t + 2 < NT) {
            stage_cp(sb + (t & 1) * STAGE_B, Ah, Al, Bth, Btl, row0, col0, K,
                     (t + 2) * 32, tid);
            CP_COMMIT();
        }
    }

#pragma unroll
    for (int mt = 0; mt < 2; mt++)
#pragma unroll
        for (int nt = 0; nt < 8; nt++) {
            int rbase = row0 + wm + mt * 16 + (lane >> 2);
            int cg = col0 + wn + nt * 8 + (lane & 3) * 2;
            float b0 = __ldg(&bias[cg]), b1 = __ldg(&bias[cg + 1]);
#pragma unroll
            for (int half = 0; half < 2; half++) {
                int row = rbase + half * 8;
                float v0 = acc[mt][nt][half * 2]     + b0;
                float v1 = acc[mt][nt][half * 2 + 1] + b1;
                if (MODE == 0) {
                    int which = cg >> 8, cl = cg & 255;
                    size_t idx = (size_t)row * 256 + cl;
                    __nv_bfloat16* H = (which == 0) ? Oh : (which == 1) ? Oh2 : Oh3;
                    __nv_bfloat16* L = (which == 0) ? Ol : (which == 1) ? Ol2 : Ol3;
                    __nv_bfloat16 hi, lo;
                    bf16_split(v0, hi, lo); H[idx] = hi;     L[idx] = lo;
                    bf16_split(v1, hi, lo); H[idx + 1] = hi; L[idx + 1] = lo;
                } else if (MODE == 1) {
                    float u0 = 0.7978845608028654f * (v0 + 0.044715f * v0 * v0 * v0);
                    float u1 = 0.7978845608028654f * (v1 + 0.044715f * v1 * v1 * v1);
                    float g0 = 0.5f * v0 * (1.f + tanh_ap(u0));
                    float g1 = 0.5f * v1 * (1.f + tanh_ap(u1));
                    size_t idx = (size_t)row * N + cg;
                    __nv_bfloat16 hi, lo;
                    bf16_split(g0, hi, lo); Oh[idx] = hi;     Ol[idx] = lo;
                    bf16_split(g1, hi, lo); Oh[idx + 1] = hi; Ol[idx + 1] = lo;
                } else if (MODE == 2) {
                    size_t idx = (size_t)row * N + cg;
                    float n0 = O0[idx] + v0, n1 = O0[idx + 1] + v1;
                    O0[idx] = n0; O0[idx + 1] = n1;
                    if (EMIT) {
                        __nv_bfloat16 hi, lo;
                        bf16_split(n0, hi, lo); Oh[idx] = hi;     Ol[idx] = lo;
                        bf16_split(n1, hi, lo); Oh[idx + 1] = hi; Ol[idx + 1] = lo;
                    }
                } else {
                    size_t idx = (size_t)row * N + cg;
                    O0[idx]     = tanh_ap(v0);
                    O0[idx + 1] = tanh_ap(v1);
                }
            }
        }
}

// ---------------------------------------------------------------------------
// dash via mma -> bf16 hi/lo output [bh][s][288]
// QPHI=true : qp = ratio*(exp(dash - diag - rowmax) + eps)
// QPHI=false: E  = exp(dash - diag); block max of raw dash -> gmax
// ---------------------------------------------------------------------------
constexpr int DRB = 144;
constexpr int DA_H = 0;
constexpr int DA_L = 128 * DRB;
constexpr int DB_H = 2 * 128 * DRB;
constexpr int DB_L = DB_H + PMP_ * DRB;
constexpr int D_SDIAG = DB_L + PMP_ * DRB;
constexpr int D_SRMAX = D_SDIAG + 512;
constexpr int DASH_SMEM = D_SRMAX + 512;

template <bool QPHI>
__global__ __launch_bounds__(256, 1) void dash_mma(
    const __nv_bfloat16* __restrict__ Xh, const __nv_bfloat16* __restrict__ Xl,
    const __nv_bfloat16* __restrict__ Ph, const __nv_bfloat16* __restrict__ Pl,
    __nv_bfloat16* __restrict__ outh, __nv_bfloat16* __restrict__ outl,
    unsigned* __restrict__ gmax) {
    extern __shared__ char smem[];
    uint32_t sb = smem_u32(smem);
    float* sdiag = (float*)(smem + D_SDIAG);
    unsigned* srmax = (unsigned*)(smem + D_SRMAX);
    int tid = threadIdx.x, lane = tid & 31, warp = tid >> 5;
    int bh = blockIdx.y, b = bh >> 2, h = bh & 3;
    int s0 = blockIdx.x * 128;

    for (int i = tid; i < 1024; i += 256) {
        int r = i >> 3, c = i & 7;
        const __nv_bfloat16* s1 = Xh + ((size_t)(b * S_ + s0 + r)) * D_ + h * DH_ + c * 8;
        const __nv_bfloat16* s2 = Xl + ((size_t)(b * S_ + s0 + r)) * D_ + h * DH_ + c * 8;
        CP_ASYNC16(sb + DA_H + r * DRB + c * 16, s1);
        CP_ASYNC16(sb + DA_L + r * DRB + c * 16, s2);
    }
    for (int i = tid; i < PMP_ * 8; i += 256) {
        int r = i >> 3, c = i & 7;
        CP_ASYNC16(sb + DB_H + r * DRB + c * 16, Ph + (size_t)r * DH_ + c * 8);
        CP_ASYNC16(sb + DB_L + r * DRB + c * 16, Pl + (size_t)r * DH_ + c * 8);
    }
    CP_COMMIT(); CP_WAIT(0);
    __syncthreads();

    if (tid < 128) {
        const __nv_bfloat16* ah = (const __nv_bfloat16*)(smem + DA_H + tid * DRB);
        const __nv_bfloat16* al = (const __nv_bfloat16*)(smem + DA_L + tid * DRB);
        float s = 0.f;
#pragma unroll
        for (int c = 0; c < DH_; c++) {
            float v = __bfloat162float(ah[c]) + __bfloat162float(al[c]);
            s = fmaf(v, v, s);
        }
        sdiag[tid] = HDN2_ * s;
        srmax[tid] = 0u;
    }
    __syncthreads();

    int wm = (warp >> 1) * 32, wn = (warp & 1) * 144;
    float acc[2][18][4] = {};
    uint32_t aoff = (uint32_t)((wm + (lane & 15)) * DRB + (lane >> 4) * 16);
    uint32_t boff = (uint32_t)((wn + ((lane >> 4) << 3) + (lane & 7)) * DRB +
                               ((lane >> 3) & 1) * 16);

#pragma unroll
    for (int kt = 0; kt < 4; kt++) {
        unsigned ah[2][4], al[2][4];
#pragma unroll
        for (int mt = 0; mt < 2; mt++) {
            uint32_t a = sb + DA_H + aoff + mt * (16 * DRB) + kt * 32;
            ldsm4(ah[mt][0], ah[mt][1], ah[mt][2], ah[mt][3], a);
            ldsm4(al[mt][0], al[mt][1], al[mt][2], al[mt][3], a + (DA_L - DA_H));
        }
#pragma unroll
        for (int n2 = 0; n2 < 9; n2++) {
            unsigned bhf[2][2], blf[2][2];
            uint32_t a = sb + DB_H + boff + n2 * (16 * DRB) + kt * 32;
            ldsm4(bhf[0][0], bhf[0][1], bhf[1][0], bhf[1][1], a);
            ldsm4(blf[0][0], blf[0][1], blf[1][0], blf[1][1], a + (DB_L - DB_H));
#pragma unroll
            for (int mt = 0; mt < 2; mt++)
#pragma unroll
                for (int j = 0; j < 2; j++) {
                    int nt = n2 * 2 + j;
                    mma_bf16(acc[mt][nt], ah[mt], bhf[j]);
                    mma_bf16(acc[mt][nt], ah[mt], blf[j]);
                    mma_bf16(acc[mt][nt], al[mt], bhf[j]);
                }
        }
    }

    // per-row max of raw dash (valid cols only)
#pragma unroll
    for (int mt = 0; mt < 2; mt++)
#pragma unroll
        for (int half = 0; half < 2; half++) {
            float p = -3.4e38f;
#pragma unroll
            for (int nt = 0; nt < 18; nt++)
#pragma unroll
                for (int e = 0; e < 2; e++) {
                    int col = wn + nt * 8 + (lane & 3) * 2 + e;
                    if (col < PM_) p = fmaxf(p, DN_ * acc[mt][nt][half * 2 + e]);
                }
            p = fmaxf(p, __shfl_xor_sync(0xffffffffu, p, 1));
            p = fmaxf(p, __shfl_xor_sync(0xffffffffu, p, 2));
            if ((lane & 3) == 0)
                atomicMax(&srmax[wm + mt * 16 + (lane >> 2) + half * 8], fmap(p));
        }
    __syncthreads();

    if (!QPHI && tid == 0) {
        unsigned m = 0u;
#pragma unroll 4
        for (int i = 0; i < 128; i++) m = max(m, srmax[i]);
        atomicMax(gmax, m);
    }

#pragma unroll
    for (int mt = 0; mt < 2; mt++)
#pragma unroll
        for (int half = 0; half < 2; half++) {
            int r = wm + mt * 16 + (lane >> 2) + half * 8;
            size_t rowbase = ((size_t)bh * S_ + s0 + r) * PMP_;
            float sub = QPHI ? (sdiag[r] + funmap(srmax[r])) : sdiag[r];
#pragma unroll
            for (int nt = 0; nt < 18; nt++) {
                int colb = wn + nt * 8 + (lane & 3) * 2;
                float o[2];
#pragma unroll
                for (int e = 0; e < 2; e++) {
                    int col = colb + e;
                    float val = 0.f;
                    if (col < PM_) {
                        float dv = DN_ * acc[mt][nt][half * 2 + e];
                        val = QPHI ? RATIO_ * (__expf(dv - sub) + KEPS_)
                                   : __expf(dv - sub);
                    }
                    o[e] = val;
                }
                __nv_bfloat16 h0, l0, h1, l1;
                bf16_split(o[0], h0, l0);
                bf16_split(o[1], h1, l1);
                *(__nv_bfloat162*)(outh + rowbase + colb) =
                    __nv_bfloat162(h0, h1);
                *(__nv_bfloat162*)(outl + rowbase + colb) =
                    __nv_bfloat162(l0, l1);
            }
        }
}

// ---------------------------------------------------------------------------
// ctx via mma: ctxE[bh][m][e] = sum_s E[s][m] * Vx[s][e], Vx col 64 = 1 (ksum)
// ---------------------------------------------------------------------------
constexpr int CE_ST = 592;
constexpr int CV_ST = 160;
constexpr int C_EH = 0;
constexpr int C_EL = 32 * CE_ST;
constexpr int C_VH = 2 * 32 * CE_ST;
constexpr int C_VL = C_VH + 32 * CV_ST;
constexpr int CSTAGE = C_VL + 32 * CV_ST;     // 48128
constexpr int CTX_SMEM = 2 * CSTAGE;          // 96256

__global__ __launch_bounds__(256) void ctx_mma(
    const __nv_bfloat16* __restrict__ Eh, const __nv_bfloat16* __restrict__ El,
    const __nv_bfloat16* __restrict__ Vh, const __nv_bfloat16* __restrict__ Vl,
    float* __restrict__ ctxE) {
    extern __shared__ char smem[];
    uint32_t sb = smem_u32(smem);
    int tid = threadIdx.x, lane = tid & 31, warp = tid >> 5;
    int bh = blockIdx.x, b = bh >> 2, h = bh & 3;
    int sbase = blockIdx.y * 512;

    auto stage = [&](int buf, int chunk) {
        uint32_t base = sb + buf * CSTAGE;
        int s0 = sbase + chunk * 32;
        for (int i = tid; i < 1152; i += 256) {
            int r = i / 36, c = i - r * 36;
            size_t g = ((size_t)bh * S_ + s0 + r) * PMP_ + c * 8;
            CP_ASYNC16(base + C_EH + r * CE_ST + c * 16, Eh + g);
            CP_ASYNC16(base + C_EL + r * CE_ST + c * 16, El + g);
        }
        {
            int i = tid;
            if (i < 256) {
                int r = i >> 3, c = i & 7;
                size_t g = ((size_t)(b * S_ + s0 + r)) * D_ + h * DH_ + c * 8;
                CP_ASYNC16(base + C_VH + r * CV_ST + c * 16, Vh + g);
                CP_ASYNC16(base + C_VL + r * CV_ST + c * 16, Vl + g);
            }
        }
        if (tid < 64) {
            int r = tid >> 1, half2 = tid & 1;
            uint4 z = make_uint4(0, 0, 0, 0);
            uint4 one = make_uint4(0x00003F80u, 0, 0, 0);
            uint32_t off = (uint32_t)(r * CV_ST + 128 + half2 * 16);
            *(uint4*)(smem + buf * CSTAGE + C_VH + off) = (half2 == 0) ? one : z;
            *(uint4*)(smem + buf * CSTAGE + C_VL + off) = z;
        }
    };

    stage(0, 0); CP_COMMIT();
    stage(1, 1); CP_COMMIT();

    int mts[3];
    mts[0] = warp * 2; mts[1] = warp * 2 + 1; mts[2] = (warp < 2) ? 16 + warp : -1;
    float acc[3][9][4] = {};

    for (int t = 0; t < 16; t++) {
        if (t + 1 < 16) CP_WAIT(1); else CP_WAIT(0);
        __syncthreads();
        uint32_t bs = sb + (t & 1) * CSTAGE;
#pragma unroll
        for (int kt = 0; kt < 2; kt++) {
            int krA = (lane & 7) + ((lane >> 4) & 1) * 8 + kt * 16;
            int mcolbit = ((lane >> 3) & 1) * 8;
            unsigned ah[3][4], al[3][4];
#pragma unroll
            for (int mt = 0; mt < 3; mt++) {
                if (mts[mt] < 0) break;
                uint32_t a = bs + C_EH + krA * CE_ST + (mts[mt] * 16 + mcolbit) * 2;
                ldsm4t(ah[mt][0], ah[mt][1], ah[mt][2], ah[mt][3], a);
                ldsm4t(al[mt][0], al[mt][1], al[mt][2], al[mt][3], a + (C_EL - C_EH));
            }
            int krB = (lane & 7) + ((lane >> 3) & 1) * 8 + kt * 16;
            int ncolbit = (lane >> 4) * 8;
#pragma unroll
            for (int p = 0; p < 5; p++) {
                unsigned bhf[4], blf[4];
                uint32_t a = bs + C_VH + krB * CV_ST + (p * 16 + ncolbit) * 2;
                ldsm4t(bhf[0], bhf[1], bhf[2], bhf[3], a);
                ldsm4t(blf[0], blf[1], blf[2], blf[3], a + (C_VL - C_VH));
#pragma unroll
                for (int j = 0; j < 2; j++) {
                    int nt = p * 2 + j;
                    if (nt > 8) break;
#pragma unroll
                    for (int mt = 0; mt < 3; mt++) {
                        if (mts[mt] < 0) break;
                        mma_bf16(acc[mt][nt], ah[mt], bhf + j * 2);
                        mma_bf16(acc[mt][nt], ah[mt], blf + j * 2);
                        mma_bf16(acc[mt][nt], al[mt], bhf + j * 2);
                    }
                }
            }
        }
        __syncthreads();
        if (t + 2 < 16) { stage(t & 1, t + 2); CP_COMMIT(); }
    }

#pragma unroll
    for (int mt = 0; mt < 3; mt++) {
        if (mts[mt] < 0) break;
#pragma unroll
        for (int nt = 0; nt < 9; nt++)
#pragma unroll
            for (int half = 0; half < 2; half++) {
                int m = mts[mt] * 16 + (lane >> 2) + half * 8;
                int e = nt * 8 + (lane & 3) * 2;
                float* dst = ctxE + ((size_t)bh * PMP_ + m) * 72 + e;
                atomicAdd(dst,     acc[mt][nt][half * 2]);
                atomicAdd(dst + 1, acc[mt][nt][half * 2 + 1]);
            }
    }
}

// vsum[bh][e] = sum_s v[b][s][h*64+e]
__global__ void vsum_kernel(const __nv_bfloat16* __restrict__ vh,
                            const __nv_bfloat16* __restrict__ vl,
                            float* __restrict__ vsum) {
    int bh = blockIdx.x, b = bh >> 2, h = bh & 3;
    int e = threadIdx.x;
    int s0 = blockIdx.y * 512;
    float s = 0.f;
    for (int i = 0; i < 512; i++) {
        size_t idx = ((size_t)(b * S_ + s0 + i)) * D_ + h * DH_ + e;
        s += __bfloat162float(vh[idx]) + __bfloat162float(vl[idx]);
    }
    atomicAdd(&vsum[bh * 64 + e], s);
}

// ctx_b = a*ctxE + correction; bf16 hi/lo [bh][288][80]
__global__ void ctxcorr_kernel(const float* __restrict__ ctxE, const float* __restrict__ vsum,
                               const unsigned* __restrict__ gmax,
                               __nv_bfloat16* __restrict__ cbh, __nv_bfloat16* __restrict__ cbl) {
    int idx = blockIdx.x * 256 + threadIdx.x;
    if (idx >= BH_ * PMP_ * 80) return;
    int bh = idx / (PMP_ * 80);
    int rem = idx - bh * (PMP_ * 80);
    int m = rem / 80, e = rem - m * 80;
    float a = RATIO_ * __expf(-funmap(*gmax));
    float c = RATIO_ * KEPS_;
    float val = 0.f;
    if (m < PM_ && e < 72) {
        float base = ctxE[((size_t)bh * PMP_ + m) * 72 + e];
        float corr = (e < 64) ? c * vsum[bh * 64 + e] : ((e == 64) ? c * (float)S_ : 0.f);
        val = a * base + corr;
    }
    __nv_bfloat16 hi, lo;
    bf16_split(val, hi, lo);
    cbh[idx] = hi; cbl[idx] = lo;
}

// ---------------------------------------------------------------------------
// attnout via mma: O[s][e] = (qp[s]·ctx_b[:,e]) / (qp[s]·ksum)  -> oh/ol bf16
// ---------------------------------------------------------------------------
constexpr int AQ_ST = 80;
constexpr int AB_ST = 160;
constexpr int A_QH = 0;
constexpr int A_QL = 128 * AQ_ST;
constexpr int A_BH2 = 2 * 128 * AQ_ST;
constexpr int A_BL2 = A_BH2 + 32 * AB_ST;
constexpr int ASTAGE = A_BL2 + 32 * AB_ST;    // 30720
constexpr int A_SDEN = 2 * ASTAGE;            // 61440
constexpr int ATT_SMEM = A_SDEN + 512;        // 61952

__global__ __launch_bounds__(256) void attnout_mma(
    const __nv_bfloat16* __restrict__ Qh, const __nv_bfloat16* __restrict__ Ql,
    const __nv_bfloat16* __restrict__ Cbh, const __nv_bfloat16* __restrict__ Cbl,
    __nv_bfloat16* __restrict__ oh, __nv_bfloat16* __restrict__ ol) {
    extern __shared__ char smem[];
    uint32_t sb = smem_u32(smem);
    float* sden = (float*)(smem + A_SDEN);
    int tid = threadIdx.x, lane = tid & 31, warp = tid >> 5;
    int bh = blockIdx.y, b = bh >> 2, h = bh & 3;
    int s0 = blockIdx.x * 128;

    auto stage = [&](int buf, int chunk) {
        uint32_t base = sb + buf * ASTAGE;
        int k0 = chunk * 32;
        for (int i = tid; i < 512; i += 256) {
            int r = i >> 2, c = i & 3;
            size_t g = ((size_t)bh * S_ + s0 + r) * PMP_ + k0 + c * 8;
            CP_ASYNC16(base + A_QH + r * AQ_ST + c * 16, Qh + g);
            CP_ASYNC16(base + A_QL + r * AQ_ST + c * 16, Ql + g);
        }
        for (int i = tid; i < 320; i += 256) {
            int r = i / 10, c = i - r * 10;
            size_t g = ((size_t)bh * PMP_ + k0 + r) * 80 + c * 8;
            CP_ASYNC16(base + A_BH2 + r * AB_ST + c * 16, Cbh + g);
            CP_ASYNC16(base + A_BL2 + r * AB_ST + c * 16, Cbl + g);
        }
    };

    stage(0, 0); CP_COMMIT();
    stage(1, 1); CP_COMMIT();

    int wm = (warp >> 1) * 32, ng = warp & 1;
    float acc[2][5][4] = {};
    uint32_t aoff = (uint32_t)((wm + (lane & 15)) * AQ_ST + (lane >> 4) * 16);

    for (int t = 0; t < 9; t++) {
        if (t + 1 < 9) CP_WAIT(1); else CP_WAIT(0);
        __syncthreads();
        uint32_t bs = sb + (t & 1) * ASTAGE;
#pragma unroll
        for (int kt = 0; kt < 2; kt++) {
            unsigned ah[2][4], al[2][4];
#pragma unroll
            for (int mt = 0; mt < 2; mt++) {
                uint32_t a = bs + A_QH + aoff + mt * (16 * AQ_ST) + kt * 32;
                ldsm4(ah[mt][0], ah[mt][1], ah[mt][2], ah[mt][3], a);
                ldsm4(al[mt][0], al[mt][1], al[mt][2], al[mt][3], a + (A_QL - A_QH));
            }
            int krB = (lane & 7) + ((lane >> 3) & 1) * 8 + kt * 16;
            int ncolbit = (lane >> 4) * 8;
#pragma unroll
            for (int pi = 0; pi < 3; pi++) {
                if (!ng && pi == 2) break;
                int p = ng ? (2 + pi) : pi;
                unsigned bhf[4], blf[4];
                uint32_t a = bs + A_BH2 + krB * AB_ST + (p * 16 + ncolbit) * 2;
                ldsm4t(bhf[0], bhf[1], bhf[2], bhf[3], a);
                ldsm4t(blf[0], blf[1], blf[2], blf[3], a + (A_BL2 - A_BH2));
#pragma unroll
                for (int j = 0; j < 2; j++) {
                    int ntg = p * 2 + j;
                    if (ntg > 8) break;
                    int ntl = ntg - ng * 4;
#pragma unroll
                    for (int mt = 0; mt < 2; mt++) {
                        mma_bf16(acc[mt][ntl], ah[mt], bhf + j * 2);
                        mma_bf16(acc[mt][ntl], ah[mt], blf + j * 2);
                        mma_bf16(acc[mt][ntl], al[mt], bhf + j * 2);
                    }
                }
            }
        }
        __syncthreads();
        if (t + 2 < 9) { stage(t & 1, t + 2); CP_COMMIT(); }
    }

    if (ng == 1 && (lane & 3) == 0) {
#pragma unroll
        for (int mt = 0; mt < 2; mt++)
#pragma unroll
            for (int half = 0; half < 2; half++) {
                int r = wm + mt * 16 + (lane >> 2) + half * 8;
                sden[r] = acc[mt][4][half * 2];
            }
    }
    __syncthreads();

#pragma unroll
    for (int mt = 0; mt < 2; mt++)
#pragma unroll
        for (int half = 0; half < 2; half++) {
            int r = wm + mt * 16 + (lane >> 2) + half * 8;
            float rinv = 1.f / sden[r];
            size_t obase = ((size_t)(b * S_ + s0 + r)) * D_ + h * DH_;
#pragma unroll
            for (int ntl = 0; ntl < 4; ntl++) {
                int e = (ng * 4 + ntl) * 8 + (lane & 3) * 2;
                float v0 = acc[mt][ntl][half * 2]     * rinv;
                float v1 = acc[mt][ntl][half * 2 + 1] * rinv;
                __nv_bfloat16 h0, l0, h1, l1;
                bf16_split(v0, h0, l0);
                bf16_split(v1, h1, l1);
                *(__nv_bfloat162*)(oh + obase + e) = __nv_bfloat162(h0, h1);
                *(__nv_bfloat162*)(ol + obase + e) = __nv_bfloat162(l0, l1);
            }
        }
}

// ---------------------------------------------------------------------------
// Per-layer init
// ---------------------------------------------------------------------------
__global__ void layer_init_kernel(float* __restrict__ ctxE, float* __restrict__ vsum,
                                  unsigned* __restrict__ km) {
    int i = blockIdx.x * 256 + threadIdx.x;
    if (i < BH_ * PMP_ * 72) ctxE[i] = 0.f;
    if (i < BH_ * 64) vsum[i] = 0.f;
    if (i == 0) *km = 0u;
}

// ---------------------------------------------------------------------------
// Pooling (score: warp-per-row)
// ---------------------------------------------------------------------------
__global__ __launch_bounds__(256) void score_kernel(
    const float* __restrict__ h, const float* __restrict__ p2w,
    const float* __restrict__ p2b, const float* __restrict__ mask,
    float* __restrict__ score) {
    int warp = threadIdx.x >> 5, lane = threadIdx.x & 31;
    int row = blockIdx.x * 8 + warp;
    int c0 = lane * 8;
    const float* rp = h + (size_t)row * D_ + c0;
    float4 a0 = *(const float4*)rp, a1 = *(const float4*)(rp + 4);
    float4 w0 = *(const float4*)(p2w + c0), w1 = *(const float4*)(p2w + c0 + 4);
    float s = a0.x * w0.x + a0.y * w0.y + a0.z * w0.z + a0.w * w0.w +
              a1.x * w1.x + a1.y * w1.y + a1.z * w1.z + a1.w * w1.w;
    s = warpsum(s);
    if (lane == 0) score[row] = expf(s + p2b[0]) * mask[row];
}

__global__ void ssum_kernel(const float* __restrict__ score, float* __restrict__ ssum) {
    __shared__ float sh[8];
    int b = blockIdx.x;
    float s = 0.f;
    for (int i = threadIdx.x; i < S_; i += 256) s += score[b * S_ + i];
    s = block_sum(s, sh);
    if (threadIdx.x == 0) ssum[b] = s;
}

__global__ void outzero_kernel(float* __restrict__ out) {
    int i = blockIdx.x * blockDim.x + threadIdx.x;
    if (i < B_ * D_) out[i] = 0.f;
}

__global__ void pool_kernel(const float* __restrict__ x, const float* __restrict__ score,
                            const float* __restrict__ ssum, float* __restrict__ out) {
    int b = blockIdx.x, chunk = blockIdx.y, d = threadIdx.x;
    float inv = 1.f / (ssum[b] + 1e-8f);
    float acc = 0.f;
    int s0 = chunk * (S_ / 64);
    for (int s = s0; s < s0 + S_ / 64; s++)
        acc = fmaf(x[((size_t)(b * S_ + s)) * D_ + d], score[b * S_ + s], acc);
    atomicAdd(&out[b * D_ + d], acc * inv);
}

// ---------------------------------------------------------------------------
// Host launcher
// ---------------------------------------------------------------------------
extern "C" void kernel_launch(void* const* d_in, const int* in_sizes, int n_in,
                              void* d_out, int out_size) {
    const float* emb  = (const float*)d_in[0];
    const float* mask = (const float*)d_in[1];
    const float* pos  = (const float*)d_in[2];
    const float* ln_g = (const float*)d_in[3];
    const float* ln_b = (const float*)d_in[4];
    const float* proj = (const float*)d_in[5];
    const float* Wq = (const float*)d_in[6];   const float* bq = (const float*)d_in[7];
    const float* Wk = (const float*)d_in[8];   const float* bk = (const float*)d_in[9];
    const float* Wv = (const float*)d_in[10];  const float* bv = (const float*)d_in[11];
    const float* Wo = (const float*)d_in[12];  const float* bo = (const float*)d_in[13];
    const float* ln1g = (const float*)d_in[14]; const float* ln1b = (const float*)d_in[15];
    const float* W1 = (const float*)d_in[16];  const float* b1 = (const float*)d_in[17];
    const float* W2 = (const float*)d_in[18];  const float* b2 = (const float*)d_in[19];
    const float* ln2g = (const float*)d_in[20]; const float* ln2b = (const float*)d_in[21];
    const float* p1w = (const float*)d_in[22]; const float* p1b = (const float*)d_in[23];
    const float* p2w = (const float*)d_in[24]; const float* p2b = (const float*)d_in[25];
    float* out = (float*)d_out;

    void* tp;
    float *x, *h, *sc, *ss, *bqkv, *ctxE, *vsum;
    unsigned* km;
    __nv_bfloat16 *wth, *wtl, *hh, *hl, *oh, *ol, *fh, *fl, *xh, *xl;
    __nv_bfloat16 *qh, *ql, *kh, *kl, *vh, *vl, *pjh, *pjl;
    __nv_bfloat16 *qph, *qpl, *eh, *el, *cbh, *cbl;
    cudaGetSymbolAddress(&tp, g_x);     x  = (float*)tp;
    cudaGetSymbolAddress(&tp, g_h);     h  = (float*)tp;
    cudaGetSymbolAddress(&tp, g_score); sc = (float*)tp;
    cudaGetSymbolAddress(&tp, g_ssum);  ss = (float*)tp;
    cudaGetSymbolAddress(&tp, g_kmaxu); km = (unsigned*)tp;
    cudaGetSymbolAddress(&tp, g_bqkv);  bqkv = (float*)tp;
    cudaGetSymbolAddress(&tp, g_ctxE);  ctxE = (float*)tp;
    cudaGetSymbolAddress(&tp, g_vsum);  vsum = (float*)tp;
    cudaGetSymbolAddress(&tp, g_wth);   wth = (__nv_bfloat16*)tp;
    cudaGetSymbolAddress(&tp, g_wtl);   wtl = (__nv_bfloat16*)tp;
    cudaGetSymbolAddress(&tp, g_hh);    hh = (__nv_bfloat16*)tp;
    cudaGetSymbolAddress(&tp, g_hl);    hl = (__nv_bfloat16*)tp;
    cudaGetSymbolAddress(&tp, g_oh);    oh = (__nv_bfloat16*)tp;
    cudaGetSymbolAddress(&tp, g_ol);    ol = (__nv_bfloat16*)tp;
    cudaGetSymbolAddress(&tp, g_fh);    fh = (__nv_bfloat16*)tp;
    cudaGetSymbolAddress(&tp, g_fl);    fl = (__nv_bfloat16*)tp;
    cudaGetSymbolAddress(&tp, g_xh);    xh = (__nv_bfloat16*)tp;
    cudaGetSymbolAddress(&tp, g_xl);    xl = (__nv_bfloat16*)tp;
    cudaGetSymbolAddress(&tp, g_qh);    qh = (__nv_bfloat16*)tp;
    cudaGetSymbolAddress(&tp, g_ql);    ql = (__nv_bfloat16*)tp;
    cudaGetSymbolAddress(&tp, g_kh);    kh = (__nv_bfloat16*)tp;
    cudaGetSymbolAddress(&tp, g_kl);    kl = (__nv_bfloat16*)tp;
    cudaGetSymbolAddress(&tp, g_vh);    vh = (__nv_bfloat16*)tp;
    cudaGetSymbolAddress(&tp, g_vl);    vl = (__nv_bfloat16*)tp;
    cudaGetSymbolAddress(&tp, g_pjh);   pjh = (__nv_bfloat16*)tp;
    cudaGetSymbolAddress(&tp, g_pjl);   pjl = (__nv_bfloat16*)tp;
    cudaGetSymbolAddress(&tp, g_qph);   qph = (__nv_bfloat16*)tp;
    cudaGetSymbolAddress(&tp, g_qpl);   qpl = (__nv_bfloat16*)tp;
    cudaGetSymbolAddress(&tp, g_eh);    eh = (__nv_bfloat16*)tp;
    cudaGetSymbolAddress(&tp, g_el);    el = (__nv_bfloat16*)tp;
    cudaGetSymbolAddress(&tp, g_cbh);   cbh = (__nv_bfloat16*)tp;
    cudaGetSymbolAddress(&tp, g_cbl);   cbl = (__nv_bfloat16*)tp;

    static bool attr_done = false;
    if (!attr_done) {
        cudaFuncSetAttribute(mm_gemm<0, false>, cudaFuncAttributeMaxDynamicSharedMemorySize, MM_SMEM);
        cudaFuncSetAttribute(mm_gemm<1, false>, cudaFuncAttributeMaxDynamicSharedMemorySize, MM_SMEM);
        cudaFuncSetAttribute(mm_gemm<2, false>, cudaFuncAttributeMaxDynamicSharedMemorySize, MM_SMEM);
        cudaFuncSetAttribute(mm_gemm<2, true>,  cudaFuncAttributeMaxDynamicSharedMemorySize, MM_SMEM);
        cudaFuncSetAttribute(mm_gemm<3, false>, cudaFuncAttributeMaxDynamicSharedMemorySize, MM_SMEM);
        cudaFuncSetAttribute(dash_mma<true>,  cudaFuncAttributeMaxDynamicSharedMemorySize, DASH_SMEM);
        cudaFuncSetAttribute(dash_mma<false>, cudaFuncAttributeMaxDynamicSharedMemorySize, DASH_SMEM);
        cudaFuncSetAttribute(ctx_mma,     cudaFuncAttributeMaxDynamicSharedMemorySize, CTX_SMEM);
        cudaFuncSetAttribute(attnout_mma, cudaFuncAttributeMaxDynamicSharedMemorySize, ATT_SMEM);
        attr_done = true;
    }

    // --- weight prep (batched over layers via gridDim.z) ---
    dim3 wb(32, 8);
    wsplit_kernel<<<dim3(8, 8, NL_), wb>>>(Wq, wth + OFF_QKV, wtl + OFF_QKV,
                                           256, 256, 0,   65536, (size_t)768 * 256);
    wsplit_kernel<<<dim3(8, 8, NL_), wb>>>(Wk, wth + OFF_QKV, wtl + OFF_QKV,
                                           256, 256, 256, 65536, (size_t)768 * 256);
    wsplit_kernel<<<dim3(8, 8, NL_), wb>>>(Wv, wth + OFF_QKV, wtl + OFF_QKV,
                                           256, 256, 512, 65536, (size_t)768 * 256);
    wsplit_kernel<<<dim3(8, 8, NL_), wb>>>(Wo, wth + OFF_WO, wtl + OFF_WO,
                                           256, 256, 0, 65536, 65536);
    wsplit_kernel<<<dim3(32, 8, NL_), wb>>>(W1, wth + OFF_W1, wtl + OFF_W1,
                                            256, 1024, 0, 262144, 262144);
    wsplit_kernel<<<dim3(8, 32, NL_), wb>>>(W2, wth + OFF_W2, wtl + OFF_W2,
                                            1024, 256, 0, 262144, 262144);
    wsplit_kernel<<<dim3(8, 8, 1), wb>>>(p1w, wth + OFF_P1, wtl + OFF_P1,
                                         256, 256, 0, 0, 0);
    bconcat_kernel<<<NL_, 256>>>(bq, bk, bv, bqkv);
    psplit_kernel<<<(NL_ * PMP_ * DH_) / 256, 256>>>(proj, pjh, pjl);

    embed_ln_kernel<<<BS_ / 8, 256>>>(emb, pos, ln_g, ln_b, x);

    for (int l = 0; l < NL_; l++) {
        // --- attention block ---
        ln_kernel<<<BS_ / 8, 256>>>(x, hh, hl, ln1g + l * D_, ln1b + l * D_);
        mm_gemm<0, false><<<dim3(6, 128), 256, MM_SMEM>>>(
            hh, hl, wth + OFF_QKV + (size_t)l * 768 * 256, wtl + OFF_QKV + (size_t)l * 768 * 256,
            bqkv + l * 768, nullptr, qh, ql, kh, kl, vh, vl, 256, 768);

        layer_init_kernel<<<(BH_ * PMP_ * 72 + 255) / 256, 256>>>(ctxE, vsum, km);

        dash_mma<true><<<dim3(S_ / 128, BH_), 256, DASH_SMEM>>>(
            qh, ql, pjh + (size_t)l * PMP_ * DH_, pjl + (size_t)l * PMP_ * DH_,
            qph, qpl, nullptr);
        dash_mma<false><<<dim3(S_ / 128, BH_), 256, DASH_SMEM>>>(
            kh, kl, pjh + (size_t)l * PMP_ * DH_, pjl + (size_t)l * PMP_ * DH_,
            eh, el, km);

        vsum_kernel<<<dim3(BH_, 8), 64>>>(vh, vl, vsum);
        ctx_mma<<<dim3(BH_, 8), 256, CTX_SMEM>>>(eh, el, vh, vl, ctxE);
        ctxcorr_kernel<<<(BH_ * PMP_ * 80 + 255) / 256, 256>>>(ctxE, vsum, km, cbh, cbl);
        attnout_mma<<<dim3(S_ / 128, BH_), 256, ATT_SMEM>>>(qph, qpl, cbh, cbl, oh, ol);

        mm_gemm<2, false><<<dim3(2, 128), 256, MM_SMEM>>>(
            oh, ol, wth + OFF_WO + (size_t)l * 65536, wtl + OFF_WO + (size_t)l * 65536,
            bo + l * 256, x, nullptr, nullptr, nullptr, nullptr, nullptr, nullptr, 256, 256);

        // --- FFN block ---
        ln_kernel<<<BS_ / 8, 256>>>(x, hh, hl, ln2g + l * D_, ln2b + l * D_);
        mm_gemm<1, false><<<dim3(8, 128), 256, MM_SMEM>>>(
            hh, hl, wth + OFF_W1 + (size_t)l * 262144, wtl + OFF_W1 + (size_t)l * 262144,
            b1 + l * 1024, nullptr, fh, fl, nullptr, nullptr, nullptr, nullptr, 256, 1024);
        mm_gemm<2, true><<<dim3(2, 128), 256, MM_SMEM>>>(
            fh, fl, wth + OFF_W2 + (size_t)l * 262144, wtl + OFF_W2 + (size_t)l * 262144,
            b2 + l * 256, x, xh, xl, nullptr, nullptr, nullptr, nullptr, 1024, 256);
    }

    // --- attention pooling ---
    mm_gemm<3, false><<<dim3(2, 128), 256, MM_SMEM>>>(
        xh, xl, wth + OFF_P1, wtl + OFF_P1, p1b, h,
        nullptr, nullptr, nullptr, nullptr, nullptr, nullptr, 256, 256);
    score_kernel<<<BS_ / 8, 256>>>(h, p2w, p2b, mask, sc);
    ssum_kernel<<<B_, 256>>>(sc, ss);
    outzero_kernel<<<(B_ * D_ + 255) / 256, 256>>>(out);
    pool_kernel<<<dim3(B_, 64), 256>>>(x, sc, ss, out);
}

// round 11
// speedup vs baseline: 2.6944x; 1.2597x over previous
#include <cuda_runtime.h>
#include <cuda_bf16.h>
#include <cstdint>

// ---------------------------------------------------------------------------
// Problem constants
// ---------------------------------------------------------------------------
constexpr int B_  = 4;
constexpr int S_  = 4096;
constexpr int D_  = 256;
constexpr int DH_ = 64;
constexpr int NL_ = 4;
constexpr int PM_ = 266;          // nb_features
constexpr int PMP_ = 288;         // padded for mma
constexpr int FF_ = 1024;
constexpr int BS_ = B_ * S_;      // 16384 rows
constexpr int BH_ = B_ * 4;       // 16

constexpr float DN_    = 0.35355339059327373f;  // 64^-0.25
constexpr float HDN2_  = 0.0625f;               // 0.5 * dn^2
constexpr float RATIO_ = 0.06131392f;           // 266^-0.5
constexpr float KEPS_  = 1e-4f;
constexpr float LNEPS_ = 1e-12f;

// ---------------------------------------------------------------------------
// Scratch (static device globals)
// ---------------------------------------------------------------------------
__device__ float g_x  [BS_ * D_];
__device__ float g_h  [BS_ * D_];     // pooling tanh output (fp32)
__device__ float g_score[BS_];
__device__ float g_ssum [B_];
__device__ unsigned g_kmaxu;

// bf16 hi/lo operand buffers
constexpr size_t OFF_QKV = 0;
constexpr size_t OFF_WO  = OFF_QKV + (size_t)NL_ * 768 * 256;
constexpr size_t OFF_W1  = OFF_WO  + (size_t)NL_ * 256 * 256;
constexpr size_t OFF_W2  = OFF_W1  + (size_t)NL_ * 1024 * 256;
constexpr size_t OFF_P1  = OFF_W2  + (size_t)NL_ * 256 * 1024;
constexpr size_t WT_TOT  = OFF_P1 + 256 * 256;

__device__ __nv_bfloat16 g_wth[WT_TOT], g_wtl[WT_TOT];
__device__ float g_bqkv[NL_ * 768];
__device__ __nv_bfloat16 g_hh[BS_ * D_], g_hl[BS_ * D_];      // LN outputs
__device__ __nv_bfloat16 g_oh[BS_ * D_];                      // attnout (single bf16)
__device__ __nv_bfloat16 g_fh[(size_t)BS_ * FF_];             // gelu (single bf16)
__device__ __nv_bfloat16 g_xh[BS_ * D_], g_xl[BS_ * D_];      // residual (pooling)
__device__ __nv_bfloat16 g_qh[BS_ * D_], g_ql[BS_ * D_];      // q hi/lo
__device__ __nv_bfloat16 g_kh[BS_ * D_], g_kl[BS_ * D_];      // k hi/lo
__device__ __nv_bfloat16 g_vh[BS_ * D_], g_vl[BS_ * D_];      // v hi/lo
__device__ __nv_bfloat16 g_pjh[NL_ * PMP_ * DH_], g_pjl[NL_ * PMP_ * DH_];

// FAVOR intermediates (single bf16)
__device__ __nv_bfloat16 g_qph[(size_t)BH_ * S_ * PMP_];
__device__ __nv_bfloat16 g_eh [(size_t)BH_ * S_ * PMP_];
__device__ float g_ctxE[BH_ * PMP_ * 72];
__device__ __nv_bfloat16 g_cbh[BH_ * PMP_ * 80], g_cbl[BH_ * PMP_ * 80];
__device__ float g_vsum[BH_ * 64];

// ---------------------------------------------------------------------------
// PTX helpers (family-portable: no tcgen05 on compute_103 targets)
// ---------------------------------------------------------------------------
__device__ __forceinline__ uint32_t smem_u32(const void* p) {
    uint32_t a;
    asm("{ .reg .u64 t; cvta.to.shared.u64 t, %1; cvt.u32.u64 %0, t; }" : "=r"(a) : "l"(p));
    return a;
}
__device__ __forceinline__ void ldsm4(unsigned& r0, unsigned& r1, unsigned& r2, unsigned& r3,
                                      uint32_t addr) {
    asm volatile("ldmatrix.sync.aligned.m8n8.x4.shared.b16 {%0,%1,%2,%3}, [%4];"
                 : "=r"(r0), "=r"(r1), "=r"(r2), "=r"(r3) : "r"(addr));
}
__device__ __forceinline__ void ldsm4t(unsigned& r0, unsigned& r1, unsigned& r2, unsigned& r3,
                                       uint32_t addr) {
    asm volatile("ldmatrix.sync.aligned.m8n8.x4.trans.shared.b16 {%0,%1,%2,%3}, [%4];"
                 : "=r"(r0), "=r"(r1), "=r"(r2), "=r"(r3) : "r"(addr));
}
__device__ __forceinline__ void mma_bf16(float* d, const unsigned* a, const unsigned* b) {
    asm volatile("mma.sync.aligned.m16n8k16.row.col.f32.bf16.bf16.f32 "
                 "{%0,%1,%2,%3}, {%4,%5,%6,%7}, {%8,%9}, {%0,%1,%2,%3};"
                 : "+f"(d[0]), "+f"(d[1]), "+f"(d[2]), "+f"(d[3])
                 : "r"(a[0]), "r"(a[1]), "r"(a[2]), "r"(a[3]), "r"(b[0]), "r"(b[1]));
}
#define CP_ASYNC16(dst, src) \
    asm volatile("cp.async.cg.shared.global [%0], [%1], 16;" :: "r"(dst), "l"(src) : "memory")
#define CP_COMMIT() asm volatile("cp.async.commit_group;" ::: "memory")
#define CP_WAIT(n)  asm volatile("cp.async.wait_group %0;" :: "n"(n) : "memory")

__device__ __forceinline__ void bf16_split(float v, __nv_bfloat16& hi, __nv_bfloat16& lo) {
    hi = __float2bfloat16(v);
    lo = __float2bfloat16(v - __bfloat162float(hi));
}
__device__ __forceinline__ float tanh_ap(float x) {
    float r;
    asm("tanh.approx.f32 %0, %1;" : "=f"(r) : "f"(x));
    return r;
}

// ---------------------------------------------------------------------------
// Reductions
// ---------------------------------------------------------------------------
__device__ __forceinline__ float warpsum(float v) {
#pragma unroll
    for (int o = 16; o > 0; o >>= 1) v += __shfl_xor_sync(0xffffffffu, v, o);
    return v;
}
__device__ __forceinline__ float block_sum(float v, float* sh) {
    int lane = threadIdx.x & 31, w = threadIdx.x >> 5, nw = blockDim.x >> 5;
    v = warpsum(v);
    if (lane == 0) sh[w] = v;
    __syncthreads();
    if (w == 0) {
        float x = (lane < nw) ? sh[lane] : 0.f;
        x = warpsum(x);
        if (lane == 0) sh[0] = x;
    }
    __syncthreads();
    float r = sh[0];
    __syncthreads();
    return r;
}
__device__ __forceinline__ unsigned fmap(float f) {
    unsigned u = __float_as_uint(f);
    return (u & 0x80000000u) ? ~u : (u | 0x80000000u);
}
__device__ __forceinline__ float funmap(unsigned u) {
    u = (u & 0x80000000u) ? (u & 0x7FFFFFFFu) : ~u;
    return __uint_as_float(u);
}

// ---------------------------------------------------------------------------
// Weight transpose + bf16 split: W [K,N] fp32 -> Th/Tl [N,K] bf16; z = layer
// ---------------------------------------------------------------------------
__global__ void wsplit_kernel(const float* __restrict__ W, __nv_bfloat16* __restrict__ Th,
                              __nv_bfloat16* __restrict__ Tl, int K, int N, int rowOff,
                              size_t sstride, size_t dstride) {
    __shared__ float ts[32][33];
    int l = blockIdx.z;
    W  += (size_t)l * sstride;
    Th += (size_t)l * dstride;
    Tl += (size_t)l * dstride;
    int kb = blockIdx.y * 32, nb = blockIdx.x * 32;
    int tx = threadIdx.x, ty = threadIdx.y;
#pragma unroll
    for (int i = 0; i < 4; i++) {
        int k = kb + ty + i * 8;
        ts[ty + i * 8][tx] = W[(size_t)k * N + nb + tx];
    }
    __syncthreads();
#pragma unroll
    for (int i = 0; i < 4; i++) {
        int n = nb + ty + i * 8;
        int k = kb + tx;
        float v = ts[tx][ty + i * 8];
        __nv_bfloat16 hi, lo;
        bf16_split(v, hi, lo);
        size_t idx = (size_t)(rowOff + n) * K + k;
        Th[idx] = hi; Tl[idx] = lo;
    }
}

__global__ void bconcat_kernel(const float* __restrict__ bq, const float* __restrict__ bk,
                               const float* __restrict__ bv, float* __restrict__ dst) {
    int l = blockIdx.x, t = threadIdx.x;
    dst[l * 768 + t]       = bq[l * 256 + t];
    dst[l * 768 + 256 + t] = bk[l * 256 + t];
    dst[l * 768 + 512 + t] = bv[l * 256 + t];
}

__global__ void psplit_kernel(const float* __restrict__ proj,
                              __nv_bfloat16* __restrict__ ph, __nv_bfloat16* __restrict__ pl) {
    int idx = blockIdx.x * 256 + threadIdx.x;
    int l = idx / (PMP_ * DH_);
    int rem = idx - l * (PMP_ * DH_);
    int r = rem >> 6, c = rem & 63;
    float v = (r < PM_) ? proj[((size_t)l * PM_ + r) * DH_ + c] : 0.f;
    __nv_bfloat16 hi, lo;
    bf16_split(v, hi, lo);
    ph[idx] = hi; pl[idx] = lo;
}

// ---------------------------------------------------------------------------
// LayerNorm — warp-per-row
// ---------------------------------------------------------------------------
__global__ __launch_bounds__(256) void embed_ln_kernel(
    const float* __restrict__ emb, const float* __restrict__ pos,
    const float* __restrict__ g, const float* __restrict__ bb,
    float* __restrict__ out) {
    int warp = threadIdx.x >> 5, lane = threadIdx.x & 31;
    int row = blockIdx.x * 8 + warp;
    int c0 = lane * 8;
    const float* ep = emb + (size_t)row * D_ + c0;
    const float* pp = pos + (size_t)(row & (S_ - 1)) * D_ + c0;
    float v[8];
    float4 a0 = *(const float4*)ep, a1 = *(const float4*)(ep + 4);
    float4 p0 = *(const float4*)pp, p1 = *(const float4*)(pp + 4);
    v[0] = a0.x + p0.x; v[1] = a0.y + p0.y; v[2] = a0.z + p0.z; v[3] = a0.w + p0.w;
    v[4] = a1.x + p1.x; v[5] = a1.y + p1.y; v[6] = a1.z + p1.z; v[7] = a1.w + p1.w;
    float s = 0.f;
#pragma unroll
    for (int j = 0; j < 8; j++) s += v[j];
    float mu = warpsum(s) * (1.0f / D_);
    float s2 = 0.f;
#pragma unroll
    for (int j = 0; j < 8; j++) { float d = v[j] - mu; s2 = fmaf(d, d, s2); }
    float rs = rsqrtf(warpsum(s2) * (1.0f / D_) + LNEPS_);
    float4 g0 = *(const float4*)(g + c0), g1 = *(const float4*)(g + c0 + 4);
    float4 b0 = *(const float4*)(bb + c0), b1 = *(const float4*)(bb + c0 + 4);
    float gg[8] = {g0.x, g0.y, g0.z, g0.w, g1.x, g1.y, g1.z, g1.w};
    float bbv[8] = {b0.x, b0.y, b0.z, b0.w, b1.x, b1.y, b1.z, b1.w};
    float o[8];
#pragma unroll
    for (int j = 0; j < 8; j++) o[j] = (v[j] - mu) * rs * gg[j] + bbv[j];
    float* op = out + (size_t)row * D_ + c0;
    *(float4*)op       = make_float4(o[0], o[1], o[2], o[3]);
    *(float4*)(op + 4) = make_float4(o[4], o[5], o[6], o[7]);
}

__global__ __launch_bounds__(256) void ln_kernel(
    const float* __restrict__ in,
    __nv_bfloat16* __restrict__ oh, __nv_bfloat16* __restrict__ ol,
    const float* __restrict__ g, const float* __restrict__ bb) {
    int warp = threadIdx.x >> 5, lane = threadIdx.x & 31;
    int row = blockIdx.x * 8 + warp;
    int c0 = lane * 8;
    const float* rp = in + (size_t)row * D_ + c0;
    float4 a0 = *(const float4*)rp, a1 = *(const float4*)(rp + 4);
    float v[8] = {a0.x, a0.y, a0.z, a0.w, a1.x, a1.y, a1.z, a1.w};
    float s = 0.f;
#pragma unroll
    for (int j = 0; j < 8; j++) s += v[j];
    float mu = warpsum(s) * (1.0f / D_);
    float s2 = 0.f;
#pragma unroll
    for (int j = 0; j < 8; j++) { float d = v[j] - mu; s2 = fmaf(d, d, s2); }
    float rs = rsqrtf(warpsum(s2) * (1.0f / D_) + LNEPS_);
    float4 g0 = *(const float4*)(g + c0), g1 = *(const float4*)(g + c0 + 4);
    float4 b0 = *(const float4*)(bb + c0), b1 = *(const float4*)(bb + c0 + 4);
    float gg[8] = {g0.x, g0.y, g0.z, g0.w, g1.x, g1.y, g1.z, g1.w};
    float bbv[8] = {b0.x, b0.y, b0.z, b0.w, b1.x, b1.y, b1.z, b1.w};
    size_t base = (size_t)row * D_ + c0;
#pragma unroll
    for (int j2 = 0; j2 < 4; j2++) {
        float x0 = (v[2 * j2] - mu) * rs * gg[2 * j2] + bbv[2 * j2];
        float x1 = (v[2 * j2 + 1] - mu) * rs * gg[2 * j2 + 1] + bbv[2 * j2 + 1];
        __nv_bfloat16 h0, l0, h1, l1;
        bf16_split(x0, h0, l0);
        bf16_split(x1, h1, l1);
        *(__nv_bfloat162*)(oh + base + 2 * j2) = __nv_bfloat162(h0, h1);
        *(__nv_bfloat162*)(ol + base + 2 * j2) = __nv_bfloat162(l0, l1);
    }
}

// ---------------------------------------------------------------------------
// mma.sync bf16 GEMM (dense): C = A @ Bt^T (+bias +epilogue)
// ALO: A has a lo array (3-term split); else single-bf16 A (2-term).
// MODE: 0 = QKV (q->Oh/Ol, k->Oh2/Ol2, v->Oh3/Ol3);
//       1 = GELU->Oh (single); 2 = residual accumulate into O0 (+Oh/Ol if EMIT);
//       3 = tanh->O0
// ---------------------------------------------------------------------------
constexpr int ROWB    = 80;
constexpr int ARR_B   = 128 * ROWB;
constexpr int STAGE_B = 4 * ARR_B;
constexpr int MM_SMEM = 2 * STAGE_B;     // 81920

template <bool ALO>
__device__ __forceinline__ void stage_cp(uint32_t sbase,
    const __nv_bfloat16* __restrict__ Ah, const __nv_bfloat16* __restrict__ Al,
    const __nv_bfloat16* __restrict__ Bh, const __nv_bfloat16* __restrict__ Bl,
    int row0, int col0, int K, int k0, int tid) {
#pragma unroll
    for (int i = 0; i < 8; i++) {
        const int arr = i >> 1;
        if (!ALO && arr == 1) continue;
        int cc = tid + (i & 1) * 256;
        int row = cc >> 2, kc = cc & 3;
        const __nv_bfloat16* src;
        int gr;
        if (arr == 0)      { src = Ah; gr = row0 + row; }
        else if (arr == 1) { src = Al; gr = row0 + row; }
        else if (arr == 2) { src = Bh; gr = col0 + row; }
        else               { src = Bl; gr = col0 + row; }
        uint32_t dst = sbase + arr * ARR_B + row * ROWB + kc * 16;
        CP_ASYNC16(dst, src + (size_t)gr * K + k0 + kc * 8);
    }
}

template <int MODE, bool EMIT, bool ALO>
__global__ __launch_bounds__(256) void mm_gemm(
    const __nv_bfloat16* __restrict__ Ah, const __nv_bfloat16* __restrict__ Al,
    const __nv_bfloat16* __restrict__ Bth, const __nv_bfloat16* __restrict__ Btl,
    const float* __restrict__ bias,
    float* __restrict__ O0,
    __nv_bfloat16* __restrict__ Oh, __nv_bfloat16* __restrict__ Ol,
    __nv_bfloat16* __restrict__ Oh2, __nv_bfloat16* __restrict__ Ol2,
    __nv_bfloat16* __restrict__ Oh3, __nv_bfloat16* __restrict__ Ol3,
    int K, int N) {
    extern __shared__ char smem[];
    uint32_t sb = smem_u32(smem);
    int tid = threadIdx.x, lane = tid & 31, warp = tid >> 5;
    int row0 = blockIdx.y * 128, col0 = blockIdx.x * 128;
    int wm = (warp >> 1) * 32, wn = (warp & 1) * 64;

    float acc[2][8][4] = {};

    int NT = K >> 5;
    stage_cp<ALO>(sb, Ah, Al, Bth, Btl, row0, col0, K, 0, tid);
    CP_COMMIT();
    if (NT > 1) {
        stage_cp<ALO>(sb + STAGE_B, Ah, Al, Bth, Btl, row0, col0, K, 32, tid);
        CP_COMMIT();
    }

    uint32_t aoff = (uint32_t)((wm + (lane & 15)) * ROWB + (lane >> 4) * 16);
    uint32_t boff = (uint32_t)((wn + ((lane >> 4) << 3) + (lane & 7)) * ROWB +
                               ((lane >> 3) & 1) * 16);

    for (int t = 0; t < NT; t++) {
        if (t + 1 < NT) CP_WAIT(1); else CP_WAIT(0);
        __syncthreads();
        uint32_t bs = sb + (t & 1) * STAGE_B;
#pragma unroll
        for (int kt = 0; kt < 2; kt++) {
            unsigned ah[2][4], al[2][4], bh[8][2], bl[8][2];
#pragma unroll
            for (int mt = 0; mt < 2; mt++) {
                uint32_t a = bs + aoff + mt * (16 * ROWB) + kt * 32;
                ldsm4(ah[mt][0], ah[mt][1], ah[mt][2], ah[mt][3], a);
                if (ALO) ldsm4(al[mt][0], al[mt][1], al[mt][2], al[mt][3], a + ARR_B);
            }
#pragma unroll
            for (int n2 = 0; n2 < 4; n2++) {
                uint32_t a = bs + 2 * ARR_B + boff + n2 * (16 * ROWB) + kt * 32;
                ldsm4(bh[2 * n2][0], bh[2 * n2][1], bh[2 * n2 + 1][0], bh[2 * n2 + 1][1], a);
                ldsm4(bl[2 * n2][0], bl[2 * n2][1], bl[2 * n2 + 1][0], bl[2 * n2 + 1][1],
                      a + ARR_B);
            }
#pragma unroll
            for (int mt = 0; mt < 2; mt++)
#pragma unroll
                for (int nt = 0; nt < 8; nt++) {
                    mma_bf16(acc[mt][nt], ah[mt], bh[nt]);
                    mma_bf16(acc[mt][nt], ah[mt], bl[nt]);
                    if (ALO) mma_bf16(acc[mt][nt], al[mt], bh[nt]);
                }
        }
        __syncthreads();
        if (t + 2 < NT) {
            stage_cp<ALO>(sb + (t & 1) * STAGE_B, Ah, Al, Bth, Btl, row0, col0, K,
                          (t + 2) * 32, tid);
            CP_COMMIT();
        }
    }

#pragma unroll
    for (int mt = 0; mt < 2; mt++)
#pragma unroll
        for (int nt = 0; nt < 8; nt++) {
            int rbase = row0 + wm + mt * 16 + (lane >> 2);
            int cg = col0 + wn + nt * 8 + (lane & 3) * 2;
            float b0 = __ldg(&bias[cg]), b1 = __ldg(&bias[cg + 1]);
#pragma unroll
            for (int half = 0; half < 2; half++) {
                int row = rbase + half * 8;
                float v0 = acc[mt][nt][half * 2]     + b0;
                float v1 = acc[mt][nt][half * 2 + 1] + b1;
                if (MODE == 0) {
                    int which = cg >> 8, cl = cg & 255;
                    size_t idx = (size_t)row * 256 + cl;
                    __nv_bfloat16* H = (which == 0) ? Oh : (which == 1) ? Oh2 : Oh3;
                    __nv_bfloat16* L = (which == 0) ? Ol : (which == 1) ? Ol2 : Ol3;
                    __nv_bfloat16 hi, lo;
                    bf16_split(v0, hi, lo); H[idx] = hi;     L[idx] = lo;
                    bf16_split(v1, hi, lo); H[idx + 1] = hi; L[idx + 1] = lo;
                } else if (MODE == 1) {
                    float u0 = 0.7978845608028654f * (v0 + 0.044715f * v0 * v0 * v0);
                    float u1 = 0.7978845608028654f * (v1 + 0.044715f * v1 * v1 * v1);
                    float g0 = 0.5f * v0 * (1.f + tanh_ap(u0));
                    float g1 = 0.5f * v1 * (1.f + tanh_ap(u1));
                    size_t idx = (size_t)row * N + cg;
                    *(__nv_bfloat162*)(Oh + idx) =
                        __nv_bfloat162(__float2bfloat16(g0), __float2bfloat16(g1));
                } else if (MODE == 2) {
                    size_t idx = (size_t)row * N + cg;
                    float n0 = O0[idx] + v0, n1 = O0[idx + 1] + v1;
                    O0[idx] = n0; O0[idx + 1] = n1;
                    if (EMIT) {
                        __nv_bfloat16 hi, lo;
                        bf16_split(n0, hi, lo); Oh[idx] = hi;     Ol[idx] = lo;
                        bf16_split(n1, hi, lo); Oh[idx + 1] = hi; Ol[idx + 1] = lo;
                    }
                } else {
                    size_t idx = (size_t)row * N + cg;
                    O0[idx]     = tanh_ap(v0);
                    O0[idx + 1] = tanh_ap(v1);
                }
            }
        }
}

// ---------------------------------------------------------------------------
// dash via mma -> single bf16 output [bh][s][288]
// QPHI=true : qp = ratio*(exp(dash - diag - rowmax) + eps)
// QPHI=false: E  = exp(dash - diag); block max of raw dash -> gmax
// ---------------------------------------------------------------------------
constexpr int DRB = 144;
constexpr int DA_H = 0;
constexpr int DA_L = 128 * DRB;
constexpr int DB_H = 2 * 128 * DRB;
constexpr int DB_L = DB_H + PMP_ * DRB;
constexpr int D_SDIAG = DB_L + PMP_ * DRB;
constexpr int D_SRMAX = D_SDIAG + 512;
constexpr int DASH_SMEM = D_SRMAX + 512;

template <bool QPHI>
__global__ __launch_bounds__(256, 1) void dash_mma(
    const __nv_bfloat16* __restrict__ Xh, const __nv_bfloat16* __restrict__ Xl,
    const __nv_bfloat16* __restrict__ Ph, const __nv_bfloat16* __restrict__ Pl,
    __nv_bfloat16* __restrict__ outh,
    unsigned* __restrict__ gmax) {
    extern __shared__ char smem[];
    uint32_t sb = smem_u32(smem);
    float* sdiag = (float*)(smem + D_SDIAG);
    unsigned* srmax = (unsigned*)(smem + D_SRMAX);
    int tid = threadIdx.x, lane = tid & 31, warp = tid >> 5;
    int bh = blockIdx.y, b = bh >> 2, h = bh & 3;
    int s0 = blockIdx.x * 128;

    for (int i = tid; i < 1024; i += 256) {
        int r = i >> 3, c = i & 7;
        const __nv_bfloat16* s1 = Xh + ((size_t)(b * S_ + s0 + r)) * D_ + h * DH_ + c * 8;
        const __nv_bfloat16* s2 = Xl + ((size_t)(b * S_ + s0 + r)) * D_ + h * DH_ + c * 8;
        CP_ASYNC16(sb + DA_H + r * DRB + c * 16, s1);
        CP_ASYNC16(sb + DA_L + r * DRB + c * 16, s2);
    }
    for (int i = tid; i < PMP_ * 8; i += 256) {
        int r = i >> 3, c = i & 7;
        CP_ASYNC16(sb + DB_H + r * DRB + c * 16, Ph + (size_t)r * DH_ + c * 8);
        CP_ASYNC16(sb + DB_L + r * DRB + c * 16, Pl + (size_t)r * DH_ + c * 8);
    }
    CP_COMMIT(); CP_WAIT(0);
    __syncthreads();

    if (tid < 128) {
        const __nv_bfloat16* ah = (const __nv_bfloat16*)(smem + DA_H + tid * DRB);
        const __nv_bfloat16* al = (const __nv_bfloat16*)(smem + DA_L + tid * DRB);
        float s = 0.f;
#pragma unroll
        for (int c = 0; c < DH_; c++) {
            float v = __bfloat162float(ah[c]) + __bfloat162float(al[c]);
            s = fmaf(v, v, s);
        }
        sdiag[tid] = HDN2_ * s;
        srmax[tid] = 0u;
    }
    __syncthreads();

    int wm = (warp >> 1) * 32, wn = (warp & 1) * 144;
    float acc[2][18][4] = {};
    uint32_t aoff = (uint32_t)((wm + (lane & 15)) * DRB + (lane >> 4) * 16);
    uint32_t boff = (uint32_t)((wn + ((lane >> 4) << 3) + (lane & 7)) * DRB +
                               ((lane >> 3) & 1) * 16);

#pragma unroll
    for (int kt = 0; kt < 4; kt++) {
        unsigned ah[2][4], al[2][4];
#pragma unroll
        for (int mt = 0; mt < 2; mt++) {
            uint32_t a = sb + DA_H + aoff + mt * (16 * DRB) + kt * 32;
            ldsm4(ah[mt][0], ah[mt][1], ah[mt][2], ah[mt][3], a);
            ldsm4(al[mt][0], al[mt][1], al[mt][2], al[mt][3], a + (DA_L - DA_H));
        }
#pragma unroll
        for (int n2 = 0; n2 < 9; n2++) {
            unsigned bhf[2][2], blf[2][2];
            uint32_t a = sb + DB_H + boff + n2 * (16 * DRB) + kt * 32;
            ldsm4(bhf[0][0], bhf[0][1], bhf[1][0], bhf[1][1], a);
            ldsm4(blf[0][0], blf[0][1], blf[1][0], blf[1][1], a + (DB_L - DB_H));
#pragma unroll
            for (int mt = 0; mt < 2; mt++)
#pragma unroll
                for (int j = 0; j < 2; j++) {
                    int nt = n2 * 2 + j;
                    mma_bf16(acc[mt][nt], ah[mt], bhf[j]);
                    mma_bf16(acc[mt][nt], ah[mt], blf[j]);
                    mma_bf16(acc[mt][nt], al[mt], bhf[j]);
                }
        }
    }

    // per-row max of raw dash (valid cols only)
#pragma unroll
    for (int mt = 0; mt < 2; mt++)
#pragma unroll
        for (int half = 0; half < 2; half++) {
            float p = -3.4e38f;
#pragma unroll
            for (int nt = 0; nt < 18; nt++)
#pragma unroll
                for (int e = 0; e < 2; e++) {
                    int col = wn + nt * 8 + (lane & 3) * 2 + e;
                    if (col < PM_) p = fmaxf(p, DN_ * acc[mt][nt][half * 2 + e]);
                }
            p = fmaxf(p, __shfl_xor_sync(0xffffffffu, p, 1));
            p = fmaxf(p, __shfl_xor_sync(0xffffffffu, p, 2));
            if ((lane & 3) == 0)
                atomicMax(&srmax[wm + mt * 16 + (lane >> 2) + half * 8], fmap(p));
        }
    __syncthreads();

    if (!QPHI && tid == 0) {
        unsigned m = 0u;
#pragma unroll 4
        for (int i = 0; i < 128; i++) m = max(m, srmax[i]);
        atomicMax(gmax, m);
    }

#pragma unroll
    for (int mt = 0; mt < 2; mt++)
#pragma unroll
        for (int half = 0; half < 2; half++) {
            int r = wm + mt * 16 + (lane >> 2) + half * 8;
            size_t rowbase = ((size_t)bh * S_ + s0 + r) * PMP_;
            float sub = QPHI ? (sdiag[r] + funmap(srmax[r])) : sdiag[r];
#pragma unroll
            for (int nt = 0; nt < 18; nt++) {
                int colb = wn + nt * 8 + (lane & 3) * 2;
                float o[2];
#pragma unroll
                for (int e = 0; e < 2; e++) {
                    int col = colb + e;
                    float val = 0.f;
                    if (col < PM_) {
                        float dv = DN_ * acc[mt][nt][half * 2 + e];
                        val = QPHI ? RATIO_ * (__expf(dv - sub) + KEPS_)
                                   : __expf(dv - sub);
                    }
                    o[e] = val;
                }
                *(__nv_bfloat162*)(outh + rowbase + colb) =
                    __nv_bfloat162(__float2bfloat16(o[0]), __float2bfloat16(o[1]));
            }
        }
}

// ---------------------------------------------------------------------------
// ctx via mma: ctxE[bh][m][e] = sum_s E[s][m] * Vx[s][e], Vx col 64 = 1 (ksum)
// E single bf16 (2-term with V hi/lo)
// ---------------------------------------------------------------------------
constexpr int CE_ST = 592;
constexpr int CV_ST = 160;
constexpr int C_EH = 0;
constexpr int C_VH = 32 * CE_ST;
constexpr int C_VL = C_VH + 32 * CV_ST;
constexpr int CSTAGE = C_VL + 32 * CV_ST;     // 29184
constexpr int CTX_SMEM = 2 * CSTAGE;          // 58368

__global__ __launch_bounds__(256) void ctx_mma(
    const __nv_bfloat16* __restrict__ Eh,
    const __nv_bfloat16* __restrict__ Vh, const __nv_bfloat16* __restrict__ Vl,
    float* __restrict__ ctxE) {
    extern __shared__ char smem[];
    uint32_t sb = smem_u32(smem);
    int tid = threadIdx.x, lane = tid & 31, warp = tid >> 5;
    int bh = blockIdx.x, b = bh >> 2, h = bh & 3;
    int sbase = blockIdx.y * 512;

    auto stage = [&](int buf, int chunk) {
        uint32_t base = sb + buf * CSTAGE;
        int s0 = sbase + chunk * 32;
        for (int i = tid; i < 1152; i += 256) {
            int r = i / 36, c = i - r * 36;
            size_t g = ((size_t)bh * S_ + s0 + r) * PMP_ + c * 8;
            CP_ASYNC16(base + C_EH + r * CE_ST + c * 16, Eh + g);
        }
        {
            int i = tid;
            if (i < 256) {
                int r = i >> 3, c = i & 7;
                size_t g = ((size_t)(b * S_ + s0 + r)) * D_ + h * DH_ + c * 8;
                CP_ASYNC16(base + C_VH + r * CV_ST + c * 16, Vh + g);
                CP_ASYNC16(base + C_VL + r * CV_ST + c * 16, Vl + g);
            }
        }
        if (tid < 64) {
            int r = tid >> 1, half2 = tid & 1;
            uint4 z = make_uint4(0, 0, 0, 0);
            uint4 one = make_uint4(0x00003F80u, 0, 0, 0);
            uint32_t off = (uint32_t)(r * CV_ST + 128 + half2 * 16);
            *(uint4*)(smem + buf * CSTAGE + C_VH + off) = (half2 == 0) ? one : z;
            *(uint4*)(smem + buf * CSTAGE + C_VL + off) = z;
        }
    };

    stage(0, 0); CP_COMMIT();
    stage(1, 1); CP_COMMIT();

    int mts[3];
    mts[0] = warp * 2; mts[1] = warp * 2 + 1; mts[2] = (warp < 2) ? 16 + warp : -1;
    float acc[3][9][4] = {};

    for (int t = 0; t < 16; t++) {
        if (t + 1 < 16) CP_WAIT(1); else CP_WAIT(0);
        __syncthreads();
        uint32_t bs = sb + (t & 1) * CSTAGE;
#pragma unroll
        for (int kt = 0; kt < 2; kt++) {
            int krA = (lane & 7) + ((lane >> 4) & 1) * 8 + kt * 16;
            int mcolbit = ((lane >> 3) & 1) * 8;
            unsigned ah[3][4];
#pragma unroll
            for (int mt = 0; mt < 3; mt++) {
                if (mts[mt] < 0) break;
                uint32_t a = bs + C_EH + krA * CE_ST + (mts[mt] * 16 + mcolbit) * 2;
                ldsm4t(ah[mt][0], ah[mt][1], ah[mt][2], ah[mt][3], a);
            }
            int krB = (lane & 7) + ((lane >> 3) & 1) * 8 + kt * 16;
            int ncolbit = (lane >> 4) * 8;
#pragma unroll
            for (int p = 0; p < 5; p++) {
                unsigned bhf[4], blf[4];
                uint32_t a = bs + C_VH + krB * CV_ST + (p * 16 + ncolbit) * 2;
                ldsm4t(bhf[0], bhf[1], bhf[2], bhf[3], a);
                ldsm4t(blf[0], blf[1], blf[2], blf[3], a + (C_VL - C_VH));
#pragma unroll
                for (int j = 0; j < 2; j++) {
                    int nt = p * 2 + j;
                    if (nt > 8) break;
#pragma unroll
                    for (int mt = 0; mt < 3; mt++) {
                        if (mts[mt] < 0) break;
                        mma_bf16(acc[mt][nt], ah[mt], bhf + j * 2);
                        mma_bf16(acc[mt][nt], ah[mt], blf + j * 2);
                    }
                }
            }
        }
        __syncthreads();
        if (t + 2 < 16) { stage(t & 1, t + 2); CP_COMMIT(); }
    }

#pragma unroll
    for (int mt = 0; mt < 3; mt++) {
        if (mts[mt] < 0) break;
#pragma unroll
        for (int nt = 0; nt < 9; nt++)
#pragma unroll
            for (int half = 0; half < 2; half++) {
                int m = mts[mt] * 16 + (lane >> 2) + half * 8;
                int e = nt * 8 + (lane & 3) * 2;
                float* dst = ctxE + ((size_t)bh * PMP_ + m) * 72 + e;
                atomicAdd(dst,     acc[mt][nt][half * 2]);
                atomicAdd(dst + 1, acc[mt][nt][half * 2 + 1]);
            }
    }
}

// vsum[bh][e] = sum_s v[b][s][h*64+e]
__global__ void vsum_kernel(const __nv_bfloat16* __restrict__ vh,
                            const __nv_bfloat16* __restrict__ vl,
                            float* __restrict__ vsum) {
    int bh = blockIdx.x, b = bh >> 2, h = bh & 3;
    int e = threadIdx.x;
    int s0 = blockIdx.y * 512;
    float s = 0.f;
    for (int i = 0; i < 512; i++) {
        size_t idx = ((size_t)(b * S_ + s0 + i)) * D_ + h * DH_ + e;
        s += __bfloat162float(vh[idx]) + __bfloat162float(vl[idx]);
    }
    atomicAdd(&vsum[bh * 64 + e], s);
}

// ctx_b = a*ctxE + correction; bf16 hi/lo [bh][288][80]
__global__ void ctxcorr_kernel(const float* __restrict__ ctxE, const float* __restrict__ vsum,
                               const unsigned* __restrict__ gmax,
                               __nv_bfloat16* __restrict__ cbh, __nv_bfloat16* __restrict__ cbl) {
    int idx = blockIdx.x * 256 + threadIdx.x;
    if (idx >= BH_ * PMP_ * 80) return;
    int bh = idx / (PMP_ * 80);
    int rem = idx - bh * (PMP_ * 80);
    int m = rem / 80, e = rem - m * 80;
    float a = RATIO_ * __expf(-funmap(*gmax));
    float c = RATIO_ * KEPS_;
    float val = 0.f;
    if (m < PM_ && e < 72) {
        float base = ctxE[((size_t)bh * PMP_ + m) * 72 + e];
        float corr = (e < 64) ? c * vsum[bh * 64 + e] : ((e == 64) ? c * (float)S_ : 0.f);
        val = a * base + corr;
    }
    __nv_bfloat16 hi, lo;
    bf16_split(val, hi, lo);
    cbh[idx] = hi; cbl[idx] = lo;
}

// ---------------------------------------------------------------------------
// attnout via mma: O[s][e] = (qp[s]·ctx_b[:,e]) / (qp[s]·ksum)  -> oh (single)
// Q single bf16 (2-term with Cb hi/lo)
// ---------------------------------------------------------------------------
constexpr int AQ_ST = 80;
constexpr int AB_ST = 160;
constexpr int A_QH = 0;
constexpr int A_BH2 = 128 * AQ_ST;            // 10240
constexpr int A_BL2 = A_BH2 + 32 * AB_ST;     // 15360
constexpr int ASTAGE = A_BL2 + 32 * AB_ST;    // 20480
constexpr int A_SDEN = 2 * ASTAGE;            // 40960
constexpr int ATT_SMEM = A_SDEN + 512;        // 41472

__global__ __launch_bounds__(256) void attnout_mma(
    const __nv_bfloat16* __restrict__ Qh,
    const __nv_bfloat16* __restrict__ Cbh, const __nv_bfloat16* __restrict__ Cbl,
    __nv_bfloat16* __restrict__ oh) {
    extern __shared__ char smem[];
    uint32_t sb = smem_u32(smem);
    float* sden = (float*)(smem + A_SDEN);
    int tid = threadIdx.x, lane = tid & 31, warp = tid >> 5;
    int bh = blockIdx.y, b = bh >> 2, h = bh & 3;
    int s0 = blockIdx.x * 128;

    auto stage = [&](int buf, int chunk) {
        uint32_t base = sb + buf * ASTAGE;
        int k0 = chunk * 32;
        for (int i = tid; i < 512; i += 256) {
            int r = i >> 2, c = i & 3;
            size_t g = ((size_t)bh * S_ + s0 + r) * PMP_ + k0 + c * 8;
            CP_ASYNC16(base + A_QH + r * AQ_ST + c * 16, Qh + g);
        }
        for (int i = tid; i < 320; i += 256) {
            int r = i / 10, c = i - r * 10;
            size_t g = ((size_t)bh * PMP_ + k0 + r) * 80 + c * 8;
            CP_ASYNC16(base + A_BH2 + r * AB_ST + c * 16, Cbh + g);
            CP_ASYNC16(base + A_BL2 + r * AB_ST + c * 16, Cbl + g);
        }
    };

    stage(0, 0); CP_COMMIT();
    stage(1, 1); CP_COMMIT();

    int wm = (warp >> 1) * 32, ng = warp & 1;
    float acc[2][5][4] = {};
    uint32_t aoff = (uint32_t)((wm + (lane & 15)) * AQ_ST + (lane >> 4) * 16);

    for (int t = 0; t < 9; t++) {
        if (t + 1 < 9) CP_WAIT(1); else CP_WAIT(0);
        __syncthreads();
        uint32_t bs = sb + (t & 1) * ASTAGE;
#pragma unroll
        for (int kt = 0; kt < 2; kt++) {
            unsigned ah[2][4];
#pragma unroll
            for (int mt = 0; mt < 2; mt++) {
                uint32_t a = bs + A_QH + aoff + mt * (16 * AQ_ST) + kt * 32;
                ldsm4(ah[mt][0], ah[mt][1], ah[mt][2], ah[mt][3], a);
            }
            int krB = (lane & 7) + ((lane >> 3) & 1) * 8 + kt * 16;
            int ncolbit = (lane >> 4) * 8;
#pragma unroll
            for (int pi = 0; pi < 3; pi++) {
                if (!ng && pi == 2) break;
                int p = ng ? (2 + pi) : pi;
                unsigned bhf[4], blf[4];
                uint32_t a = bs + A_BH2 + krB * AB_ST + (p * 16 + ncolbit) * 2;
                ldsm4t(bhf[0], bhf[1], bhf[2], bhf[3], a);
                ldsm4t(blf[0], blf[1], blf[2], blf[3], a + (A_BL2 - A_BH2));
#pragma unroll
                for (int j = 0; j < 2; j++) {
                    int ntg = p * 2 + j;
                    if (ntg > 8) break;
                    int ntl = ntg - ng * 4;
#pragma unroll
                    for (int mt = 0; mt < 2; mt++) {
                        mma_bf16(acc[mt][ntl], ah[mt], bhf + j * 2);
                        mma_bf16(acc[mt][ntl], ah[mt], blf + j * 2);
                    }
                }
            }
        }
        __syncthreads();
        if (t + 2 < 9) { stage(t & 1, t + 2); CP_COMMIT(); }
    }

    if (ng == 1 && (lane & 3) == 0) {
#pragma unroll
        for (int mt = 0; mt < 2; mt++)
#pragma unroll
            for (int half = 0; half < 2; half++) {
                int r = wm + mt * 16 + (lane >> 2) + half * 8;
                sden[r] = acc[mt][4][half * 2];
            }
    }
    __syncthreads();

#pragma unroll
    for (int mt = 0; mt < 2; mt++)
#pragma unroll
        for (int half = 0; half < 2; half++) {
            int r = wm + mt * 16 + (lane >> 2) + half * 8;
            float rinv = 1.f / sden[r];
            size_t obase = ((size_t)(b * S_ + s0 + r)) * D_ + h * DH_;
#pragma unroll
            for (int ntl = 0; ntl < 4; ntl++) {
                int e = (ng * 4 + ntl) * 8 + (lane & 3) * 2;
                float v0 = acc[mt][ntl][half * 2]     * rinv;
                float v1 = acc[mt][ntl][half * 2 + 1] * rinv;
                *(__nv_bfloat162*)(oh + obase + e) =
                    __nv_bfloat162(__float2bfloat16(v0), __float2bfloat16(v1));
            }
        }
}

// ---------------------------------------------------------------------------
// Per-layer init
// ---------------------------------------------------------------------------
__global__ void layer_init_kernel(float* __restrict__ ctxE, float* __restrict__ vsum,
                                  unsigned* __restrict__ km) {
    int i = blockIdx.x * 256 + threadIdx.x;
    if (i < BH_ * PMP_ * 72) ctxE[i] = 0.f;
    if (i < BH_ * 64) vsum[i] = 0.f;
    if (i == 0) *km = 0u;
}

// ---------------------------------------------------------------------------
// Pooling (score: warp-per-row)
// ---------------------------------------------------------------------------
__global__ __launch_bounds__(256) void score_kernel(
    const float* __restrict__ h, const float* __restrict__ p2w,
    const float* __restrict__ p2b, const float* __restrict__ mask,
    float* __restrict__ score) {
    int warp = threadIdx.x >> 5, lane = threadIdx.x & 31;
    int row = blockIdx.x * 8 + warp;
    int c0 = lane * 8;
    const float* rp = h + (size_t)row * D_ + c0;
    float4 a0 = *(const float4*)rp, a1 = *(const float4*)(rp + 4);
    float4 w0 = *(const float4*)(p2w + c0), w1 = *(const float4*)(p2w + c0 + 4);
    float s = a0.x * w0.x + a0.y * w0.y + a0.z * w0.z + a0.w * w0.w +
              a1.x * w1.x + a1.y * w1.y + a1.z * w1.z + a1.w * w1.w;
    s = warpsum(s);
    if (lane == 0) score[row] = expf(s + p2b[0]) * mask[row];
}

__global__ void ssum_kernel(const float* __restrict__ score, float* __restrict__ ssum) {
    __shared__ float sh[8];
    int b = blockIdx.x;
    float s = 0.f;
    for (int i = threadIdx.x; i < S_; i += 256) s += score[b * S_ + i];
    s = block_sum(s, sh);
    if (threadIdx.x == 0) ssum[b] = s;
}

__global__ void outzero_kernel(float* __restrict__ out) {
    int i = blockIdx.x * blockDim.x + threadIdx.x;
    if (i < B_ * D_) out[i] = 0.f;
}

__global__ void pool_kernel(const float* __restrict__ x, const float* __restrict__ score,
                            const float* __restrict__ ssum, float* __restrict__ out) {
    int b = blockIdx.x, chunk = blockIdx.y, d = threadIdx.x;
    float inv = 1.f / (ssum[b] + 1e-8f);
    float acc = 0.f;
    int s0 = chunk * (S_ / 64);
    for (int s = s0; s < s0 + S_ / 64; s++)
        acc = fmaf(x[((size_t)(b * S_ + s)) * D_ + d], score[b * S_ + s], acc);
    atomicAdd(&out[b * D_ + d], acc * inv);
}

// ---------------------------------------------------------------------------
// Host launcher
// ---------------------------------------------------------------------------
extern "C" void kernel_launch(void* const* d_in, const int* in_sizes, int n_in,
                              void* d_out, int out_size) {
    const float* emb  = (const float*)d_in[0];
    const float* mask = (const float*)d_in[1];
    const float* pos  = (const float*)d_in[2];
    const float* ln_g = (const float*)d_in[3];
    const float* ln_b = (const float*)d_in[4];
    const float* proj = (const float*)d_in[5];
    const float* Wq = (const float*)d_in[6];   const float* bq = (const float*)d_in[7];
    const float* Wk = (const float*)d_in[8];   const float* bk = (const float*)d_in[9];
    const float* Wv = (const float*)d_in[10];  const float* bv = (const float*)d_in[11];
    const float* Wo = (const float*)d_in[12];  const float* bo = (const float*)d_in[13];
    const float* ln1g = (const float*)d_in[14]; const float* ln1b = (const float*)d_in[15];
    const float* W1 = (const float*)d_in[16];  const float* b1 = (const float*)d_in[17];
    const float* W2 = (const float*)d_in[18];  const float* b2 = (const float*)d_in[19];
    const float* ln2g = (const float*)d_in[20]; const float* ln2b = (const float*)d_in[21];
    const float* p1w = (const float*)d_in[22]; const float* p1b = (const float*)d_in[23];
    const float* p2w = (const float*)d_in[24]; const float* p2b = (const float*)d_in[25];
    float* out = (float*)d_out;

    void* tp;
    float *x, *h, *sc, *ss, *bqkv, *ctxE, *vsum;
    unsigned* km;
    __nv_bfloat16 *wth, *wtl, *hh, *hl, *oh, *fh, *xh, *xl;
    __nv_bfloat16 *qh, *ql, *kh, *kl, *vh, *vl, *pjh, *pjl;
    __nv_bfloat16 *qph, *eh, *cbh, *cbl;
    cudaGetSymbolAddress(&tp, g_x);     x  = (float*)tp;
    cudaGetSymbolAddress(&tp, g_h);     h  = (float*)tp;
    cudaGetSymbolAddress(&tp, g_score); sc = (float*)tp;
    cudaGetSymbolAddress(&tp, g_ssum);  ss = (float*)tp;
    cudaGetSymbolAddress(&tp, g_kmaxu); km = (unsigned*)tp;
    cudaGetSymbolAddress(&tp, g_bqkv);  bqkv = (float*)tp;
    cudaGetSymbolAddress(&tp, g_ctxE);  ctxE = (float*)tp;
    cudaGetSymbolAddress(&tp, g_vsum);  vsum = (float*)tp;
    cudaGetSymbolAddress(&tp, g_wth);   wth = (__nv_bfloat16*)tp;
    cudaGetSymbolAddress(&tp, g_wtl);   wtl = (__nv_bfloat16*)tp;
    cudaGetSymbolAddress(&tp, g_hh);    hh = (__nv_bfloat16*)tp;
    cudaGetSymbolAddress(&tp, g_hl);    hl = (__nv_bfloat16*)tp;
    cudaGetSymbolAddress(&tp, g_oh);    oh = (__nv_bfloat16*)tp;
    cudaGetSymbolAddress(&tp, g_fh);    fh = (__nv_bfloat16*)tp;
    cudaGetSymbolAddress(&tp, g_xh);    xh = (__nv_bfloat16*)tp;
    cudaGetSymbolAddress(&tp, g_xl);    xl = (__nv_bfloat16*)tp;
    cudaGetSymbolAddress(&tp, g_qh);    qh = (__nv_bfloat16*)tp;
    cudaGetSymbolAddress(&tp, g_ql);    ql = (__nv_bfloat16*)tp;
    cudaGetSymbolAddress(&tp, g_kh);    kh = (__nv_bfloat16*)tp;
    cudaGetSymbolAddress(&tp, g_kl);    kl = (__nv_bfloat16*)tp;
    cudaGetSymbolAddress(&tp, g_vh);    vh = (__nv_bfloat16*)tp;
    cudaGetSymbolAddress(&tp, g_vl);    vl = (__nv_bfloat16*)tp;
    cudaGetSymbolAddress(&tp, g_pjh);   pjh = (__nv_bfloat16*)tp;
    cudaGetSymbolAddress(&tp, g_pjl);   pjl = (__nv_bfloat16*)tp;
    cudaGetSymbolAddress(&tp, g_qph);   qph = (__nv_bfloat16*)tp;
    cudaGetSymbolAddress(&tp, g_eh);    eh = (__nv_bfloat16*)tp;
    cudaGetSymbolAddress(&tp, g_cbh);   cbh = (__nv_bfloat16*)tp;
    cudaGetSymbolAddress(&tp, g_cbl);   cbl = (__nv_bfloat16*)tp;

    static bool attr_done = false;
    if (!attr_done) {
        cudaFuncSetAttribute(mm_gemm<0, false, true>,  cudaFuncAttributeMaxDynamicSharedMemorySize, MM_SMEM);
        cudaFuncSetAttribute(mm_gemm<1, false, true>,  cudaFuncAttributeMaxDynamicSharedMemorySize, MM_SMEM);
        cudaFuncSetAttribute(mm_gemm<2, false, false>, cudaFuncAttributeMaxDynamicSharedMemorySize, MM_SMEM);
        cudaFuncSetAttribute(mm_gemm<2, true, false>,  cudaFuncAttributeMaxDynamicSharedMemorySize, MM_SMEM);
        cudaFuncSetAttribute(mm_gemm<3, false, true>,  cudaFuncAttributeMaxDynamicSharedMemorySize, MM_SMEM);
        cudaFuncSetAttribute(dash_mma<true>,  cudaFuncAttributeMaxDynamicSharedMemorySize, DASH_SMEM);
        cudaFuncSetAttribute(dash_mma<false>, cudaFuncAttributeMaxDynamicSharedMemorySize, DASH_SMEM);
        cudaFuncSetAttribute(ctx_mma,     cudaFuncAttributeMaxDynamicSharedMemorySize, CTX_SMEM);
        cudaFuncSetAttribute(attnout_mma, cudaFuncAttributeMaxDynamicSharedMemorySize, ATT_SMEM);
        attr_done = true;
    }

    // --- weight prep (batched over layers via gridDim.z) ---
    dim3 wb(32, 8);
    wsplit_kernel<<<dim3(8, 8, NL_), wb>>>(Wq, wth + OFF_QKV, wtl + OFF_QKV,
                                           256, 256, 0,   65536, (size_t)768 * 256);
    wsplit_kernel<<<dim3(8, 8, NL_), wb>>>(Wk, wth + OFF_QKV, wtl + OFF_QKV,
                                           256, 256, 256, 65536, (size_t)768 * 256);
    wsplit_kernel<<<dim3(8, 8, NL_), wb>>>(Wv, wth + OFF_QKV, wtl + OFF_QKV,
                                           256, 256, 512, 65536, (size_t)768 * 256);
    wsplit_kernel<<<dim3(8, 8, NL_), wb>>>(Wo, wth + OFF_WO, wtl + OFF_WO,
                                           256, 256, 0, 65536, 65536);
    wsplit_kernel<<<dim3(32, 8, NL_), wb>>>(W1, wth + OFF_W1, wtl + OFF_W1,
                                            256, 1024, 0, 262144, 262144);
    wsplit_kernel<<<dim3(8, 32, NL_), wb>>>(W2, wth + OFF_W2, wtl + OFF_W2,
                                            1024, 256, 0, 262144, 262144);
    wsplit_kernel<<<dim3(8, 8, 1), wb>>>(p1w, wth + OFF_P1, wtl + OFF_P1,
                                         256, 256, 0, 0, 0);
    bconcat_kernel<<<NL_, 256>>>(bq, bk, bv, bqkv);
    psplit_kernel<<<(NL_ * PMP_ * DH_) / 256, 256>>>(proj, pjh, pjl);

    embed_ln_kernel<<<BS_ / 8, 256>>>(emb, pos, ln_g, ln_b, x);

    for (int l = 0; l < NL_; l++) {
        // --- attention block ---
        ln_kernel<<<BS_ / 8, 256>>>(x, hh, hl, ln1g + l * D_, ln1b + l * D_);
        mm_gemm<0, false, true><<<dim3(6, 128), 256, MM_SMEM>>>(
            hh, hl, wth + OFF_QKV + (size_t)l * 768 * 256, wtl + OFF_QKV + (size_t)l * 768 * 256,
            bqkv + l * 768, nullptr, qh, ql, kh, kl, vh, vl, 256, 768);

        layer_init_kernel<<<(BH_ * PMP_ * 72 + 255) / 256, 256>>>(ctxE, vsum, km);

        dash_mma<true><<<dim3(S_ / 128, BH_), 256, DASH_SMEM>>>(
            qh, ql, pjh + (size_t)l * PMP_ * DH_, pjl + (size_t)l * PMP_ * DH_,
            qph, nullptr);
        dash_mma<false><<<dim3(S_ / 128, BH_), 256, DASH_SMEM>>>(
            kh, kl, pjh + (size_t)l * PMP_ * DH_, pjl + (size_t)l * PMP_ * DH_,
            eh, km);

        vsum_kernel<<<dim3(BH_, 8), 64>>>(vh, vl, vsum);
        ctx_mma<<<dim3(BH_, 8), 256, CTX_SMEM>>>(eh, vh, vl, ctxE);
        ctxcorr_kernel<<<(BH_ * PMP_ * 80 + 255) / 256, 256>>>(ctxE, vsum, km, cbh, cbl);
        attnout_mma<<<dim3(S_ / 128, BH_), 256, ATT_SMEM>>>(qph, cbh, cbl, oh);

        mm_gemm<2, false, false><<<dim3(2, 128), 256, MM_SMEM>>>(
            oh, nullptr, wth + OFF_WO + (size_t)l * 65536, wtl + OFF_WO + (size_t)l * 65536,
            bo + l * 256, x, nullptr, nullptr, nullptr, nullptr, nullptr, nullptr, 256, 256);

        // --- FFN block ---
        ln_kernel<<<BS_ / 8, 256>>>(x, hh, hl, ln2g + l * D_, ln2b + l * D_);
        mm_gemm<1, false, true><<<dim3(8, 128), 256, MM_SMEM>>>(
            hh, hl, wth + OFF_W1 + (size_t)l * 262144, wtl + OFF_W1 + (size_t)l * 262144,
            b1 + l * 1024, nullptr, fh, nullptr, nullptr, nullptr, nullptr, nullptr, 256, 1024);
        if (l == NL_ - 1) {
            mm_gemm<2, true, false><<<dim3(2, 128), 256, MM_SMEM>>>(
                fh, nullptr, wth + OFF_W2 + (size_t)l * 262144, wtl + OFF_W2 + (size_t)l * 262144,
                b2 + l * 256, x, xh, xl, nullptr, nullptr, nullptr, nullptr, 1024, 256);
        } else {
            mm_gemm<2, false, false><<<dim3(2, 128), 256, MM_SMEM>>>(
                fh, nullptr, wth + OFF_W2 + (size_t)l * 262144, wtl + OFF_W2 + (size_t)l * 262144,
                b2 + l * 256, x, nullptr, nullptr, nullptr, nullptr, nullptr, nullptr, 1024, 256);
        }
    }

    // --- attention pooling ---
    mm_gemm<3, false, true><<<dim3(2, 128), 256, MM_SMEM>>>(
        xh, xl, wth + OFF_P1, wtl + OFF_P1, p1b, h,
        nullptr, nullptr, nullptr, nullptr, nullptr, nullptr, 256, 256);
    score_kernel<<<BS_ / 8, 256>>>(h, p2w, p2b, mask, sc);
    ssum_kernel<<<B_, 256>>>(sc, ss);
    outzero_kernel<<<(B_ * D_ + 255) / 256, 256>>>(out);
    pool_kernel<<<dim3(B_, 64), 256>>>(x, sc, ss, out);
}

// round 13
// speedup vs baseline: 3.0845x; 1.1448x over previous
#include <cuda_runtime.h>
#include <cuda_bf16.h>
#include <cstdint>

// ---------------------------------------------------------------------------
// Problem constants
// ---------------------------------------------------------------------------
constexpr int B_  = 4;
constexpr int S_  = 4096;
constexpr int D_  = 256;
constexpr int DH_ = 64;
constexpr int NL_ = 4;
constexpr int PM_ = 266;          // nb_features
constexpr int PMP_ = 288;         // padded for mma
constexpr int FF_ = 1024;
constexpr int BS_ = B_ * S_;      // 16384 rows
constexpr int BH_ = B_ * 4;       // 16

constexpr float DN_    = 0.35355339059327373f;  // 64^-0.25
constexpr float HDN2_  = 0.0625f;               // 0.5 * dn^2
constexpr float RATIO_ = 0.06131392f;           // 266^-0.5
constexpr float KEPS_  = 1e-4f;
constexpr float LNEPS_ = 1e-12f;

// ---------------------------------------------------------------------------
// Scratch (static device globals)
// ---------------------------------------------------------------------------
__device__ float g_x  [BS_ * D_];
__device__ float g_h  [BS_ * D_];     // pooling tanh output (fp32)
__device__ float g_score[BS_];
__device__ float g_ssum [B_];
__device__ unsigned g_kmaxu;

// bf16 hi/lo operand buffers
constexpr size_t OFF_QKV = 0;
constexpr size_t OFF_WO  = OFF_QKV + (size_t)NL_ * 768 * 256;
constexpr size_t OFF_W1  = OFF_WO  + (size_t)NL_ * 256 * 256;
constexpr size_t OFF_W2  = OFF_W1  + (size_t)NL_ * 1024 * 256;
constexpr size_t OFF_P1  = OFF_W2  + (size_t)NL_ * 256 * 1024;
constexpr size_t WT_TOT  = OFF_P1 + 256 * 256;

__device__ __nv_bfloat16 g_wth[WT_TOT], g_wtl[WT_TOT];
__device__ float g_bqkv[NL_ * 768];
__device__ __nv_bfloat16 g_hh[BS_ * D_], g_hl[BS_ * D_];      // LN outputs
__device__ __nv_bfloat16 g_oh[BS_ * D_];                      // attnout (single bf16)
__device__ __nv_bfloat16 g_fh[(size_t)BS_ * FF_];             // gelu (single bf16)
__device__ __nv_bfloat16 g_xh[BS_ * D_], g_xl[BS_ * D_];      // residual (pooling)
__device__ __nv_bfloat16 g_qh[BS_ * D_], g_ql[BS_ * D_];      // q hi/lo
__device__ __nv_bfloat16 g_kh[BS_ * D_], g_kl[BS_ * D_];      // k hi/lo
__device__ __nv_bfloat16 g_vh[BS_ * D_];                      // v (single bf16)
__device__ __nv_bfloat16 g_pjh[NL_ * PMP_ * DH_], g_pjl[NL_ * PMP_ * DH_];

// FAVOR intermediates (single bf16)
__device__ __nv_bfloat16 g_qph[(size_t)BH_ * S_ * PMP_];
__device__ __nv_bfloat16 g_eh [(size_t)BH_ * S_ * PMP_];
__device__ float g_ctxE[BH_ * PMP_ * 72];
__device__ __nv_bfloat16 g_cbh[BH_ * PMP_ * 80], g_cbl[BH_ * PMP_ * 80];
__device__ float g_vsum[BH_ * 64];

// ---------------------------------------------------------------------------
// PTX helpers (family-portable: no tcgen05 on compute_103 targets)
// ---------------------------------------------------------------------------
__device__ __forceinline__ uint32_t smem_u32(const void* p) {
    uint32_t a;
    asm("{ .reg .u64 t; cvta.to.shared.u64 t, %1; cvt.u32.u64 %0, t; }" : "=r"(a) : "l"(p));
    return a;
}
__device__ __forceinline__ void ldsm4(unsigned& r0, unsigned& r1, unsigned& r2, unsigned& r3,
                                      uint32_t addr) {
    asm volatile("ldmatrix.sync.aligned.m8n8.x4.shared.b16 {%0,%1,%2,%3}, [%4];"
                 : "=r"(r0), "=r"(r1), "=r"(r2), "=r"(r3) : "r"(addr));
}
__device__ __forceinline__ void ldsm4t(unsigned& r0, unsigned& r1, unsigned& r2, unsigned& r3,
                                       uint32_t addr) {
    asm volatile("ldmatrix.sync.aligned.m8n8.x4.trans.shared.b16 {%0,%1,%2,%3}, [%4];"
                 : "=r"(r0), "=r"(r1), "=r"(r2), "=r"(r3) : "r"(addr));
}
__device__ __forceinline__ void mma_bf16(float* d, const unsigned* a, const unsigned* b) {
    asm volatile("mma.sync.aligned.m16n8k16.row.col.f32.bf16.bf16.f32 "
                 "{%0,%1,%2,%3}, {%4,%5,%6,%7}, {%8,%9}, {%0,%1,%2,%3};"
                 : "+f"(d[0]), "+f"(d[1]), "+f"(d[2]), "+f"(d[3])
                 : "r"(a[0]), "r"(a[1]), "r"(a[2]), "r"(a[3]), "r"(b[0]), "r"(b[1]));
}
#define CP_ASYNC16(dst, src) \
    asm volatile("cp.async.cg.shared.global [%0], [%1], 16;" :: "r"(dst), "l"(src) : "memory")
#define CP_COMMIT() asm volatile("cp.async.commit_group;" ::: "memory")
#define CP_WAIT(n)  asm volatile("cp.async.wait_group %0;" :: "n"(n) : "memory")

__device__ __forceinline__ void bf16_split(float v, __nv_bfloat16& hi, __nv_bfloat16& lo) {
    hi = __float2bfloat16(v);
    lo = __float2bfloat16(v - __bfloat162float(hi));
}
__device__ __forceinline__ float tanh_ap(float x) {
    float r;
    asm("tanh.approx.f32 %0, %1;" : "=f"(r) : "f"(x));
    return r;
}

// ---------------------------------------------------------------------------
// Reductions
// ---------------------------------------------------------------------------
__device__ __forceinline__ float warpsum(float v) {
#pragma unroll
    for (int o = 16; o > 0; o >>= 1) v += __shfl_xor_sync(0xffffffffu, v, o);
    return v;
}
__device__ __forceinline__ float block_sum(float v, float* sh) {
    int lane = threadIdx.x & 31, w = threadIdx.x >> 5, nw = blockDim.x >> 5;
    v = warpsum(v);
    if (lane == 0) sh[w] = v;
    __syncthreads();
    if (w == 0) {
        float x = (lane < nw) ? sh[lane] : 0.f;
        x = warpsum(x);
        if (lane == 0) sh[0] = x;
    }
    __syncthreads();
    float r = sh[0];
    __syncthreads();
    return r;
}
__device__ __forceinline__ unsigned fmap(float f) {
    unsigned u = __float_as_uint(f);
    return (u & 0x80000000u) ? ~u : (u | 0x80000000u);
}
__device__ __forceinline__ float funmap(unsigned u) {
    u = (u & 0x80000000u) ? (u & 0x7FFFFFFFu) : ~u;
    return __uint_as_float(u);
}

// ---------------------------------------------------------------------------
// Weight transpose + bf16 split: W [K,N] fp32 -> Th/Tl [N,K] bf16; z = layer
// ---------------------------------------------------------------------------
__global__ void wsplit_kernel(const float* __restrict__ W, __nv_bfloat16* __restrict__ Th,
                              __nv_bfloat16* __restrict__ Tl, int K, int N, int rowOff,
                              size_t sstride, size_t dstride) {
    __shared__ float ts[32][33];
    int l = blockIdx.z;
    W  += (size_t)l * sstride;
    Th += (size_t)l * dstride;
    Tl += (size_t)l * dstride;
    int kb = blockIdx.y * 32, nb = blockIdx.x * 32;
    int tx = threadIdx.x, ty = threadIdx.y;
#pragma unroll
    for (int i = 0; i < 4; i++) {
        int k = kb + ty + i * 8;
        ts[ty + i * 8][tx] = W[(size_t)k * N + nb + tx];
    }
    __syncthreads();
#pragma unroll
    for (int i = 0; i < 4; i++) {
        int n = nb + ty + i * 8;
        int k = kb + tx;
        float v = ts[tx][ty + i * 8];
        __nv_bfloat16 hi, lo;
        bf16_split(v, hi, lo);
        size_t idx = (size_t)(rowOff + n) * K + k;
        Th[idx] = hi; Tl[idx] = lo;
    }
}

__global__ void bconcat_kernel(const float* __restrict__ bq, const float* __restrict__ bk,
                               const float* __restrict__ bv, float* __restrict__ dst) {
    int l = blockIdx.x, t = threadIdx.x;
    dst[l * 768 + t]       = bq[l * 256 + t];
    dst[l * 768 + 256 + t] = bk[l * 256 + t];
    dst[l * 768 + 512 + t] = bv[l * 256 + t];
}

__global__ void psplit_kernel(const float* __restrict__ proj,
                              __nv_bfloat16* __restrict__ ph, __nv_bfloat16* __restrict__ pl) {
    int idx = blockIdx.x * 256 + threadIdx.x;
    int l = idx / (PMP_ * DH_);
    int rem = idx - l * (PMP_ * DH_);
    int r = rem >> 6, c = rem & 63;
    float v = (r < PM_) ? proj[((size_t)l * PM_ + r) * DH_ + c] : 0.f;
    __nv_bfloat16 hi, lo;
    bf16_split(v, hi, lo);
    ph[idx] = hi; pl[idx] = lo;
}

// ---------------------------------------------------------------------------
// LayerNorm — warp-per-row
// ---------------------------------------------------------------------------
__global__ __launch_bounds__(256) void embed_ln_kernel(
    const float* __restrict__ emb, const float* __restrict__ pos,
    const float* __restrict__ g, const float* __restrict__ bb,
    float* __restrict__ out) {
    int warp = threadIdx.x >> 5, lane = threadIdx.x & 31;
    int row = blockIdx.x * 8 + warp;
    int c0 = lane * 8;
    const float* ep = emb + (size_t)row * D_ + c0;
    const float* pp = pos + (size_t)(row & (S_ - 1)) * D_ + c0;
    float v[8];
    float4 a0 = *(const float4*)ep, a1 = *(const float4*)(ep + 4);
    float4 p0 = *(const float4*)pp, p1 = *(const float4*)(pp + 4);
    v[0] = a0.x + p0.x; v[1] = a0.y + p0.y; v[2] = a0.z + p0.z; v[3] = a0.w + p0.w;
    v[4] = a1.x + p1.x; v[5] = a1.y + p1.y; v[6] = a1.z + p1.z; v[7] = a1.w + p1.w;
    float s = 0.f;
#pragma unroll
    for (int j = 0; j < 8; j++) s += v[j];
    float mu = warpsum(s) * (1.0f / D_);
    float s2 = 0.f;
#pragma unroll
    for (int j = 0; j < 8; j++) { float d = v[j] - mu; s2 = fmaf(d, d, s2); }
    float rs = rsqrtf(warpsum(s2) * (1.0f / D_) + LNEPS_);
    float4 g0 = *(const float4*)(g + c0), g1 = *(const float4*)(g + c0 + 4);
    float4 b0 = *(const float4*)(bb + c0), b1 = *(const float4*)(bb + c0 + 4);
    float gg[8] = {g0.x, g0.y, g0.z, g0.w, g1.x, g1.y, g1.z, g1.w};
    float bbv[8] = {b0.x, b0.y, b0.z, b0.w, b1.x, b1.y, b1.z, b1.w};
    float o[8];
#pragma unroll
    for (int j = 0; j < 8; j++) o[j] = (v[j] - mu) * rs * gg[j] + bbv[j];
    float* op = out + (size_t)row * D_ + c0;
    *(float4*)op       = make_float4(o[0], o[1], o[2], o[3]);
    *(float4*)(op + 4) = make_float4(o[4], o[5], o[6], o[7]);
}

__global__ __launch_bounds__(256) void ln_kernel(
    const float* __restrict__ in,
    __nv_bfloat16* __restrict__ oh, __nv_bfloat16* __restrict__ ol,
    const float* __restrict__ g, const float* __restrict__ bb) {
    int warp = threadIdx.x >> 5, lane = threadIdx.x & 31;
    int row = blockIdx.x * 8 + warp;
    int c0 = lane * 8;
    const float* rp = in + (size_t)row * D_ + c0;
    float4 a0 = *(const float4*)rp, a1 = *(const float4*)(rp + 4);
    float v[8] = {a0.x, a0.y, a0.z, a0.w, a1.x, a1.y, a1.z, a1.w};
    float s = 0.f;
#pragma unroll
    for (int j = 0; j < 8; j++) s += v[j];
    float mu = warpsum(s) * (1.0f / D_);
    float s2 = 0.f;
#pragma unroll
    for (int j = 0; j < 8; j++) { float d = v[j] - mu; s2 = fmaf(d, d, s2); }
    float rs = rsqrtf(warpsum(s2) * (1.0f / D_) + LNEPS_);
    float4 g0 = *(const float4*)(g + c0), g1 = *(const float4*)(g + c0 + 4);
    float4 b0 = *(const float4*)(bb + c0), b1 = *(const float4*)(bb + c0 + 4);
    float gg[8] = {g0.x, g0.y, g0.z, g0.w, g1.x, g1.y, g1.z, g1.w};
    float bbv[8] = {b0.x, b0.y, b0.z, b0.w, b1.x, b1.y, b1.z, b1.w};
    size_t base = (size_t)row * D_ + c0;
#pragma unroll
    for (int j2 = 0; j2 < 4; j2++) {
        float x0 = (v[2 * j2] - mu) * rs * gg[2 * j2] + bbv[2 * j2];
        float x1 = (v[2 * j2 + 1] - mu) * rs * gg[2 * j2 + 1] + bbv[2 * j2 + 1];
        __nv_bfloat16 h0, l0, h1, l1;
        bf16_split(x0, h0, l0);
        bf16_split(x1, h1, l1);
        *(__nv_bfloat162*)(oh + base + 2 * j2) = __nv_bfloat162(h0, h1);
        *(__nv_bfloat162*)(ol + base + 2 * j2) = __nv_bfloat162(l0, l1);
    }
}

// ---------------------------------------------------------------------------
// mma.sync bf16 GEMM (dense): C = A @ Bt^T (+bias +epilogue)
// ALO: A has a lo array (3-term split); else single-bf16 A (2-term).
// MODE: 0 = QKV (q->Oh/Ol, k->Oh2/Ol2, v->Oh3 single);
//       1 = GELU->Oh (single); 2 = residual accumulate into O0 (+Oh/Ol if EMIT);
//       3 = tanh->O0
// ---------------------------------------------------------------------------
constexpr int ROWB    = 80;
constexpr int ARR_B   = 128 * ROWB;
constexpr int STAGE_B = 4 * ARR_B;
constexpr int MM_SMEM = 2 * STAGE_B;     // 81920

template <bool ALO>
__device__ __forceinline__ void stage_cp(uint32_t sbase,
    const __nv_bfloat16* __restrict__ Ah, const __nv_bfloat16* __restrict__ Al,
    const __nv_bfloat16* __restrict__ Bh, const __nv_bfloat16* __restrict__ Bl,
    int row0, int col0, int K, int k0, int tid) {
#pragma unroll
    for (int i = 0; i < 8; i++) {
        const int arr = i >> 1;
        if (!ALO && arr == 1) continue;
        int cc = tid + (i & 1) * 256;
        int row = cc >> 2, kc = cc & 3;
        const __nv_bfloat16* src;
        int gr;
        if (arr == 0)      { src = Ah; gr = row0 + row; }
        else if (arr == 1) { src = Al; gr = row0 + row; }
        else if (arr == 2) { src = Bh; gr = col0 + row; }
        else               { src = Bl; gr = col0 + row; }
        uint32_t dst = sbase + arr * ARR_B + row * ROWB + kc * 16;
        CP_ASYNC16(dst, src + (size_t)gr * K + k0 + kc * 8);
    }
}

template <int MODE, bool EMIT, bool ALO>
__global__ __launch_bounds__(256) void mm_gemm(
    const __nv_bfloat16* __restrict__ Ah, const __nv_bfloat16* __restrict__ Al,
    const __nv_bfloat16* __restrict__ Bth, const __nv_bfloat16* __restrict__ Btl,
    const float* __restrict__ bias,
    float* __restrict__ O0,
    __nv_bfloat16* __restrict__ Oh, __nv_bfloat16* __restrict__ Ol,
    __nv_bfloat16* __restrict__ Oh2, __nv_bfloat16* __restrict__ Ol2,
    __nv_bfloat16* __restrict__ Oh3,
    int K, int N) {
    extern __shared__ char smem[];
    uint32_t sb = smem_u32(smem);
    int tid = threadIdx.x, lane = tid & 31, warp = tid >> 5;
    int row0 = blockIdx.y * 128, col0 = blockIdx.x * 128;
    int wm = (warp >> 1) * 32, wn = (warp & 1) * 64;

    float acc[2][8][4] = {};

    int NT = K >> 5;
    stage_cp<ALO>(sb, Ah, Al, Bth, Btl, row0, col0, K, 0, tid);
    CP_COMMIT();
    if (NT > 1) {
        stage_cp<ALO>(sb + STAGE_B, Ah, Al, Bth, Btl, row0, col0, K, 32, tid);
        CP_COMMIT();
    }

    uint32_t aoff = (uint32_t)((wm + (lane & 15)) * ROWB + (lane >> 4) * 16);
    uint32_t boff = (uint32_t)((wn + ((lane >> 4) << 3) + (lane & 7)) * ROWB +
                               ((lane >> 3) & 1) * 16);

    for (int t = 0; t < NT; t++) {
        if (t + 1 < NT) CP_WAIT(1); else CP_WAIT(0);
        __syncthreads();
        uint32_t bs = sb + (t & 1) * STAGE_B;
#pragma unroll
        for (int kt = 0; kt < 2; kt++) {
            unsigned ah[2][4], al[2][4], bh[8][2], bl[8][2];
#pragma unroll
            for (int mt = 0; mt < 2; mt++) {
                uint32_t a = bs + aoff + mt * (16 * ROWB) + kt * 32;
                ldsm4(ah[mt][0], ah[mt][1], ah[mt][2], ah[mt][3], a);
                if (ALO) ldsm4(al[mt][0], al[mt][1], al[mt][2], al[mt][3], a + ARR_B);
            }
#pragma unroll
            for (int n2 = 0; n2 < 4; n2++) {
                uint32_t a = bs + 2 * ARR_B + boff + n2 * (16 * ROWB) + kt * 32;
                ldsm4(bh[2 * n2][0], bh[2 * n2][1], bh[2 * n2 + 1][0], bh[2 * n2 + 1][1], a);
                ldsm4(bl[2 * n2][0], bl[2 * n2][1], bl[2 * n2 + 1][0], bl[2 * n2 + 1][1],
                      a + ARR_B);
            }
#pragma unroll
            for (int mt = 0; mt < 2; mt++)
#pragma unroll
                for (int nt = 0; nt < 8; nt++) {
                    mma_bf16(acc[mt][nt], ah[mt], bh[nt]);
                    mma_bf16(acc[mt][nt], ah[mt], bl[nt]);
                    if (ALO) mma_bf16(acc[mt][nt], al[mt], bh[nt]);
                }
        }
        __syncthreads();
        if (t + 2 < NT) {
            stage_cp<ALO>(sb + (t & 1) * STAGE_B, Ah, Al, Bth, Btl, row0, col0, K,
                          (t + 2) * 32, tid);
            CP_COMMIT();
        }
    }

#pragma unroll
    for (int mt = 0; mt < 2; mt++)
#pragma unroll
        for (int nt = 0; nt < 8; nt++) {
            int rbase = row0 + wm + mt * 16 + (lane >> 2);
            int cg = col0 + wn + nt * 8 + (lane & 3) * 2;
            float b0 = __ldg(&bias[cg]), b1 = __ldg(&bias[cg + 1]);
#pragma unroll
            for (int half = 0; half < 2; half++) {
                int row = rbase + half * 8;
                float v0 = acc[mt][nt][half * 2]     + b0;
                float v1 = acc[mt][nt][half * 2 + 1] + b1;
                if (MODE == 0) {
                    int which = cg >> 8, cl = cg & 255;
                    size_t idx = (size_t)row * 256 + cl;
                    if (which == 2) {
                        *(__nv_bfloat162*)(Oh3 + idx) =
                            __nv_bfloat162(__float2bfloat16(v0), __float2bfloat16(v1));
                    } else {
                        __nv_bfloat16* H = which ? Oh2 : Oh;
                        __nv_bfloat16* L = which ? Ol2 : Ol;
                        __nv_bfloat16 hi, lo;
                        bf16_split(v0, hi, lo); H[idx] = hi;     L[idx] = lo;
                        bf16_split(v1, hi, lo); H[idx + 1] = hi; L[idx + 1] = lo;
                    }
                } else if (MODE == 1) {
                    float u0 = 0.7978845608028654f * (v0 + 0.044715f * v0 * v0 * v0);
                    float u1 = 0.7978845608028654f * (v1 + 0.044715f * v1 * v1 * v1);
                    float g0 = 0.5f * v0 * (1.f + tanh_ap(u0));
                    float g1 = 0.5f * v1 * (1.f + tanh_ap(u1));
                    size_t idx = (size_t)row * N + cg;
                    *(__nv_bfloat162*)(Oh + idx) =
                        __nv_bfloat162(__float2bfloat16(g0), __float2bfloat16(g1));
                } else if (MODE == 2) {
                    size_t idx = (size_t)row * N + cg;
                    float n0 = O0[idx] + v0, n1 = O0[idx + 1] + v1;
                    O0[idx] = n0; O0[idx + 1] = n1;
                    if (EMIT) {
                        __nv_bfloat16 hi, lo;
                        bf16_split(n0, hi, lo); Oh[idx] = hi;     Ol[idx] = lo;
                        bf16_split(n1, hi, lo); Oh[idx + 1] = hi; Ol[idx + 1] = lo;
                    }
                } else {
                    size_t idx = (size_t)row * N + cg;
                    O0[idx]     = tanh_ap(v0);
                    O0[idx + 1] = tanh_ap(v1);
                }
            }
        }
}

// ---------------------------------------------------------------------------
// dash via mma -> single bf16 output [bh][s][288]
// 64-row blocks (2 CTAs/SM); QPHI=true: fused q-phi; QPHI=false: E + global max
// ---------------------------------------------------------------------------
constexpr int DRB = 144;
constexpr int DA_H = 0;
constexpr int DA_L = 64 * DRB;                  // 9216
constexpr int DB_H = 2 * 64 * DRB;              // 18432
constexpr int DB_L = DB_H + PMP_ * DRB;         // 59904
constexpr int D_SDIAG = DB_L + PMP_ * DRB;      // 101376
constexpr int D_SRMAX = D_SDIAG + 256;
constexpr int DASH_SMEM = D_SRMAX + 256;        // 101888

template <bool QPHI>
__global__ __launch_bounds__(256, 2) void dash_mma(
    const __nv_bfloat16* __restrict__ Xh, const __nv_bfloat16* __restrict__ Xl,
    const __nv_bfloat16* __restrict__ Ph, const __nv_bfloat16* __restrict__ Pl,
    __nv_bfloat16* __restrict__ outh,
    unsigned* __restrict__ gmax) {
    extern __shared__ char smem[];
    uint32_t sb = smem_u32(smem);
    float* sdiag = (float*)(smem + D_SDIAG);
    unsigned* srmax = (unsigned*)(smem + D_SRMAX);
    int tid = threadIdx.x, lane = tid & 31, warp = tid >> 5;
    int bh = blockIdx.y, b = bh >> 2, h = bh & 3;
    int s0 = blockIdx.x * 64;

    for (int i = tid; i < 512; i += 256) {
        int r = i >> 3, c = i & 7;
        const __nv_bfloat16* s1 = Xh + ((size_t)(b * S_ + s0 + r)) * D_ + h * DH_ + c * 8;
        const __nv_bfloat16* s2 = Xl + ((size_t)(b * S_ + s0 + r)) * D_ + h * DH_ + c * 8;
        CP_ASYNC16(sb + DA_H + r * DRB + c * 16, s1);
        CP_ASYNC16(sb + DA_L + r * DRB + c * 16, s2);
    }
    for (int i = tid; i < PMP_ * 8; i += 256) {
        int r = i >> 3, c = i & 7;
        CP_ASYNC16(sb + DB_H + r * DRB + c * 16, Ph + (size_t)r * DH_ + c * 8);
        CP_ASYNC16(sb + DB_L + r * DRB + c * 16, Pl + (size_t)r * DH_ + c * 8);
    }
    CP_COMMIT(); CP_WAIT(0);
    __syncthreads();

    if (tid < 64) {
        const __nv_bfloat16* ah = (const __nv_bfloat16*)(smem + DA_H + tid * DRB);
        const __nv_bfloat16* al = (const __nv_bfloat16*)(smem + DA_L + tid * DRB);
        float s = 0.f;
#pragma unroll
        for (int c = 0; c < DH_; c++) {
            float v = __bfloat162float(ah[c]) + __bfloat162float(al[c]);
            s = fmaf(v, v, s);
        }
        sdiag[tid] = HDN2_ * s;
        srmax[tid] = 0u;
    }
    __syncthreads();

    int wm = (warp >> 1) * 16, wn = (warp & 1) * 144;
    float acc[18][4] = {};
    uint32_t aoff = (uint32_t)((wm + (lane & 15)) * DRB + (lane >> 4) * 16);
    uint32_t boff = (uint32_t)((wn + ((lane >> 4) << 3) + (lane & 7)) * DRB +
                               ((lane >> 3) & 1) * 16);

#pragma unroll
    for (int kt = 0; kt < 4; kt++) {
        unsigned ah[4], al[4];
        {
            uint32_t a = sb + DA_H + aoff + kt * 32;
            ldsm4(ah[0], ah[1], ah[2], ah[3], a);
            ldsm4(al[0], al[1], al[2], al[3], a + (DA_L - DA_H));
        }
#pragma unroll
        for (int n2 = 0; n2 < 9; n2++) {
            unsigned bhf[2][2], blf[2][2];
            uint32_t a = sb + DB_H + boff + n2 * (16 * DRB) + kt * 32;
            ldsm4(bhf[0][0], bhf[0][1], bhf[1][0], bhf[1][1], a);
            ldsm4(blf[0][0], blf[0][1], blf[1][0], blf[1][1], a + (DB_L - DB_H));
#pragma unroll
            for (int j = 0; j < 2; j++) {
                int nt = n2 * 2 + j;
                mma_bf16(acc[nt], ah, bhf[j]);
                mma_bf16(acc[nt], ah, blf[j]);
                mma_bf16(acc[nt], al, bhf[j]);
            }
        }
    }

    // per-row max of raw dash (valid cols only)
#pragma unroll
    for (int half = 0; half < 2; half++) {
        float p = -3.4e38f;
#pragma unroll
        for (int nt = 0; nt < 18; nt++)
#pragma unroll
            for (int e = 0; e < 2; e++) {
                int col = wn + nt * 8 + (lane & 3) * 2 + e;
                if (col < PM_) p = fmaxf(p, DN_ * acc[nt][half * 2 + e]);
            }
        p = fmaxf(p, __shfl_xor_sync(0xffffffffu, p, 1));
        p = fmaxf(p, __shfl_xor_sync(0xffffffffu, p, 2));
        if ((lane & 3) == 0)
            atomicMax(&srmax[wm + (lane >> 2) + half * 8], fmap(p));
    }
    __syncthreads();

    if (!QPHI && tid == 0) {
        unsigned m = 0u;
#pragma unroll 4
        for (int i = 0; i < 64; i++) m = max(m, srmax[i]);
        atomicMax(gmax, m);
    }

#pragma unroll
    for (int half = 0; half < 2; half++) {
        int r = wm + (lane >> 2) + half * 8;
        size_t rowbase = ((size_t)bh * S_ + s0 + r) * PMP_;
        float sub = QPHI ? (sdiag[r] + funmap(srmax[r])) : sdiag[r];
#pragma unroll
        for (int nt = 0; nt < 18; nt++) {
            int colb = wn + nt * 8 + (lane & 3) * 2;
            float o[2];
#pragma unroll
            for (int e = 0; e < 2; e++) {
                int col = colb + e;
                float val = 0.f;
                if (col < PM_) {
                    float dv = DN_ * acc[nt][half * 2 + e];
                    val = QPHI ? RATIO_ * (__expf(dv - sub) + KEPS_)
                               : __expf(dv - sub);
                }
                o[e] = val;
            }
            *(__nv_bfloat162*)(outh + rowbase + colb) =
                __nv_bfloat162(__float2bfloat16(o[0]), __float2bfloat16(o[1]));
        }
    }
}

// ---------------------------------------------------------------------------
// ctx via mma: ctxE[bh][m][e] = sum_s E[s][m] * Vx[s][e], Vx col 64 = 1 (ksum)
// E single bf16, V single bf16 (1-term); split-K x16
// ---------------------------------------------------------------------------
constexpr int CE_ST = 592;
constexpr int CV_ST = 160;
constexpr int C_EH = 0;
constexpr int C_VH = 32 * CE_ST;              // 18944
constexpr int CSTAGE = C_VH + 32 * CV_ST;     // 24064
constexpr int CTX_SMEM = 2 * CSTAGE;          // 48128

__global__ __launch_bounds__(256) void ctx_mma(
    const __nv_bfloat16* __restrict__ Eh,
    const __nv_bfloat16* __restrict__ Vh,
    float* __restrict__ ctxE) {
    extern __shared__ char smem[];
    uint32_t sb = smem_u32(smem);
    int tid = threadIdx.x, lane = tid & 31, warp = tid >> 5;
    int bh = blockIdx.x, b = bh >> 2, h = bh & 3;
    int sbase = blockIdx.y * 256;

    auto stage = [&](int buf, int chunk) {
        uint32_t base = sb + buf * CSTAGE;
        int s0 = sbase + chunk * 32;
        for (int i = tid; i < 1152; i += 256) {
            int r = i / 36, c = i - r * 36;
            size_t g = ((size_t)bh * S_ + s0 + r) * PMP_ + c * 8;
            CP_ASYNC16(base + C_EH + r * CE_ST + c * 16, Eh + g);
        }
        {
            int i = tid;
            if (i < 256) {
                int r = i >> 3, c = i & 7;
                size_t g = ((size_t)(b * S_ + s0 + r)) * D_ + h * DH_ + c * 8;
                CP_ASYNC16(base + C_VH + r * CV_ST + c * 16, Vh + g);
            }
        }
        if (tid < 64) {
            int r = tid >> 1, half2 = tid & 1;
            uint4 z = make_uint4(0, 0, 0, 0);
            uint4 one = make_uint4(0x00003F80u, 0, 0, 0);
            uint32_t off = (uint32_t)(r * CV_ST + 128 + half2 * 16);
            *(uint4*)(smem + buf * CSTAGE + C_VH + off) = (half2 == 0) ? one : z;
        }
    };

    stage(0, 0); CP_COMMIT();
    stage(1, 1); CP_COMMIT();

    int mts[3];
    mts[0] = warp * 2; mts[1] = warp * 2 + 1; mts[2] = (warp < 2) ? 16 + warp : -1;
    float acc[3][9][4] = {};

    for (int t = 0; t < 8; t++) {
        if (t + 1 < 8) CP_WAIT(1); else CP_WAIT(0);
        __syncthreads();
        uint32_t bs = sb + (t & 1) * CSTAGE;
#pragma unroll
        for (int kt = 0; kt < 2; kt++) {
            int krA = (lane & 7) + ((lane >> 4) & 1) * 8 + kt * 16;
            int mcolbit = ((lane >> 3) & 1) * 8;
            unsigned ah[3][4];
#pragma unroll
            for (int mt = 0; mt < 3; mt++) {
                if (mts[mt] < 0) break;
                uint32_t a = bs + C_EH + krA * CE_ST + (mts[mt] * 16 + mcolbit) * 2;
                ldsm4t(ah[mt][0], ah[mt][1], ah[mt][2], ah[mt][3], a);
            }
            int krB = (lane & 7) + ((lane >> 3) & 1) * 8 + kt * 16;
            int ncolbit = (lane >> 4) * 8;
#pragma unroll
            for (int p = 0; p < 5; p++) {
                unsigned bhf[4];
                uint32_t a = bs + C_VH + krB * CV_ST + (p * 16 + ncolbit) * 2;
                ldsm4t(bhf[0], bhf[1], bhf[2], bhf[3], a);
#pragma unroll
                for (int j = 0; j < 2; j++) {
                    int nt = p * 2 + j;
                    if (nt > 8) break;
#pragma unroll
                    for (int mt = 0; mt < 3; mt++) {
                        if (mts[mt] < 0) break;
                        mma_bf16(acc[mt][nt], ah[mt], bhf + j * 2);
                    }
                }
            }
        }
        __syncthreads();
        if (t + 2 < 8) { stage(t & 1, t + 2); CP_COMMIT(); }
    }

#pragma unroll
    for (int mt = 0; mt < 3; mt++) {
        if (mts[mt] < 0) break;
#pragma unroll
        for (int nt = 0; nt < 9; nt++)
#pragma unroll
            for (int half = 0; half < 2; half++) {
                int m = mts[mt] * 16 + (lane >> 2) + half * 8;
                int e = nt * 8 + (lane & 3) * 2;
                float* dst = ctxE + ((size_t)bh * PMP_ + m) * 72 + e;
                atomicAdd(dst,     acc[mt][nt][half * 2]);
                atomicAdd(dst + 1, acc[mt][nt][half * 2 + 1]);
            }
    }
}

// vsum[bh][e] = sum_s v[b][s][h*64+e]
__global__ void vsum_kernel(const __nv_bfloat16* __restrict__ vh,
                            float* __restrict__ vsum) {
    int bh = blockIdx.x, b = bh >> 2, h = bh & 3;
    int e = threadIdx.x;
    int s0 = blockIdx.y * 256;
    float s = 0.f;
    for (int i = 0; i < 256; i++) {
        size_t idx = ((size_t)(b * S_ + s0 + i)) * D_ + h * DH_ + e;
        s += __bfloat162float(vh[idx]);
    }
    atomicAdd(&vsum[bh * 64 + e], s);
}

// ctx_b = a*ctxE + correction; bf16 hi/lo [bh][288][80]
__global__ void ctxcorr_kernel(const float* __restrict__ ctxE, const float* __restrict__ vsum,
                               const unsigned* __restrict__ gmax,
                               __nv_bfloat16* __restrict__ cbh, __nv_bfloat16* __restrict__ cbl) {
    int idx = blockIdx.x * 256 + threadIdx.x;
    if (idx >= BH_ * PMP_ * 80) return;
    int bh = idx / (PMP_ * 80);
    int rem = idx - bh * (PMP_ * 80);
    int m = rem / 80, e = rem - m * 80;
    float a = RATIO_ * __expf(-funmap(*gmax));
    float c = RATIO_ * KEPS_;
    float val = 0.f;
    if (m < PM_ && e < 72) {
        float base = ctxE[((size_t)bh * PMP_ + m) * 72 + e];
        float corr = (e < 64) ? c * vsum[bh * 64 + e] : ((e == 64) ? c * (float)S_ : 0.f);
        val = a * base + corr;
    }
    __nv_bfloat16 hi, lo;
    bf16_split(val, hi, lo);
    cbh[idx] = hi; cbl[idx] = lo;
}

// ---------------------------------------------------------------------------
// attnout via mma: O[s][e] = (qp[s]·ctx_b[:,e]) / (qp[s]·ksum)  -> oh (single)
// Q single bf16 (2-term with Cb hi/lo)
// ---------------------------------------------------------------------------
constexpr int AQ_ST = 80;
constexpr int AB_ST = 160;
constexpr int A_QH = 0;
constexpr int A_BH2 = 128 * AQ_ST;            // 10240
constexpr int A_BL2 = A_BH2 + 32 * AB_ST;     // 15360
constexpr int ASTAGE = A_BL2 + 32 * AB_ST;    // 20480
constexpr int A_SDEN = 2 * ASTAGE;            // 40960
constexpr int ATT_SMEM = A_SDEN + 512;        // 41472

__global__ __launch_bounds__(256) void attnout_mma(
    const __nv_bfloat16* __restrict__ Qh,
    const __nv_bfloat16* __restrict__ Cbh, const __nv_bfloat16* __restrict__ Cbl,
    __nv_bfloat16* __restrict__ oh) {
    extern __shared__ char smem[];
    uint32_t sb = smem_u32(smem);
    float* sden = (float*)(smem + A_SDEN);
    int tid = threadIdx.x, lane = tid & 31, warp = tid >> 5;
    int bh = blockIdx.y, b = bh >> 2, h = bh & 3;
    int s0 = blockIdx.x * 128;

    auto stage = [&](int buf, int chunk) {
        uint32_t base = sb + buf * ASTAGE;
        int k0 = chunk * 32;
        for (int i = tid; i < 512; i += 256) {
            int r = i >> 2, c = i & 3;
            size_t g = ((size_t)bh * S_ + s0 + r) * PMP_ + k0 + c * 8;
            CP_ASYNC16(base + A_QH + r * AQ_ST + c * 16, Qh + g);
        }
        for (int i = tid; i < 320; i += 256) {
            int r = i / 10, c = i - r * 10;
            size_t g = ((size_t)bh * PMP_ + k0 + r) * 80 + c * 8;
            CP_ASYNC16(base + A_BH2 + r * AB_ST + c * 16, Cbh + g);
            CP_ASYNC16(base + A_BL2 + r * AB_ST + c * 16, Cbl + g);
        }
    };

    stage(0, 0); CP_COMMIT();
    stage(1, 1); CP_COMMIT();

    int wm = (warp >> 1) * 32, ng = warp & 1;
    float acc[2][5][4] = {};
    uint32_t aoff = (uint32_t)((wm + (lane & 15)) * AQ_ST + (lane >> 4) * 16);

    for (int t = 0; t < 9; t++) {
        if (t + 1 < 9) CP_WAIT(1); else CP_WAIT(0);
        __syncthreads();
        uint32_t bs = sb + (t & 1) * ASTAGE;
#pragma unroll
        for (int kt = 0; kt < 2; kt++) {
            unsigned ah[2][4];
#pragma unroll
            for (int mt = 0; mt < 2; mt++) {
                uint32_t a = bs + A_QH + aoff + mt * (16 * AQ_ST) + kt * 32;
                ldsm4(ah[mt][0], ah[mt][1], ah[mt][2], ah[mt][3], a);
            }
            int krB = (lane & 7) + ((lane >> 3) & 1) * 8 + kt * 16;
            int ncolbit = (lane >> 4) * 8;
#pragma unroll
            for (int pi = 0; pi < 3; pi++) {
                if (!ng && pi == 2) break;
                int p = ng ? (2 + pi) : pi;
                unsigned bhf[4], blf[4];
                uint32_t a = bs + A_BH2 + krB * AB_ST + (p * 16 + ncolbit) * 2;
                ldsm4t(bhf[0], bhf[1], bhf[2], bhf[3], a);
                ldsm4t(blf[0], blf[1], blf[2], blf[3], a + (A_BL2 - A_BH2));
#pragma unroll
                for (int j = 0; j < 2; j++) {
                    int ntg = p * 2 + j;
                    if (ntg > 8) break;
                    int ntl = ntg - ng * 4;
#pragma unroll
                    for (int mt = 0; mt < 2; mt++) {
                        mma_bf16(acc[mt][ntl], ah[mt], bhf + j * 2);
                        mma_bf16(acc[mt][ntl], ah[mt], blf + j * 2);
                    }
                }
            }
        }
        __syncthreads();
        if (t + 2 < 9) { stage(t & 1, t + 2); CP_COMMIT(); }
    }

    if (ng == 1 && (lane & 3) == 0) {
#pragma unroll
        for (int mt = 0; mt < 2; mt++)
#pragma unroll
            for (int half = 0; half < 2; half++) {
                int r = wm + mt * 16 + (lane >> 2) + half * 8;
                sden[r] = acc[mt][4][half * 2];
            }
    }
    __syncthreads();

#pragma unroll
    for (int mt = 0; mt < 2; mt++)
#pragma unroll
        for (int half = 0; half < 2; half++) {
            int r = wm + mt * 16 + (lane >> 2) + half * 8;
            float rinv = 1.f / sden[r];
            size_t obase = ((size_t)(b * S_ + s0 + r)) * D_ + h * DH_;
#pragma unroll
            for (int ntl = 0; ntl < 4; ntl++) {
                int e = (ng * 4 + ntl) * 8 + (lane & 3) * 2;
                float v0 = acc[mt][ntl][half * 2]     * rinv;
                float v1 = acc[mt][ntl][half * 2 + 1] * rinv;
                *(__nv_bfloat162*)(oh + obase + e) =
                    __nv_bfloat162(__float2bfloat16(v0), __float2bfloat16(v1));
            }
        }
}

// ---------------------------------------------------------------------------
// Per-layer init
// ---------------------------------------------------------------------------
__global__ void layer_init_kernel(float* __restrict__ ctxE, float* __restrict__ vsum,
                                  unsigned* __restrict__ km) {
    int i = blockIdx.x * 256 + threadIdx.x;
    if (i < BH_ * PMP_ * 72) ctxE[i] = 0.f;
    if (i < BH_ * 64) vsum[i] = 0.f;
    if (i == 0) *km = 0u;
}

// ---------------------------------------------------------------------------
// Pooling
// ---------------------------------------------------------------------------
__global__ __launch_bounds__(256) void score_kernel(
    const float* __restrict__ h, const float* __restrict__ p2w,
    const float* __restrict__ p2b, const float* __restrict__ mask,
    float* __restrict__ score) {
    int warp = threadIdx.x >> 5, lane = threadIdx.x & 31;
    int row = blockIdx.x * 8 + warp;
    int c0 = lane * 8;
    const float* rp = h + (size_t)row * D_ + c0;
    float4 a0 = *(const float4*)rp, a1 = *(const float4*)(rp + 4);
    float4 w0 = *(const float4*)(p2w + c0), w1 = *(const float4*)(p2w + c0 + 4);
    float s = a0.x * w0.x + a0.y * w0.y + a0.z * w0.z + a0.w * w0.w +
              a1.x * w1.x + a1.y * w1.y + a1.z * w1.z + a1.w * w1.w;
    s = warpsum(s);
    if (lane == 0) score[row] = expf(s + p2b[0]) * mask[row];
}

__global__ void ssum_kernel(const float* __restrict__ score, float* __restrict__ ssum) {
    __shared__ float sh[8];
    int b = blockIdx.x;
    float s = 0.f;
    for (int i = threadIdx.x; i < S_; i += 256) s += score[b * S_ + i];
    s = block_sum(s, sh);
    if (threadIdx.x == 0) ssum[b] = s;
}

__global__ void outzero_kernel(float* __restrict__ out) {
    int i = blockIdx.x * blockDim.x + threadIdx.x;
    if (i < B_ * D_) out[i] = 0.f;
}

__global__ void pool_kernel(const float* __restrict__ x, const float* __restrict__ score,
                            const float* __restrict__ ssum, float* __restrict__ out) {
    int b = blockIdx.x, chunk = blockIdx.y, d = threadIdx.x;
    float inv = 1.f / (ssum[b] + 1e-8f);
    float acc = 0.f;
    int s0 = chunk * (S_ / 64);
    for (int s = s0; s < s0 + S_ / 64; s++)
        acc = fmaf(x[((size_t)(b * S_ + s)) * D_ + d], score[b * S_ + s], acc);
    atomicAdd(&out[b * D_ + d], acc * inv);
}

// ---------------------------------------------------------------------------
// Host launcher
// ---------------------------------------------------------------------------
extern "C" void kernel_launch(void* const* d_in, const int* in_sizes, int n_in,
                              void* d_out, int out_size) {
    const float* emb  = (const float*)d_in[0];
    const float* mask = (const float*)d_in[1];
    const float* pos  = (const float*)d_in[2];
    const float* ln_g = (const float*)d_in[3];
    const float* ln_b = (const float*)d_in[4];
    const float* proj = (const float*)d_in[5];
    const float* Wq = (const float*)d_in[6];   const float* bq = (const float*)d_in[7];
    const float* Wk = (const float*)d_in[8];   const float* bk = (const float*)d_in[9];
    const float* Wv = (const float*)d_in[10];  const float* bv = (const float*)d_in[11];
    const float* Wo = (const float*)d_in[12];  const float* bo = (const float*)d_in[13];
    const float* ln1g = (const float*)d_in[14]; const float* ln1b = (const float*)d_in[15];
    const float* W1 = (const float*)d_in[16];  const float* b1 = (const float*)d_in[17];
    const float* W2 = (const float*)d_in[18];  const float* b2 = (const float*)d_in[19];
    const float* ln2g = (const float*)d_in[20]; const float* ln2b = (const float*)d_in[21];
    const float* p1w = (const float*)d_in[22]; const float* p1b = (const float*)d_in[23];
    const float* p2w = (const float*)d_in[24]; const float* p2b = (const float*)d_in[25];
    float* out = (float*)d_out;

    void* tp;
    float *x, *h, *sc, *ss, *bqkv, *ctxE, *vsum;
    unsigned* km;
    __nv_bfloat16 *wth, *wtl, *hh, *hl, *oh, *fh, *xh, *xl;
    __nv_bfloat16 *qh, *ql, *kh, *kl, *vh, *pjh, *pjl;
    __nv_bfloat16 *qph, *eh, *cbh, *cbl;
    cudaGetSymbolAddress(&tp, g_x);     x  = (float*)tp;
    cudaGetSymbolAddress(&tp, g_h);     h  = (float*)tp;
    cudaGetSymbolAddress(&tp, g_score); sc = (float*)tp;
    cudaGetSymbolAddress(&tp, g_ssum);  ss = (float*)tp;
    cudaGetSymbolAddress(&tp, g_kmaxu); km = (unsigned*)tp;
    cudaGetSymbolAddress(&tp, g_bqkv);  bqkv = (float*)tp;
    cudaGetSymbolAddress(&tp, g_ctxE);  ctxE = (float*)tp;
    cudaGetSymbolAddress(&tp, g_vsum);  vsum = (float*)tp;
    cudaGetSymbolAddress(&tp, g_wth);   wth = (__nv_bfloat16*)tp;
    cudaGetSymbolAddress(&tp, g_wtl);   wtl = (__nv_bfloat16*)tp;
    cudaGetSymbolAddress(&tp, g_hh);    hh = (__nv_bfloat16*)tp;
    cudaGetSymbolAddress(&tp, g_hl);    hl = (__nv_bfloat16*)tp;
    cudaGetSymbolAddress(&tp, g_oh);    oh = (__nv_bfloat16*)tp;
    cudaGetSymbolAddress(&tp, g_fh);    fh = (__nv_bfloat16*)tp;
    cudaGetSymbolAddress(&tp, g_xh);    xh = (__nv_bfloat16*)tp;
    cudaGetSymbolAddress(&tp, g_xl);    xl = (__nv_bfloat16*)tp;
    cudaGetSymbolAddress(&tp, g_qh);    qh = (__nv_bfloat16*)tp;
    cudaGetSymbolAddress(&tp, g_ql);    ql = (__nv_bfloat16*)tp;
    cudaGetSymbolAddress(&tp, g_kh);    kh = (__nv_bfloat16*)tp;
    cudaGetSymbolAddress(&tp, g_kl);    kl = (__nv_bfloat16*)tp;
    cudaGetSymbolAddress(&tp, g_vh);    vh = (__nv_bfloat16*)tp;
    cudaGetSymbolAddress(&tp, g_pjh);   pjh = (__nv_bfloat16*)tp;
    cudaGetSymbolAddress(&tp, g_pjl);   pjl = (__nv_bfloat16*)tp;
    cudaGetSymbolAddress(&tp, g_qph);   qph = (__nv_bfloat16*)tp;
    cudaGetSymbolAddress(&tp, g_eh);    eh = (__nv_bfloat16*)tp;
    cudaGetSymbolAddress(&tp, g_cbh);   cbh = (__nv_bfloat16*)tp;
    cudaGetSymbolAddress(&tp, g_cbl);   cbl = (__nv_bfloat16*)tp;

    static bool attr_done = false;
    if (!attr_done) {
        cudaFuncSetAttribute(mm_gemm<0, false, true>,  cudaFuncAttributeMaxDynamicSharedMemorySize, MM_SMEM);
        cudaFuncSetAttribute(mm_gemm<1, false, true>,  cudaFuncAttributeMaxDynamicSharedMemorySize, MM_SMEM);
        cudaFuncSetAttribute(mm_gemm<2, false, false>, cudaFuncAttributeMaxDynamicSharedMemorySize, MM_SMEM);
        cudaFuncSetAttribute(mm_gemm<2, true, false>,  cudaFuncAttributeMaxDynamicSharedMemorySize, MM_SMEM);
        cudaFuncSetAttribute(mm_gemm<3, false, true>,  cudaFuncAttributeMaxDynamicSharedMemorySize, MM_SMEM);
        cudaFuncSetAttribute(dash_mma<true>,  cudaFuncAttributeMaxDynamicSharedMemorySize, DASH_SMEM);
        cudaFuncSetAttribute(dash_mma<false>, cudaFuncAttributeMaxDynamicSharedMemorySize, DASH_SMEM);
        cudaFuncSetAttribute(ctx_mma,     cudaFuncAttributeMaxDynamicSharedMemorySize, CTX_SMEM);
        cudaFuncSetAttribute(attnout_mma, cudaFuncAttributeMaxDynamicSharedMemorySize, ATT_SMEM);
        attr_done = true;
    }

    // --- weight prep (batched over layers via gridDim.z) ---
    dim3 wb(32, 8);
    wsplit_kernel<<<dim3(8, 8, NL_), wb>>>(Wq, wth + OFF_QKV, wtl + OFF_QKV,
                                           256, 256, 0,   65536, (size_t)768 * 256);
    wsplit_kernel<<<dim3(8, 8, NL_), wb>>>(Wk, wth + OFF_QKV, wtl + OFF_QKV,
                                           256, 256, 256, 65536, (size_t)768 * 256);
    wsplit_kernel<<<dim3(8, 8, NL_), wb>>>(Wv, wth + OFF_QKV, wtl + OFF_QKV,
                                           256, 256, 512, 65536, (size_t)768 * 256);
    wsplit_kernel<<<dim3(8, 8, NL_), wb>>>(Wo, wth + OFF_WO, wtl + OFF_WO,
                                           256, 256, 0, 65536, 65536);
    wsplit_kernel<<<dim3(32, 8, NL_), wb>>>(W1, wth + OFF_W1, wtl + OFF_W1,
                                            256, 1024, 0, 262144, 262144);
    wsplit_kernel<<<dim3(8, 32, NL_), wb>>>(W2, wth + OFF_W2, wtl + OFF_W2,
                                            1024, 256, 0, 262144, 262144);
    wsplit_kernel<<<dim3(8, 8, 1), wb>>>(p1w, wth + OFF_P1, wtl + OFF_P1,
                                         256, 256, 0, 0, 0);
    bconcat_kernel<<<NL_, 256>>>(bq, bk, bv, bqkv);
    psplit_kernel<<<(NL_ * PMP_ * DH_) / 256, 256>>>(proj, pjh, pjl);

    embed_ln_kernel<<<BS_ / 8, 256>>>(emb, pos, ln_g, ln_b, x);

    for (int l = 0; l < NL_; l++) {
        // --- attention block ---
        ln_kernel<<<BS_ / 8, 256>>>(x, hh, hl, ln1g + l * D_, ln1b + l * D_);
        mm_gemm<0, false, true><<<dim3(6, 128), 256, MM_SMEM>>>(
            hh, hl, wth + OFF_QKV + (size_t)l * 768 * 256, wtl + OFF_QKV + (size_t)l * 768 * 256,
            bqkv + l * 768, nullptr, qh, ql, kh, kl, vh, 256, 768);

        layer_init_kernel<<<(BH_ * PMP_ * 72 + 255) / 256, 256>>>(ctxE, vsum, km);

        dash_mma<true><<<dim3(S_ / 64, BH_), 256, DASH_SMEM>>>(
            qh, ql, pjh + (size_t)l * PMP_ * DH_, pjl + (size_t)l * PMP_ * DH_,
            qph, nullptr);
        dash_mma<false><<<dim3(S_ / 64, BH_), 256, DASH_SMEM>>>(
            kh, kl, pjh + (size_t)l * PMP_ * DH_, pjl + (size_t)l * PMP_ * DH_,
            eh, km);

        vsum_kernel<<<dim3(BH_, 16), 64>>>(vh, vsum);
        ctx_mma<<<dim3(BH_, 16), 256, CTX_SMEM>>>(eh, vh, ctxE);
        ctxcorr_kernel<<<(BH_ * PMP_ * 80 + 255) / 256, 256>>>(ctxE, vsum, km, cbh, cbl);
        attnout_mma<<<dim3(S_ / 128, BH_), 256, ATT_SMEM>>>(qph, cbh, cbl, oh);

        mm_gemm<2, false, false><<<dim3(2, 128), 256, MM_SMEM>>>(
            oh, nullptr, wth + OFF_WO + (size_t)l * 65536, wtl + OFF_WO + (size_t)l * 65536,
            bo + l * 256, x, nullptr, nullptr, nullptr, nullptr, nullptr, 256, 256);

        // --- FFN block ---
        ln_kernel<<<BS_ / 8, 256>>>(x, hh, hl, ln2g + l * D_, ln2b + l * D_);
        mm_gemm<1, false, true><<<dim3(8, 128), 256, MM_SMEM>>>(
            hh, hl, wth + OFF_W1 + (size_t)l * 262144, wtl + OFF_W1 + (size_t)l * 262144,
            b1 + l * 1024, nullptr, fh, nullptr, nullptr, nullptr, nullptr, 256, 1024);
        if (l == NL_ - 1) {
            mm_gemm<2, true, false><<<dim3(2, 128), 256, MM_SMEM>>>(
                fh, nullptr, wth + OFF_W2 + (size_t)l * 262144, wtl + OFF_W2 + (size_t)l * 262144,
                b2 + l * 256, x, xh, xl, nullptr, nullptr, nullptr, 1024, 256);
        } else {
            mm_gemm<2, false, false><<<dim3(2, 128), 256, MM_SMEM>>>(
                fh, nullptr, wth + OFF_W2 + (size_t)l * 262144, wtl + OFF_W2 + (size_t)l * 262144,
                b2 + l * 256, x, nullptr, nullptr, nullptr, nullptr, nullptr, 1024, 256);
        }
    }

    // --- attention pooling ---
    mm_gemm<3, false, true><<<dim3(2, 128), 256, MM_SMEM>>>(
        xh, xl, wth + OFF_P1, wtl + OFF_P1, p1b, h,
        nullptr, nullptr, nullptr, nullptr, nullptr, 256, 256);
    score_kernel<<<BS_ / 8, 256>>>(h, p2w, p2b, mask, sc);
    ssum_kernel<<<B_, 256>>>(sc, ss);
    outzero_kernel<<<(B_ * D_ + 255) / 256, 256>>>(out);
    pool_kernel<<<dim3(B_, 64), 256>>>(x, sc, ss, out);
}

// round 14
// speedup vs baseline: 3.2817x; 1.0639x over previous
#include <cuda_runtime.h>
#include <cuda_bf16.h>
#include <cstdint>

// ---------------------------------------------------------------------------
// Problem constants
// ---------------------------------------------------------------------------
constexpr int B_  = 4;
constexpr int S_  = 4096;
constexpr int D_  = 256;
constexpr int DH_ = 64;
constexpr int NL_ = 4;
constexpr int PM_ = 266;          // nb_features
constexpr int PMP_ = 288;         // padded for mma
constexpr int FF_ = 1024;
constexpr int BS_ = B_ * S_;      // 16384 rows
constexpr int BH_ = B_ * 4;       // 16

constexpr float DN_    = 0.35355339059327373f;  // 64^-0.25
constexpr float HDN2_  = 0.0625f;               // 0.5 * dn^2
constexpr float RATIO_ = 0.06131392f;           // 266^-0.5
constexpr float KEPS_  = 1e-4f;
constexpr float LNEPS_ = 1e-12f;

// ---------------------------------------------------------------------------
// Scratch (static device globals)
// ---------------------------------------------------------------------------
__device__ float g_x  [BS_ * D_];
__device__ float g_h  [BS_ * D_];     // pooling tanh output (fp32)
__device__ float g_score[BS_];
__device__ float g_ssum [B_];
__device__ unsigned g_kmaxu;

// bf16 hi/lo operand buffers
constexpr size_t OFF_QKV = 0;
constexpr size_t OFF_WO  = OFF_QKV + (size_t)NL_ * 768 * 256;
constexpr size_t OFF_W1  = OFF_WO  + (size_t)NL_ * 256 * 256;
constexpr size_t OFF_W2  = OFF_W1  + (size_t)NL_ * 1024 * 256;
constexpr size_t OFF_P1  = OFF_W2  + (size_t)NL_ * 256 * 1024;
constexpr size_t WT_TOT  = OFF_P1 + 256 * 256;

__device__ __nv_bfloat16 g_wth[WT_TOT], g_wtl[WT_TOT];
__device__ float g_bqkv[NL_ * 768];
__device__ __nv_bfloat16 g_hh[BS_ * D_], g_hl[BS_ * D_];      // LN outputs (ln1 hi/lo; ln2 uses hh only)
__device__ __nv_bfloat16 g_oh[BS_ * D_];                      // attnout (single bf16)
__device__ __nv_bfloat16 g_fh[(size_t)BS_ * FF_];             // gelu (single bf16)
__device__ __nv_bfloat16 g_xh[BS_ * D_], g_xl[BS_ * D_];      // residual (pooling)
__device__ __nv_bfloat16 g_qh[BS_ * D_], g_ql[BS_ * D_];      // q hi/lo
__device__ __nv_bfloat16 g_kh[BS_ * D_], g_kl[BS_ * D_];      // k hi/lo
__device__ __nv_bfloat16 g_vh[BS_ * D_];                      // v (single bf16)
__device__ __nv_bfloat16 g_pjh[NL_ * PMP_ * DH_], g_pjl[NL_ * PMP_ * DH_];

// FAVOR intermediates (single bf16)
__device__ __nv_bfloat16 g_qph[(size_t)BH_ * S_ * PMP_];
__device__ __nv_bfloat16 g_eh [(size_t)BH_ * S_ * PMP_];
__device__ float g_ctxE[BH_ * PMP_ * 72];
__device__ __nv_bfloat16 g_cbh[BH_ * PMP_ * 80], g_cbl[BH_ * PMP_ * 80];

// ---------------------------------------------------------------------------
// PTX helpers (family-portable: no tcgen05 on compute_103 targets)
// ---------------------------------------------------------------------------
__device__ __forceinline__ uint32_t smem_u32(const void* p) {
    uint32_t a;
    asm("{ .reg .u64 t; cvta.to.shared.u64 t, %1; cvt.u32.u64 %0, t; }" : "=r"(a) : "l"(p));
    return a;
}
__device__ __forceinline__ void ldsm4(unsigned& r0, unsigned& r1, unsigned& r2, unsigned& r3,
                                      uint32_t addr) {
    asm volatile("ldmatrix.sync.aligned.m8n8.x4.shared.b16 {%0,%1,%2,%3}, [%4];"
                 : "=r"(r0), "=r"(r1), "=r"(r2), "=r"(r3) : "r"(addr));
}
__device__ __forceinline__ void ldsm4t(unsigned& r0, unsigned& r1, unsigned& r2, unsigned& r3,
                                       uint32_t addr) {
    asm volatile("ldmatrix.sync.aligned.m8n8.x4.trans.shared.b16 {%0,%1,%2,%3}, [%4];"
                 : "=r"(r0), "=r"(r1), "=r"(r2), "=r"(r3) : "r"(addr));
}
__device__ __forceinline__ void mma_bf16(float* d, const unsigned* a, const unsigned* b) {
    asm volatile("mma.sync.aligned.m16n8k16.row.col.f32.bf16.bf16.f32 "
                 "{%0,%1,%2,%3}, {%4,%5,%6,%7}, {%8,%9}, {%0,%1,%2,%3};"
                 : "+f"(d[0]), "+f"(d[1]), "+f"(d[2]), "+f"(d[3])
                 : "r"(a[0]), "r"(a[1]), "r"(a[2]), "r"(a[3]), "r"(b[0]), "r"(b[1]));
}
#define CP_ASYNC16(dst, src) \
    asm volatile("cp.async.cg.shared.global [%0], [%1], 16;" :: "r"(dst), "l"(src) : "memory")
#define CP_COMMIT() asm volatile("cp.async.commit_group;" ::: "memory")
#define CP_WAIT(n)  asm volatile("cp.async.wait_group %0;" :: "n"(n) : "memory")

__device__ __forceinline__ void bf16_split(float v, __nv_bfloat16& hi, __nv_bfloat16& lo) {
    hi = __float2bfloat16(v);
    lo = __float2bfloat16(v - __bfloat162float(hi));
}
__device__ __forceinline__ float tanh_ap(float x) {
    float r;
    asm("tanh.approx.f32 %0, %1;" : "=f"(r) : "f"(x));
    return r;
}

// ---------------------------------------------------------------------------
// Reductions
// ---------------------------------------------------------------------------
__device__ __forceinline__ float warpsum(float v) {
#pragma unroll
    for (int o = 16; o > 0; o >>= 1) v += __shfl_xor_sync(0xffffffffu, v, o);
    return v;
}
__device__ __forceinline__ float block_sum(float v, float* sh) {
    int lane = threadIdx.x & 31, w = threadIdx.x >> 5, nw = blockDim.x >> 5;
    v = warpsum(v);
    if (lane == 0) sh[w] = v;
    __syncthreads();
    if (w == 0) {
        float x = (lane < nw) ? sh[lane] : 0.f;
        x = warpsum(x);
        if (lane == 0) sh[0] = x;
    }
    __syncthreads();
    float r = sh[0];
    __syncthreads();
    return r;
}
__device__ __forceinline__ unsigned fmap(float f) {
    unsigned u = __float_as_uint(f);
    return (u & 0x80000000u) ? ~u : (u | 0x80000000u);
}
__device__ __forceinline__ float funmap(unsigned u) {
    u = (u & 0x80000000u) ? (u & 0x7FFFFFFFu) : ~u;
    return __uint_as_float(u);
}

// ---------------------------------------------------------------------------
// Weight transpose + bf16 split: W [K,N] fp32 -> Th/Tl [N,K] bf16; z = layer
// ---------------------------------------------------------------------------
__global__ void wsplit_kernel(const float* __restrict__ W, __nv_bfloat16* __restrict__ Th,
                              __nv_bfloat16* __restrict__ Tl, int K, int N, int rowOff,
                              size_t sstride, size_t dstride) {
    __shared__ float ts[32][33];
    int l = blockIdx.z;
    W  += (size_t)l * sstride;
    Th += (size_t)l * dstride;
    Tl += (size_t)l * dstride;
    int kb = blockIdx.y * 32, nb = blockIdx.x * 32;
    int tx = threadIdx.x, ty = threadIdx.y;
#pragma unroll
    for (int i = 0; i < 4; i++) {
        int k = kb + ty + i * 8;
        ts[ty + i * 8][tx] = W[(size_t)k * N + nb + tx];
    }
    __syncthreads();
#pragma unroll
    for (int i = 0; i < 4; i++) {
        int n = nb + ty + i * 8;
        int k = kb + tx;
        float v = ts[tx][ty + i * 8];
        __nv_bfloat16 hi, lo;
        bf16_split(v, hi, lo);
        size_t idx = (size_t)(rowOff + n) * K + k;
        Th[idx] = hi; Tl[idx] = lo;
    }
}

__global__ void bconcat_kernel(const float* __restrict__ bq, const float* __restrict__ bk,
                               const float* __restrict__ bv, float* __restrict__ dst) {
    int l = blockIdx.x, t = threadIdx.x;
    dst[l * 768 + t]       = bq[l * 256 + t];
    dst[l * 768 + 256 + t] = bk[l * 256 + t];
    dst[l * 768 + 512 + t] = bv[l * 256 + t];
}

__global__ void psplit_kernel(const float* __restrict__ proj,
                              __nv_bfloat16* __restrict__ ph, __nv_bfloat16* __restrict__ pl) {
    int idx = blockIdx.x * 256 + threadIdx.x;
    int l = idx / (PMP_ * DH_);
    int rem = idx - l * (PMP_ * DH_);
    int r = rem >> 6, c = rem & 63;
    float v = (r < PM_) ? proj[((size_t)l * PM_ + r) * DH_ + c] : 0.f;
    __nv_bfloat16 hi, lo;
    bf16_split(v, hi, lo);
    ph[idx] = hi; pl[idx] = lo;
}

// ---------------------------------------------------------------------------
// LayerNorm — warp-per-row
// ---------------------------------------------------------------------------
__global__ __launch_bounds__(256) void embed_ln_kernel(
    const float* __restrict__ emb, const float* __restrict__ pos,
    const float* __restrict__ g, const float* __restrict__ bb,
    float* __restrict__ out) {
    int warp = threadIdx.x >> 5, lane = threadIdx.x & 31;
    int row = blockIdx.x * 8 + warp;
    int c0 = lane * 8;
    const float* ep = emb + (size_t)row * D_ + c0;
    const float* pp = pos + (size_t)(row & (S_ - 1)) * D_ + c0;
    float v[8];
    float4 a0 = *(const float4*)ep, a1 = *(const float4*)(ep + 4);
    float4 p0 = *(const float4*)pp, p1 = *(const float4*)(pp + 4);
    v[0] = a0.x + p0.x; v[1] = a0.y + p0.y; v[2] = a0.z + p0.z; v[3] = a0.w + p0.w;
    v[4] = a1.x + p1.x; v[5] = a1.y + p1.y; v[6] = a1.z + p1.z; v[7] = a1.w + p1.w;
    float s = 0.f;
#pragma unroll
    for (int j = 0; j < 8; j++) s += v[j];
    float mu = warpsum(s) * (1.0f / D_);
    float s2 = 0.f;
#pragma unroll
    for (int j = 0; j < 8; j++) { float d = v[j] - mu; s2 = fmaf(d, d, s2); }
    float rs = rsqrtf(warpsum(s2) * (1.0f / D_) + LNEPS_);
    float4 g0 = *(const float4*)(g + c0), g1 = *(const float4*)(g + c0 + 4);
    float4 b0 = *(const float4*)(bb + c0), b1 = *(const float4*)(bb + c0 + 4);
    float gg[8] = {g0.x, g0.y, g0.z, g0.w, g1.x, g1.y, g1.z, g1.w};
    float bbv[8] = {b0.x, b0.y, b0.z, b0.w, b1.x, b1.y, b1.z, b1.w};
    float o[8];
#pragma unroll
    for (int j = 0; j < 8; j++) o[j] = (v[j] - mu) * rs * gg[j] + bbv[j];
    float* op = out + (size_t)row * D_ + c0;
    *(float4*)op       = make_float4(o[0], o[1], o[2], o[3]);
    *(float4*)(op + 4) = make_float4(o[4], o[5], o[6], o[7]);
}

template <bool LO>
__global__ __launch_bounds__(256) void ln_kernel(
    const float* __restrict__ in,
    __nv_bfloat16* __restrict__ oh, __nv_bfloat16* __restrict__ ol,
    const float* __restrict__ g, const float* __restrict__ bb) {
    int warp = threadIdx.x >> 5, lane = threadIdx.x & 31;
    int row = blockIdx.x * 8 + warp;
    int c0 = lane * 8;
    const float* rp = in + (size_t)row * D_ + c0;
    float4 a0 = *(const float4*)rp, a1 = *(const float4*)(rp + 4);
    float v[8] = {a0.x, a0.y, a0.z, a0.w, a1.x, a1.y, a1.z, a1.w};
    float s = 0.f;
#pragma unroll
    for (int j = 0; j < 8; j++) s += v[j];
    float mu = warpsum(s) * (1.0f / D_);
    float s2 = 0.f;
#pragma unroll
    for (int j = 0; j < 8; j++) { float d = v[j] - mu; s2 = fmaf(d, d, s2); }
    float rs = rsqrtf(warpsum(s2) * (1.0f / D_) + LNEPS_);
    float4 g0 = *(const float4*)(g + c0), g1 = *(const float4*)(g + c0 + 4);
    float4 b0 = *(const float4*)(bb + c0), b1 = *(const float4*)(bb + c0 + 4);
    float gg[8] = {g0.x, g0.y, g0.z, g0.w, g1.x, g1.y, g1.z, g1.w};
    float bbv[8] = {b0.x, b0.y, b0.z, b0.w, b1.x, b1.y, b1.z, b1.w};
    size_t base = (size_t)row * D_ + c0;
#pragma unroll
    for (int j2 = 0; j2 < 4; j2++) {
        float x0 = (v[2 * j2] - mu) * rs * gg[2 * j2] + bbv[2 * j2];
        float x1 = (v[2 * j2 + 1] - mu) * rs * gg[2 * j2 + 1] + bbv[2 * j2 + 1];
        if (LO) {
            __nv_bfloat16 h0, l0, h1, l1;
            bf16_split(x0, h0, l0);
            bf16_split(x1, h1, l1);
            *(__nv_bfloat162*)(oh + base + 2 * j2) = __nv_bfloat162(h0, h1);
            *(__nv_bfloat162*)(ol + base + 2 * j2) = __nv_bfloat162(l0, l1);
        } else {
            *(__nv_bfloat162*)(oh + base + 2 * j2) =
                __nv_bfloat162(__float2bfloat16(x0), __float2bfloat16(x1));
        }
    }
}

// ---------------------------------------------------------------------------
// mma.sync bf16 GEMM (dense): C = A @ Bt^T (+bias +epilogue)
// ALO: A has a lo array (3-term split); else single-bf16 A (2-term).
// MODE: 0 = QKV (q->Oh/Ol, k->Oh2/Ol2, v->Oh3 single);
//       1 = GELU->Oh (single); 2 = residual accumulate into O0 (+Oh/Ol if EMIT);
//       3 = tanh->O0
// ---------------------------------------------------------------------------
constexpr int ROWB    = 80;
constexpr int ARR_B   = 128 * ROWB;
constexpr int STAGE_B = 4 * ARR_B;
constexpr int MM_SMEM = 2 * STAGE_B;     // 81920

template <bool ALO>
__device__ __forceinline__ void stage_cp(uint32_t sbase,
    const __nv_bfloat16* __restrict__ Ah, const __nv_bfloat16* __restrict__ Al,
    const __nv_bfloat16* __restrict__ Bh, const __nv_bfloat16* __restrict__ Bl,
    int row0, int col0, int K, int k0, int tid) {
#pragma unroll
    for (int i = 0; i < 8; i++) {
        const int arr = i >> 1;
        if (!ALO && arr == 1) continue;
        int cc = tid + (i & 1) * 256;
        int row = cc >> 2, kc = cc & 3;
        const __nv_bfloat16* src;
        int gr;
        if (arr == 0)      { src = Ah; gr = row0 + row; }
        else if (arr == 1) { src = Al; gr = row0 + row; }
        else if (arr == 2) { src = Bh; gr = col0 + row; }
        else               { src = Bl; gr = col0 + row; }
        uint32_t dst = sbase + arr * ARR_B + row * ROWB + kc * 16;
        CP_ASYNC16(dst, src + (size_t)gr * K + k0 + kc * 8);
    }
}

template <int MODE, bool EMIT, bool ALO>
__global__ __launch_bounds__(256) void mm_gemm(
    const __nv_bfloat16* __restrict__ Ah, const __nv_bfloat16* __restrict__ Al,
    const __nv_bfloat16* __restrict__ Bth, const __nv_bfloat16* __restrict__ Btl,
    const float* __restrict__ bias,
    float* __restrict__ O0,
    __nv_bfloat16* __restrict__ Oh, __nv_bfloat16* __restrict__ Ol,
    __nv_bfloat16* __restrict__ Oh2, __nv_bfloat16* __restrict__ Ol2,
    __nv_bfloat16* __restrict__ Oh3,
    int K, int N) {
    extern __shared__ char smem[];
    uint32_t sb = smem_u32(smem);
    int tid = threadIdx.x, lane = tid & 31, warp = tid >> 5;
    int row0 = blockIdx.y * 128, col0 = blockIdx.x * 128;
    int wm = (warp >> 1) * 32, wn = (warp & 1) * 64;

    float acc[2][8][4] = {};

    int NT = K >> 5;
    stage_cp<ALO>(sb, Ah, Al, Bth, Btl, row0, col0, K, 0, tid);
    CP_COMMIT();
    if (NT > 1) {
        stage_cp<ALO>(sb + STAGE_B, Ah, Al, Bth, Btl, row0, col0, K, 32, tid);
        CP_COMMIT();
    }

    uint32_t aoff = (uint32_t)((wm + (lane & 15)) * ROWB + (lane >> 4) * 16);
    uint32_t boff = (uint32_t)((wn + ((lane >> 4) << 3) + (lane & 7)) * ROWB +
                               ((lane >> 3) & 1) * 16);

    for (int t = 0; t < NT; t++) {
        if (t + 1 < NT) CP_WAIT(1); else CP_WAIT(0);
        __syncthreads();
        uint32_t bs = sb + (t & 1) * STAGE_B;
#pragma unroll
        for (int kt = 0; kt < 2; kt++) {
            unsigned ah[2][4], al[2][4], bh[8][2], bl[8][2];
#pragma unroll
            for (int mt = 0; mt < 2; mt++) {
                uint32_t a = bs + aoff + mt * (16 * ROWB) + kt * 32;
                ldsm4(ah[mt][0], ah[mt][1], ah[mt][2], ah[mt][3], a);
                if (ALO) ldsm4(al[mt][0], al[mt][1], al[mt][2], al[mt][3], a + ARR_B);
            }
#pragma unroll
            for (int n2 = 0; n2 < 4; n2++) {
                uint32_t a = bs + 2 * ARR_B + boff + n2 * (16 * ROWB) + kt * 32;
                ldsm4(bh[2 * n2][0], bh[2 * n2][1], bh[2 * n2 + 1][0], bh[2 * n2 + 1][1], a);
                ldsm4(bl[2 * n2][0], bl[2 * n2][1], bl[2 * n2 + 1][0], bl[2 * n2 + 1][1],
                      a + ARR_B);
            }
#pragma unroll
            for (int mt = 0; mt < 2; mt++)
#pragma unroll
                for (int nt = 0; nt < 8; nt++) {
                    mma_bf16(acc[mt][nt], ah[mt], bh[nt]);
                    mma_bf16(acc[mt][nt], ah[mt], bl[nt]);
                    if (ALO) mma_bf16(acc[mt][nt], al[mt], bh[nt]);
                }
        }
        __syncthreads();
        if (t + 2 < NT) {
            stage_cp<ALO>(sb + (t & 1) * STAGE_B, Ah, Al, Bth, Btl, row0, col0, K,
                          (t + 2) * 32, tid);
            CP_COMMIT();
        }
    }

#pragma unroll
    for (int mt = 0; mt < 2; mt++)
#pragma unroll
        for (int nt = 0; nt < 8; nt++) {
            int rbase = row0 + wm + mt * 16 + (lane >> 2);
            int cg = col0 + wn + nt * 8 + (lane & 3) * 2;
            float b0 = __ldg(&bias[cg]), b1 = __ldg(&bias[cg + 1]);
#pragma unroll
            for (int half = 0; half < 2; half++) {
                int row = rbase + half * 8;
                float v0 = acc[mt][nt][half * 2]     + b0;
                float v1 = acc[mt][nt][half * 2 + 1] + b1;
                if (MODE == 0) {
                    int which = cg >> 8, cl = cg & 255;
                    size_t idx = (size_t)row * 256 + cl;
                    if (which == 2) {
                        *(__nv_bfloat162*)(Oh3 + idx) =
                            __nv_bfloat162(__float2bfloat16(v0), __float2bfloat16(v1));
                    } else {
                        __nv_bfloat16* H = which ? Oh2 : Oh;
                        __nv_bfloat16* L = which ? Ol2 : Ol;
                        __nv_bfloat16 hi, lo;
                        bf16_split(v0, hi, lo); H[idx] = hi;     L[idx] = lo;
                        bf16_split(v1, hi, lo); H[idx + 1] = hi; L[idx + 1] = lo;
                    }
                } else if (MODE == 1) {
                    float u0 = 0.7978845608028654f * (v0 + 0.044715f * v0 * v0 * v0);
                    float u1 = 0.7978845608028654f * (v1 + 0.044715f * v1 * v1 * v1);
                    float g0 = 0.5f * v0 * (1.f + tanh_ap(u0));
                    float g1 = 0.5f * v1 * (1.f + tanh_ap(u1));
                    size_t idx = (size_t)row * N + cg;
                    *(__nv_bfloat162*)(Oh + idx) =
                        __nv_bfloat162(__float2bfloat16(g0), __float2bfloat16(g1));
                } else if (MODE == 2) {
                    size_t idx = (size_t)row * N + cg;
                    float n0 = O0[idx] + v0, n1 = O0[idx + 1] + v1;
                    O0[idx] = n0; O0[idx + 1] = n1;
                    if (EMIT) {
                        __nv_bfloat16 hi, lo;
                        bf16_split(n0, hi, lo); Oh[idx] = hi;     Ol[idx] = lo;
                        bf16_split(n1, hi, lo); Oh[idx + 1] = hi; Ol[idx + 1] = lo;
                    }
                } else {
                    size_t idx = (size_t)row * N + cg;
                    O0[idx]     = tanh_ap(v0);
                    O0[idx + 1] = tanh_ap(v1);
                }
            }
        }
}

// ---------------------------------------------------------------------------
// dash via mma -> single bf16 output [bh][s][288]
// 64-row blocks (2 CTAs/SM); QPHI=true: fused q-phi; QPHI=false: E + global max,
// with E[s][PM_] = 1.0 (ones-row => ctx_mma produces vsum in ctxE row PM_).
// ---------------------------------------------------------------------------
constexpr int DRB = 144;
constexpr int DA_H = 0;
constexpr int DA_L = 64 * DRB;                  // 9216
constexpr int DB_H = 2 * 64 * DRB;              // 18432
constexpr int DB_L = DB_H + PMP_ * DRB;         // 59904
constexpr int D_SDIAG = DB_L + PMP_ * DRB;      // 101376
constexpr int D_SRMAX = D_SDIAG + 256;
constexpr int DASH_SMEM = D_SRMAX + 256;        // 101888

template <bool QPHI>
__global__ __launch_bounds__(256, 2) void dash_mma(
    const __nv_bfloat16* __restrict__ Xh, const __nv_bfloat16* __restrict__ Xl,
    const __nv_bfloat16* __restrict__ Ph, const __nv_bfloat16* __restrict__ Pl,
    __nv_bfloat16* __restrict__ outh,
    unsigned* __restrict__ gmax) {
    extern __shared__ char smem[];
    uint32_t sb = smem_u32(smem);
    float* sdiag = (float*)(smem + D_SDIAG);
    unsigned* srmax = (unsigned*)(smem + D_SRMAX);
    int tid = threadIdx.x, lane = tid & 31, warp = tid >> 5;
    int bh = blockIdx.y, b = bh >> 2, h = bh & 3;
    int s0 = blockIdx.x * 64;

    for (int i = tid; i < 512; i += 256) {
        int r = i >> 3, c = i & 7;
        const __nv_bfloat16* s1 = Xh + ((size_t)(b * S_ + s0 + r)) * D_ + h * DH_ + c * 8;
        const __nv_bfloat16* s2 = Xl + ((size_t)(b * S_ + s0 + r)) * D_ + h * DH_ + c * 8;
        CP_ASYNC16(sb + DA_H + r * DRB + c * 16, s1);
        CP_ASYNC16(sb + DA_L + r * DRB + c * 16, s2);
    }
    for (int i = tid; i < PMP_ * 8; i += 256) {
        int r = i >> 3, c = i & 7;
        CP_ASYNC16(sb + DB_H + r * DRB + c * 16, Ph + (size_t)r * DH_ + c * 8);
        CP_ASYNC16(sb + DB_L + r * DRB + c * 16, Pl + (size_t)r * DH_ + c * 8);
    }
    CP_COMMIT(); CP_WAIT(0);
    __syncthreads();

    if (tid < 64) {
        const __nv_bfloat16* ah = (const __nv_bfloat16*)(smem + DA_H + tid * DRB);
        const __nv_bfloat16* al = (const __nv_bfloat16*)(smem + DA_L + tid * DRB);
        float s = 0.f;
#pragma unroll
        for (int c = 0; c < DH_; c++) {
            float v = __bfloat162float(ah[c]) + __bfloat162float(al[c]);
            s = fmaf(v, v, s);
        }
        sdiag[tid] = HDN2_ * s;
        srmax[tid] = 0u;
    }
    __syncthreads();

    int wm = (warp >> 1) * 16, wn = (warp & 1) * 144;
    float acc[18][4] = {};
    uint32_t aoff = (uint32_t)((wm + (lane & 15)) * DRB + (lane >> 4) * 16);
    uint32_t boff = (uint32_t)((wn + ((lane >> 4) << 3) + (lane & 7)) * DRB +
                               ((lane >> 3) & 1) * 16);

#pragma unroll
    for (int kt = 0; kt < 4; kt++) {
        unsigned ah[4], al[4];
        {
            uint32_t a = sb + DA_H + aoff + kt * 32;
            ldsm4(ah[0], ah[1], ah[2], ah[3], a);
            ldsm4(al[0], al[1], al[2], al[3], a + (DA_L - DA_H));
        }
#pragma unroll
        for (int n2 = 0; n2 < 9; n2++) {
            unsigned bhf[2][2], blf[2][2];
            uint32_t a = sb + DB_H + boff + n2 * (16 * DRB) + kt * 32;
            ldsm4(bhf[0][0], bhf[0][1], bhf[1][0], bhf[1][1], a);
            ldsm4(blf[0][0], blf[0][1], blf[1][0], blf[1][1], a + (DB_L - DB_H));
#pragma unroll
            for (int j = 0; j < 2; j++) {
                int nt = n2 * 2 + j;
                mma_bf16(acc[nt], ah, bhf[j]);
                mma_bf16(acc[nt], ah, blf[j]);
                mma_bf16(acc[nt], al, bhf[j]);
            }
        }
    }

    // per-row max of raw dash (valid cols only)
#pragma unroll
    for (int half = 0; half < 2; half++) {
        float p = -3.4e38f;
#pragma unroll
        for (int nt = 0; nt < 18; nt++)
#pragma unroll
            for (int e = 0; e < 2; e++) {
                int col = wn + nt * 8 + (lane & 3) * 2 + e;
                if (col < PM_) p = fmaxf(p, DN_ * acc[nt][half * 2 + e]);
            }
        p = fmaxf(p, __shfl_xor_sync(0xffffffffu, p, 1));
        p = fmaxf(p, __shfl_xor_sync(0xffffffffu, p, 2));
        if ((lane & 3) == 0)
            atomicMax(&srmax[wm + (lane >> 2) + half * 8], fmap(p));
    }
    __syncthreads();

    if (!QPHI && tid == 0) {
        unsigned m = 0u;
#pragma unroll 4
        for (int i = 0; i < 64; i++) m = max(m, srmax[i]);
        atomicMax(gmax, m);
    }

#pragma unroll
    for (int half = 0; half < 2; half++) {
        int r = wm + (lane >> 2) + half * 8;
        size_t rowbase = ((size_t)bh * S_ + s0 + r) * PMP_;
        float sub = QPHI ? (sdiag[r] + funmap(srmax[r])) : sdiag[r];
#pragma unroll
        for (int nt = 0; nt < 18; nt++) {
            int colb = wn + nt * 8 + (lane & 3) * 2;
            float o[2];
#pragma unroll
            for (int e = 0; e < 2; e++) {
                int col = colb + e;
                float val = 0.f;
                if (col < PM_) {
                    float dv = DN_ * acc[nt][half * 2 + e];
                    val = QPHI ? RATIO_ * (__expf(dv - sub) + KEPS_)
                               : __expf(dv - sub);
                } else if (!QPHI && col == PM_) {
                    val = 1.0f;   // ones-row: ctxE[PM_][e] = vsum[e]
                }
                o[e] = val;
            }
            *(__nv_bfloat162*)(outh + rowbase + colb) =
                __nv_bfloat162(__float2bfloat16(o[0]), __float2bfloat16(o[1]));
        }
    }
}

// ---------------------------------------------------------------------------
// ctx via mma: ctxE[bh][m][e] = sum_s E[s][m] * Vx[s][e], Vx col 64 = 1 (ksum);
// E row PM_ = 1 (vsum). E single bf16, V single bf16 (1-term); split-K x16
// ---------------------------------------------------------------------------
constexpr int CE_ST = 592;
constexpr int CV_ST = 160;
constexpr int C_EH = 0;
constexpr int C_VH = 32 * CE_ST;              // 18944
constexpr int CSTAGE = C_VH + 32 * CV_ST;     // 24064
constexpr int CTX_SMEM = 2 * CSTAGE;          // 48128

__global__ __launch_bounds__(256) void ctx_mma(
    const __nv_bfloat16* __restrict__ Eh,
    const __nv_bfloat16* __restrict__ Vh,
    float* __restrict__ ctxE) {
    extern __shared__ char smem[];
    uint32_t sb = smem_u32(smem);
    int tid = threadIdx.x, lane = tid & 31, warp = tid >> 5;
    int bh = blockIdx.x, b = bh >> 2, h = bh & 3;
    int sbase = blockIdx.y * 256;

    auto stage = [&](int buf, int chunk) {
        uint32_t base = sb + buf * CSTAGE;
        int s0 = sbase + chunk * 32;
        for (int i = tid; i < 1152; i += 256) {
            int r = i / 36, c = i - r * 36;
            size_t g = ((size_t)bh * S_ + s0 + r) * PMP_ + c * 8;
            CP_ASYNC16(base + C_EH + r * CE_ST + c * 16, Eh + g);
        }
        {
            int i = tid;
            if (i < 256) {
                int r = i >> 3, c = i & 7;
                size_t g = ((size_t)(b * S_ + s0 + r)) * D_ + h * DH_ + c * 8;
                CP_ASYNC16(base + C_VH + r * CV_ST + c * 16, Vh + g);
            }
        }
        if (tid < 64) {
            int r = tid >> 1, half2 = tid & 1;
            uint4 z = make_uint4(0, 0, 0, 0);
            uint4 one = make_uint4(0x00003F80u, 0, 0, 0);
            uint32_t off = (uint32_t)(r * CV_ST + 128 + half2 * 16);
            *(uint4*)(smem + buf * CSTAGE + C_VH + off) = (half2 == 0) ? one : z;
        }
    };

    stage(0, 0); CP_COMMIT();
    stage(1, 1); CP_COMMIT();

    int mts[3];
    mts[0] = warp * 2; mts[1] = warp * 2 + 1; mts[2] = (warp < 2) ? 16 + warp : -1;
    float acc[3][9][4] = {};

    for (int t = 0; t < 8; t++) {
        if (t + 1 < 8) CP_WAIT(1); else CP_WAIT(0);
        __syncthreads();
        uint32_t bs = sb + (t & 1) * CSTAGE;
#pragma unroll
        for (int kt = 0; kt < 2; kt++) {
            int krA = (lane & 7) + ((lane >> 4) & 1) * 8 + kt * 16;
            int mcolbit = ((lane >> 3) & 1) * 8;
            unsigned ah[3][4];
#pragma unroll
            for (int mt = 0; mt < 3; mt++) {
                if (mts[mt] < 0) break;
                uint32_t a = bs + C_EH + krA * CE_ST + (mts[mt] * 16 + mcolbit) * 2;
                ldsm4t(ah[mt][0], ah[mt][1], ah[mt][2], ah[mt][3], a);
            }
            int krB = (lane & 7) + ((lane >> 3) & 1) * 8 + kt * 16;
            int ncolbit = (lane >> 4) * 8;
#pragma unroll
            for (int p = 0; p < 5; p++) {
                unsigned bhf[4];
                uint32_t a = bs + C_VH + krB * CV_ST + (p * 16 + ncolbit) * 2;
                ldsm4t(bhf[0], bhf[1], bhf[2], bhf[3], a);
#pragma unroll
                for (int j = 0; j < 2; j++) {
                    int nt = p * 2 + j;
                    if (nt > 8) break;
#pragma unroll
                    for (int mt = 0; mt < 3; mt++) {
                        if (mts[mt] < 0) break;
                        mma_bf16(acc[mt][nt], ah[mt], bhf + j * 2);
                    }
                }
            }
        }
        __syncthreads();
        if (t + 2 < 8) { stage(t & 1, t + 2); CP_COMMIT(); }
    }

#pragma unroll
    for (int mt = 0; mt < 3; mt++) {
        if (mts[mt] < 0) break;
#pragma unroll
        for (int nt = 0; nt < 9; nt++)
#pragma unroll
            for (int half = 0; half < 2; half++) {
                int m = mts[mt] * 16 + (lane >> 2) + half * 8;
                int e = nt * 8 + (lane & 3) * 2;
                float* dst = ctxE + ((size_t)bh * PMP_ + m) * 72 + e;
                atomicAdd(dst,     acc[mt][nt][half * 2]);
                atomicAdd(dst + 1, acc[mt][nt][half * 2 + 1]);
            }
    }
}

// ctx_b = a*ctxE + correction; bf16 hi/lo [bh][288][80]; vsum = ctxE row PM_
__global__ void ctxcorr_kernel(const float* __restrict__ ctxE,
                               const unsigned* __restrict__ gmax,
                               __nv_bfloat16* __restrict__ cbh, __nv_bfloat16* __restrict__ cbl) {
    int idx = blockIdx.x * 256 + threadIdx.x;
    if (idx >= BH_ * PMP_ * 80) return;
    int bh = idx / (PMP_ * 80);
    int rem = idx - bh * (PMP_ * 80);
    int m = rem / 80, e = rem - m * 80;
    float a = RATIO_ * __expf(-funmap(*gmax));
    float c = RATIO_ * KEPS_;
    float val = 0.f;
    if (m < PM_ && e < 72) {
        float base = ctxE[((size_t)bh * PMP_ + m) * 72 + e];
        float corr;
        if (e < 64)       corr = c * ctxE[((size_t)bh * PMP_ + PM_) * 72 + e];  // vsum
        else if (e == 64) corr = c * (float)S_;
        else              corr = 0.f;
        val = a * base + corr;
    }
    __nv_bfloat16 hi, lo;
    bf16_split(val, hi, lo);
    cbh[idx] = hi; cbl[idx] = lo;
}

// ---------------------------------------------------------------------------
// attnout via mma: O[s][e] = (qp[s]·ctx_b[:,e]) / (qp[s]·ksum)  -> oh (single)
// ---------------------------------------------------------------------------
constexpr int AQ_ST = 80;
constexpr int AB_ST = 160;
constexpr int A_QH = 0;
constexpr int A_BH2 = 128 * AQ_ST;            // 10240
constexpr int A_BL2 = A_BH2 + 32 * AB_ST;     // 15360
constexpr int ASTAGE = A_BL2 + 32 * AB_ST;    // 20480
constexpr int A_SDEN = 2 * ASTAGE;            // 40960
constexpr int ATT_SMEM = A_SDEN + 512;        // 41472

__global__ __launch_bounds__(256) void attnout_mma(
    const __nv_bfloat16* __restrict__ Qh,
    const __nv_bfloat16* __restrict__ Cbh, const __nv_bfloat16* __restrict__ Cbl,
    __nv_bfloat16* __restrict__ oh) {
    extern __shared__ char smem[];
    uint32_t sb = smem_u32(smem);
    float* sden = (float*)(smem + A_SDEN);
    int tid = threadIdx.x, lane = tid & 31, warp = tid >> 5;
    int bh = blockIdx.y, b = bh >> 2, h = bh & 3;
    int s0 = blockIdx.x * 128;

    auto stage = [&](int buf, int chunk) {
        uint32_t base = sb + buf * ASTAGE;
        int k0 = chunk * 32;
        for (int i = tid; i < 512; i += 256) {
            int r = i >> 2, c = i & 3;
            size_t g = ((size_t)bh * S_ + s0 + r) * PMP_ + k0 + c * 8;
            CP_ASYNC16(base + A_QH + r * AQ_ST + c * 16, Qh + g);
        }
        for (int i = tid; i < 320; i += 256) {
            int r = i / 10, c = i - r * 10;
            size_t g = ((size_t)bh * PMP_ + k0 + r) * 80 + c * 8;
            CP_ASYNC16(base + A_BH2 + r * AB_ST + c * 16, Cbh + g);
            CP_ASYNC16(base + A_BL2 + r * AB_ST + c * 16, Cbl + g);
        }
    };

    stage(0, 0); CP_COMMIT();
    stage(1, 1); CP_COMMIT();

    int wm = (warp >> 1) * 32, ng = warp & 1;
    float acc[2][5][4] = {};
    uint32_t aoff = (uint32_t)((wm + (lane & 15)) * AQ_ST + (lane >> 4) * 16);

    for (int t = 0; t < 9; t++) {
        if (t + 1 < 9) CP_WAIT(1); else CP_WAIT(0);
        __syncthreads();
        uint32_t bs = sb + (t & 1) * ASTAGE;
#pragma unroll
        for (int kt = 0; kt < 2; kt++) {
            unsigned ah[2][4];
#pragma unroll
            for (int mt = 0; mt < 2; mt++) {
                uint32_t a = bs + A_QH + aoff + mt * (16 * AQ_ST) + kt * 32;
                ldsm4(ah[mt][0], ah[mt][1], ah[mt][2], ah[mt][3], a);
            }
            int krB = (lane & 7) + ((lane >> 3) & 1) * 8 + kt * 16;
            int ncolbit = (lane >> 4) * 8;
#pragma unroll
            for (int pi = 0; pi < 3; pi++) {
                if (!ng && pi == 2) break;
                int p = ng ? (2 + pi) : pi;
                unsigned bhf[4], blf[4];
                uint32_t a = bs + A_BH2 + krB * AB_ST + (p * 16 + ncolbit) * 2;
                ldsm4t(bhf[0], bhf[1], bhf[2], bhf[3], a);
                ldsm4t(blf[0], blf[1], blf[2], blf[3], a + (A_BL2 - A_BH2));
#pragma unroll
                for (int j = 0; j < 2; j++) {
                    int ntg = p * 2 + j;
                    if (ntg > 8) break;
                    int ntl = ntg - ng * 4;
#pragma unroll
                    for (int mt = 0; mt < 2; mt++) {
                        mma_bf16(acc[mt][ntl], ah[mt], bhf + j * 2);
                        mma_bf16(acc[mt][ntl], ah[mt], blf + j * 2);
                    }
                }
            }
        }
        __syncthreads();
        if (t + 2 < 9) { stage(t & 1, t + 2); CP_COMMIT(); }
    }

    if (ng == 1 && (lane & 3) == 0) {
#pragma unroll
        for (int mt = 0; mt < 2; mt++)
#pragma unroll
            for (int half = 0; half < 2; half++) {
                int r = wm + mt * 16 + (lane >> 2) + half * 8;
                sden[r] = acc[mt][4][half * 2];
            }
    }
    __syncthreads();

#pragma unroll
    for (int mt = 0; mt < 2; mt++)
#pragma unroll
        for (int half = 0; half < 2; half++) {
            int r = wm + mt * 16 + (lane >> 2) + half * 8;
            float rinv = 1.f / sden[r];
            size_t obase = ((size_t)(b * S_ + s0 + r)) * D_ + h * DH_;
#pragma unroll
            for (int ntl = 0; ntl < 4; ntl++) {
                int e = (ng * 4 + ntl) * 8 + (lane & 3) * 2;
                float v0 = acc[mt][ntl][half * 2]     * rinv;
                float v1 = acc[mt][ntl][half * 2 + 1] * rinv;
                *(__nv_bfloat162*)(oh + obase + e) =
                    __nv_bfloat162(__float2bfloat16(v0), __float2bfloat16(v1));
            }
        }
}

// ---------------------------------------------------------------------------
// Per-layer init
// ---------------------------------------------------------------------------
__global__ void layer_init_kernel(float* __restrict__ ctxE, unsigned* __restrict__ km) {
    int i = blockIdx.x * 256 + threadIdx.x;
    if (i < BH_ * PMP_ * 72) ctxE[i] = 0.f;
    if (i == 0) *km = 0u;
}

// ---------------------------------------------------------------------------
// Pooling
// ---------------------------------------------------------------------------
__global__ __launch_bounds__(256) void score_kernel(
    const float* __restrict__ h, const float* __restrict__ p2w,
    const float* __restrict__ p2b, const float* __restrict__ mask,
    float* __restrict__ score) {
    int warp = threadIdx.x >> 5, lane = threadIdx.x & 31;
    int row = blockIdx.x * 8 + warp;
    int c0 = lane * 8;
    const float* rp = h + (size_t)row * D_ + c0;
    float4 a0 = *(const float4*)rp, a1 = *(const float4*)(rp + 4);
    float4 w0 = *(const float4*)(p2w + c0), w1 = *(const float4*)(p2w + c0 + 4);
    float s = a0.x * w0.x + a0.y * w0.y + a0.z * w0.z + a0.w * w0.w +
              a1.x * w1.x + a1.y * w1.y + a1.z * w1.z + a1.w * w1.w;
    s = warpsum(s);
    if (lane == 0) score[row] = expf(s + p2b[0]) * mask[row];
}

__global__ void ssum_kernel(const float* __restrict__ score, float* __restrict__ ssum) {
    __shared__ float sh[8];
    int b = blockIdx.x;
    float s = 0.f;
    for (int i = threadIdx.x; i < S_; i += 256) s += score[b * S_ + i];
    s = block_sum(s, sh);
    if (threadIdx.x == 0) ssum[b] = s;
}

__global__ void outzero_kernel(float* __restrict__ out) {
    int i = blockIdx.x * blockDim.x + threadIdx.x;
    if (i < B_ * D_) out[i] = 0.f;
}

__global__ void pool_kernel(const float* __restrict__ x, const float* __restrict__ score,
                            const float* __restrict__ ssum, float* __restrict__ out) {
    int b = blockIdx.x, chunk = blockIdx.y, d = threadIdx.x;
    float inv = 1.f / (ssum[b] + 1e-8f);
    float acc = 0.f;
    int s0 = chunk * (S_ / 64);
    for (int s = s0; s < s0 + S_ / 64; s++)
        acc = fmaf(x[((size_t)(b * S_ + s)) * D_ + d], score[b * S_ + s], acc);
    atomicAdd(&out[b * D_ + d], acc * inv);
}

// ---------------------------------------------------------------------------
// Host launcher
// ---------------------------------------------------------------------------
extern "C" void kernel_launch(void* const* d_in, const int* in_sizes, int n_in,
                              void* d_out, int out_size) {
    const float* emb  = (const float*)d_in[0];
    const float* mask = (const float*)d_in[1];
    const float* pos  = (const float*)d_in[2];
    const float* ln_g = (const float*)d_in[3];
    const float* ln_b = (const float*)d_in[4];
    const float* proj = (const float*)d_in[5];
    const float* Wq = (const float*)d_in[6];   const float* bq = (const float*)d_in[7];
    const float* Wk = (const float*)d_in[8];   const float* bk = (const float*)d_in[9];
    const float* Wv = (const float*)d_in[10];  const float* bv = (const float*)d_in[11];
    const float* Wo = (const float*)d_in[12];  const float* bo = (const float*)d_in[13];
    const float* ln1g = (const float*)d_in[14]; const float* ln1b = (const float*)d_in[15];
    const float* W1 = (const float*)d_in[16];  const float* b1 = (const float*)d_in[17];
    const float* W2 = (const float*)d_in[18];  const float* b2 = (const float*)d_in[19];
    const float* ln2g = (const float*)d_in[20]; const float* ln2b = (const float*)d_in[21];
    const float* p1w = (const float*)d_in[22]; const float* p1b = (const float*)d_in[23];
    const float* p2w = (const float*)d_in[24]; const float* p2b = (const float*)d_in[25];
    float* out = (float*)d_out;

    void* tp;
    float *x, *h, *sc, *ss, *bqkv, *ctxE;
    unsigned* km;
    __nv_bfloat16 *wth, *wtl, *hh, *hl, *oh, *fh, *xh, *xl;
    __nv_bfloat16 *qh, *ql, *kh, *kl, *vh, *pjh, *pjl;
    __nv_bfloat16 *qph, *eh, *cbh, *cbl;
    cudaGetSymbolAddress(&tp, g_x);     x  = (float*)tp;
    cudaGetSymbolAddress(&tp, g_h);     h  = (float*)tp;
    cudaGetSymbolAddress(&tp, g_score); sc = (float*)tp;
    cudaGetSymbolAddress(&tp, g_ssum);  ss = (float*)tp;
    cudaGetSymbolAddress(&tp, g_kmaxu); km = (unsigned*)tp;
    cudaGetSymbolAddress(&tp, g_bqkv);  bqkv = (float*)tp;
    cudaGetSymbolAddress(&tp, g_ctxE);  ctxE = (float*)tp;
    cudaGetSymbolAddress(&tp, g_wth);   wth = (__nv_bfloat16*)tp;
    cudaGetSymbolAddress(&tp, g_wtl);   wtl = (__nv_bfloat16*)tp;
    cudaGetSymbolAddress(&tp, g_hh);    hh = (__nv_bfloat16*)tp;
    cudaGetSymbolAddress(&tp, g_hl);    hl = (__nv_bfloat16*)tp;
    cudaGetSymbolAddress(&tp, g_oh);    oh = (__nv_bfloat16*)tp;
    cudaGetSymbolAddress(&tp, g_fh);    fh = (__nv_bfloat16*)tp;
    cudaGetSymbolAddress(&tp, g_xh);    xh = (__nv_bfloat16*)tp;
    cudaGetSymbolAddress(&tp, g_xl);    xl = (__nv_bfloat16*)tp;
    cudaGetSymbolAddress(&tp, g_qh);    qh = (__nv_bfloat16*)tp;
    cudaGetSymbolAddress(&tp, g_ql);    ql = (__nv_bfloat16*)tp;
    cudaGetSymbolAddress(&tp, g_kh);    kh = (__nv_bfloat16*)tp;
    cudaGetSymbolAddress(&tp, g_kl);    kl = (__nv_bfloat16*)tp;
    cudaGetSymbolAddress(&tp, g_vh);    vh = (__nv_bfloat16*)tp;
    cudaGetSymbolAddress(&tp, g_pjh);   pjh = (__nv_bfloat16*)tp;
    cudaGetSymbolAddress(&tp, g_pjl);   pjl = (__nv_bfloat16*)tp;
    cudaGetSymbolAddress(&tp, g_qph);   qph = (__nv_bfloat16*)tp;
    cudaGetSymbolAddress(&tp, g_eh);    eh = (__nv_bfloat16*)tp;
    cudaGetSymbolAddress(&tp, g_cbh);   cbh = (__nv_bfloat16*)tp;
    cudaGetSymbolAddress(&tp, g_cbl);   cbl = (__nv_bfloat16*)tp;

    static bool attr_done = false;
    if (!attr_done) {
        cudaFuncSetAttribute(mm_gemm<0, false, true>,  cudaFuncAttributeMaxDynamicSharedMemorySize, MM_SMEM);
        cudaFuncSetAttribute(mm_gemm<1, false, false>, cudaFuncAttributeMaxDynamicSharedMemorySize, MM_SMEM);
        cudaFuncSetAttribute(mm_gemm<2, false, false>, cudaFuncAttributeMaxDynamicSharedMemorySize, MM_SMEM);
        cudaFuncSetAttribute(mm_gemm<2, true, false>,  cudaFuncAttributeMaxDynamicSharedMemorySize, MM_SMEM);
        cudaFuncSetAttribute(mm_gemm<3, false, true>,  cudaFuncAttributeMaxDynamicSharedMemorySize, MM_SMEM);
        cudaFuncSetAttribute(dash_mma<true>,  cudaFuncAttributeMaxDynamicSharedMemorySize, DASH_SMEM);
        cudaFuncSetAttribute(dash_mma<false>, cudaFuncAttributeMaxDynamicSharedMemorySize, DASH_SMEM);
        cudaFuncSetAttribute(ctx_mma,     cudaFuncAttributeMaxDynamicSharedMemorySize, CTX_SMEM);
        cudaFuncSetAttribute(attnout_mma, cudaFuncAttributeMaxDynamicSharedMemorySize, ATT_SMEM);
        attr_done = true;
    }

    // --- weight prep (batched over layers via gridDim.z) ---
    dim3 wb(32, 8);
    wsplit_kernel<<<dim3(8, 8, NL_), wb>>>(Wq, wth + OFF_QKV, wtl + OFF_QKV,
                                           256, 256, 0,   65536, (size_t)768 * 256);
    wsplit_kernel<<<dim3(8, 8, NL_), wb>>>(Wk, wth + OFF_QKV, wtl + OFF_QKV,
                                           256, 256, 256, 65536, (size_t)768 * 256);
    wsplit_kernel<<<dim3(8, 8, NL_), wb>>>(Wv, wth + OFF_QKV, wtl + OFF_QKV,
                                           256, 256, 512, 65536, (size_t)768 * 256);
    wsplit_kernel<<<dim3(8, 8, NL_), wb>>>(Wo, wth + OFF_WO, wtl + OFF_WO,
                                           256, 256, 0, 65536, 65536);
    wsplit_kernel<<<dim3(32, 8, NL_), wb>>>(W1, wth + OFF_W1, wtl + OFF_W1,
                                            256, 1024, 0, 262144, 262144);
    wsplit_kernel<<<dim3(8, 32, NL_), wb>>>(W2, wth + OFF_W2, wtl + OFF_W2,
                                            1024, 256, 0, 262144, 262144);
    wsplit_kernel<<<dim3(8, 8, 1), wb>>>(p1w, wth + OFF_P1, wtl + OFF_P1,
                                         256, 256, 0, 0, 0);
    bconcat_kernel<<<NL_, 256>>>(bq, bk, bv, bqkv);
    psplit_kernel<<<(NL_ * PMP_ * DH_) / 256, 256>>>(proj, pjh, pjl);

    embed_ln_kernel<<<BS_ / 8, 256>>>(emb, pos, ln_g, ln_b, x);

    for (int l = 0; l < NL_; l++) {
        // --- attention block ---
        ln_kernel<true><<<BS_ / 8, 256>>>(x, hh, hl, ln1g + l * D_, ln1b + l * D_);
        mm_gemm<0, false, true><<<dim3(6, 128), 256, MM_SMEM>>>(
            hh, hl, wth + OFF_QKV + (size_t)l * 768 * 256, wtl + OFF_QKV + (size_t)l * 768 * 256,
            bqkv + l * 768, nullptr, qh, ql, kh, kl, vh, 256, 768);

        layer_init_kernel<<<(BH_ * PMP_ * 72 + 255) / 256, 256>>>(ctxE, km);

        dash_mma<true><<<dim3(S_ / 64, BH_), 256, DASH_SMEM>>>(
            qh, ql, pjh + (size_t)l * PMP_ * DH_, pjl + (size_t)l * PMP_ * DH_,
            qph, nullptr);
        dash_mma<false><<<dim3(S_ / 64, BH_), 256, DASH_SMEM>>>(
            kh, kl, pjh + (size_t)l * PMP_ * DH_, pjl + (size_t)l * PMP_ * DH_,
            eh, km);

        ctx_mma<<<dim3(BH_, 16), 256, CTX_SMEM>>>(eh, vh, ctxE);
        ctxcorr_kernel<<<(BH_ * PMP_ * 80 + 255) / 256, 256>>>(ctxE, km, cbh, cbl);
        attnout_mma<<<dim3(S_ / 128, BH_), 256, ATT_SMEM>>>(qph, cbh, cbl, oh);

        mm_gemm<2, false, false><<<dim3(2, 128), 256, MM_SMEM>>>(
            oh, nullptr, wth + OFF_WO + (size_t)l * 65536, wtl + OFF_WO + (size_t)l * 65536,
            bo + l * 256, x, nullptr, nullptr, nullptr, nullptr, nullptr, 256, 256);

        // --- FFN block ---
        ln_kernel<false><<<BS_ / 8, 256>>>(x, hh, nullptr, ln2g + l * D_, ln2b + l * D_);
        mm_gemm<1, false, false><<<dim3(8, 128), 256, MM_SMEM>>>(
            hh, nullptr, wth + OFF_W1 + (size_t)l * 262144, wtl + OFF_W1 + (size_t)l * 262144,
            b1 + l * 1024, nullptr, fh, nullptr, nullptr, nullptr, nullptr, 256, 1024);
        if (l == NL_ - 1) {
            mm_gemm<2, true, false><<<dim3(2, 128), 256, MM_SMEM>>>(
                fh, nullptr, wth + OFF_W2 + (size_t)l * 262144, wtl + OFF_W2 + (size_t)l * 262144,
                b2 + l * 256, x, xh, xl, nullptr, nullptr, nullptr, 1024, 256);
        } else {
            mm_gemm<2, false, false><<<dim3(2, 128), 256, MM_SMEM>>>(
                fh, nullptr, wth + OFF_W2 + (size_t)l * 262144, wtl + OFF_W2 + (size_t)l * 262144,
                b2 + l * 256, x, nullptr, nullptr, nullptr, nullptr, nullptr, 1024, 256);
        }
    }

    // --- attention pooling ---
    mm_gemm<3, false, true><<<dim3(2, 128), 256, MM_SMEM>>>(
        xh, xl, wth + OFF_P1, wtl + OFF_P1, p1b, h,
        nullptr, nullptr, nullptr, nullptr, nullptr, 256, 256);
    score_kernel<<<BS_ / 8, 256>>>(h, p2w, p2b, mask, sc);
    ssum_kernel<<<B_, 256>>>(sc, ss);
    outzero_kernel<<<(B_ * D_ + 255) / 256, 256>>>(out);
    pool_kernel<<<dim3(B_, 64), 256>>>(x, sc, ss, out);
}

// round 15
// speedup vs baseline: 3.3570x; 1.0230x over previous
#include <cuda_runtime.h>
#include <cuda_bf16.h>
#include <cstdint>

// ---------------------------------------------------------------------------
// Problem constants
// ---------------------------------------------------------------------------
constexpr int B_  = 4;
constexpr int S_  = 4096;
constexpr int D_  = 256;
constexpr int DH_ = 64;
constexpr int NL_ = 4;
constexpr int PM_ = 266;          // nb_features
constexpr int PMP_ = 288;         // padded for mma
constexpr int FF_ = 1024;
constexpr int BS_ = B_ * S_;      // 16384 rows
constexpr int BH_ = B_ * 4;       // 16

constexpr float DN_    = 0.35355339059327373f;  // 64^-0.25
constexpr float HDN2_  = 0.0625f;               // 0.5 * dn^2
constexpr float RATIO_ = 0.06131392f;           // 266^-0.5
constexpr float KEPS_  = 1e-4f;
constexpr float LNEPS_ = 1e-12f;

// ---------------------------------------------------------------------------
// Scratch (static device globals)
// ---------------------------------------------------------------------------
__device__ float g_x  [BS_ * D_];
__device__ float g_h  [BS_ * D_];     // pooling tanh output (fp32)
__device__ float g_score[BS_];
__device__ float g_ssum [B_];
__device__ unsigned g_kmaxu;

// bf16 hi/lo operand buffers
constexpr size_t OFF_QKV = 0;
constexpr size_t OFF_WO  = OFF_QKV + (size_t)NL_ * 768 * 256;
constexpr size_t OFF_W1  = OFF_WO  + (size_t)NL_ * 256 * 256;
constexpr size_t OFF_W2  = OFF_W1  + (size_t)NL_ * 1024 * 256;
constexpr size_t OFF_P1  = OFF_W2  + (size_t)NL_ * 256 * 1024;
constexpr size_t WT_TOT  = OFF_P1 + 256 * 256;

__device__ __nv_bfloat16 g_wth[WT_TOT], g_wtl[WT_TOT];
__device__ float g_bqkv[NL_ * 768];
__device__ __nv_bfloat16 g_hh[BS_ * D_], g_hl[BS_ * D_];      // LN outputs (ln1 hi/lo; ln2 hh only)
__device__ __nv_bfloat16 g_oh[BS_ * D_];                      // attnout (single bf16)
__device__ __nv_bfloat16 g_fh[(size_t)BS_ * FF_];             // gelu (single bf16)
__device__ __nv_bfloat16 g_xh[BS_ * D_], g_xl[BS_ * D_];      // residual (pooling)
__device__ __nv_bfloat16 g_qh[BS_ * D_], g_ql[BS_ * D_];      // q hi/lo
__device__ __nv_bfloat16 g_kh[BS_ * D_], g_kl[BS_ * D_];      // k hi/lo
__device__ __nv_bfloat16 g_vh[BS_ * D_];                      // v (single bf16)
__device__ __nv_bfloat16 g_pjh[NL_ * PMP_ * DH_], g_pjl[NL_ * PMP_ * DH_];

// FAVOR intermediates (single bf16)
__device__ __nv_bfloat16 g_qph[(size_t)BH_ * S_ * PMP_];
__device__ __nv_bfloat16 g_eh [(size_t)BH_ * S_ * PMP_];
__device__ float g_ctxE[BH_ * PMP_ * 72];
__device__ __nv_bfloat16 g_cbh[BH_ * PMP_ * 80];              // ctx_b (single bf16)

// ---------------------------------------------------------------------------
// PTX helpers (family-portable: no tcgen05 on compute_103 targets)
// ---------------------------------------------------------------------------
__device__ __forceinline__ uint32_t smem_u32(const void* p) {
    uint32_t a;
    asm("{ .reg .u64 t; cvta.to.shared.u64 t, %1; cvt.u32.u64 %0, t; }" : "=r"(a) : "l"(p));
    return a;
}
__device__ __forceinline__ void ldsm4(unsigned& r0, unsigned& r1, unsigned& r2, unsigned& r3,
                                      uint32_t addr) {
    asm volatile("ldmatrix.sync.aligned.m8n8.x4.shared.b16 {%0,%1,%2,%3}, [%4];"
                 : "=r"(r0), "=r"(r1), "=r"(r2), "=r"(r3) : "r"(addr));
}
__device__ __forceinline__ void ldsm4t(unsigned& r0, unsigned& r1, unsigned& r2, unsigned& r3,
                                       uint32_t addr) {
    asm volatile("ldmatrix.sync.aligned.m8n8.x4.trans.shared.b16 {%0,%1,%2,%3}, [%4];"
                 : "=r"(r0), "=r"(r1), "=r"(r2), "=r"(r3) : "r"(addr));
}
__device__ __forceinline__ void mma_bf16(float* d, const unsigned* a, const unsigned* b) {
    asm volatile("mma.sync.aligned.m16n8k16.row.col.f32.bf16.bf16.f32 "
                 "{%0,%1,%2,%3}, {%4,%5,%6,%7}, {%8,%9}, {%0,%1,%2,%3};"
                 : "+f"(d[0]), "+f"(d[1]), "+f"(d[2]), "+f"(d[3])
                 : "r"(a[0]), "r"(a[1]), "r"(a[2]), "r"(a[3]), "r"(b[0]), "r"(b[1]));
}
#define CP_ASYNC16(dst, src) \
    asm volatile("cp.async.cg.shared.global [%0], [%1], 16;" :: "r"(dst), "l"(src) : "memory")
#define CP_COMMIT() asm volatile("cp.async.commit_group;" ::: "memory")
#define CP_WAIT(n)  asm volatile("cp.async.wait_group %0;" :: "n"(n) : "memory")

__device__ __forceinline__ void bf16_split(float v, __nv_bfloat16& hi, __nv_bfloat16& lo) {
    hi = __float2bfloat16(v);
    lo = __float2bfloat16(v - __bfloat162float(hi));
}
__device__ __forceinline__ float tanh_ap(float x) {
    float r;
    asm("tanh.approx.f32 %0, %1;" : "=f"(r) : "f"(x));
    return r;
}

// ---------------------------------------------------------------------------
// Reductions
// ---------------------------------------------------------------------------
__device__ __forceinline__ float warpsum(float v) {
#pragma unroll
    for (int o = 16; o > 0; o >>= 1) v += __shfl_xor_sync(0xffffffffu, v, o);
    return v;
}
__device__ __forceinline__ float block_sum(float v, float* sh) {
    int lane = threadIdx.x & 31, w = threadIdx.x >> 5, nw = blockDim.x >> 5;
    v = warpsum(v);
    if (lane == 0) sh[w] = v;
    __syncthreads();
    if (w == 0) {
        float x = (lane < nw) ? sh[lane] : 0.f;
        x = warpsum(x);
        if (lane == 0) sh[0] = x;
    }
    __syncthreads();
    float r = sh[0];
    __syncthreads();
    return r;
}
__device__ __forceinline__ unsigned fmap(float f) {
    unsigned u = __float_as_uint(f);
    return (u & 0x80000000u) ? ~u : (u | 0x80000000u);
}
__device__ __forceinline__ float funmap(unsigned u) {
    u = (u & 0x80000000u) ? (u & 0x7FFFFFFFu) : ~u;
    return __uint_as_float(u);
}

// ---------------------------------------------------------------------------
// Weight transpose + bf16 split: W [K,N] fp32 -> Th/Tl [N,K] bf16; z = layer
// ---------------------------------------------------------------------------
__global__ void wsplit_kernel(const float* __restrict__ W, __nv_bfloat16* __restrict__ Th,
                              __nv_bfloat16* __restrict__ Tl, int K, int N, int rowOff,
                              size_t sstride, size_t dstride) {
    __shared__ float ts[32][33];
    int l = blockIdx.z;
    W  += (size_t)l * sstride;
    Th += (size_t)l * dstride;
    Tl += (size_t)l * dstride;
    int kb = blockIdx.y * 32, nb = blockIdx.x * 32;
    int tx = threadIdx.x, ty = threadIdx.y;
#pragma unroll
    for (int i = 0; i < 4; i++) {
        int k = kb + ty + i * 8;
        ts[ty + i * 8][tx] = W[(size_t)k * N + nb + tx];
    }
    __syncthreads();
#pragma unroll
    for (int i = 0; i < 4; i++) {
        int n = nb + ty + i * 8;
        int k = kb + tx;
        float v = ts[tx][ty + i * 8];
        __nv_bfloat16 hi, lo;
        bf16_split(v, hi, lo);
        size_t idx = (size_t)(rowOff + n) * K + k;
        Th[idx] = hi; Tl[idx] = lo;
    }
}

__global__ void bconcat_kernel(const float* __restrict__ bq, const float* __restrict__ bk,
                               const float* __restrict__ bv, float* __restrict__ dst) {
    int l = blockIdx.x, t = threadIdx.x;
    dst[l * 768 + t]       = bq[l * 256 + t];
    dst[l * 768 + 256 + t] = bk[l * 256 + t];
    dst[l * 768 + 512 + t] = bv[l * 256 + t];
}

__global__ void psplit_kernel(const float* __restrict__ proj,
                              __nv_bfloat16* __restrict__ ph, __nv_bfloat16* __restrict__ pl) {
    int idx = blockIdx.x * 256 + threadIdx.x;
    int l = idx / (PMP_ * DH_);
    int rem = idx - l * (PMP_ * DH_);
    int r = rem >> 6, c = rem & 63;
    float v = (r < PM_) ? proj[((size_t)l * PM_ + r) * DH_ + c] : 0.f;
    __nv_bfloat16 hi, lo;
    bf16_split(v, hi, lo);
    ph[idx] = hi; pl[idx] = lo;
}

// ---------------------------------------------------------------------------
// LayerNorm — warp-per-row
// ---------------------------------------------------------------------------
__global__ __launch_bounds__(256) void embed_ln_kernel(
    const float* __restrict__ emb, const float* __restrict__ pos,
    const float* __restrict__ g, const float* __restrict__ bb,
    float* __restrict__ out) {
    int warp = threadIdx.x >> 5, lane = threadIdx.x & 31;
    int row = blockIdx.x * 8 + warp;
    int c0 = lane * 8;
    const float* ep = emb + (size_t)row * D_ + c0;
    const float* pp = pos + (size_t)(row & (S_ - 1)) * D_ + c0;
    float v[8];
    float4 a0 = *(const float4*)ep, a1 = *(const float4*)(ep + 4);
    float4 p0 = *(const float4*)pp, p1 = *(const float4*)(pp + 4);
    v[0] = a0.x + p0.x; v[1] = a0.y + p0.y; v[2] = a0.z + p0.z; v[3] = a0.w + p0.w;
    v[4] = a1.x + p1.x; v[5] = a1.y + p1.y; v[6] = a1.z + p1.z; v[7] = a1.w + p1.w;
    float s = 0.f;
#pragma unroll
    for (int j = 0; j < 8; j++) s += v[j];
    float mu = warpsum(s) * (1.0f / D_);
    float s2 = 0.f;
#pragma unroll
    for (int j = 0; j < 8; j++) { float d = v[j] - mu; s2 = fmaf(d, d, s2); }
    float rs = rsqrtf(warpsum(s2) * (1.0f / D_) + LNEPS_);
    float4 g0 = *(const float4*)(g + c0), g1 = *(const float4*)(g + c0 + 4);
    float4 b0 = *(const float4*)(bb + c0), b1 = *(const float4*)(bb + c0 + 4);
    float gg[8] = {g0.x, g0.y, g0.z, g0.w, g1.x, g1.y, g1.z, g1.w};
    float bbv[8] = {b0.x, b0.y, b0.z, b0.w, b1.x, b1.y, b1.z, b1.w};
    float o[8];
#pragma unroll
    for (int j = 0; j < 8; j++) o[j] = (v[j] - mu) * rs * gg[j] + bbv[j];
    float* op = out + (size_t)row * D_ + c0;
    *(float4*)op       = make_float4(o[0], o[1], o[2], o[3]);
    *(float4*)(op + 4) = make_float4(o[4], o[5], o[6], o[7]);
}

template <bool LO>
__global__ __launch_bounds__(256) void ln_kernel(
    const float* __restrict__ in,
    __nv_bfloat16* __restrict__ oh, __nv_bfloat16* __restrict__ ol,
    const float* __restrict__ g, const float* __restrict__ bb) {
    int warp = threadIdx.x >> 5, lane = threadIdx.x & 31;
    int row = blockIdx.x * 8 + warp;
    int c0 = lane * 8;
    const float* rp = in + (size_t)row * D_ + c0;
    float4 a0 = *(const float4*)rp, a1 = *(const float4*)(rp + 4);
    float v[8] = {a0.x, a0.y, a0.z, a0.w, a1.x, a1.y, a1.z, a1.w};
    float s = 0.f;
#pragma unroll
    for (int j = 0; j < 8; j++) s += v[j];
    float mu = warpsum(s) * (1.0f / D_);
    float s2 = 0.f;
#pragma unroll
    for (int j = 0; j < 8; j++) { float d = v[j] - mu; s2 = fmaf(d, d, s2); }
    float rs = rsqrtf(warpsum(s2) * (1.0f / D_) + LNEPS_);
    float4 g0 = *(const float4*)(g + c0), g1 = *(const float4*)(g + c0 + 4);
    float4 b0 = *(const float4*)(bb + c0), b1 = *(const float4*)(bb + c0 + 4);
    float gg[8] = {g0.x, g0.y, g0.z, g0.w, g1.x, g1.y, g1.z, g1.w};
    float bbv[8] = {b0.x, b0.y, b0.z, b0.w, b1.x, b1.y, b1.z, b1.w};
    size_t base = (size_t)row * D_ + c0;
#pragma unroll
    for (int j2 = 0; j2 < 4; j2++) {
        float x0 = (v[2 * j2] - mu) * rs * gg[2 * j2] + bbv[2 * j2];
        float x1 = (v[2 * j2 + 1] - mu) * rs * gg[2 * j2 + 1] + bbv[2 * j2 + 1];
        if (LO) {
            __nv_bfloat16 h0, l0, h1, l1;
            bf16_split(x0, h0, l0);
            bf16_split(x1, h1, l1);
            *(__nv_bfloat162*)(oh + base + 2 * j2) = __nv_bfloat162(h0, h1);
            *(__nv_bfloat162*)(ol + base + 2 * j2) = __nv_bfloat162(l0, l1);
        } else {
            *(__nv_bfloat162*)(oh + base + 2 * j2) =
                __nv_bfloat162(__float2bfloat16(x0), __float2bfloat16(x1));
        }
    }
}

// ---------------------------------------------------------------------------
// mma.sync bf16 GEMM (dense): C = A @ Bt^T (+bias +epilogue)
// ALO: A has a lo array (3-term split); else single-bf16 A (2-term).
// MODE: 0 = QKV (q->Oh/Ol, k->Oh2/Ol2, v->Oh3 single);
//       1 = GELU->Oh (single); 2 = residual accumulate into O0 (+Oh/Ol if EMIT);
//       3 = tanh->O0
// ---------------------------------------------------------------------------
constexpr int ROWB    = 80;
constexpr int ARR_B   = 128 * ROWB;
constexpr int STAGE_B = 4 * ARR_B;
constexpr int MM_SMEM = 2 * STAGE_B;     // 81920

template <bool ALO>
__device__ __forceinline__ void stage_cp(uint32_t sbase,
    const __nv_bfloat16* __restrict__ Ah, const __nv_bfloat16* __restrict__ Al,
    const __nv_bfloat16* __restrict__ Bh, const __nv_bfloat16* __restrict__ Bl,
    int row0, int col0, int K, int k0, int tid) {
#pragma unroll
    for (int i = 0; i < 8; i++) {
        const int arr = i >> 1;
        if (!ALO && arr == 1) continue;
        int cc = tid + (i & 1) * 256;
        int row = cc >> 2, kc = cc & 3;
        const __nv_bfloat16* src;
        int gr;
        if (arr == 0)      { src = Ah; gr = row0 + row; }
        else if (arr == 1) { src = Al; gr = row0 + row; }
        else if (arr == 2) { src = Bh; gr = col0 + row; }
        else               { src = Bl; gr = col0 + row; }
        uint32_t dst = sbase + arr * ARR_B + row * ROWB + kc * 16;
        CP_ASYNC16(dst, src + (size_t)gr * K + k0 + kc * 8);
    }
}

template <int MODE, bool EMIT, bool ALO>
__global__ __launch_bounds__(256) void mm_gemm(
    const __nv_bfloat16* __restrict__ Ah, const __nv_bfloat16* __restrict__ Al,
    const __nv_bfloat16* __restrict__ Bth, const __nv_bfloat16* __restrict__ Btl,
    const float* __restrict__ bias,
    float* __restrict__ O0,
    __nv_bfloat16* __restrict__ Oh, __nv_bfloat16* __restrict__ Ol,
    __nv_bfloat16* __restrict__ Oh2, __nv_bfloat16* __restrict__ Ol2,
    __nv_bfloat16* __restrict__ Oh3,
    int K, int N) {
    extern __shared__ char smem[];
    uint32_t sb = smem_u32(smem);
    int tid = threadIdx.x, lane = tid & 31, warp = tid >> 5;
    int row0 = blockIdx.y * 128, col0 = blockIdx.x * 128;
    int wm = (warp >> 1) * 32, wn = (warp & 1) * 64;

    float acc[2][8][4] = {};

    int NT = K >> 5;
    stage_cp<ALO>(sb, Ah, Al, Bth, Btl, row0, col0, K, 0, tid);
    CP_COMMIT();
    if (NT > 1) {
        stage_cp<ALO>(sb + STAGE_B, Ah, Al, Bth, Btl, row0, col0, K, 32, tid);
        CP_COMMIT();
    }

    uint32_t aoff = (uint32_t)((wm + (lane & 15)) * ROWB + (lane >> 4) * 16);
    uint32_t boff = (uint32_t)((wn + ((lane >> 4) << 3) + (lane & 7)) * ROWB +
                               ((lane >> 3) & 1) * 16);

    for (int t = 0; t < NT; t++) {
        if (t + 1 < NT) CP_WAIT(1); else CP_WAIT(0);
        __syncthreads();
        uint32_t bs = sb + (t & 1) * STAGE_B;
#pragma unroll
        for (int kt = 0; kt < 2; kt++) {
            unsigned ah[2][4], al[2][4], bh[8][2], bl[8][2];
#pragma unroll
            for (int mt = 0; mt < 2; mt++) {
                uint32_t a = bs + aoff + mt * (16 * ROWB) + kt * 32;
                ldsm4(ah[mt][0], ah[mt][1], ah[mt][2], ah[mt][3], a);
                if (ALO) ldsm4(al[mt][0], al[mt][1], al[mt][2], al[mt][3], a + ARR_B);
            }
#pragma unroll
            for (int n2 = 0; n2 < 4; n2++) {
                uint32_t a = bs + 2 * ARR_B + boff + n2 * (16 * ROWB) + kt * 32;
                ldsm4(bh[2 * n2][0], bh[2 * n2][1], bh[2 * n2 + 1][0], bh[2 * n2 + 1][1], a);
                ldsm4(bl[2 * n2][0], bl[2 * n2][1], bl[2 * n2 + 1][0], bl[2 * n2 + 1][1],
                      a + ARR_B);
            }
#pragma unroll
            for (int mt = 0; mt < 2; mt++)
#pragma unroll
                for (int nt = 0; nt < 8; nt++) {
                    mma_bf16(acc[mt][nt], ah[mt], bh[nt]);
                    mma_bf16(acc[mt][nt], ah[mt], bl[nt]);
                    if (ALO) mma_bf16(acc[mt][nt], al[mt], bh[nt]);
                }
        }
        __syncthreads();
        if (t + 2 < NT) {
            stage_cp<ALO>(sb + (t & 1) * STAGE_B, Ah, Al, Bth, Btl, row0, col0, K,
                          (t + 2) * 32, tid);
            CP_COMMIT();
        }
    }

#pragma unroll
    for (int mt = 0; mt < 2; mt++)
#pragma unroll
        for (int nt = 0; nt < 8; nt++) {
            int rbase = row0 + wm + mt * 16 + (lane >> 2);
            int cg = col0 + wn + nt * 8 + (lane & 3) * 2;
            float b0 = __ldg(&bias[cg]), b1 = __ldg(&bias[cg + 1]);
#pragma unroll
            for (int half = 0; half < 2; half++) {
                int row = rbase + half * 8;
                float v0 = acc[mt][nt][half * 2]     + b0;
                float v1 = acc[mt][nt][half * 2 + 1] + b1;
                if (MODE == 0) {
                    int which = cg >> 8, cl = cg & 255;
                    size_t idx = (size_t)row * 256 + cl;
                    if (which == 2) {
                        *(__nv_bfloat162*)(Oh3 + idx) =
                            __nv_bfloat162(__float2bfloat16(v0), __float2bfloat16(v1));
                    } else {
                        __nv_bfloat16* H = which ? Oh2 : Oh;
                        __nv_bfloat16* L = which ? Ol2 : Ol;
                        __nv_bfloat16 hi, lo;
                        bf16_split(v0, hi, lo); H[idx] = hi;     L[idx] = lo;
                        bf16_split(v1, hi, lo); H[idx + 1] = hi; L[idx + 1] = lo;
                    }
                } else if (MODE == 1) {
                    float u0 = 0.7978845608028654f * (v0 + 0.044715f * v0 * v0 * v0);
                    float u1 = 0.7978845608028654f * (v1 + 0.044715f * v1 * v1 * v1);
                    float g0 = 0.5f * v0 * (1.f + tanh_ap(u0));
                    float g1 = 0.5f * v1 * (1.f + tanh_ap(u1));
                    size_t idx = (size_t)row * N + cg;
                    *(__nv_bfloat162*)(Oh + idx) =
                        __nv_bfloat162(__float2bfloat16(g0), __float2bfloat16(g1));
                } else if (MODE == 2) {
                    size_t idx = (size_t)row * N + cg;
                    float n0 = O0[idx] + v0, n1 = O0[idx + 1] + v1;
                    O0[idx] = n0; O0[idx + 1] = n1;
                    if (EMIT) {
                        __nv_bfloat16 hi, lo;
                        bf16_split(n0, hi, lo); Oh[idx] = hi;     Ol[idx] = lo;
                        bf16_split(n1, hi, lo); Oh[idx + 1] = hi; Ol[idx + 1] = lo;
                    }
                } else {
                    size_t idx = (size_t)row * N + cg;
                    O0[idx]     = tanh_ap(v0);
                    O0[idx + 1] = tanh_ap(v1);
                }
            }
        }
}

// ---------------------------------------------------------------------------
// dash via mma -> single bf16 output [bh][s][288]
// Merged q/k launch: blockIdx.z == 0 -> fused q-phi (per-row stabilizer);
//                    blockIdx.z == 1 -> E = exp(dash - diag) + global max,
//                    with E[s][PM_] = 1.0 (ones-row => ctxE row PM_ = vsum).
// 64-row blocks (2 CTAs/SM).
// ---------------------------------------------------------------------------
constexpr int DRB = 144;
constexpr int DA_H = 0;
constexpr int DA_L = 64 * DRB;                  // 9216
constexpr int DB_H = 2 * 64 * DRB;              // 18432
constexpr int DB_L = DB_H + PMP_ * DRB;         // 59904
constexpr int D_SDIAG = DB_L + PMP_ * DRB;      // 101376
constexpr int D_SRMAX = D_SDIAG + 256;
constexpr int DASH_SMEM = D_SRMAX + 256;        // 101888

__global__ __launch_bounds__(256, 2) void dash_mma(
    const __nv_bfloat16* __restrict__ Qxh, const __nv_bfloat16* __restrict__ Qxl,
    const __nv_bfloat16* __restrict__ Kxh, const __nv_bfloat16* __restrict__ Kxl,
    const __nv_bfloat16* __restrict__ Ph, const __nv_bfloat16* __restrict__ Pl,
    __nv_bfloat16* __restrict__ qout, __nv_bfloat16* __restrict__ eout,
    unsigned* __restrict__ gmax) {
    extern __shared__ char smem[];
    uint32_t sb = smem_u32(smem);
    float* sdiag = (float*)(smem + D_SDIAG);
    unsigned* srmax = (unsigned*)(smem + D_SRMAX);
    int tid = threadIdx.x, lane = tid & 31, warp = tid >> 5;
    int bh = blockIdx.y, b = bh >> 2, h = bh & 3;
    int s0 = blockIdx.x * 64;
    bool qphi = (blockIdx.z == 0);
    const __nv_bfloat16* Xh = qphi ? Qxh : Kxh;
    const __nv_bfloat16* Xl = qphi ? Qxl : Kxl;
    __nv_bfloat16* outh = qphi ? qout : eout;

    for (int i = tid; i < 512; i += 256) {
        int r = i >> 3, c = i & 7;
        const __nv_bfloat16* s1 = Xh + ((size_t)(b * S_ + s0 + r)) * D_ + h * DH_ + c * 8;
        const __nv_bfloat16* s2 = Xl + ((size_t)(b * S_ + s0 + r)) * D_ + h * DH_ + c * 8;
        CP_ASYNC16(sb + DA_H + r * DRB + c * 16, s1);
        CP_ASYNC16(sb + DA_L + r * DRB + c * 16, s2);
    }
    for (int i = tid; i < PMP_ * 8; i += 256) {
        int r = i >> 3, c = i & 7;
        CP_ASYNC16(sb + DB_H + r * DRB + c * 16, Ph + (size_t)r * DH_ + c * 8);
        CP_ASYNC16(sb + DB_L + r * DRB + c * 16, Pl + (size_t)r * DH_ + c * 8);
    }
    CP_COMMIT(); CP_WAIT(0);
    __syncthreads();

    if (tid < 64) {
        const __nv_bfloat16* ah = (const __nv_bfloat16*)(smem + DA_H + tid * DRB);
        const __nv_bfloat16* al = (const __nv_bfloat16*)(smem + DA_L + tid * DRB);
        float s = 0.f;
#pragma unroll
        for (int c = 0; c < DH_; c++) {
            float v = __bfloat162float(ah[c]) + __bfloat162float(al[c]);
            s = fmaf(v, v, s);
        }
        sdiag[tid] = HDN2_ * s;
        srmax[tid] = 0u;
    }
    __syncthreads();

    int wm = (warp >> 1) * 16, wn = (warp & 1) * 144;
    float acc[18][4] = {};
    uint32_t aoff = (uint32_t)((wm + (lane & 15)) * DRB + (lane >> 4) * 16);
    uint32_t boff = (uint32_t)((wn + ((lane >> 4) << 3) + (lane & 7)) * DRB +
                               ((lane >> 3) & 1) * 16);

#pragma unroll
    for (int kt = 0; kt < 4; kt++) {
        unsigned ah[4], al[4];
        {
            uint32_t a = sb + DA_H + aoff + kt * 32;
            ldsm4(ah[0], ah[1], ah[2], ah[3], a);
            ldsm4(al[0], al[1], al[2], al[3], a + (DA_L - DA_H));
        }
#pragma unroll
        for (int n2 = 0; n2 < 9; n2++) {
            unsigned bhf[2][2], blf[2][2];
            uint32_t a = sb + DB_H + boff + n2 * (16 * DRB) + kt * 32;
            ldsm4(bhf[0][0], bhf[0][1], bhf[1][0], bhf[1][1], a);
            ldsm4(blf[0][0], blf[0][1], blf[1][0], blf[1][1], a + (DB_L - DB_H));
#pragma unroll
            for (int j = 0; j < 2; j++) {
                int nt = n2 * 2 + j;
                mma_bf16(acc[nt], ah, bhf[j]);
                mma_bf16(acc[nt], ah, blf[j]);
                mma_bf16(acc[nt], al, bhf[j]);
            }
        }
    }

    // per-row max of raw dash (valid cols only)
#pragma unroll
    for (int half = 0; half < 2; half++) {
        float p = -3.4e38f;
#pragma unroll
        for (int nt = 0; nt < 18; nt++)
#pragma unroll
            for (int e = 0; e < 2; e++) {
                int col = wn + nt * 8 + (lane & 3) * 2 + e;
                if (col < PM_) p = fmaxf(p, DN_ * acc[nt][half * 2 + e]);
            }
        p = fmaxf(p, __shfl_xor_sync(0xffffffffu, p, 1));
        p = fmaxf(p, __shfl_xor_sync(0xffffffffu, p, 2));
        if ((lane & 3) == 0)
            atomicMax(&srmax[wm + (lane >> 2) + half * 8], fmap(p));
    }
    __syncthreads();

    if (!qphi && tid == 0) {
        unsigned m = 0u;
#pragma unroll 4
        for (int i = 0; i < 64; i++) m = max(m, srmax[i]);
        atomicMax(gmax, m);
    }

#pragma unroll
    for (int half = 0; half < 2; half++) {
        int r = wm + (lane >> 2) + half * 8;
        size_t rowbase = ((size_t)bh * S_ + s0 + r) * PMP_;
        float sub = qphi ? (sdiag[r] + funmap(srmax[r])) : sdiag[r];
#pragma unroll
        for (int nt = 0; nt < 18; nt++) {
            int colb = wn + nt * 8 + (lane & 3) * 2;
            float o[2];
#pragma unroll
            for (int e = 0; e < 2; e++) {
                int col = colb + e;
                float val = 0.f;
                if (col < PM_) {
                    float dv = DN_ * acc[nt][half * 2 + e];
                    val = qphi ? RATIO_ * (__expf(dv - sub) + KEPS_)
                               : __expf(dv - sub);
                } else if (!qphi && col == PM_) {
                    val = 1.0f;   // ones-row: ctxE[PM_][e] = vsum[e]
                }
                o[e] = val;
            }
            *(__nv_bfloat162*)(outh + rowbase + colb) =
                __nv_bfloat162(__float2bfloat16(o[0]), __float2bfloat16(o[1]));
        }
    }
}

// ---------------------------------------------------------------------------
// ctx via mma: ctxE[bh][m][e] = sum_s E[s][m] * Vx[s][e], Vx col 64 = 1 (ksum);
// E row PM_ = 1 (vsum). E single bf16, V single bf16 (1-term); split-K x16
// ---------------------------------------------------------------------------
constexpr int CE_ST = 592;
constexpr int CV_ST = 160;
constexpr int C_EH = 0;
constexpr int C_VH = 32 * CE_ST;              // 18944
constexpr int CSTAGE = C_VH + 32 * CV_ST;     // 24064
constexpr int CTX_SMEM = 2 * CSTAGE;          // 48128

__global__ __launch_bounds__(256) void ctx_mma(
    const __nv_bfloat16* __restrict__ Eh,
    const __nv_bfloat16* __restrict__ Vh,
    float* __restrict__ ctxE) {
    extern __shared__ char smem[];
    uint32_t sb = smem_u32(smem);
    int tid = threadIdx.x, lane = tid & 31, warp = tid >> 5;
    int bh = blockIdx.x, b = bh >> 2, h = bh & 3;
    int sbase = blockIdx.y * 256;

    auto stage = [&](int buf, int chunk) {
        uint32_t base = sb + buf * CSTAGE;
        int s0 = sbase + chunk * 32;
        for (int i = tid; i < 1152; i += 256) {
            int r = i / 36, c = i - r * 36;
            size_t g = ((size_t)bh * S_ + s0 + r) * PMP_ + c * 8;
            CP_ASYNC16(base + C_EH + r * CE_ST + c * 16, Eh + g);
        }
        {
            int i = tid;
            if (i < 256) {
                int r = i >> 3, c = i & 7;
                size_t g = ((size_t)(b * S_ + s0 + r)) * D_ + h * DH_ + c * 8;
                CP_ASYNC16(base + C_VH + r * CV_ST + c * 16, Vh + g);
            }
        }
        if (tid < 64) {
            int r = tid >> 1, half2 = tid & 1;
            uint4 z = make_uint4(0, 0, 0, 0);
            uint4 one = make_uint4(0x00003F80u, 0, 0, 0);
            uint32_t off = (uint32_t)(r * CV_ST + 128 + half2 * 16);
            *(uint4*)(smem + buf * CSTAGE + C_VH + off) = (half2 == 0) ? one : z;
        }
    };

    stage(0, 0); CP_COMMIT();
    stage(1, 1); CP_COMMIT();

    int mts[3];
    mts[0] = warp * 2; mts[1] = warp * 2 + 1; mts[2] = (warp < 2) ? 16 + warp : -1;
    float acc[3][9][4] = {};

    for (int t = 0; t < 8; t++) {
        if (t + 1 < 8) CP_WAIT(1); else CP_WAIT(0);
        __syncthreads();
        uint32_t bs = sb + (t & 1) * CSTAGE;
#pragma unroll
        for (int kt = 0; kt < 2; kt++) {
            int krA = (lane & 7) + ((lane >> 4) & 1) * 8 + kt * 16;
            int mcolbit = ((lane >> 3) & 1) * 8;
            unsigned ah[3][4];
#pragma unroll
            for (int mt = 0; mt < 3; mt++) {
                if (mts[mt] < 0) break;
                uint32_t a = bs + C_EH + krA * CE_ST + (mts[mt] * 16 + mcolbit) * 2;
                ldsm4t(ah[mt][0], ah[mt][1], ah[mt][2], ah[mt][3], a);
            }
            int krB = (lane & 7) + ((lane >> 3) & 1) * 8 + kt * 16;
            int ncolbit = (lane >> 4) * 8;
#pragma unroll
            for (int p = 0; p < 5; p++) {
                unsigned bhf[4];
                uint32_t a = bs + C_VH + krB * CV_ST + (p * 16 + ncolbit) * 2;
                ldsm4t(bhf[0], bhf[1], bhf[2], bhf[3], a);
#pragma unroll
                for (int j = 0; j < 2; j++) {
                    int nt = p * 2 + j;
                    if (nt > 8) break;
#pragma unroll
                    for (int mt = 0; mt < 3; mt++) {
                        if (mts[mt] < 0) break;
                        mma_bf16(acc[mt][nt], ah[mt], bhf + j * 2);
                    }
                }
            }
        }
        __syncthreads();
        if (t + 2 < 8) { stage(t & 1, t + 2); CP_COMMIT(); }
    }

#pragma unroll
    for (int mt = 0; mt < 3; mt++) {
        if (mts[mt] < 0) break;
#pragma unroll
        for (int nt = 0; nt < 9; nt++)
#pragma unroll
            for (int half = 0; half < 2; half++) {
                int m = mts[mt] * 16 + (lane >> 2) + half * 8;
                int e = nt * 8 + (lane & 3) * 2;
                float* dst = ctxE + ((size_t)bh * PMP_ + m) * 72 + e;
                atomicAdd(dst,     acc[mt][nt][half * 2]);
                atomicAdd(dst + 1, acc[mt][nt][half * 2 + 1]);
            }
    }
}

// ctx_b = a*ctxE + correction; single bf16 [bh][288][80]; vsum = ctxE row PM_
__global__ void ctxcorr_kernel(const float* __restrict__ ctxE,
                               const unsigned* __restrict__ gmax,
                               __nv_bfloat16* __restrict__ cbh) {
    int idx = blockIdx.x * 256 + threadIdx.x;
    if (idx >= BH_ * PMP_ * 80) return;
    int bh = idx / (PMP_ * 80);
    int rem = idx - bh * (PMP_ * 80);
    int m = rem / 80, e = rem - m * 80;
    float a = RATIO_ * __expf(-funmap(*gmax));
    float c = RATIO_ * KEPS_;
    float val = 0.f;
    if (m < PM_ && e < 72) {
        float base = ctxE[((size_t)bh * PMP_ + m) * 72 + e];
        float corr;
        if (e < 64)       corr = c * ctxE[((size_t)bh * PMP_ + PM_) * 72 + e];  // vsum
        else if (e == 64) corr = c * (float)S_;
        else              corr = 0.f;
        val = a * base + corr;
    }
    cbh[idx] = __float2bfloat16(val);
}

// ---------------------------------------------------------------------------
// attnout via mma: O[s][e] = (qp[s]·ctx_b[:,e]) / (qp[s]·ksum)  -> oh (single)
// Q single, Cb single (1-term)
// ---------------------------------------------------------------------------
constexpr int AQ_ST = 80;
constexpr int AB_ST = 160;
constexpr int A_QH = 0;
constexpr int A_BH2 = 128 * AQ_ST;            // 10240
constexpr int ASTAGE = A_BH2 + 32 * AB_ST;    // 15360
constexpr int A_SDEN = 2 * ASTAGE;            // 30720
constexpr int ATT_SMEM = A_SDEN + 512;        // 31232

__global__ __launch_bounds__(256) void attnout_mma(
    const __nv_bfloat16* __restrict__ Qh,
    const __nv_bfloat16* __restrict__ Cbh,
    __nv_bfloat16* __restrict__ oh) {
    extern __shared__ char smem[];
    uint32_t sb = smem_u32(smem);
    float* sden = (float*)(smem + A_SDEN);
    int tid = threadIdx.x, lane = tid & 31, warp = tid >> 5;
    int bh = blockIdx.y, b = bh >> 2, h = bh & 3;
    int s0 = blockIdx.x * 128;

    auto stage = [&](int buf, int chunk) {
        uint32_t base = sb + buf * ASTAGE;
        int k0 = chunk * 32;
        for (int i = tid; i < 512; i += 256) {
            int r = i >> 2, c = i & 3;
            size_t g = ((size_t)bh * S_ + s0 + r) * PMP_ + k0 + c * 8;
            CP_ASYNC16(base + A_QH + r * AQ_ST + c * 16, Qh + g);
        }
        for (int i = tid; i < 320; i += 256) {
            int r = i / 10, c = i - r * 10;
            size_t g = ((size_t)bh * PMP_ + k0 + r) * 80 + c * 8;
            CP_ASYNC16(base + A_BH2 + r * AB_ST + c * 16, Cbh + g);
        }
    };

    stage(0, 0); CP_COMMIT();
    stage(1, 1); CP_COMMIT();

    int wm = (warp >> 1) * 32, ng = warp & 1;
    float acc[2][5][4] = {};
    uint32_t aoff = (uint32_t)((wm + (lane & 15)) * AQ_ST + (lane >> 4) * 16);

    for (int t = 0; t < 9; t++) {
        if (t + 1 < 9) CP_WAIT(1); else CP_WAIT(0);
        __syncthreads();
        uint32_t bs = sb + (t & 1) * ASTAGE;
#pragma unroll
        for (int kt = 0; kt < 2; kt++) {
            unsigned ah[2][4];
#pragma unroll
            for (int mt = 0; mt < 2; mt++) {
                uint32_t a = bs + A_QH + aoff + mt * (16 * AQ_ST) + kt * 32;
                ldsm4(ah[mt][0], ah[mt][1], ah[mt][2], ah[mt][3], a);
            }
            int krB = (lane & 7) + ((lane >> 3) & 1) * 8 + kt * 16;
            int ncolbit = (lane >> 4) * 8;
#pragma unroll
            for (int pi = 0; pi < 3; pi++) {
                if (!ng && pi == 2) break;
                int p = ng ? (2 + pi) : pi;
                unsigned bhf[4];
                uint32_t a = bs + A_BH2 + krB * AB_ST + (p * 16 + ncolbit) * 2;
                ldsm4t(bhf[0], bhf[1], bhf[2], bhf[3], a);
#pragma unroll
                for (int j = 0; j < 2; j++) {
                    int ntg = p * 2 + j;
                    if (ntg > 8) break;
                    int ntl = ntg - ng * 4;
#pragma unroll
                    for (int mt = 0; mt < 2; mt++)
                        mma_bf16(acc[mt][ntl], ah[mt], bhf + j * 2);
                }
            }
        }
        __syncthreads();
        if (t + 2 < 9) { stage(t & 1, t + 2); CP_COMMIT(); }
    }

    if (ng == 1 && (lane & 3) == 0) {
#pragma unroll
        for (int mt = 0; mt < 2; mt++)
#pragma unroll
            for (int half = 0; half < 2; half++) {
                int r = wm + mt * 16 + (lane >> 2) + half * 8;
                sden[r] = acc[mt][4][half * 2];
            }
    }
    __syncthreads();

#pragma unroll
    for (int mt = 0; mt < 2; mt++)
#pragma unroll
        for (int half = 0; half < 2; half++) {
            int r = wm + mt * 16 + (lane >> 2) + half * 8;
            float rinv = 1.f / sden[r];
            size_t obase = ((size_t)(b * S_ + s0 + r)) * D_ + h * DH_;
#pragma unroll
            for (int ntl = 0; ntl < 4; ntl++) {
                int e = (ng * 4 + ntl) * 8 + (lane & 3) * 2;
                float v0 = acc[mt][ntl][half * 2]     * rinv;
                float v1 = acc[mt][ntl][half * 2 + 1] * rinv;
                *(__nv_bfloat162*)(oh + obase + e) =
                    __nv_bfloat162(__float2bfloat16(v0), __float2bfloat16(v1));
            }
        }
}

// ---------------------------------------------------------------------------
// Per-layer init
// ---------------------------------------------------------------------------
__global__ void layer_init_kernel(float* __restrict__ ctxE, unsigned* __restrict__ km) {
    int i = blockIdx.x * 256 + threadIdx.x;
    if (i < BH_ * PMP_ * 72) ctxE[i] = 0.f;
    if (i == 0) *km = 0u;
}

// ---------------------------------------------------------------------------
// Pooling
// ---------------------------------------------------------------------------
__global__ __launch_bounds__(256) void score_kernel(
    const float* __restrict__ h, const float* __restrict__ p2w,
    const float* __restrict__ p2b, const float* __restrict__ mask,
    float* __restrict__ score) {
    int warp = threadIdx.x >> 5, lane = threadIdx.x & 31;
    int row = blockIdx.x * 8 + warp;
    int c0 = lane * 8;
    const float* rp = h + (size_t)row * D_ + c0;
    float4 a0 = *(const float4*)rp, a1 = *(const float4*)(rp + 4);
    float4 w0 = *(const float4*)(p2w + c0), w1 = *(const float4*)(p2w + c0 + 4);
    float s = a0.x * w0.x + a0.y * w0.y + a0.z * w0.z + a0.w * w0.w +
              a1.x * w1.x + a1.y * w1.y + a1.z * w1.z + a1.w * w1.w;
    s = warpsum(s);
    if (lane == 0) score[row] = expf(s + p2b[0]) * mask[row];
}

__global__ void ssum_kernel(const float* __restrict__ score, float* __restrict__ ssum) {
    __shared__ float sh[8];
    int b = blockIdx.x;
    float s = 0.f;
    for (int i = threadIdx.x; i < S_; i += 256) s += score[b * S_ + i];
    s = block_sum(s, sh);
    if (threadIdx.x == 0) ssum[b] = s;
}

__global__ void outzero_kernel(float* __restrict__ out) {
    int i = blockIdx.x * blockDim.x + threadIdx.x;
    if (i < B_ * D_) out[i] = 0.f;
}

__global__ void pool_kernel(const float* __restrict__ x, const float* __restrict__ score,
                            const float* __restrict__ ssum, float* __restrict__ out) {
    int b = blockIdx.x, chunk = blockIdx.y, d = threadIdx.x;
    float inv = 1.f / (ssum[b] + 1e-8f);
    float acc = 0.f;
    int s0 = chunk * (S_ / 64);
    for (int s = s0; s < s0 + S_ / 64; s++)
        acc = fmaf(x[((size_t)(b * S_ + s)) * D_ + d], score[b * S_ + s], acc);
    atomicAdd(&out[b * D_ + d], acc * inv);
}

// ---------------------------------------------------------------------------
// Host launcher
// ---------------------------------------------------------------------------
extern "C" void kernel_launch(void* const* d_in, const int* in_sizes, int n_in,
                              void* d_out, int out_size) {
    const float* emb  = (const float*)d_in[0];
    const float* mask = (const float*)d_in[1];
    const float* pos  = (const float*)d_in[2];
    const float* ln_g = (const float*)d_in[3];
    const float* ln_b = (const float*)d_in[4];
    const float* proj = (const float*)d_in[5];
    const float* Wq = (const float*)d_in[6];   const float* bq = (const float*)d_in[7];
    const float* Wk = (const float*)d_in[8];   const float* bk = (const float*)d_in[9];
    const float* Wv = (const float*)d_in[10];  const float* bv = (const float*)d_in[11];
    const float* Wo = (const float*)d_in[12];  const float* bo = (const float*)d_in[13];
    const float* ln1g = (const float*)d_in[14]; const float* ln1b = (const float*)d_in[15];
    const float* W1 = (const float*)d_in[16];  const float* b1 = (const float*)d_in[17];
    const float* W2 = (const float*)d_in[18];  const float* b2 = (const float*)d_in[19];
    const float* ln2g = (const float*)d_in[20]; const float* ln2b = (const float*)d_in[21];
    const float* p1w = (const float*)d_in[22]; const float* p1b = (const float*)d_in[23];
    const float* p2w = (const float*)d_in[24]; const float* p2b = (const float*)d_in[25];
    float* out = (float*)d_out;

    void* tp;
    float *x, *h, *sc, *ss, *bqkv, *ctxE;
    unsigned* km;
    __nv_bfloat16 *wth, *wtl, *hh, *hl, *oh, *fh, *xh, *xl;
    __nv_bfloat16 *qh, *ql, *kh, *kl, *vh, *pjh, *pjl;
    __nv_bfloat16 *qph, *eh, *cbh;
    cudaGetSymbolAddress(&tp, g_x);     x  = (float*)tp;
    cudaGetSymbolAddress(&tp, g_h);     h  = (float*)tp;
    cudaGetSymbolAddress(&tp, g_score); sc = (float*)tp;
    cudaGetSymbolAddress(&tp, g_ssum);  ss = (float*)tp;
    cudaGetSymbolAddress(&tp, g_kmaxu); km = (unsigned*)tp;
    cudaGetSymbolAddress(&tp, g_bqkv);  bqkv = (float*)tp;
    cudaGetSymbolAddress(&tp, g_ctxE);  ctxE = (float*)tp;
    cudaGetSymbolAddress(&tp, g_wth);   wth = (__nv_bfloat16*)tp;
    cudaGetSymbolAddress(&tp, g_wtl);   wtl = (__nv_bfloat16*)tp;
    cudaGetSymbolAddress(&tp, g_hh);    hh = (__nv_bfloat16*)tp;
    cudaGetSymbolAddress(&tp, g_hl);    hl = (__nv_bfloat16*)tp;
    cudaGetSymbolAddress(&tp, g_oh);    oh = (__nv_bfloat16*)tp;
    cudaGetSymbolAddress(&tp, g_fh);    fh = (__nv_bfloat16*)tp;
    cudaGetSymbolAddress(&tp, g_xh);    xh = (__nv_bfloat16*)tp;
    cudaGetSymbolAddress(&tp, g_xl);    xl = (__nv_bfloat16*)tp;
    cudaGetSymbolAddress(&tp, g_qh);    qh = (__nv_bfloat16*)tp;
    cudaGetSymbolAddress(&tp, g_ql);    ql = (__nv_bfloat16*)tp;
    cudaGetSymbolAddress(&tp, g_kh);    kh = (__nv_bfloat16*)tp;
    cudaGetSymbolAddress(&tp, g_kl);    kl = (__nv_bfloat16*)tp;
    cudaGetSymbolAddress(&tp, g_vh);    vh = (__nv_bfloat16*)tp;
    cudaGetSymbolAddress(&tp, g_pjh);   pjh = (__nv_bfloat16*)tp;
    cudaGetSymbolAddress(&tp, g_pjl);   pjl = (__nv_bfloat16*)tp;
    cudaGetSymbolAddress(&tp, g_qph);   qph = (__nv_bfloat16*)tp;
    cudaGetSymbolAddress(&tp, g_eh);    eh = (__nv_bfloat16*)tp;
    cudaGetSymbolAddress(&tp, g_cbh);   cbh = (__nv_bfloat16*)tp;

    static bool attr_done = false;
    if (!attr_done) {
        cudaFuncSetAttribute(mm_gemm<0, false, true>,  cudaFuncAttributeMaxDynamicSharedMemorySize, MM_SMEM);
        cudaFuncSetAttribute(mm_gemm<1, false, false>, cudaFuncAttributeMaxDynamicSharedMemorySize, MM_SMEM);
        cudaFuncSetAttribute(mm_gemm<2, false, false>, cudaFuncAttributeMaxDynamicSharedMemorySize, MM_SMEM);
        cudaFuncSetAttribute(mm_gemm<2, true, false>,  cudaFuncAttributeMaxDynamicSharedMemorySize, MM_SMEM);
        cudaFuncSetAttribute(mm_gemm<3, false, true>,  cudaFuncAttributeMaxDynamicSharedMemorySize, MM_SMEM);
        cudaFuncSetAttribute(dash_mma,    cudaFuncAttributeMaxDynamicSharedMemorySize, DASH_SMEM);
        cudaFuncSetAttribute(ctx_mma,     cudaFuncAttributeMaxDynamicSharedMemorySize, CTX_SMEM);
        cudaFuncSetAttribute(attnout_mma, cudaFuncAttributeMaxDynamicSharedMemorySize, ATT_SMEM);
        attr_done = true;
    }

    // --- weight prep (batched over layers via gridDim.z) ---
    dim3 wb(32, 8);
    wsplit_kernel<<<dim3(8, 8, NL_), wb>>>(Wq, wth + OFF_QKV, wtl + OFF_QKV,
                                           256, 256, 0,   65536, (size_t)768 * 256);
    wsplit_kernel<<<dim3(8, 8, NL_), wb>>>(Wk, wth + OFF_QKV, wtl + OFF_QKV,
                                           256, 256, 256, 65536, (size_t)768 * 256);
    wsplit_kernel<<<dim3(8, 8, NL_), wb>>>(Wv, wth + OFF_QKV, wtl + OFF_QKV,
                                           256, 256, 512, 65536, (size_t)768 * 256);
    wsplit_kernel<<<dim3(8, 8, NL_), wb>>>(Wo, wth + OFF_WO, wtl + OFF_WO,
                                           256, 256, 0, 65536, 65536);
    wsplit_kernel<<<dim3(32, 8, NL_), wb>>>(W1, wth + OFF_W1, wtl + OFF_W1,
                                            256, 1024, 0, 262144, 262144);
    wsplit_kernel<<<dim3(8, 32, NL_), wb>>>(W2, wth + OFF_W2, wtl + OFF_W2,
                                            1024, 256, 0, 262144, 262144);
    wsplit_kernel<<<dim3(8, 8, 1), wb>>>(p1w, wth + OFF_P1, wtl + OFF_P1,
                                         256, 256, 0, 0, 0);
    bconcat_kernel<<<NL_, 256>>>(bq, bk, bv, bqkv);
    psplit_kernel<<<(NL_ * PMP_ * DH_) / 256, 256>>>(proj, pjh, pjl);

    embed_ln_kernel<<<BS_ / 8, 256>>>(emb, pos, ln_g, ln_b, x);

    for (int l = 0; l < NL_; l++) {
        // --- attention block ---
        ln_kernel<true><<<BS_ / 8, 256>>>(x, hh, hl, ln1g + l * D_, ln1b + l * D_);
        mm_gemm<0, false, true><<<dim3(6, 128), 256, MM_SMEM>>>(
            hh, hl, wth + OFF_QKV + (size_t)l * 768 * 256, wtl + OFF_QKV + (size_t)l * 768 * 256,
            bqkv + l * 768, nullptr, qh, ql, kh, kl, vh, 256, 768);

        layer_init_kernel<<<(BH_ * PMP_ * 72 + 255) / 256, 256>>>(ctxE, km);

        dash_mma<<<dim3(S_ / 64, BH_, 2), 256, DASH_SMEM>>>(
            qh, ql, kh, kl,
            pjh + (size_t)l * PMP_ * DH_, pjl + (size_t)l * PMP_ * DH_,
            qph, eh, km);

        ctx_mma<<<dim3(BH_, 16), 256, CTX_SMEM>>>(eh, vh, ctxE);
        ctxcorr_kernel<<<(BH_ * PMP_ * 80 + 255) / 256, 256>>>(ctxE, km, cbh);
        attnout_mma<<<dim3(S_ / 128, BH_), 256, ATT_SMEM>>>(qph, cbh, oh);

        mm_gemm<2, false, false><<<dim3(2, 128), 256, MM_SMEM>>>(
            oh, nullptr, wth + OFF_WO + (size_t)l * 65536, wtl + OFF_WO + (size_t)l * 65536,
            bo + l * 256, x, nullptr, nullptr, nullptr, nullptr, nullptr, 256, 256);

        // --- FFN block ---
        ln_kernel<false><<<BS_ / 8, 256>>>(x, hh, nullptr, ln2g + l * D_, ln2b + l * D_);
        mm_gemm<1, false, false><<<dim3(8, 128), 256, MM_SMEM>>>(
            hh, nullptr, wth + OFF_W1 + (size_t)l * 262144, wtl + OFF_W1 + (size_t)l * 262144,
            b1 + l * 1024, nullptr, fh, nullptr, nullptr, nullptr, nullptr, 256, 1024);
        if (l == NL_ - 1) {
            mm_gemm<2, true, false><<<dim3(2, 128), 256, MM_SMEM>>>(
                fh, nullptr, wth + OFF_W2 + (size_t)l * 262144, wtl + OFF_W2 + (size_t)l * 262144,
                b2 + l * 256, x, xh, xl, nullptr, nullptr, nullptr, 1024, 256);
        } else {
            mm_gemm<2, false, false><<<dim3(2, 128), 256, MM_SMEM>>>(
                fh, nullptr, wth + OFF_W2 + (size_t)l * 262144, wtl + OFF_W2 + (size_t)l * 262144,
                b2 + l * 256, x, nullptr, nullptr, nullptr, nullptr, nullptr, 1024, 256);
        }
    }

    // --- attention pooling ---
    mm_gemm<3, false, true><<<dim3(2, 128), 256, MM_SMEM>>>(
        xh, xl, wth + OFF_P1, wtl + OFF_P1, p1b, h,
        nullptr, nullptr, nullptr, nullptr, nullptr, 256, 256);
    score_kernel<<<BS_ / 8, 256>>>(h, p2w, p2b, mask, sc);
    ssum_kernel<<<B_, 256>>>(sc, ss);
    outzero_kernel<<<(B_ * D_ + 255) / 256, 256>>>(out);
    pool_kernel<<<dim3(B_, 64), 256>>>(x, sc, ss, out);
}